// round 1
// baseline (speedup 1.0000x reference)
#include <cuda_runtime.h>
#include <math.h>

#define CDIV(a,b) (((a)+(b)-1)/(b))

// ---------------- static scratch (no allocations allowed) ----------------
__device__ float g_col1[737280 * 27];        // conv1 im2col
__device__ float g_wt1 [27 * 64];
__device__ float g_y1  [737280 * 64];        // conv1 out NHWC (B,40,72,64)
__device__ float g_p1  [184320 * 64];        // pool1 NHWC (B,20,36,64)
__device__ float g_col2[184320 * 576];       // conv2 im2col
__device__ float g_wt2 [576 * 64];
__device__ float g_y2  [184320 * 64];        // conv2 out NHWC (B,20,36,64)
__device__ float g_x   [46080 * 64];         // tokens / residual stream (B,180,64)
__device__ float g_h   [46080 * 64];         // LN output
__device__ float g_qkv [46080 * 2304];       // fused qkv
__device__ float g_ao  [46080 * 768];        // attention output (B,180,768)
__device__ float g_ff  [46080 * 256];        // MLP hidden
__device__ float g_col3[8192 * 576];         // pcaps im2col
__device__ float g_wtp [576 * 256];
__device__ float g_pc  [8192 * 256];         // pcaps out NHWC (B,4,8,256)
__device__ float g_caps[256 * 1024 * 8];
__device__ float g_u   [256 * 1024 * 48];

// ---------------- im2col kernels ----------------
__global__ void im2col1_k(const float* __restrict__ x, float* __restrict__ col) {
    long idx = (long)blockIdx.x * blockDim.x + threadIdx.x;
    const long total = (long)737280 * 27;
    if (idx >= total) return;
    int kk = (int)(idx % 27);
    long m = idx / 27;
    int ow = (int)(m % 72);
    int t  = (int)(m / 72);
    int oh = t % 40;
    int b  = t / 40;
    int kw = kk % 3, kh = (kk / 3) % 3, ci = kk / 9;
    int ih = oh + kh - 1, iw = ow + kw - 1;
    float v = 0.f;
    if (ih >= 0 && ih < 40 && iw >= 0 && iw < 72)
        v = x[(((long)b * 3 + ci) * 40 + ih) * 72 + iw];
    col[idx] = v;
}

__global__ void im2col2_k(const float* __restrict__ p1, float* __restrict__ col) {
    long idx = (long)blockIdx.x * blockDim.x + threadIdx.x;
    const long total = (long)184320 * 576;
    if (idx >= total) return;
    int kk = (int)(idx % 576);
    long m = idx / 576;
    int ow = (int)(m % 36);
    int t  = (int)(m / 36);
    int oh = t % 20;
    int b  = t / 20;
    int ci = kk % 64;
    int kw = (kk / 64) % 3;
    int kh = kk / 192;
    int ih = oh + kh - 1, iw = ow + kw - 1;
    float v = 0.f;
    if (ih >= 0 && ih < 20 && iw >= 0 && iw < 36)
        v = p1[(((long)b * 20 + ih) * 36 + iw) * 64 + ci];
    col[idx] = v;
}

// pcaps: input tokens g_x viewed as (B, 10, 18, 64); conv k3 s2 p0 -> (B,4,8,*)
__global__ void im2col3_k(const float* __restrict__ tk, float* __restrict__ col) {
    long idx = (long)blockIdx.x * blockDim.x + threadIdx.x;
    const long total = (long)8192 * 576;
    if (idx >= total) return;
    int kk = (int)(idx % 576);
    long m = idx / 576;
    int ow = (int)(m % 8);
    int t  = (int)(m / 8);
    int oh = t % 4;
    int b  = t / 4;
    int ci = kk % 64;
    int kw = (kk / 64) % 3;
    int kh = kk / 192;
    int ih = oh * 2 + kh, iw = ow * 2 + kw;
    col[idx] = tk[((long)b * 180 + ih * 18 + iw) * 64 + ci];
}

// ---------------- weight transposes ----------------
// conv1: k-index order (ci,kh,kw) == OIHW inner order
__global__ void wtrans_inner(const float* __restrict__ w, float* __restrict__ wt, int O, int K) {
    int i = blockIdx.x * blockDim.x + threadIdx.x;
    if (i >= O * K) return;
    int o = i / K, k = i % K;
    wt[k * O + o] = w[i];
}
// conv2/pcaps: k-index order (kh,kw,ci) to keep im2col reads coalesced
__global__ void wtrans_hwc(const float* __restrict__ w, float* __restrict__ wt, int O, int CI) {
    int K = CI * 9;
    int i = blockIdx.x * blockDim.x + threadIdx.x;
    if (i >= O * K) return;
    int o = i / K, r = i % K;
    int ci = r / 9, kh = (r % 9) / 3, kw = r % 3;
    wt[((kh * 3 + kw) * CI + ci) * O + o] = w[i];
}

// ---------------- generic tiled SGEMM ----------------
// C[M,N] = epilogue(A[M,K] @ B[K,N]); EPI: 0 none, 1 relu, 2 +bias, 3 +bias then gelu, 4 res + acc + bias
template <int EPI>
__global__ void __launch_bounds__(256) sgemm_k(const float* __restrict__ A, const float* __restrict__ Bm,
                                               const float* __restrict__ bias, const float* __restrict__ res,
                                               float* __restrict__ C, int M, int N, int K) {
    __shared__ float As[16][68];
    __shared__ float Bs[16][68];
    const int bm = blockIdx.y * 64, bn = blockIdx.x * 64;
    const int tid = threadIdx.x;
    const int tx = tid % 16, ty = tid / 16;
    const int acol = tid % 16, arow0 = tid / 16;
    const int bcol = tid % 64, brow0 = tid / 64;

    float acc[4][4];
#pragma unroll
    for (int i = 0; i < 4; i++)
#pragma unroll
        for (int j = 0; j < 4; j++) acc[i][j] = 0.f;

    for (int k0 = 0; k0 < K; k0 += 16) {
        __syncthreads();
#pragma unroll
        for (int i = 0; i < 4; i++) {
            int r = arow0 + 16 * i;
            int gm = bm + r, gk = k0 + acol;
            As[acol][r] = (gm < M && gk < K) ? A[(long)gm * K + gk] : 0.f;
        }
#pragma unroll
        for (int i = 0; i < 4; i++) {
            int kr = brow0 + 4 * i;
            int gk = k0 + kr, gn = bn + bcol;
            Bs[kr][bcol] = (gk < K && gn < N) ? Bm[(long)gk * N + gn] : 0.f;
        }
        __syncthreads();
#pragma unroll
        for (int k = 0; k < 16; k++) {
            float4 a4 = *(const float4*)&As[k][ty * 4];
            float4 b4 = *(const float4*)&Bs[k][tx * 4];
            float a[4] = {a4.x, a4.y, a4.z, a4.w};
            float b[4] = {b4.x, b4.y, b4.z, b4.w};
#pragma unroll
            for (int i = 0; i < 4; i++)
#pragma unroll
                for (int j = 0; j < 4; j++) acc[i][j] = fmaf(a[i], b[j], acc[i][j]);
        }
    }

#pragma unroll
    for (int i = 0; i < 4; i++) {
        int row = bm + ty * 4 + i;
        if (row >= M) continue;
#pragma unroll
        for (int j = 0; j < 4; j++) {
            int col = bn + tx * 4 + j;
            if (col >= N) continue;
            float v = acc[i][j];
            if (EPI == 1) v = fmaxf(v, 0.f);
            if (EPI == 2 || EPI == 3 || EPI == 4) v += bias[col];
            if (EPI == 3) v = 0.5f * v * (1.f + erff(v * 0.70710678118654752f));
            if (EPI == 4) v += res[(long)row * N + col];
            C[(long)row * N + col] = v;
        }
    }
}

// ---------------- maxpool 3x3 s2 p1 on NHWC (+ optional pos-emb add) ----------------
__global__ void maxpool_k(const float* __restrict__ in, float* __restrict__ out,
                          int Bn, int IH, int IW, int C, int OH, int OW,
                          const float* __restrict__ pos) {
    long idx = (long)blockIdx.x * blockDim.x + threadIdx.x;
    long total = (long)Bn * OH * OW * C;
    if (idx >= total) return;
    int c = (int)(idx % C);
    long r = idx / C;
    int ow = (int)(r % OW); r /= OW;
    int oh = (int)(r % OH);
    int b  = (int)(r / OH);
    float m = -1e30f;
#pragma unroll
    for (int kh = 0; kh < 3; kh++) {
        int ih = oh * 2 - 1 + kh;
        if (ih < 0 || ih >= IH) continue;
#pragma unroll
        for (int kw = 0; kw < 3; kw++) {
            int iw = ow * 2 - 1 + kw;
            if (iw < 0 || iw >= IW) continue;
            m = fmaxf(m, in[(((long)b * IH + ih) * IW + iw) * C + c]);
        }
    }
    if (pos) m += pos[(oh * OW + ow) * C + c];
    out[idx] = m;
}

// ---------------- LayerNorm over last dim (64), one warp per token ----------------
__global__ void ln64_k(const float* __restrict__ x, const float* __restrict__ g,
                       const float* __restrict__ bta, float* __restrict__ out, int ntok) {
    int warp = (blockIdx.x * blockDim.x + threadIdx.x) >> 5;
    int lane = threadIdx.x & 31;
    if (warp >= ntok) return;
    float v0 = x[(long)warp * 64 + lane];
    float v1 = x[(long)warp * 64 + 32 + lane];
    float s = v0 + v1;
#pragma unroll
    for (int o = 16; o; o >>= 1) s += __shfl_xor_sync(0xffffffffu, s, o);
    float mean = s * (1.f / 64.f);
    float d0 = v0 - mean, d1 = v1 - mean;
    float q = d0 * d0 + d1 * d1;
#pragma unroll
    for (int o = 16; o; o >>= 1) q += __shfl_xor_sync(0xffffffffu, q, o);
    float rstd = rsqrtf(q * (1.f / 64.f) + 1e-5f);
    out[(long)warp * 64 + lane]      = d0 * rstd * g[lane] + bta[lane];
    out[(long)warp * 64 + 32 + lane] = d1 * rstd * g[lane + 32] + bta[lane + 32];
}

// ---------------- fused attention: one block per (b, head) ----------------
// smem: q[180][64], kT[64][181], v[180][64], p[8 warps][4 rows][180]
#define ATTN_SMEM ((180 * 64 + 64 * 181 + 180 * 64 + 8 * 4 * 180) * 4)
__global__ void __launch_bounds__(256) attn_k(const float* __restrict__ qkv, float* __restrict__ out) {
    extern __shared__ float sm[];
    float* q_s = sm;
    float* kT  = sm + 180 * 64;
    float* v_s = kT + 64 * 181;
    float* p_s = v_s + 180 * 64;

    int b = blockIdx.x / 12, h = blockIdx.x % 12;
    int tid = threadIdx.x, lane = tid & 31, w = tid >> 5;

    const float* base = qkv + (long)b * 180 * 2304 + h * 64;
    for (int i = tid; i < 180 * 64; i += 256) {
        int n = i >> 6, d = i & 63;
        const float* src = base + (long)n * 2304 + d;
        q_s[i] = src[0];
        kT[d * 181 + n] = src[768];
        v_s[i] = src[1536];
    }
    __syncthreads();

    float* pw = p_s + w * 4 * 180;
    float* outbase = out + (long)b * 180 * 768 + h * 64;

    for (int n0 = w * 4; n0 < 180; n0 += 32) {
        float acc[4][6];
#pragma unroll
        for (int r = 0; r < 4; r++)
#pragma unroll
            for (int jj = 0; jj < 6; jj++) acc[r][jj] = 0.f;

        // scores = Q(4 rows) . K^T
        for (int d = 0; d < 64; d++) {
            float q0 = q_s[(n0 + 0) * 64 + d];
            float q1 = q_s[(n0 + 1) * 64 + d];
            float q2 = q_s[(n0 + 2) * 64 + d];
            float q3 = q_s[(n0 + 3) * 64 + d];
            const float* kr = &kT[d * 181];
#pragma unroll
            for (int jj = 0; jj < 6; jj++) {
                int j = lane + 32 * jj;
                float kv = (jj < 5 || j < 180) ? kr[j] : 0.f;
                acc[0][jj] = fmaf(q0, kv, acc[0][jj]);
                acc[1][jj] = fmaf(q1, kv, acc[1][jj]);
                acc[2][jj] = fmaf(q2, kv, acc[2][jj]);
                acc[3][jj] = fmaf(q3, kv, acc[3][jj]);
            }
        }
        // softmax per row (warp owns full row)
#pragma unroll
        for (int r = 0; r < 4; r++) {
            float mx = -1e30f;
#pragma unroll
            for (int jj = 0; jj < 6; jj++) {
                int j = lane + 32 * jj;
                float s = acc[r][jj] * 0.125f;
                if (j < 180 && s > mx) mx = s;
            }
#pragma unroll
            for (int o = 16; o; o >>= 1) mx = fmaxf(mx, __shfl_xor_sync(0xffffffffu, mx, o));
            float e[6];
            float sum = 0.f;
#pragma unroll
            for (int jj = 0; jj < 6; jj++) {
                int j = lane + 32 * jj;
                e[jj] = (j < 180) ? expf(acc[r][jj] * 0.125f - mx) : 0.f;
                sum += e[jj];
            }
#pragma unroll
            for (int o = 16; o; o >>= 1) sum += __shfl_xor_sync(0xffffffffu, sum, o);
            float inv = 1.f / sum;
#pragma unroll
            for (int jj = 0; jj < 6; jj++) {
                int j = lane + 32 * jj;
                if (j < 180) pw[r * 180 + j] = e[jj] * inv;
            }
        }
        __syncwarp();
        // O = P . V
        float o0[4] = {0, 0, 0, 0}, o1[4] = {0, 0, 0, 0};
        for (int j = 0; j < 180; j++) {
            float vv0 = v_s[j * 64 + lane];
            float vv1 = v_s[j * 64 + 32 + lane];
#pragma unroll
            for (int r = 0; r < 4; r++) {
                float p = pw[r * 180 + j];
                o0[r] = fmaf(p, vv0, o0[r]);
                o1[r] = fmaf(p, vv1, o1[r]);
            }
        }
#pragma unroll
        for (int r = 0; r < 4; r++) {
            outbase[(long)(n0 + r) * 768 + lane]      = o0[r];
            outbase[(long)(n0 + r) * 768 + 32 + lane] = o1[r];
        }
        __syncwarp();
    }
}

// ---------------- primary caps: gather + squash ----------------
__global__ void caps_squash_k(const float* __restrict__ pc, float* __restrict__ caps) {
    int idx = blockIdx.x * blockDim.x + threadIdx.x; // b*1024 + i
    if (idx >= 256 * 1024) return;
    int i = idx & 1023, b = idx >> 10;
    int i32 = i >> 5, y = (i >> 3) & 3, xq = i & 7;
    const float* src = pc + (((long)b * 4 + y) * 8 + xq) * 256 + i32 * 8;
    float t[8];
    float l2 = 0.f;
#pragma unroll
    for (int e = 0; e < 8; e++) { t[e] = src[e]; l2 += t[e] * t[e]; }
    float sc = sqrtf(l2) / (1.f + l2);
#pragma unroll
    for (int e = 0; e < 8; e++) caps[(long)idx * 8 + e] = t[e] * sc;
}

// ---------------- capsule predictions u[b,i,:] ----------------
__global__ void caps_u_k(const float* __restrict__ caps, const float* __restrict__ cw,
                         float* __restrict__ u) {
    __shared__ float w_s[8 * 48];
    int i = blockIdx.x;
    for (int t = threadIdx.x; t < 384; t += 256) w_s[t] = cw[(long)i * 384 + t];
    __syncthreads();
    int b = threadIdx.x;
    float ce[8];
    const float* cp = caps + ((long)b * 1024 + i) * 8;
#pragma unroll
    for (int e = 0; e < 8; e++) ce[e] = cp[e];
    float* up = u + ((long)b * 1024 + i) * 48;
#pragma unroll 4
    for (int o = 0; o < 48; o++) {
        float s = 0.f;
#pragma unroll
        for (int e = 0; e < 8; e++) s = fmaf(ce[e], w_s[e * 48 + o], s);
        up[o] = s;
    }
}

// ---------------- dynamic routing, one block per batch element ----------------
__global__ void __launch_bounds__(256) routing_k(const float* __restrict__ u,
                                                 const float* __restrict__ br,
                                                 float* __restrict__ out) {
    __shared__ float bb[1024 * 3];
    __shared__ float S[48];
    __shared__ float v[48];
    int b = blockIdx.x, tid = threadIdx.x, lane = tid & 31;
    for (int i = tid; i < 3072; i += 256) bb[i] = br[i];
    __syncthreads();
    const float* ub = u + (long)b * 1024 * 48;

    for (int it = 0; it < 4; it++) {
        if (tid < 48) S[tid] = 0.f;
        __syncthreads();
        float acc[48];
#pragma unroll
        for (int o = 0; o < 48; o++) acc[o] = 0.f;
        for (int i = tid; i < 1024; i += 256) {
            float b0 = bb[i * 3], b1 = bb[i * 3 + 1], b2 = bb[i * 3 + 2];
            float m = fmaxf(b0, fmaxf(b1, b2));
            float e0 = expf(b0 - m), e1 = expf(b1 - m), e2 = expf(b2 - m);
            float inv = 1.f / (e0 + e1 + e2);
            float c[3] = {e0 * inv, e1 * inv, e2 * inv};
            const float* up = ub + (long)i * 48;
#pragma unroll
            for (int j = 0; j < 3; j++)
#pragma unroll
                for (int o = 0; o < 16; o++)
                    acc[j * 16 + o] = fmaf(c[j], up[j * 16 + o], acc[j * 16 + o]);
        }
#pragma unroll
        for (int o = 0; o < 48; o++) {
            float s = acc[o];
#pragma unroll
            for (int d = 16; d; d >>= 1) s += __shfl_xor_sync(0xffffffffu, s, d);
            if (lane == 0) atomicAdd(&S[o], s);
        }
        __syncthreads();
        if (tid < 3) {
            float l2 = 0.f;
            for (int o = 0; o < 16; o++) { float t = S[tid * 16 + o]; l2 += t * t; }
            float sc = sqrtf(l2) / (1.f + l2);
            for (int o = 0; o < 16; o++) v[tid * 16 + o] = S[tid * 16 + o] * sc;
            if (it == 3) out[b * 3 + tid] = l2 / (1.f + l2);  // |v| = l2/(1+l2)
        }
        __syncthreads();
        if (it < 3) {
            for (int i = tid; i < 1024; i += 256) {
                const float* up = ub + (long)i * 48;
#pragma unroll
                for (int j = 0; j < 3; j++) {
                    float s = 0.f;
#pragma unroll
                    for (int o = 0; o < 16; o++) s = fmaf(up[j * 16 + o], v[j * 16 + o], s);
                    bb[i * 3 + j] += s;
                }
            }
            __syncthreads();
        }
    }
}

// ---------------- host ----------------
extern "C" void kernel_launch(void* const* d_in, const int* in_sizes, int n_in,
                              void* d_out, int out_size) {
    const float* x_in    = (const float*)d_in[0];
    const float* conv1_w = (const float*)d_in[1];
    const float* conv2_w = (const float*)d_in[2];
    const float* pos_emb = (const float*)d_in[3];
    const float* ln1_g   = (const float*)d_in[4];
    const float* ln1_b   = (const float*)d_in[5];
    const float* qkv_w   = (const float*)d_in[6];
    const float* out_w   = (const float*)d_in[7];
    const float* out_b   = (const float*)d_in[8];
    const float* ln2_g   = (const float*)d_in[9];
    const float* ln2_b   = (const float*)d_in[10];
    const float* ff1_w   = (const float*)d_in[11];
    const float* ff1_b   = (const float*)d_in[12];
    const float* ff2_w   = (const float*)d_in[13];
    const float* ff2_b   = (const float*)d_in[14];
    const float* pcaps_w = (const float*)d_in[15];
    const float* pcaps_b = (const float*)d_in[16];
    const float* caps_w  = (const float*)d_in[17];
    const float* b_route = (const float*)d_in[18];
    float* out = (float*)d_out;

    float *col1, *wt1, *y1, *p1, *col2, *wt2, *y2, *xb, *hb, *qkv, *ao, *ff, *col3, *wtp, *pc, *caps, *u;
    cudaGetSymbolAddress((void**)&col1, g_col1);
    cudaGetSymbolAddress((void**)&wt1,  g_wt1);
    cudaGetSymbolAddress((void**)&y1,   g_y1);
    cudaGetSymbolAddress((void**)&p1,   g_p1);
    cudaGetSymbolAddress((void**)&col2, g_col2);
    cudaGetSymbolAddress((void**)&wt2,  g_wt2);
    cudaGetSymbolAddress((void**)&y2,   g_y2);
    cudaGetSymbolAddress((void**)&xb,   g_x);
    cudaGetSymbolAddress((void**)&hb,   g_h);
    cudaGetSymbolAddress((void**)&qkv,  g_qkv);
    cudaGetSymbolAddress((void**)&ao,   g_ao);
    cudaGetSymbolAddress((void**)&ff,   g_ff);
    cudaGetSymbolAddress((void**)&col3, g_col3);
    cudaGetSymbolAddress((void**)&wtp,  g_wtp);
    cudaGetSymbolAddress((void**)&pc,   g_pc);
    cudaGetSymbolAddress((void**)&caps, g_caps);
    cudaGetSymbolAddress((void**)&u,    g_u);

    cudaFuncSetAttribute(attn_k, cudaFuncAttributeMaxDynamicSharedMemorySize, ATTN_SMEM);

    // ---- ConvEmbed ----
    im2col1_k<<<(int)CDIV((long)737280 * 27, 256), 256>>>(x_in, col1);
    wtrans_inner<<<CDIV(64 * 27, 256), 256>>>(conv1_w, wt1, 64, 27);
    sgemm_k<1><<<dim3(1, 737280 / 64), 256>>>(col1, wt1, nullptr, nullptr, y1, 737280, 64, 27);
    maxpool_k<<<(int)CDIV((long)256 * 20 * 36 * 64, 256), 256>>>(y1, p1, 256, 40, 72, 64, 20, 36, nullptr);
    im2col2_k<<<(int)CDIV((long)184320 * 576, 256), 256>>>(p1, col2);
    wtrans_hwc<<<CDIV(64 * 576, 256), 256>>>(conv2_w, wt2, 64, 64);
    sgemm_k<1><<<dim3(1, 184320 / 64), 256>>>(col2, wt2, nullptr, nullptr, y2, 184320, 64, 576);
    // pool2 writes directly into token layout and adds pos_emb
    maxpool_k<<<(int)CDIV((long)256 * 10 * 18 * 64, 256), 256>>>(y2, xb, 256, 20, 36, 64, 10, 18, pos_emb);

    // ---- Transformer: 12 shared layers applied twice ----
    const int M = 46080;
    for (int pass = 0; pass < 2; pass++) {
        for (int l = 0; l < 12; l++) {
            const float* qw  = qkv_w + (long)l * 64 * 2304;
            const float* ow  = out_w + (long)l * 768 * 64;
            const float* ob  = out_b + (long)l * 64;
            const float* f1w = ff1_w + (long)l * 64 * 256;
            const float* f1b = ff1_b + (long)l * 256;
            const float* f2w = ff2_w + (long)l * 256 * 64;
            const float* f2b = ff2_b + (long)l * 64;

            ln64_k<<<M / 8, 256>>>(xb, ln1_g + l * 64, ln1_b + l * 64, hb, M);
            sgemm_k<0><<<dim3(2304 / 64, M / 64), 256>>>(hb, qw, nullptr, nullptr, qkv, M, 2304, 64);
            attn_k<<<256 * 12, 256, ATTN_SMEM>>>(qkv, ao);
            sgemm_k<4><<<dim3(1, M / 64), 256>>>(ao, ow, ob, xb, xb, M, 64, 768);
            ln64_k<<<M / 8, 256>>>(xb, ln2_g + l * 64, ln2_b + l * 64, hb, M);
            sgemm_k<3><<<dim3(256 / 64, M / 64), 256>>>(hb, f1w, f1b, nullptr, ff, M, 256, 64);
            sgemm_k<4><<<dim3(1, M / 64), 256>>>(ff, f2w, f2b, xb, xb, M, 64, 256);
        }
    }

    // ---- PrimaryCaps + routing ----
    im2col3_k<<<(int)CDIV((long)8192 * 576, 256), 256>>>(xb, col3);
    wtrans_hwc<<<CDIV(256 * 576, 256), 256>>>(pcaps_w, wtp, 256, 64);
    sgemm_k<2><<<dim3(256 / 64, 8192 / 64), 256>>>(col3, wtp, pcaps_b, nullptr, pc, 8192, 256, 576);
    caps_squash_k<<<CDIV(256 * 1024, 256), 256>>>(pc, caps);
    caps_u_k<<<1024, 256>>>(caps, caps_w, u);
    routing_k<<<256, 256>>>(u, b_route, out);
}

// round 2
// speedup vs baseline: 1.0293x; 1.0293x over previous
#include <cuda_runtime.h>
#include <math.h>

#define CDIV(a,b) (((a)+(b)-1)/(b))

// ---------------- static scratch (no allocations allowed) ----------------
__device__ float g_col1[737280 * 28];        // conv1 im2col (K padded 27->28)
__device__ float g_wt1 [28 * 64];
__device__ float g_y1  [737280 * 64];        // conv1 out NHWC (B,40,72,64)
__device__ float g_p1  [184320 * 64];        // pool1 NHWC (B,20,36,64)
__device__ float g_col2[184320 * 576];       // conv2 im2col
__device__ float g_wt2 [576 * 64];
__device__ float g_y2  [184320 * 64];        // conv2 out NHWC (B,20,36,64)
__device__ float g_x   [46080 * 64];         // tokens / residual stream (B,180,64)
__device__ float g_h   [46080 * 64];         // LN output
__device__ float g_qkv [46080 * 2304];       // fused qkv
__device__ float g_ao  [46080 * 768];        // attention output (B,180,768)
__device__ float g_ff  [46080 * 256];        // MLP hidden
__device__ float g_col3[8192 * 576];         // pcaps im2col
__device__ float g_wtp [576 * 256];
__device__ float g_pc  [8192 * 256];         // pcaps out NHWC (B,4,8,256)
__device__ float g_caps[256 * 1024 * 8];
__device__ float g_u   [256 * 1024 * 48];

// ---------------- im2col kernels ----------------
__global__ void im2col1_k(const float* __restrict__ x, float* __restrict__ col) {
    long idx = (long)blockIdx.x * blockDim.x + threadIdx.x;
    const long total = (long)737280 * 28;
    if (idx >= total) return;
    int kk = (int)(idx % 28);
    long m = idx / 28;
    if (kk == 27) { col[idx] = 0.f; return; }
    int ow = (int)(m % 72);
    int t  = (int)(m / 72);
    int oh = t % 40;
    int b  = t / 40;
    int kw = kk % 3, kh = (kk / 3) % 3, ci = kk / 9;
    int ih = oh + kh - 1, iw = ow + kw - 1;
    float v = 0.f;
    if (ih >= 0 && ih < 40 && iw >= 0 && iw < 72)
        v = x[(((long)b * 3 + ci) * 40 + ih) * 72 + iw];
    col[idx] = v;
}

__global__ void im2col2_k(const float* __restrict__ p1, float* __restrict__ col) {
    long idx = (long)blockIdx.x * blockDim.x + threadIdx.x;
    const long total = (long)184320 * 576;
    if (idx >= total) return;
    int kk = (int)(idx % 576);
    long m = idx / 576;
    int ow = (int)(m % 36);
    int t  = (int)(m / 36);
    int oh = t % 20;
    int b  = t / 20;
    int ci = kk % 64;
    int kw = (kk / 64) % 3;
    int kh = kk / 192;
    int ih = oh + kh - 1, iw = ow + kw - 1;
    float v = 0.f;
    if (ih >= 0 && ih < 20 && iw >= 0 && iw < 36)
        v = p1[(((long)b * 20 + ih) * 36 + iw) * 64 + ci];
    col[idx] = v;
}

// pcaps: input tokens g_x viewed as (B, 10, 18, 64); conv k3 s2 p0 -> (B,4,8,*)
__global__ void im2col3_k(const float* __restrict__ tk, float* __restrict__ col) {
    long idx = (long)blockIdx.x * blockDim.x + threadIdx.x;
    const long total = (long)8192 * 576;
    if (idx >= total) return;
    int kk = (int)(idx % 576);
    long m = idx / 576;
    int ow = (int)(m % 8);
    int t  = (int)(m / 8);
    int oh = t % 4;
    int b  = t / 4;
    int ci = kk % 64;
    int kw = (kk / 64) % 3;
    int kh = kk / 192;
    int ih = oh * 2 + kh, iw = ow * 2 + kw;
    col[idx] = tk[((long)b * 180 + ih * 18 + iw) * 64 + ci];
}

// ---------------- weight transposes ----------------
// conv1: k-index order (ci,kh,kw) == OIHW inner order, pad K 27->28 with zeros
__global__ void wtrans1(const float* __restrict__ w, float* __restrict__ wt) {
    int i = blockIdx.x * blockDim.x + threadIdx.x;
    if (i >= 64 * 28) return;
    int o = i / 28, k = i % 28;
    wt[k * 64 + o] = (k < 27) ? w[o * 27 + k] : 0.f;
}
// conv2/pcaps: k-index order (kh,kw,ci) to keep im2col reads coalesced
__global__ void wtrans_hwc(const float* __restrict__ w, float* __restrict__ wt, int O, int CI) {
    int K = CI * 9;
    int i = blockIdx.x * blockDim.x + threadIdx.x;
    if (i >= O * K) return;
    int o = i / K, r = i % K;
    int ci = r / 9, kh = (r % 9) / 3, kw = r % 3;
    wt[((kh * 3 + kw) * CI + ci) * O + o] = w[i];
}

// ---------------- SGEMM v2: 128x64 tile, 8x8 microtile, 128 threads ----------------
// C[M,N] = epilogue(A[M,K] @ B[K,N])
// EPI: 0 none, 1 relu, 2 +bias, 3 +bias then gelu, 4 +bias +res
// Requires: M % 128 == 0, N % 64 == 0, K % 4 == 0, A 16B-aligned rows (K%4==0)
template <int EPI>
__global__ void __launch_bounds__(128) sgemm_k(const float* __restrict__ A, const float* __restrict__ Bm,
                                               const float* __restrict__ bias, const float* __restrict__ res,
                                               float* __restrict__ C, int M, int N, int K) {
    __shared__ float As[16][132];
    __shared__ float Bs[16][68];
    const int bm = blockIdx.y * 128, bn = blockIdx.x * 64;
    const int tid = threadIdx.x;
    const int tx = tid & 7, ty = tid >> 3;
    const int m0 = ty * 8, n0c = tx * 8;
    const int bk = tid >> 4, bn2 = (tid & 15) * 4;

    float acc[8][8];
#pragma unroll
    for (int i = 0; i < 8; i++)
#pragma unroll
        for (int j = 0; j < 8; j++) acc[i][j] = 0.f;

    const float* Arow = A + (long)(bm + tid) * K;

    for (int k0 = 0; k0 < K; k0 += 16) {
        float4 av[4], bv[2];
#pragma unroll
        for (int i = 0; i < 4; i++) {
            int gk = k0 + 4 * i;
            av[i] = (gk < K) ? *(const float4*)(Arow + gk) : make_float4(0.f, 0.f, 0.f, 0.f);
        }
#pragma unroll
        for (int i = 0; i < 2; i++) {
            int gk = k0 + bk + 8 * i;
            bv[i] = (gk < K) ? *(const float4*)(Bm + (long)gk * N + bn + bn2)
                             : make_float4(0.f, 0.f, 0.f, 0.f);
        }
        __syncthreads();
#pragma unroll
        for (int i = 0; i < 4; i++) {
            As[4 * i + 0][tid] = av[i].x;
            As[4 * i + 1][tid] = av[i].y;
            As[4 * i + 2][tid] = av[i].z;
            As[4 * i + 3][tid] = av[i].w;
        }
        *(float4*)&Bs[bk][bn2]     = bv[0];
        *(float4*)&Bs[bk + 8][bn2] = bv[1];
        __syncthreads();
#pragma unroll
        for (int k = 0; k < 16; k++) {
            float a[8], b[8];
            *(float4*)&a[0] = *(const float4*)&As[k][m0];
            *(float4*)&a[4] = *(const float4*)&As[k][m0 + 4];
            *(float4*)&b[0] = *(const float4*)&Bs[k][n0c];
            *(float4*)&b[4] = *(const float4*)&Bs[k][n0c + 4];
#pragma unroll
            for (int i = 0; i < 8; i++)
#pragma unroll
                for (int j = 0; j < 8; j++) acc[i][j] = fmaf(a[i], b[j], acc[i][j]);
        }
    }

    float bvals[8];
    if (EPI >= 2) {
#pragma unroll
        for (int j = 0; j < 8; j++) bvals[j] = bias[bn + n0c + j];
    }
#pragma unroll
    for (int i = 0; i < 8; i++) {
        long row = bm + m0 + i;
        float v[8];
#pragma unroll
        for (int j = 0; j < 8; j++) {
            float t = acc[i][j];
            if (EPI == 1) t = fmaxf(t, 0.f);
            if (EPI >= 2) t += bvals[j];
            if (EPI == 3) t = 0.5f * t * (1.f + erff(t * 0.70710678118654752f));
            v[j] = t;
        }
        if (EPI == 4) {
            float4 r0 = *(const float4*)(res + row * N + bn + n0c);
            float4 r1 = *(const float4*)(res + row * N + bn + n0c + 4);
            v[0] += r0.x; v[1] += r0.y; v[2] += r0.z; v[3] += r0.w;
            v[4] += r1.x; v[5] += r1.y; v[6] += r1.z; v[7] += r1.w;
        }
        *(float4*)(C + row * N + bn + n0c)     = make_float4(v[0], v[1], v[2], v[3]);
        *(float4*)(C + row * N + bn + n0c + 4) = make_float4(v[4], v[5], v[6], v[7]);
    }
}

// ---------------- maxpool 3x3 s2 p1 on NHWC (+ optional pos-emb add) ----------------
__global__ void maxpool_k(const float* __restrict__ in, float* __restrict__ out,
                          int Bn, int IH, int IW, int C, int OH, int OW,
                          const float* __restrict__ pos) {
    long idx = (long)blockIdx.x * blockDim.x + threadIdx.x;
    long total = (long)Bn * OH * OW * C;
    if (idx >= total) return;
    int c = (int)(idx % C);
    long r = idx / C;
    int ow = (int)(r % OW); r /= OW;
    int oh = (int)(r % OH);
    int b  = (int)(r / OH);
    float m = -1e30f;
#pragma unroll
    for (int kh = 0; kh < 3; kh++) {
        int ih = oh * 2 - 1 + kh;
        if (ih < 0 || ih >= IH) continue;
#pragma unroll
        for (int kw = 0; kw < 3; kw++) {
            int iw = ow * 2 - 1 + kw;
            if (iw < 0 || iw >= IW) continue;
            m = fmaxf(m, in[(((long)b * IH + ih) * IW + iw) * C + c]);
        }
    }
    if (pos) m += pos[(oh * OW + ow) * C + c];
    out[idx] = m;
}

// ---------------- LayerNorm over last dim (64), one warp per token ----------------
__global__ void ln64_k(const float* __restrict__ x, const float* __restrict__ g,
                       const float* __restrict__ bta, float* __restrict__ out, int ntok) {
    int warp = (blockIdx.x * blockDim.x + threadIdx.x) >> 5;
    int lane = threadIdx.x & 31;
    if (warp >= ntok) return;
    float v0 = x[(long)warp * 64 + lane];
    float v1 = x[(long)warp * 64 + 32 + lane];
    float s = v0 + v1;
#pragma unroll
    for (int o = 16; o; o >>= 1) s += __shfl_xor_sync(0xffffffffu, s, o);
    float mean = s * (1.f / 64.f);
    float d0 = v0 - mean, d1 = v1 - mean;
    float q = d0 * d0 + d1 * d1;
#pragma unroll
    for (int o = 16; o; o >>= 1) q += __shfl_xor_sync(0xffffffffu, q, o);
    float rstd = rsqrtf(q * (1.f / 64.f) + 1e-5f);
    out[(long)warp * 64 + lane]      = d0 * rstd * g[lane] + bta[lane];
    out[(long)warp * 64 + 32 + lane] = d1 * rstd * g[lane + 32] + bta[lane + 32];
}

// ---------------- fused attention v2: one block per (b, head) ----------------
// smem: q[184][64] (rows 180..183 zero), kT[64][192] (cols 180..191 zero),
//       v[180][64], p[8 warps][8 rows][180]
#define KT_W 192
#define ATTN_SMEM ((184 * 64 + 64 * KT_W + 180 * 64 + 8 * 8 * 180) * 4)
__global__ void __launch_bounds__(256) attn_k(const float* __restrict__ qkv, float* __restrict__ out) {
    extern __shared__ float sm[];
    float* q_s = sm;                   // [184][64]
    float* kT  = q_s + 184 * 64;       // [64][192]
    float* v_s = kT + 64 * KT_W;       // [180][64]
    float* p_s = v_s + 180 * 64;       // [8][8][180]

    int b = blockIdx.x / 12, h = blockIdx.x % 12;
    int tid = threadIdx.x, lane = tid & 31, w = tid >> 5;

    const float* base = qkv + (long)b * 180 * 2304 + h * 64;

    // q, v fill (coalesced float4)
    for (int i = tid; i < 180 * 16; i += 256) {
        int n = i >> 4, dq = (i & 15) << 2;
        const float* src = base + (long)n * 2304 + dq;
        *(float4*)&q_s[n * 64 + dq] = *(const float4*)(src);
        *(float4*)&v_s[n * 64 + dq] = *(const float4*)(src + 1536);
    }
    // zero pad q rows 180..183
    for (int i = tid; i < 4 * 64; i += 256) q_s[180 * 64 + i] = 0.f;
    // kT fill: conflict-free stores (lane = n), L1-cached strided reads
    {
        int d0 = tid >> 5;
        for (int d = d0; d < 64; d += 8)
            for (int n = lane; n < 180; n += 32)
                kT[d * KT_W + n] = base[(long)n * 2304 + 768 + d];
        for (int i = tid; i < 64 * 12; i += 256) {
            int d = i / 12, c = 180 + (i % 12);
            kT[d * KT_W + c] = 0.f;
        }
    }
    __syncthreads();

    float* pw = p_s + w * 8 * 180;
    float* outb = out + (long)b * 180 * 768 + h * 64;
    const int j1 = 2 * lane + 64, j2 = 2 * lane + 128;

    for (int n0 = w * 8; n0 < 180; n0 += 64) {
        // ---- QK: 8 rows x 192 j-slots ----
        float2 acc[8][3];
#pragma unroll
        for (int r = 0; r < 8; r++)
#pragma unroll
            for (int s = 0; s < 3; s++) acc[r][s] = make_float2(0.f, 0.f);

        for (int d = 0; d < 64; d += 4) {
            float4 q[8];
#pragma unroll
            for (int r = 0; r < 8; r++) q[r] = *(const float4*)&q_s[(n0 + r) * 64 + d];
#pragma unroll
            for (int dd = 0; dd < 4; dd++) {
                const float* kr = &kT[(d + dd) * KT_W];
                float2 k0 = *(const float2*)&kr[2 * lane];
                float2 k1 = *(const float2*)&kr[j1];
                float2 k2 = *(const float2*)&kr[j2];
#pragma unroll
                for (int r = 0; r < 8; r++) {
                    float qv = (&q[r].x)[dd];
                    acc[r][0].x = fmaf(qv, k0.x, acc[r][0].x);
                    acc[r][0].y = fmaf(qv, k0.y, acc[r][0].y);
                    acc[r][1].x = fmaf(qv, k1.x, acc[r][1].x);
                    acc[r][1].y = fmaf(qv, k1.y, acc[r][1].y);
                    acc[r][2].x = fmaf(qv, k2.x, acc[r][2].x);
                    acc[r][2].y = fmaf(qv, k2.y, acc[r][2].y);
                }
            }
        }
        // ---- softmax per row ----
        bool v2x = (j2 < 180), v2y = (j2 + 1 < 180);
#pragma unroll
        for (int r = 0; r < 8; r++) {
            float s0x = acc[r][0].x * 0.125f, s0y = acc[r][0].y * 0.125f;
            float s1x = acc[r][1].x * 0.125f, s1y = acc[r][1].y * 0.125f;
            float s2x = acc[r][2].x * 0.125f, s2y = acc[r][2].y * 0.125f;
            float mx = fmaxf(fmaxf(s0x, s0y), fmaxf(s1x, s1y));
            mx = fmaxf(mx, fmaxf(v2x ? s2x : -1e30f, v2y ? s2y : -1e30f));
#pragma unroll
            for (int o = 16; o; o >>= 1) mx = fmaxf(mx, __shfl_xor_sync(0xffffffffu, mx, o));
            float e0x = __expf(s0x - mx), e0y = __expf(s0y - mx);
            float e1x = __expf(s1x - mx), e1y = __expf(s1y - mx);
            float e2x = v2x ? __expf(s2x - mx) : 0.f;
            float e2y = v2y ? __expf(s2y - mx) : 0.f;
            float sum = e0x + e0y + e1x + e1y + e2x + e2y;
#pragma unroll
            for (int o = 16; o; o >>= 1) sum += __shfl_xor_sync(0xffffffffu, sum, o);
            float inv = 1.f / sum;
            *(float2*)&pw[r * 180 + 2 * lane] = make_float2(e0x * inv, e0y * inv);
            *(float2*)&pw[r * 180 + j1]       = make_float2(e1x * inv, e1y * inv);
            if (j2 < 180)
                *(float2*)&pw[r * 180 + j2]   = make_float2(e2x * inv, e2y * inv);
        }
        __syncwarp();
        // ---- AV: 8 rows, float4 p, scalar V ----
        float o0[8], o1[8];
#pragma unroll
        for (int r = 0; r < 8; r++) { o0[r] = 0.f; o1[r] = 0.f; }
        for (int j0 = 0; j0 < 180; j0 += 4) {
            float4 p[8];
#pragma unroll
            for (int r = 0; r < 8; r++) p[r] = *(const float4*)&pw[r * 180 + j0];
#pragma unroll
            for (int jj = 0; jj < 4; jj++) {
                float va = v_s[(j0 + jj) * 64 + lane];
                float vb = v_s[(j0 + jj) * 64 + 32 + lane];
#pragma unroll
                for (int r = 0; r < 8; r++) {
                    float pv = (&p[r].x)[jj];
                    o0[r] = fmaf(pv, va, o0[r]);
                    o1[r] = fmaf(pv, vb, o1[r]);
                }
            }
        }
#pragma unroll
        for (int r = 0; r < 8; r++) {
            int n = n0 + r;
            if (n < 180) {
                outb[(long)n * 768 + lane]      = o0[r];
                outb[(long)n * 768 + 32 + lane] = o1[r];
            }
        }
        __syncwarp();
    }
}

// ---------------- primary caps: gather + squash ----------------
__global__ void caps_squash_k(const float* __restrict__ pc, float* __restrict__ caps) {
    int idx = blockIdx.x * blockDim.x + threadIdx.x; // b*1024 + i
    if (idx >= 256 * 1024) return;
    int i = idx & 1023, b = idx >> 10;
    int i32 = i >> 5, y = (i >> 3) & 3, xq = i & 7;
    const float* src = pc + (((long)b * 4 + y) * 8 + xq) * 256 + i32 * 8;
    float t[8];
    float l2 = 0.f;
#pragma unroll
    for (int e = 0; e < 8; e++) { t[e] = src[e]; l2 += t[e] * t[e]; }
    float sc = sqrtf(l2) / (1.f + l2);
#pragma unroll
    for (int e = 0; e < 8; e++) caps[(long)idx * 8 + e] = t[e] * sc;
}

// ---------------- capsule predictions u[b,i,:] ----------------
__global__ void caps_u_k(const float* __restrict__ caps, const float* __restrict__ cw,
                         float* __restrict__ u) {
    __shared__ float w_s[8 * 48];
    int i = blockIdx.x;
    for (int t = threadIdx.x; t < 384; t += 256) w_s[t] = cw[(long)i * 384 + t];
    __syncthreads();
    int b = threadIdx.x;
    float ce[8];
    const float* cp = caps + ((long)b * 1024 + i) * 8;
#pragma unroll
    for (int e = 0; e < 8; e++) ce[e] = cp[e];
    float* up = u + ((long)b * 1024 + i) * 48;
#pragma unroll 4
    for (int o = 0; o < 48; o++) {
        float s = 0.f;
#pragma unroll
        for (int e = 0; e < 8; e++) s = fmaf(ce[e], w_s[e * 48 + o], s);
        up[o] = s;
    }
}

// ---------------- dynamic routing, one block per batch element ----------------
__global__ void __launch_bounds__(256) routing_k(const float* __restrict__ u,
                                                 const float* __restrict__ br,
                                                 float* __restrict__ out) {
    __shared__ float bb[1024 * 3];
    __shared__ float S[48];
    __shared__ float v[48];
    int b = blockIdx.x, tid = threadIdx.x, lane = tid & 31;
    for (int i = tid; i < 3072; i += 256) bb[i] = br[i];
    __syncthreads();
    const float* ub = u + (long)b * 1024 * 48;

    for (int it = 0; it < 4; it++) {
        if (tid < 48) S[tid] = 0.f;
        __syncthreads();
        float acc[48];
#pragma unroll
        for (int o = 0; o < 48; o++) acc[o] = 0.f;
        for (int i = tid; i < 1024; i += 256) {
            float b0 = bb[i * 3], b1 = bb[i * 3 + 1], b2 = bb[i * 3 + 2];
            float m = fmaxf(b0, fmaxf(b1, b2));
            float e0 = expf(b0 - m), e1 = expf(b1 - m), e2 = expf(b2 - m);
            float inv = 1.f / (e0 + e1 + e2);
            float c[3] = {e0 * inv, e1 * inv, e2 * inv};
            const float* up = ub + (long)i * 48;
#pragma unroll
            for (int j = 0; j < 3; j++)
#pragma unroll
                for (int o = 0; o < 16; o++)
                    acc[j * 16 + o] = fmaf(c[j], up[j * 16 + o], acc[j * 16 + o]);
        }
#pragma unroll
        for (int o = 0; o < 48; o++) {
            float s = acc[o];
#pragma unroll
            for (int d = 16; d; d >>= 1) s += __shfl_xor_sync(0xffffffffu, s, d);
            if (lane == 0) atomicAdd(&S[o], s);
        }
        __syncthreads();
        if (tid < 3) {
            float l2 = 0.f;
            for (int o = 0; o < 16; o++) { float t = S[tid * 16 + o]; l2 += t * t; }
            float sc = sqrtf(l2) / (1.f + l2);
            for (int o = 0; o < 16; o++) v[tid * 16 + o] = S[tid * 16 + o] * sc;
            if (it == 3) out[b * 3 + tid] = l2 / (1.f + l2);  // |v| = l2/(1+l2)
        }
        __syncthreads();
        if (it < 3) {
            for (int i = tid; i < 1024; i += 256) {
                const float* up = ub + (long)i * 48;
#pragma unroll
                for (int j = 0; j < 3; j++) {
                    float s = 0.f;
#pragma unroll
                    for (int o = 0; o < 16; o++) s = fmaf(up[j * 16 + o], v[j * 16 + o], s);
                    bb[i * 3 + j] += s;
                }
            }
            __syncthreads();
        }
    }
}

// ---------------- host ----------------
extern "C" void kernel_launch(void* const* d_in, const int* in_sizes, int n_in,
                              void* d_out, int out_size) {
    const float* x_in    = (const float*)d_in[0];
    const float* conv1_w = (const float*)d_in[1];
    const float* conv2_w = (const float*)d_in[2];
    const float* pos_emb = (const float*)d_in[3];
    const float* ln1_g   = (const float*)d_in[4];
    const float* ln1_b   = (const float*)d_in[5];
    const float* qkv_w   = (const float*)d_in[6];
    const float* out_w   = (const float*)d_in[7];
    const float* out_b   = (const float*)d_in[8];
    const float* ln2_g   = (const float*)d_in[9];
    const float* ln2_b   = (const float*)d_in[10];
    const float* ff1_w   = (const float*)d_in[11];
    const float* ff1_b   = (const float*)d_in[12];
    const float* ff2_w   = (const float*)d_in[13];
    const float* ff2_b   = (const float*)d_in[14];
    const float* pcaps_w = (const float*)d_in[15];
    const float* pcaps_b = (const float*)d_in[16];
    const float* caps_w  = (const float*)d_in[17];
    const float* b_route = (const float*)d_in[18];
    float* out = (float*)d_out;

    float *col1, *wt1, *y1, *p1, *col2, *wt2, *y2, *xb, *hb, *qkv, *ao, *ff, *col3, *wtp, *pc, *caps, *u;
    cudaGetSymbolAddress((void**)&col1, g_col1);
    cudaGetSymbolAddress((void**)&wt1,  g_wt1);
    cudaGetSymbolAddress((void**)&y1,   g_y1);
    cudaGetSymbolAddress((void**)&p1,   g_p1);
    cudaGetSymbolAddress((void**)&col2, g_col2);
    cudaGetSymbolAddress((void**)&wt2,  g_wt2);
    cudaGetSymbolAddress((void**)&y2,   g_y2);
    cudaGetSymbolAddress((void**)&xb,   g_x);
    cudaGetSymbolAddress((void**)&hb,   g_h);
    cudaGetSymbolAddress((void**)&qkv,  g_qkv);
    cudaGetSymbolAddress((void**)&ao,   g_ao);
    cudaGetSymbolAddress((void**)&ff,   g_ff);
    cudaGetSymbolAddress((void**)&col3, g_col3);
    cudaGetSymbolAddress((void**)&wtp,  g_wtp);
    cudaGetSymbolAddress((void**)&pc,   g_pc);
    cudaGetSymbolAddress((void**)&caps, g_caps);
    cudaGetSymbolAddress((void**)&u,    g_u);

    cudaFuncSetAttribute(attn_k, cudaFuncAttributeMaxDynamicSharedMemorySize, ATTN_SMEM);

    // ---- ConvEmbed ----
    im2col1_k<<<(int)CDIV((long)737280 * 28, 256), 256>>>(x_in, col1);
    wtrans1<<<CDIV(64 * 28, 256), 256>>>(conv1_w, wt1);
    sgemm_k<1><<<dim3(1, 737280 / 128), 128>>>(col1, wt1, nullptr, nullptr, y1, 737280, 64, 28);
    maxpool_k<<<(int)CDIV((long)256 * 20 * 36 * 64, 256), 256>>>(y1, p1, 256, 40, 72, 64, 20, 36, nullptr);
    im2col2_k<<<(int)CDIV((long)184320 * 576, 256), 256>>>(p1, col2);
    wtrans_hwc<<<CDIV(64 * 576, 256), 256>>>(conv2_w, wt2, 64, 64);
    sgemm_k<1><<<dim3(1, 184320 / 128), 128>>>(col2, wt2, nullptr, nullptr, y2, 184320, 64, 576);
    // pool2 writes directly into token layout and adds pos_emb
    maxpool_k<<<(int)CDIV((long)256 * 10 * 18 * 64, 256), 256>>>(y2, xb, 256, 20, 36, 64, 10, 18, pos_emb);

    // ---- Transformer: 12 shared layers applied twice ----
    const int M = 46080;
    for (int pass = 0; pass < 2; pass++) {
        for (int l = 0; l < 12; l++) {
            const float* qw  = qkv_w + (long)l * 64 * 2304;
            const float* ow  = out_w + (long)l * 768 * 64;
            const float* ob  = out_b + (long)l * 64;
            const float* f1w = ff1_w + (long)l * 64 * 256;
            const float* f1b = ff1_b + (long)l * 256;
            const float* f2w = ff2_w + (long)l * 256 * 64;
            const float* f2b = ff2_b + (long)l * 64;

            ln64_k<<<M / 8, 256>>>(xb, ln1_g + l * 64, ln1_b + l * 64, hb, M);
            sgemm_k<0><<<dim3(2304 / 64, M / 128), 128>>>(hb, qw, nullptr, nullptr, qkv, M, 2304, 64);
            attn_k<<<256 * 12, 256, ATTN_SMEM>>>(qkv, ao);
            sgemm_k<4><<<dim3(1, M / 128), 128>>>(ao, ow, ob, xb, xb, M, 64, 768);
            ln64_k<<<M / 8, 256>>>(xb, ln2_g + l * 64, ln2_b + l * 64, hb, M);
            sgemm_k<3><<<dim3(256 / 64, M / 128), 128>>>(hb, f1w, f1b, nullptr, ff, M, 256, 64);
            sgemm_k<4><<<dim3(1, M / 128), 128>>>(ff, f2w, f2b, xb, xb, M, 64, 256);
        }
    }

    // ---- PrimaryCaps + routing ----
    im2col3_k<<<(int)CDIV((long)8192 * 576, 256), 256>>>(xb, col3);
    wtrans_hwc<<<CDIV(256 * 576, 256), 256>>>(pcaps_w, wtp, 256, 64);
    sgemm_k<2><<<dim3(256 / 64, 8192 / 128), 128>>>(col3, wtp, pcaps_b, nullptr, pc, 8192, 256, 576);
    caps_squash_k<<<CDIV(256 * 1024, 256), 256>>>(pc, caps);
    caps_u_k<<<1024, 256>>>(caps, caps_w, u);
    routing_k<<<256, 256>>>(u, b_route, out);
}

// round 3
// speedup vs baseline: 1.4264x; 1.3858x over previous
#include <cuda_runtime.h>
#include <math.h>
#include <stdint.h>

#define CDIV(a,b) (((a)+(b)-1)/(b))

// ---------------- static scratch (no allocations allowed) ----------------
__device__ float g_col1[737280 * 28];        // conv1 im2col (K padded 27->28)
__device__ float g_wt1 [28 * 64];
__device__ float g_y1  [737280 * 64];        // conv1 out NHWC (B,40,72,64)
__device__ float g_p1  [184320 * 64];        // pool1 NHWC (B,20,36,64)
__device__ float g_col2[184320 * 576];       // conv2 im2col
__device__ float g_wt2 [576 * 64];
__device__ float g_y2  [184320 * 64];        // conv2 out NHWC (B,20,36,64)
__device__ float g_x   [46080 * 64];         // tokens / residual stream (B,180,64)
__device__ float g_h   [46080 * 64];         // LN output
__device__ float g_qkv [46080 * 2304];       // fused qkv
__device__ float g_ao  [46080 * 768];        // attention output (B,180,768)
__device__ float g_ff  [46080 * 256];        // MLP hidden
__device__ float g_col3[8192 * 576];         // pcaps im2col
__device__ float g_wtp [576 * 256];
__device__ float g_pc  [8192 * 256];         // pcaps out NHWC (B,4,8,256)
__device__ float g_caps[256 * 1024 * 8];
__device__ float g_u   [256 * 1024 * 48];

// ---------------- im2col kernels ----------------
__global__ void im2col1_k(const float* __restrict__ x, float* __restrict__ col) {
    long idx = (long)blockIdx.x * blockDim.x + threadIdx.x;
    const long total = (long)737280 * 28;
    if (idx >= total) return;
    int kk = (int)(idx % 28);
    long m = idx / 28;
    if (kk == 27) { col[idx] = 0.f; return; }
    int ow = (int)(m % 72);
    int t  = (int)(m / 72);
    int oh = t % 40;
    int b  = t / 40;
    int kw = kk % 3, kh = (kk / 3) % 3, ci = kk / 9;
    int ih = oh + kh - 1, iw = ow + kw - 1;
    float v = 0.f;
    if (ih >= 0 && ih < 40 && iw >= 0 && iw < 72)
        v = x[(((long)b * 3 + ci) * 40 + ih) * 72 + iw];
    col[idx] = v;
}

__global__ void im2col2_k(const float* __restrict__ p1, float* __restrict__ col) {
    long idx = (long)blockIdx.x * blockDim.x + threadIdx.x;
    const long total = (long)184320 * 576;
    if (idx >= total) return;
    int kk = (int)(idx % 576);
    long m = idx / 576;
    int ow = (int)(m % 36);
    int t  = (int)(m / 36);
    int oh = t % 20;
    int b  = t / 20;
    int ci = kk % 64;
    int kw = (kk / 64) % 3;
    int kh = kk / 192;
    int ih = oh + kh - 1, iw = ow + kw - 1;
    float v = 0.f;
    if (ih >= 0 && ih < 20 && iw >= 0 && iw < 36)
        v = p1[(((long)b * 20 + ih) * 36 + iw) * 64 + ci];
    col[idx] = v;
}

// pcaps: input tokens g_x viewed as (B, 10, 18, 64); conv k3 s2 p0 -> (B,4,8,*)
__global__ void im2col3_k(const float* __restrict__ tk, float* __restrict__ col) {
    long idx = (long)blockIdx.x * blockDim.x + threadIdx.x;
    const long total = (long)8192 * 576;
    if (idx >= total) return;
    int kk = (int)(idx % 576);
    long m = idx / 576;
    int ow = (int)(m % 8);
    int t  = (int)(m / 8);
    int oh = t % 4;
    int b  = t / 4;
    int ci = kk % 64;
    int kw = (kk / 64) % 3;
    int kh = kk / 192;
    int ih = oh * 2 + kh, iw = ow * 2 + kw;
    col[idx] = tk[((long)b * 180 + ih * 18 + iw) * 64 + ci];
}

// ---------------- weight transposes ----------------
__global__ void wtrans1(const float* __restrict__ w, float* __restrict__ wt) {
    int i = blockIdx.x * blockDim.x + threadIdx.x;
    if (i >= 64 * 28) return;
    int o = i / 28, k = i % 28;
    wt[k * 64 + o] = (k < 27) ? w[o * 27 + k] : 0.f;
}
__global__ void wtrans_hwc(const float* __restrict__ w, float* __restrict__ wt, int O, int CI) {
    int K = CI * 9;
    int i = blockIdx.x * blockDim.x + threadIdx.x;
    if (i >= O * K) return;
    int o = i / K, r = i % K;
    int ci = r / 9, kh = (r % 9) / 3, kw = r % 3;
    wt[((kh * 3 + kw) * CI + ci) * O + o] = w[i];
}

// ---------------- SGEMM: 128x64 tile, 8x8 microtile, 128 threads ----------------
template <int EPI>
__global__ void __launch_bounds__(128) sgemm_k(const float* __restrict__ A, const float* __restrict__ Bm,
                                               const float* __restrict__ bias, const float* __restrict__ res,
                                               float* __restrict__ C, int M, int N, int K) {
    __shared__ float As[16][132];
    __shared__ float Bs[16][68];
    const int bm = blockIdx.y * 128, bn = blockIdx.x * 64;
    const int tid = threadIdx.x;
    const int tx = tid & 7, ty = tid >> 3;
    const int m0 = ty * 8, n0c = tx * 8;
    const int bk = tid >> 4, bn2 = (tid & 15) * 4;

    float acc[8][8];
#pragma unroll
    for (int i = 0; i < 8; i++)
#pragma unroll
        for (int j = 0; j < 8; j++) acc[i][j] = 0.f;

    const float* Arow = A + (long)(bm + tid) * K;

    for (int k0 = 0; k0 < K; k0 += 16) {
        float4 av[4], bv[2];
#pragma unroll
        for (int i = 0; i < 4; i++) {
            int gk = k0 + 4 * i;
            av[i] = (gk < K) ? *(const float4*)(Arow + gk) : make_float4(0.f, 0.f, 0.f, 0.f);
        }
#pragma unroll
        for (int i = 0; i < 2; i++) {
            int gk = k0 + bk + 8 * i;
            bv[i] = (gk < K) ? *(const float4*)(Bm + (long)gk * N + bn + bn2)
                             : make_float4(0.f, 0.f, 0.f, 0.f);
        }
        __syncthreads();
#pragma unroll
        for (int i = 0; i < 4; i++) {
            As[4 * i + 0][tid] = av[i].x;
            As[4 * i + 1][tid] = av[i].y;
            As[4 * i + 2][tid] = av[i].z;
            As[4 * i + 3][tid] = av[i].w;
        }
        *(float4*)&Bs[bk][bn2]     = bv[0];
        *(float4*)&Bs[bk + 8][bn2] = bv[1];
        __syncthreads();
#pragma unroll
        for (int k = 0; k < 16; k++) {
            float a[8], b[8];
            *(float4*)&a[0] = *(const float4*)&As[k][m0];
            *(float4*)&a[4] = *(const float4*)&As[k][m0 + 4];
            *(float4*)&b[0] = *(const float4*)&Bs[k][n0c];
            *(float4*)&b[4] = *(const float4*)&Bs[k][n0c + 4];
#pragma unroll
            for (int i = 0; i < 8; i++)
#pragma unroll
                for (int j = 0; j < 8; j++) acc[i][j] = fmaf(a[i], b[j], acc[i][j]);
        }
    }

    float bvals[8];
    if (EPI >= 2) {
#pragma unroll
        for (int j = 0; j < 8; j++) bvals[j] = bias[bn + n0c + j];
    }
#pragma unroll
    for (int i = 0; i < 8; i++) {
        long row = bm + m0 + i;
        float v[8];
#pragma unroll
        for (int j = 0; j < 8; j++) {
            float t = acc[i][j];
            if (EPI == 1) t = fmaxf(t, 0.f);
            if (EPI >= 2) t += bvals[j];
            if (EPI == 3) t = 0.5f * t * (1.f + erff(t * 0.70710678118654752f));
            v[j] = t;
        }
        if (EPI == 4) {
            float4 r0 = *(const float4*)(res + row * N + bn + n0c);
            float4 r1 = *(const float4*)(res + row * N + bn + n0c + 4);
            v[0] += r0.x; v[1] += r0.y; v[2] += r0.z; v[3] += r0.w;
            v[4] += r1.x; v[5] += r1.y; v[6] += r1.z; v[7] += r1.w;
        }
        *(float4*)(C + row * N + bn + n0c)     = make_float4(v[0], v[1], v[2], v[3]);
        *(float4*)(C + row * N + bn + n0c + 4) = make_float4(v[4], v[5], v[6], v[7]);
    }
}

// ---------------- maxpool 3x3 s2 p1 on NHWC (+ optional pos-emb add) ----------------
__global__ void maxpool_k(const float* __restrict__ in, float* __restrict__ out,
                          int Bn, int IH, int IW, int C, int OH, int OW,
                          const float* __restrict__ pos) {
    long idx = (long)blockIdx.x * blockDim.x + threadIdx.x;
    long total = (long)Bn * OH * OW * C;
    if (idx >= total) return;
    int c = (int)(idx % C);
    long r = idx / C;
    int ow = (int)(r % OW); r /= OW;
    int oh = (int)(r % OH);
    int b  = (int)(r / OH);
    float m = -1e30f;
#pragma unroll
    for (int kh = 0; kh < 3; kh++) {
        int ih = oh * 2 - 1 + kh;
        if (ih < 0 || ih >= IH) continue;
#pragma unroll
        for (int kw = 0; kw < 3; kw++) {
            int iw = ow * 2 - 1 + kw;
            if (iw < 0 || iw >= IW) continue;
            m = fmaxf(m, in[(((long)b * IH + ih) * IW + iw) * C + c]);
        }
    }
    if (pos) m += pos[(oh * OW + ow) * C + c];
    out[idx] = m;
}

// ---------------- LayerNorm over last dim (64), one warp per token ----------------
__global__ void ln64_k(const float* __restrict__ x, const float* __restrict__ g,
                       const float* __restrict__ bta, float* __restrict__ out, int ntok) {
    int warp = (blockIdx.x * blockDim.x + threadIdx.x) >> 5;
    int lane = threadIdx.x & 31;
    if (warp >= ntok) return;
    float v0 = x[(long)warp * 64 + lane];
    float v1 = x[(long)warp * 64 + 32 + lane];
    float s = v0 + v1;
#pragma unroll
    for (int o = 16; o; o >>= 1) s += __shfl_xor_sync(0xffffffffu, s, o);
    float mean = s * (1.f / 64.f);
    float d0 = v0 - mean, d1 = v1 - mean;
    float q = d0 * d0 + d1 * d1;
#pragma unroll
    for (int o = 16; o; o >>= 1) q += __shfl_xor_sync(0xffffffffu, q, o);
    float rstd = rsqrtf(q * (1.f / 64.f) + 1e-5f);
    out[(long)warp * 64 + lane]      = d0 * rstd * g[lane] + bta[lane];
    out[(long)warp * 64 + 32 + lane] = d1 * rstd * g[lane + 32] + bta[lane + 32];
}

// ---------------- tf32 helpers ----------------
__device__ __forceinline__ float f2tf(float f) {
    uint32_t r;
    asm("cvt.rna.tf32.f32 %0, %1;" : "=r"(r) : "f"(f));
    return __uint_as_float(r);
}
__device__ __forceinline__ void mma_tf32(float d[4], const uint32_t a[4], const uint32_t b[2],
                                         const float c[4]) {
    asm("mma.sync.aligned.m16n8k8.row.col.f32.tf32.tf32.f32 "
        "{%0,%1,%2,%3},{%4,%5,%6,%7},{%8,%9},{%10,%11,%12,%13};"
        : "=f"(d[0]), "=f"(d[1]), "=f"(d[2]), "=f"(d[3])
        : "r"(a[0]), "r"(a[1]), "r"(a[2]), "r"(a[3]), "r"(b[0]), "r"(b[1]),
          "f"(c[0]), "f"(c[1]), "f"(c[2]), "f"(c[3]));
}

// ---------------- fused tensor-core attention: one block per (b, head) ----------------
// smem floats: Qs[96][68] (half of rows), Ks[192][68], Vs[192][72], Ss[96][196]
#define QS_OFF 0
#define KS_OFF (96 * 68)
#define VS_OFF (KS_OFF + 192 * 68)
#define SS_OFF (VS_OFF + 192 * 72)
#define ATTN2_SMEM ((SS_OFF + 96 * 196) * 4)

__global__ void __launch_bounds__(256) attn_mma_k(const float* __restrict__ qkv,
                                                  float* __restrict__ out) {
    extern __shared__ float sm[];
    float* Qs = sm + QS_OFF;
    float* Ks = sm + KS_OFF;
    float* Vs = sm + VS_OFF;
    float* Ss = sm + SS_OFF;

    int b = blockIdx.x / 12, h = blockIdx.x % 12;
    int tid = threadIdx.x, lane = tid & 31, w = tid >> 5;
    int g4 = lane >> 2, c4 = lane & 3;

    const float* base = qkv + (long)b * 180 * 2304 + h * 64;

    // ---- K, V fill (tf32-converted), rows 180..191 zero ----
    for (int i = tid; i < 180 * 16; i += 256) {
        int n = i >> 4, d = (i & 15) << 2;
        float4 kv = *(const float4*)(base + (long)n * 2304 + 768 + d);
        float4 vv = *(const float4*)(base + (long)n * 2304 + 1536 + d);
        float* kp = &Ks[n * 68 + d];
        kp[0] = f2tf(kv.x); kp[1] = f2tf(kv.y); kp[2] = f2tf(kv.z); kp[3] = f2tf(kv.w);
        float* vp = &Vs[n * 72 + d];
        vp[0] = f2tf(vv.x); vp[1] = f2tf(vv.y); vp[2] = f2tf(vv.z); vp[3] = f2tf(vv.w);
    }
    for (int i = tid; i < 12 * 68; i += 256) Ks[180 * 68 + i] = 0.f;
    for (int i = tid; i < 12 * 72; i += 256) Vs[180 * 72 + i] = 0.f;

    for (int half = 0; half < 2; half++) {
        int row0 = half * 96;
        __syncthreads();
        // ---- Q fill for this half (tf32) ----
        for (int i = tid; i < 96 * 16; i += 256) {
            int r = i >> 4, d = (i & 15) << 2;
            int n = row0 + r;
            float* qp = &Qs[r * 68 + d];
            if (n < 180) {
                float4 q = *(const float4*)(base + (long)n * 2304 + d);
                qp[0] = f2tf(q.x); qp[1] = f2tf(q.y); qp[2] = f2tf(q.z); qp[3] = f2tf(q.w);
            } else {
                qp[0] = 0.f; qp[1] = 0.f; qp[2] = 0.f; qp[3] = 0.f;
            }
        }
        __syncthreads();

        // ---- stage 1: S = (Q K^T) * 0.125, warp w owns n-tiles {3w,3w+1,3w+2} ----
        {
            uint32_t bf[3][8][2];
#pragma unroll
            for (int nn = 0; nn < 3; nn++) {
                int brow = (w * 3 + nn) * 8 + g4;
#pragma unroll
                for (int ks = 0; ks < 8; ks++) {
                    int k0 = ks * 8 + c4;
                    bf[nn][ks][0] = __float_as_uint(Ks[brow * 68 + k0]);
                    bf[nn][ks][1] = __float_as_uint(Ks[brow * 68 + k0 + 4]);
                }
            }
            for (int mt = 0; mt < 6; mt++) {
                uint32_t af[8][4];
                int arow = mt * 16 + g4;
#pragma unroll
                for (int ks = 0; ks < 8; ks++) {
                    int k0 = ks * 8 + c4;
                    af[ks][0] = __float_as_uint(Qs[arow * 68 + k0]);
                    af[ks][1] = __float_as_uint(Qs[(arow + 8) * 68 + k0]);
                    af[ks][2] = __float_as_uint(Qs[arow * 68 + k0 + 4]);
                    af[ks][3] = __float_as_uint(Qs[(arow + 8) * 68 + k0 + 4]);
                }
#pragma unroll
                for (int nn = 0; nn < 3; nn++) {
                    float acc[4] = {0.f, 0.f, 0.f, 0.f};
#pragma unroll
                    for (int ks = 0; ks < 8; ks++) mma_tf32(acc, af[ks], bf[nn][ks], acc);
                    int srow = mt * 16 + g4;
                    int scol = (w * 3 + nn) * 8 + 2 * c4;
                    *(float2*)&Ss[srow * 196 + scol]       = make_float2(acc[0] * 0.125f, acc[1] * 0.125f);
                    *(float2*)&Ss[(srow + 8) * 196 + scol] = make_float2(acc[2] * 0.125f, acc[3] * 0.125f);
                }
            }
        }
        __syncthreads();

        // ---- stage 2: softmax rows (warp w handles rows w, w+8, ...) ----
        for (int r = 0; r < 12; r++) {
            int row = w + 8 * r;
            float s[6];
            float mx = -1e30f;
#pragma unroll
            for (int c = 0; c < 6; c++) {
                int col = lane + 32 * c;
                s[c] = (col < 180) ? Ss[row * 196 + col] : -1e30f;
                mx = fmaxf(mx, s[c]);
            }
#pragma unroll
            for (int o = 16; o; o >>= 1) mx = fmaxf(mx, __shfl_xor_sync(0xffffffffu, mx, o));
            float sum = 0.f;
#pragma unroll
            for (int c = 0; c < 6; c++) {
                int col = lane + 32 * c;
                s[c] = (col < 180) ? __expf(s[c] - mx) : 0.f;
                sum += s[c];
            }
#pragma unroll
            for (int o = 16; o; o >>= 1) sum += __shfl_xor_sync(0xffffffffu, sum, o);
            float inv = 1.f / sum;
#pragma unroll
            for (int c = 0; c < 6; c++)
                Ss[row * 196 + lane + 32 * c] = f2tf(s[c] * inv);
        }
        __syncthreads();

        // ---- stage 3: O = P V, warp w owns output cols [8w, 8w+8) ----
        {
            int ncol = w * 8;
            uint32_t bf[24][2];
#pragma unroll
            for (int ks = 0; ks < 24; ks++) {
                int k0 = ks * 8 + c4;
                bf[ks][0] = __float_as_uint(Vs[k0 * 72 + ncol + g4]);
                bf[ks][1] = __float_as_uint(Vs[(k0 + 4) * 72 + ncol + g4]);
            }
            for (int mt = 0; mt < 6; mt++) {
                float acc[4] = {0.f, 0.f, 0.f, 0.f};
                int arow = mt * 16 + g4;
#pragma unroll
                for (int ks = 0; ks < 24; ks++) {
                    uint32_t a[4];
                    int k0 = ks * 8 + c4;
                    a[0] = __float_as_uint(Ss[arow * 196 + k0]);
                    a[1] = __float_as_uint(Ss[(arow + 8) * 196 + k0]);
                    a[2] = __float_as_uint(Ss[arow * 196 + k0 + 4]);
                    a[3] = __float_as_uint(Ss[(arow + 8) * 196 + k0 + 4]);
                    mma_tf32(acc, a, bf[ks], acc);
                }
                int grow = row0 + mt * 16 + g4;
                long gcol = h * 64 + ncol + 2 * c4;
                if (grow < 180)
                    *(float2*)(out + ((long)b * 180 + grow) * 768 + gcol) = make_float2(acc[0], acc[1]);
                if (grow + 8 < 180)
                    *(float2*)(out + ((long)b * 180 + grow + 8) * 768 + gcol) = make_float2(acc[2], acc[3]);
            }
        }
    }
}

// ---------------- primary caps: gather + squash ----------------
__global__ void caps_squash_k(const float* __restrict__ pc, float* __restrict__ caps) {
    int idx = blockIdx.x * blockDim.x + threadIdx.x; // b*1024 + i
    if (idx >= 256 * 1024) return;
    int i = idx & 1023, b = idx >> 10;
    int i32 = i >> 5, y = (i >> 3) & 3, xq = i & 7;
    const float* src = pc + (((long)b * 4 + y) * 8 + xq) * 256 + i32 * 8;
    float t[8];
    float l2 = 0.f;
#pragma unroll
    for (int e = 0; e < 8; e++) { t[e] = src[e]; l2 += t[e] * t[e]; }
    float sc = sqrtf(l2) / (1.f + l2);
#pragma unroll
    for (int e = 0; e < 8; e++) caps[(long)idx * 8 + e] = t[e] * sc;
}

// ---------------- capsule predictions u[b,i,:] ----------------
__global__ void caps_u_k(const float* __restrict__ caps, const float* __restrict__ cw,
                         float* __restrict__ u) {
    __shared__ float w_s[8 * 48];
    int i = blockIdx.x;
    for (int t = threadIdx.x; t < 384; t += 256) w_s[t] = cw[(long)i * 384 + t];
    __syncthreads();
    int b = threadIdx.x;
    float ce[8];
    const float* cp = caps + ((long)b * 1024 + i) * 8;
#pragma unroll
    for (int e = 0; e < 8; e++) ce[e] = cp[e];
    float* up = u + ((long)b * 1024 + i) * 48;
#pragma unroll 4
    for (int o = 0; o < 48; o++) {
        float s = 0.f;
#pragma unroll
        for (int e = 0; e < 8; e++) s = fmaf(ce[e], w_s[e * 48 + o], s);
        up[o] = s;
    }
}

// ---------------- dynamic routing, one block per batch element ----------------
__global__ void __launch_bounds__(256) routing_k(const float* __restrict__ u,
                                                 const float* __restrict__ br,
                                                 float* __restrict__ out) {
    __shared__ float bb[1024 * 3];
    __shared__ float S[48];
    __shared__ float v[48];
    int b = blockIdx.x, tid = threadIdx.x, lane = tid & 31;
    for (int i = tid; i < 3072; i += 256) bb[i] = br[i];
    __syncthreads();
    const float* ub = u + (long)b * 1024 * 48;

    for (int it = 0; it < 4; it++) {
        if (tid < 48) S[tid] = 0.f;
        __syncthreads();
        float acc[48];
#pragma unroll
        for (int o = 0; o < 48; o++) acc[o] = 0.f;
        for (int i = tid; i < 1024; i += 256) {
            float b0 = bb[i * 3], b1 = bb[i * 3 + 1], b2 = bb[i * 3 + 2];
            float m = fmaxf(b0, fmaxf(b1, b2));
            float e0 = expf(b0 - m), e1 = expf(b1 - m), e2 = expf(b2 - m);
            float inv = 1.f / (e0 + e1 + e2);
            float c[3] = {e0 * inv, e1 * inv, e2 * inv};
            const float* up = ub + (long)i * 48;
#pragma unroll
            for (int j = 0; j < 3; j++)
#pragma unroll
                for (int o = 0; o < 16; o++)
                    acc[j * 16 + o] = fmaf(c[j], up[j * 16 + o], acc[j * 16 + o]);
        }
#pragma unroll
        for (int o = 0; o < 48; o++) {
            float s = acc[o];
#pragma unroll
            for (int d = 16; d; d >>= 1) s += __shfl_xor_sync(0xffffffffu, s, d);
            if (lane == 0) atomicAdd(&S[o], s);
        }
        __syncthreads();
        if (tid < 3) {
            float l2 = 0.f;
            for (int o = 0; o < 16; o++) { float t = S[tid * 16 + o]; l2 += t * t; }
            float sc = sqrtf(l2) / (1.f + l2);
            for (int o = 0; o < 16; o++) v[tid * 16 + o] = S[tid * 16 + o] * sc;
            if (it == 3) out[b * 3 + tid] = l2 / (1.f + l2);  // |v| = l2/(1+l2)
        }
        __syncthreads();
        if (it < 3) {
            for (int i = tid; i < 1024; i += 256) {
                const float* up = ub + (long)i * 48;
#pragma unroll
                for (int j = 0; j < 3; j++) {
                    float s = 0.f;
#pragma unroll
                    for (int o = 0; o < 16; o++) s = fmaf(up[j * 16 + o], v[j * 16 + o], s);
                    bb[i * 3 + j] += s;
                }
            }
            __syncthreads();
        }
    }
}

// ---------------- host ----------------
extern "C" void kernel_launch(void* const* d_in, const int* in_sizes, int n_in,
                              void* d_out, int out_size) {
    const float* x_in    = (const float*)d_in[0];
    const float* conv1_w = (const float*)d_in[1];
    const float* conv2_w = (const float*)d_in[2];
    const float* pos_emb = (const float*)d_in[3];
    const float* ln1_g   = (const float*)d_in[4];
    const float* ln1_b   = (const float*)d_in[5];
    const float* qkv_w   = (const float*)d_in[6];
    const float* out_w   = (const float*)d_in[7];
    const float* out_b   = (const float*)d_in[8];
    const float* ln2_g   = (const float*)d_in[9];
    const float* ln2_b   = (const float*)d_in[10];
    const float* ff1_w   = (const float*)d_in[11];
    const float* ff1_b   = (const float*)d_in[12];
    const float* ff2_w   = (const float*)d_in[13];
    const float* ff2_b   = (const float*)d_in[14];
    const float* pcaps_w = (const float*)d_in[15];
    const float* pcaps_b = (const float*)d_in[16];
    const float* caps_w  = (const float*)d_in[17];
    const float* b_route = (const float*)d_in[18];
    float* out = (float*)d_out;

    float *col1, *wt1, *y1, *p1, *col2, *wt2, *y2, *xb, *hb, *qkv, *ao, *ff, *col3, *wtp, *pc, *caps, *u;
    cudaGetSymbolAddress((void**)&col1, g_col1);
    cudaGetSymbolAddress((void**)&wt1,  g_wt1);
    cudaGetSymbolAddress((void**)&y1,   g_y1);
    cudaGetSymbolAddress((void**)&p1,   g_p1);
    cudaGetSymbolAddress((void**)&col2, g_col2);
    cudaGetSymbolAddress((void**)&wt2,  g_wt2);
    cudaGetSymbolAddress((void**)&y2,   g_y2);
    cudaGetSymbolAddress((void**)&xb,   g_x);
    cudaGetSymbolAddress((void**)&hb,   g_h);
    cudaGetSymbolAddress((void**)&qkv,  g_qkv);
    cudaGetSymbolAddress((void**)&ao,   g_ao);
    cudaGetSymbolAddress((void**)&ff,   g_ff);
    cudaGetSymbolAddress((void**)&col3, g_col3);
    cudaGetSymbolAddress((void**)&wtp,  g_wtp);
    cudaGetSymbolAddress((void**)&pc,   g_pc);
    cudaGetSymbolAddress((void**)&caps, g_caps);
    cudaGetSymbolAddress((void**)&u,    g_u);

    cudaFuncSetAttribute(attn_mma_k, cudaFuncAttributeMaxDynamicSharedMemorySize, ATTN2_SMEM);

    // ---- ConvEmbed ----
    im2col1_k<<<(int)CDIV((long)737280 * 28, 256), 256>>>(x_in, col1);
    wtrans1<<<CDIV(64 * 28, 256), 256>>>(conv1_w, wt1);
    sgemm_k<1><<<dim3(1, 737280 / 128), 128>>>(col1, wt1, nullptr, nullptr, y1, 737280, 64, 28);
    maxpool_k<<<(int)CDIV((long)256 * 20 * 36 * 64, 256), 256>>>(y1, p1, 256, 40, 72, 64, 20, 36, nullptr);
    im2col2_k<<<(int)CDIV((long)184320 * 576, 256), 256>>>(p1, col2);
    wtrans_hwc<<<CDIV(64 * 576, 256), 256>>>(conv2_w, wt2, 64, 64);
    sgemm_k<1><<<dim3(1, 184320 / 128), 128>>>(col2, wt2, nullptr, nullptr, y2, 184320, 64, 576);
    maxpool_k<<<(int)CDIV((long)256 * 10 * 18 * 64, 256), 256>>>(y2, xb, 256, 20, 36, 64, 10, 18, pos_emb);

    // ---- Transformer: 12 shared layers applied twice ----
    const int M = 46080;
    for (int pass = 0; pass < 2; pass++) {
        for (int l = 0; l < 12; l++) {
            const float* qw  = qkv_w + (long)l * 64 * 2304;
            const float* ow  = out_w + (long)l * 768 * 64;
            const float* ob  = out_b + (long)l * 64;
            const float* f1w = ff1_w + (long)l * 64 * 256;
            const float* f1b = ff1_b + (long)l * 256;
            const float* f2w = ff2_w + (long)l * 256 * 64;
            const float* f2b = ff2_b + (long)l * 64;

            ln64_k<<<M / 8, 256>>>(xb, ln1_g + l * 64, ln1_b + l * 64, hb, M);
            sgemm_k<0><<<dim3(2304 / 64, M / 128), 128>>>(hb, qw, nullptr, nullptr, qkv, M, 2304, 64);
            attn_mma_k<<<256 * 12, 256, ATTN2_SMEM>>>(qkv, ao);
            sgemm_k<4><<<dim3(1, M / 128), 128>>>(ao, ow, ob, xb, xb, M, 64, 768);
            ln64_k<<<M / 8, 256>>>(xb, ln2_g + l * 64, ln2_b + l * 64, hb, M);
            sgemm_k<3><<<dim3(256 / 64, M / 128), 128>>>(hb, f1w, f1b, nullptr, ff, M, 256, 64);
            sgemm_k<4><<<dim3(1, M / 128), 128>>>(ff, f2w, f2b, xb, xb, M, 64, 256);
        }
    }

    // ---- PrimaryCaps + routing ----
    im2col3_k<<<(int)CDIV((long)8192 * 576, 256), 256>>>(xb, col3);
    wtrans_hwc<<<CDIV(256 * 576, 256), 256>>>(pcaps_w, wtp, 256, 64);
    sgemm_k<2><<<dim3(256 / 64, 8192 / 128), 128>>>(col3, wtp, pcaps_b, nullptr, pc, 8192, 256, 576);
    caps_squash_k<<<CDIV(256 * 1024, 256), 256>>>(pc, caps);
    caps_u_k<<<1024, 256>>>(caps, caps_w, u);
    routing_k<<<256, 256>>>(u, b_route, out);
}

// round 4
// speedup vs baseline: 1.8239x; 1.2787x over previous
#include <cuda_runtime.h>
#include <math.h>
#include <stdint.h>

#define CDIV(a,b) (((a)+(b)-1)/(b))

// ---------------- static scratch (no allocations allowed) ----------------
__device__ float g_col1[737280 * 28];        // conv1 im2col (K padded 27->28)
__device__ float g_wt1 [28 * 64];
__device__ float g_y1  [737280 * 64];        // conv1 out NHWC (B,40,72,64)
__device__ float g_p1  [184320 * 64];        // pool1 NHWC (B,20,36,64)
__device__ float g_col2[184320 * 576];       // conv2 im2col
__device__ float g_wt2 [576 * 64];
__device__ float g_y2  [184320 * 64];        // conv2 out NHWC (B,20,36,64)
__device__ float g_x   [46080 * 64];         // tokens / residual stream (B,180,64)
__device__ float g_h   [46080 * 64];         // LN output
__device__ float g_qkv [46080 * 2304];       // fused qkv
__device__ float g_ao  [46080 * 768];        // attention output (B,180,768)
__device__ float g_ff  [46080 * 256];        // MLP hidden
__device__ float g_col3[8192 * 576];         // pcaps im2col
__device__ float g_wtp [576 * 256];
__device__ float g_pc  [8192 * 256];         // pcaps out NHWC (B,4,8,256)
__device__ float g_caps[256 * 1024 * 8];
__device__ float g_u   [256 * 1024 * 48];

// ---------------- im2col kernels ----------------
__global__ void im2col1_k(const float* __restrict__ x, float* __restrict__ col) {
    long idx = (long)blockIdx.x * blockDim.x + threadIdx.x;
    const long total = (long)737280 * 28;
    if (idx >= total) return;
    int kk = (int)(idx % 28);
    long m = idx / 28;
    if (kk == 27) { col[idx] = 0.f; return; }
    int ow = (int)(m % 72);
    int t  = (int)(m / 72);
    int oh = t % 40;
    int b  = t / 40;
    int kw = kk % 3, kh = (kk / 3) % 3, ci = kk / 9;
    int ih = oh + kh - 1, iw = ow + kw - 1;
    float v = 0.f;
    if (ih >= 0 && ih < 40 && iw >= 0 && iw < 72)
        v = x[(((long)b * 3 + ci) * 40 + ih) * 72 + iw];
    col[idx] = v;
}

__global__ void im2col2_k(const float* __restrict__ p1, float* __restrict__ col) {
    long idx = (long)blockIdx.x * blockDim.x + threadIdx.x;
    const long total = (long)184320 * 576;
    if (idx >= total) return;
    int kk = (int)(idx % 576);
    long m = idx / 576;
    int ow = (int)(m % 36);
    int t  = (int)(m / 36);
    int oh = t % 20;
    int b  = t / 20;
    int ci = kk % 64;
    int kw = (kk / 64) % 3;
    int kh = kk / 192;
    int ih = oh + kh - 1, iw = ow + kw - 1;
    float v = 0.f;
    if (ih >= 0 && ih < 20 && iw >= 0 && iw < 36)
        v = p1[(((long)b * 20 + ih) * 36 + iw) * 64 + ci];
    col[idx] = v;
}

// pcaps: input tokens g_x viewed as (B, 10, 18, 64); conv k3 s2 p0 -> (B,4,8,*)
__global__ void im2col3_k(const float* __restrict__ tk, float* __restrict__ col) {
    long idx = (long)blockIdx.x * blockDim.x + threadIdx.x;
    const long total = (long)8192 * 576;
    if (idx >= total) return;
    int kk = (int)(idx % 576);
    long m = idx / 576;
    int ow = (int)(m % 8);
    int t  = (int)(m / 8);
    int oh = t % 4;
    int b  = t / 4;
    int ci = kk % 64;
    int kw = (kk / 64) % 3;
    int kh = kk / 192;
    int ih = oh * 2 + kh, iw = ow * 2 + kw;
    col[idx] = tk[((long)b * 180 + ih * 18 + iw) * 64 + ci];
}

// ---------------- weight transposes ----------------
__global__ void wtrans1(const float* __restrict__ w, float* __restrict__ wt) {
    int i = blockIdx.x * blockDim.x + threadIdx.x;
    if (i >= 64 * 28) return;
    int o = i / 28, k = i % 28;
    wt[k * 64 + o] = (k < 27) ? w[o * 27 + k] : 0.f;
}
__global__ void wtrans_hwc(const float* __restrict__ w, float* __restrict__ wt, int O, int CI) {
    int K = CI * 9;
    int i = blockIdx.x * blockDim.x + threadIdx.x;
    if (i >= O * K) return;
    int o = i / K, r = i % K;
    int ci = r / 9, kh = (r % 9) / 3, kw = r % 3;
    wt[((kh * 3 + kw) * CI + ci) * O + o] = w[i];
}

// ---------------- tf32 helpers ----------------
__device__ __forceinline__ float f2tf(float f) {
    uint32_t r;
    asm("cvt.rna.tf32.f32 %0, %1;" : "=r"(r) : "f"(f));
    return __uint_as_float(r);
}
__device__ __forceinline__ void mma_tf32(float d[4], const uint32_t a[4], const uint32_t b[2],
                                         const float c[4]) {
    asm("mma.sync.aligned.m16n8k8.row.col.f32.tf32.tf32.f32 "
        "{%0,%1,%2,%3},{%4,%5,%6,%7},{%8,%9},{%10,%11,%12,%13};"
        : "=f"(d[0]), "=f"(d[1]), "=f"(d[2]), "=f"(d[3])
        : "r"(a[0]), "r"(a[1]), "r"(a[2]), "r"(a[3]), "r"(b[0]), "r"(b[1]),
          "f"(c[0]), "f"(c[1]), "f"(c[2]), "f"(c[3]));
}

// ---------------- tf32 tensor-core GEMM: 128x64 tile, 256 threads ----------------
// C[M,N] = epilogue(A[M,K] @ B[K,N]); EPI: 0 none, 1 relu, 2 +bias, 3 +bias gelu, 4 +bias +res
// Requires: M % 128 == 0, N % 64 == 0, K % 4 == 0
template <int EPI>
__global__ void __launch_bounds__(256) tgemm_k(const float* __restrict__ A, const float* __restrict__ Bm,
                                               const float* __restrict__ bias, const float* __restrict__ res,
                                               float* __restrict__ C, int M, int N, int K) {
    __shared__ float As[128 * 36];   // [m][k], stride 36
    __shared__ float Bs[32 * 68];    // [k][n], stride 68
    const int bm = blockIdx.y * 128, bn = blockIdx.x * 64;
    const int tid = threadIdx.x, lane = tid & 31, w = tid >> 5;
    const int g4 = lane >> 2, c4 = lane & 3;
    const int wm = (w & 3) * 32, wn = (w >> 2) * 32;

    float acc[2][4][4];
#pragma unroll
    for (int mt = 0; mt < 2; mt++)
#pragma unroll
        for (int nt = 0; nt < 4; nt++)
#pragma unroll
            for (int i = 0; i < 4; i++) acc[mt][nt][i] = 0.f;

    const int ar = tid >> 1, akb = (tid & 1) * 16;           // A load: row, k-block
    const int bk = tid >> 3, bn0 = (tid & 7) * 8;            // B load: k-row, n-offset
    const float* Arow = A + (long)(bm + ar) * K;

    for (int k0 = 0; k0 < K; k0 += 32) {
        float4 av[4], bv[2];
#pragma unroll
        for (int i = 0; i < 4; i++) {
            int gk = k0 + akb + 4 * i;
            av[i] = (gk + 4 <= K) ? *(const float4*)(Arow + gk) : make_float4(0.f, 0.f, 0.f, 0.f);
        }
        {
            int gk = k0 + bk;
            if (gk < K) {
                bv[0] = *(const float4*)(Bm + (long)gk * N + bn + bn0);
                bv[1] = *(const float4*)(Bm + (long)gk * N + bn + bn0 + 4);
            } else {
                bv[0] = make_float4(0.f, 0.f, 0.f, 0.f);
                bv[1] = bv[0];
            }
        }
        __syncthreads();
#pragma unroll
        for (int i = 0; i < 4; i++) {
            float* p = &As[ar * 36 + akb + 4 * i];
            p[0] = f2tf(av[i].x); p[1] = f2tf(av[i].y); p[2] = f2tf(av[i].z); p[3] = f2tf(av[i].w);
        }
        {
            float* p = &Bs[bk * 68 + bn0];
            p[0] = f2tf(bv[0].x); p[1] = f2tf(bv[0].y); p[2] = f2tf(bv[0].z); p[3] = f2tf(bv[0].w);
            p[4] = f2tf(bv[1].x); p[5] = f2tf(bv[1].y); p[6] = f2tf(bv[1].z); p[7] = f2tf(bv[1].w);
        }
        __syncthreads();
#pragma unroll
        for (int ks = 0; ks < 4; ks++) {
            uint32_t bfr[4][2], afr[2][4];
#pragma unroll
            for (int nt = 0; nt < 4; nt++) {
                int col = wn + nt * 8 + g4;
                bfr[nt][0] = __float_as_uint(Bs[(ks * 8 + c4) * 68 + col]);
                bfr[nt][1] = __float_as_uint(Bs[(ks * 8 + c4 + 4) * 68 + col]);
            }
#pragma unroll
            for (int mt = 0; mt < 2; mt++) {
                int base = (wm + mt * 16 + g4) * 36 + ks * 8 + c4;
                afr[mt][0] = __float_as_uint(As[base]);
                afr[mt][1] = __float_as_uint(As[base + 8 * 36]);
                afr[mt][2] = __float_as_uint(As[base + 4]);
                afr[mt][3] = __float_as_uint(As[base + 8 * 36 + 4]);
            }
#pragma unroll
            for (int mt = 0; mt < 2; mt++)
#pragma unroll
                for (int nt = 0; nt < 4; nt++)
                    mma_tf32(acc[mt][nt], afr[mt], bfr[nt], acc[mt][nt]);
        }
        __syncthreads();
    }

    // ---- epilogue ----
#pragma unroll
    for (int nt = 0; nt < 4; nt++) {
        int col = bn + wn + nt * 8 + 2 * c4;
        float b0 = 0.f, b1 = 0.f;
        if (EPI >= 2) { b0 = bias[col]; b1 = bias[col + 1]; }
#pragma unroll
        for (int mt = 0; mt < 2; mt++) {
#pragma unroll
            for (int half = 0; half < 2; half++) {
                long row = bm + wm + mt * 16 + g4 + 8 * half;
                float v0 = acc[mt][nt][2 * half], v1 = acc[mt][nt][2 * half + 1];
                if (EPI == 1) { v0 = fmaxf(v0, 0.f); v1 = fmaxf(v1, 0.f); }
                if (EPI >= 2) { v0 += b0; v1 += b1; }
                if (EPI == 3) {
                    v0 = 0.5f * v0 * (1.f + erff(v0 * 0.70710678118654752f));
                    v1 = 0.5f * v1 * (1.f + erff(v1 * 0.70710678118654752f));
                }
                if (EPI == 4) {
                    float2 r = *(const float2*)(res + row * N + col);
                    v0 += r.x; v1 += r.y;
                }
                *(float2*)(C + row * N + col) = make_float2(v0, v1);
            }
        }
    }
}

// ---------------- maxpool 3x3 s2 p1 on NHWC (+ optional pos-emb add) ----------------
__global__ void maxpool_k(const float* __restrict__ in, float* __restrict__ out,
                          int Bn, int IH, int IW, int C, int OH, int OW,
                          const float* __restrict__ pos) {
    long idx = (long)blockIdx.x * blockDim.x + threadIdx.x;
    long total = (long)Bn * OH * OW * C;
    if (idx >= total) return;
    int c = (int)(idx % C);
    long r = idx / C;
    int ow = (int)(r % OW); r /= OW;
    int oh = (int)(r % OH);
    int b  = (int)(r / OH);
    float m = -1e30f;
#pragma unroll
    for (int kh = 0; kh < 3; kh++) {
        int ih = oh * 2 - 1 + kh;
        if (ih < 0 || ih >= IH) continue;
#pragma unroll
        for (int kw = 0; kw < 3; kw++) {
            int iw = ow * 2 - 1 + kw;
            if (iw < 0 || iw >= IW) continue;
            m = fmaxf(m, in[(((long)b * IH + ih) * IW + iw) * C + c]);
        }
    }
    if (pos) m += pos[(oh * OW + ow) * C + c];
    out[idx] = m;
}

// ---------------- LayerNorm over last dim (64), one warp per token ----------------
__global__ void ln64_k(const float* __restrict__ x, const float* __restrict__ g,
                       const float* __restrict__ bta, float* __restrict__ out, int ntok) {
    int warp = (blockIdx.x * blockDim.x + threadIdx.x) >> 5;
    int lane = threadIdx.x & 31;
    if (warp >= ntok) return;
    float v0 = x[(long)warp * 64 + lane];
    float v1 = x[(long)warp * 64 + 32 + lane];
    float s = v0 + v1;
#pragma unroll
    for (int o = 16; o; o >>= 1) s += __shfl_xor_sync(0xffffffffu, s, o);
    float mean = s * (1.f / 64.f);
    float d0 = v0 - mean, d1 = v1 - mean;
    float q = d0 * d0 + d1 * d1;
#pragma unroll
    for (int o = 16; o; o >>= 1) q += __shfl_xor_sync(0xffffffffu, q, o);
    float rstd = rsqrtf(q * (1.f / 64.f) + 1e-5f);
    out[(long)warp * 64 + lane]      = d0 * rstd * g[lane] + bta[lane];
    out[(long)warp * 64 + 32 + lane] = d1 * rstd * g[lane + 32] + bta[lane + 32];
}

// ---------------- fused tensor-core attention: one block per (b, head) ----------------
// smem floats: Qs[96][68] (half of rows), Ks[192][68], Vs[192][72], Ss[96][196]
#define QS_OFF 0
#define KS_OFF (96 * 68)
#define VS_OFF (KS_OFF + 192 * 68)
#define SS_OFF (VS_OFF + 192 * 72)
#define ATTN2_SMEM ((SS_OFF + 96 * 196) * 4)

__global__ void __launch_bounds__(256) attn_mma_k(const float* __restrict__ qkv,
                                                  float* __restrict__ out) {
    extern __shared__ float sm[];
    float* Qs = sm + QS_OFF;
    float* Ks = sm + KS_OFF;
    float* Vs = sm + VS_OFF;
    float* Ss = sm + SS_OFF;

    int b = blockIdx.x / 12, h = blockIdx.x % 12;
    int tid = threadIdx.x, lane = tid & 31, w = tid >> 5;
    int g4 = lane >> 2, c4 = lane & 3;

    const float* base = qkv + (long)b * 180 * 2304 + h * 64;

    // ---- K, V fill (tf32-converted), rows 180..191 zero ----
    for (int i = tid; i < 180 * 16; i += 256) {
        int n = i >> 4, d = (i & 15) << 2;
        float4 kv = *(const float4*)(base + (long)n * 2304 + 768 + d);
        float4 vv = *(const float4*)(base + (long)n * 2304 + 1536 + d);
        float* kp = &Ks[n * 68 + d];
        kp[0] = f2tf(kv.x); kp[1] = f2tf(kv.y); kp[2] = f2tf(kv.z); kp[3] = f2tf(kv.w);
        float* vp = &Vs[n * 72 + d];
        vp[0] = f2tf(vv.x); vp[1] = f2tf(vv.y); vp[2] = f2tf(vv.z); vp[3] = f2tf(vv.w);
    }
    for (int i = tid; i < 12 * 68; i += 256) Ks[180 * 68 + i] = 0.f;
    for (int i = tid; i < 12 * 72; i += 256) Vs[180 * 72 + i] = 0.f;

    for (int half = 0; half < 2; half++) {
        int row0 = half * 96;
        __syncthreads();
        // ---- Q fill for this half (tf32) ----
        for (int i = tid; i < 96 * 16; i += 256) {
            int r = i >> 4, d = (i & 15) << 2;
            int n = row0 + r;
            float* qp = &Qs[r * 68 + d];
            if (n < 180) {
                float4 q = *(const float4*)(base + (long)n * 2304 + d);
                qp[0] = f2tf(q.x); qp[1] = f2tf(q.y); qp[2] = f2tf(q.z); qp[3] = f2tf(q.w);
            } else {
                qp[0] = 0.f; qp[1] = 0.f; qp[2] = 0.f; qp[3] = 0.f;
            }
        }
        __syncthreads();

        // ---- stage 1: S = (Q K^T) * 0.125, warp w owns n-tiles {3w,3w+1,3w+2} ----
        {
            uint32_t bf[3][8][2];
#pragma unroll
            for (int nn = 0; nn < 3; nn++) {
                int brow = (w * 3 + nn) * 8 + g4;
#pragma unroll
                for (int ks = 0; ks < 8; ks++) {
                    int k0 = ks * 8 + c4;
                    bf[nn][ks][0] = __float_as_uint(Ks[brow * 68 + k0]);
                    bf[nn][ks][1] = __float_as_uint(Ks[brow * 68 + k0 + 4]);
                }
            }
            for (int mt = 0; mt < 6; mt++) {
                uint32_t af[8][4];
                int arow = mt * 16 + g4;
#pragma unroll
                for (int ks = 0; ks < 8; ks++) {
                    int k0 = ks * 8 + c4;
                    af[ks][0] = __float_as_uint(Qs[arow * 68 + k0]);
                    af[ks][1] = __float_as_uint(Qs[(arow + 8) * 68 + k0]);
                    af[ks][2] = __float_as_uint(Qs[arow * 68 + k0 + 4]);
                    af[ks][3] = __float_as_uint(Qs[(arow + 8) * 68 + k0 + 4]);
                }
#pragma unroll
                for (int nn = 0; nn < 3; nn++) {
                    float acc[4] = {0.f, 0.f, 0.f, 0.f};
#pragma unroll
                    for (int ks = 0; ks < 8; ks++) mma_tf32(acc, af[ks], bf[nn][ks], acc);
                    int srow = mt * 16 + g4;
                    int scol = (w * 3 + nn) * 8 + 2 * c4;
                    *(float2*)&Ss[srow * 196 + scol]       = make_float2(acc[0] * 0.125f, acc[1] * 0.125f);
                    *(float2*)&Ss[(srow + 8) * 196 + scol] = make_float2(acc[2] * 0.125f, acc[3] * 0.125f);
                }
            }
        }
        __syncthreads();

        // ---- stage 2: softmax rows (warp w handles rows w, w+8, ...) ----
        for (int r = 0; r < 12; r++) {
            int row = w + 8 * r;
            float s[6];
            float mx = -1e30f;
#pragma unroll
            for (int c = 0; c < 6; c++) {
                int col = lane + 32 * c;
                s[c] = (col < 180) ? Ss[row * 196 + col] : -1e30f;
                mx = fmaxf(mx, s[c]);
            }
#pragma unroll
            for (int o = 16; o; o >>= 1) mx = fmaxf(mx, __shfl_xor_sync(0xffffffffu, mx, o));
            float sum = 0.f;
#pragma unroll
            for (int c = 0; c < 6; c++) {
                int col = lane + 32 * c;
                s[c] = (col < 180) ? __expf(s[c] - mx) : 0.f;
                sum += s[c];
            }
#pragma unroll
            for (int o = 16; o; o >>= 1) sum += __shfl_xor_sync(0xffffffffu, sum, o);
            float inv = 1.f / sum;
#pragma unroll
            for (int c = 0; c < 6; c++)
                Ss[row * 196 + lane + 32 * c] = f2tf(s[c] * inv);
        }
        __syncthreads();

        // ---- stage 3: O = P V, warp w owns output cols [8w, 8w+8) ----
        {
            int ncol = w * 8;
            uint32_t bf[24][2];
#pragma unroll
            for (int ks = 0; ks < 24; ks++) {
                int k0 = ks * 8 + c4;
                bf[ks][0] = __float_as_uint(Vs[k0 * 72 + ncol + g4]);
                bf[ks][1] = __float_as_uint(Vs[(k0 + 4) * 72 + ncol + g4]);
            }
            for (int mt = 0; mt < 6; mt++) {
                float acc[4] = {0.f, 0.f, 0.f, 0.f};
                int arow = mt * 16 + g4;
#pragma unroll
                for (int ks = 0; ks < 24; ks++) {
                    uint32_t a[4];
                    int k0 = ks * 8 + c4;
                    a[0] = __float_as_uint(Ss[arow * 196 + k0]);
                    a[1] = __float_as_uint(Ss[(arow + 8) * 196 + k0]);
                    a[2] = __float_as_uint(Ss[arow * 196 + k0 + 4]);
                    a[3] = __float_as_uint(Ss[(arow + 8) * 196 + k0 + 4]);
                    mma_tf32(acc, a, bf[ks], acc);
                }
                int grow = row0 + mt * 16 + g4;
                long gcol = h * 64 + ncol + 2 * c4;
                if (grow < 180)
                    *(float2*)(out + ((long)b * 180 + grow) * 768 + gcol) = make_float2(acc[0], acc[1]);
                if (grow + 8 < 180)
                    *(float2*)(out + ((long)b * 180 + grow + 8) * 768 + gcol) = make_float2(acc[2], acc[3]);
            }
        }
    }
}

// ---------------- primary caps: gather + squash ----------------
__global__ void caps_squash_k(const float* __restrict__ pc, float* __restrict__ caps) {
    int idx = blockIdx.x * blockDim.x + threadIdx.x; // b*1024 + i
    if (idx >= 256 * 1024) return;
    int i = idx & 1023, b = idx >> 10;
    int i32 = i >> 5, y = (i >> 3) & 3, xq = i & 7;
    const float* src = pc + (((long)b * 4 + y) * 8 + xq) * 256 + i32 * 8;
    float t[8];
    float l2 = 0.f;
#pragma unroll
    for (int e = 0; e < 8; e++) { t[e] = src[e]; l2 += t[e] * t[e]; }
    float sc = sqrtf(l2) / (1.f + l2);
#pragma unroll
    for (int e = 0; e < 8; e++) caps[(long)idx * 8 + e] = t[e] * sc;
}

// ---------------- capsule predictions u[b,i,:] ----------------
__global__ void caps_u_k(const float* __restrict__ caps, const float* __restrict__ cw,
                         float* __restrict__ u) {
    __shared__ float w_s[8 * 48];
    int i = blockIdx.x;
    for (int t = threadIdx.x; t < 384; t += 256) w_s[t] = cw[(long)i * 384 + t];
    __syncthreads();
    int b = threadIdx.x;
    float ce[8];
    const float* cp = caps + ((long)b * 1024 + i) * 8;
#pragma unroll
    for (int e = 0; e < 8; e++) ce[e] = cp[e];
    float* up = u + ((long)b * 1024 + i) * 48;
#pragma unroll 4
    for (int o = 0; o < 48; o++) {
        float s = 0.f;
#pragma unroll
        for (int e = 0; e < 8; e++) s = fmaf(ce[e], w_s[e * 48 + o], s);
        up[o] = s;
    }
}

// ---------------- dynamic routing, one block per batch element ----------------
__global__ void __launch_bounds__(256) routing_k(const float* __restrict__ u,
                                                 const float* __restrict__ br,
                                                 float* __restrict__ out) {
    __shared__ float bb[1024 * 3];
    __shared__ float S[48];
    __shared__ float v[48];
    int b = blockIdx.x, tid = threadIdx.x, lane = tid & 31;
    for (int i = tid; i < 3072; i += 256) bb[i] = br[i];
    __syncthreads();
    const float* ub = u + (long)b * 1024 * 48;

    for (int it = 0; it < 4; it++) {
        if (tid < 48) S[tid] = 0.f;
        __syncthreads();
        float acc[48];
#pragma unroll
        for (int o = 0; o < 48; o++) acc[o] = 0.f;
        for (int i = tid; i < 1024; i += 256) {
            float b0 = bb[i * 3], b1 = bb[i * 3 + 1], b2 = bb[i * 3 + 2];
            float m = fmaxf(b0, fmaxf(b1, b2));
            float e0 = expf(b0 - m), e1 = expf(b1 - m), e2 = expf(b2 - m);
            float inv = 1.f / (e0 + e1 + e2);
            float c[3] = {e0 * inv, e1 * inv, e2 * inv};
            const float* up = ub + (long)i * 48;
#pragma unroll
            for (int j = 0; j < 3; j++)
#pragma unroll
                for (int o = 0; o < 16; o++)
                    acc[j * 16 + o] = fmaf(c[j], up[j * 16 + o], acc[j * 16 + o]);
        }
#pragma unroll
        for (int o = 0; o < 48; o++) {
            float s = acc[o];
#pragma unroll
            for (int d = 16; d; d >>= 1) s += __shfl_xor_sync(0xffffffffu, s, d);
            if (lane == 0) atomicAdd(&S[o], s);
        }
        __syncthreads();
        if (tid < 3) {
            float l2 = 0.f;
            for (int o = 0; o < 16; o++) { float t = S[tid * 16 + o]; l2 += t * t; }
            float sc = sqrtf(l2) / (1.f + l2);
            for (int o = 0; o < 16; o++) v[tid * 16 + o] = S[tid * 16 + o] * sc;
            if (it == 3) out[b * 3 + tid] = l2 / (1.f + l2);  // |v| = l2/(1+l2)
        }
        __syncthreads();
        if (it < 3) {
            for (int i = tid; i < 1024; i += 256) {
                const float* up = ub + (long)i * 48;
#pragma unroll
                for (int j = 0; j < 3; j++) {
                    float s = 0.f;
#pragma unroll
                    for (int o = 0; o < 16; o++) s = fmaf(up[j * 16 + o], v[j * 16 + o], s);
                    bb[i * 3 + j] += s;
                }
            }
            __syncthreads();
        }
    }
}

// ---------------- host ----------------
extern "C" void kernel_launch(void* const* d_in, const int* in_sizes, int n_in,
                              void* d_out, int out_size) {
    const float* x_in    = (const float*)d_in[0];
    const float* conv1_w = (const float*)d_in[1];
    const float* conv2_w = (const float*)d_in[2];
    const float* pos_emb = (const float*)d_in[3];
    const float* ln1_g   = (const float*)d_in[4];
    const float* ln1_b   = (const float*)d_in[5];
    const float* qkv_w   = (const float*)d_in[6];
    const float* out_w   = (const float*)d_in[7];
    const float* out_b   = (const float*)d_in[8];
    const float* ln2_g   = (const float*)d_in[9];
    const float* ln2_b   = (const float*)d_in[10];
    const float* ff1_w   = (const float*)d_in[11];
    const float* ff1_b   = (const float*)d_in[12];
    const float* ff2_w   = (const float*)d_in[13];
    const float* ff2_b   = (const float*)d_in[14];
    const float* pcaps_w = (const float*)d_in[15];
    const float* pcaps_b = (const float*)d_in[16];
    const float* caps_w  = (const float*)d_in[17];
    const float* b_route = (const float*)d_in[18];
    float* out = (float*)d_out;

    float *col1, *wt1, *y1, *p1, *col2, *wt2, *y2, *xb, *hb, *qkv, *ao, *ff, *col3, *wtp, *pc, *caps, *u;
    cudaGetSymbolAddress((void**)&col1, g_col1);
    cudaGetSymbolAddress((void**)&wt1,  g_wt1);
    cudaGetSymbolAddress((void**)&y1,   g_y1);
    cudaGetSymbolAddress((void**)&p1,   g_p1);
    cudaGetSymbolAddress((void**)&col2, g_col2);
    cudaGetSymbolAddress((void**)&wt2,  g_wt2);
    cudaGetSymbolAddress((void**)&y2,   g_y2);
    cudaGetSymbolAddress((void**)&xb,   g_x);
    cudaGetSymbolAddress((void**)&hb,   g_h);
    cudaGetSymbolAddress((void**)&qkv,  g_qkv);
    cudaGetSymbolAddress((void**)&ao,   g_ao);
    cudaGetSymbolAddress((void**)&ff,   g_ff);
    cudaGetSymbolAddress((void**)&col3, g_col3);
    cudaGetSymbolAddress((void**)&wtp,  g_wtp);
    cudaGetSymbolAddress((void**)&pc,   g_pc);
    cudaGetSymbolAddress((void**)&caps, g_caps);
    cudaGetSymbolAddress((void**)&u,    g_u);

    cudaFuncSetAttribute(attn_mma_k, cudaFuncAttributeMaxDynamicSharedMemorySize, ATTN2_SMEM);

    // ---- ConvEmbed ----
    im2col1_k<<<(int)CDIV((long)737280 * 28, 256), 256>>>(x_in, col1);
    wtrans1<<<CDIV(64 * 28, 256), 256>>>(conv1_w, wt1);
    tgemm_k<1><<<dim3(1, 737280 / 128), 256>>>(col1, wt1, nullptr, nullptr, y1, 737280, 64, 28);
    maxpool_k<<<(int)CDIV((long)256 * 20 * 36 * 64, 256), 256>>>(y1, p1, 256, 40, 72, 64, 20, 36, nullptr);
    im2col2_k<<<(int)CDIV((long)184320 * 576, 256), 256>>>(p1, col2);
    wtrans_hwc<<<CDIV(64 * 576, 256), 256>>>(conv2_w, wt2, 64, 64);
    tgemm_k<1><<<dim3(1, 184320 / 128), 256>>>(col2, wt2, nullptr, nullptr, y2, 184320, 64, 576);
    maxpool_k<<<(int)CDIV((long)256 * 10 * 18 * 64, 256), 256>>>(y2, xb, 256, 20, 36, 64, 10, 18, pos_emb);

    // ---- Transformer: 12 shared layers applied twice ----
    const int M = 46080;
    for (int pass = 0; pass < 2; pass++) {
        for (int l = 0; l < 12; l++) {
            const float* qw  = qkv_w + (long)l * 64 * 2304;
            const float* ow  = out_w + (long)l * 768 * 64;
            const float* ob  = out_b + (long)l * 64;
            const float* f1w = ff1_w + (long)l * 64 * 256;
            const float* f1b = ff1_b + (long)l * 256;
            const float* f2w = ff2_w + (long)l * 256 * 64;
            const float* f2b = ff2_b + (long)l * 64;

            ln64_k<<<M / 8, 256>>>(xb, ln1_g + l * 64, ln1_b + l * 64, hb, M);
            tgemm_k<0><<<dim3(2304 / 64, M / 128), 256>>>(hb, qw, nullptr, nullptr, qkv, M, 2304, 64);
            attn_mma_k<<<256 * 12, 256, ATTN2_SMEM>>>(qkv, ao);
            tgemm_k<4><<<dim3(1, M / 128), 256>>>(ao, ow, ob, xb, xb, M, 64, 768);
            ln64_k<<<M / 8, 256>>>(xb, ln2_g + l * 64, ln2_b + l * 64, hb, M);
            tgemm_k<3><<<dim3(256 / 64, M / 128), 256>>>(hb, f1w, f1b, nullptr, ff, M, 256, 64);
            tgemm_k<4><<<dim3(1, M / 128), 256>>>(ff, f2w, f2b, xb, xb, M, 64, 256);
        }
    }

    // ---- PrimaryCaps + routing ----
    im2col3_k<<<(int)CDIV((long)8192 * 576, 256), 256>>>(xb, col3);
    wtrans_hwc<<<CDIV(256 * 576, 256), 256>>>(pcaps_w, wtp, 256, 64);
    tgemm_k<2><<<dim3(256 / 64, 8192 / 128), 256>>>(col3, wtp, pcaps_b, nullptr, pc, 8192, 256, 576);
    caps_squash_k<<<CDIV(256 * 1024, 256), 256>>>(pc, caps);
    caps_u_k<<<1024, 256>>>(caps, caps_w, u);
    routing_k<<<256, 256>>>(u, b_route, out);
}

// round 5
// speedup vs baseline: 2.1959x; 1.2039x over previous
#include <cuda_runtime.h>
#include <math.h>
#include <stdint.h>

#define CDIV(a,b) (((a)+(b)-1)/(b))

// ---------------- static scratch (no allocations allowed) ----------------
__device__ float g_col1[737280 * 28];        // conv1 im2col (K padded 27->28)
__device__ float g_wt1 [28 * 64];
__device__ float g_y1  [737280 * 64];        // conv1 out NHWC (B,40,72,64)
__device__ float g_p1  [184320 * 64];        // pool1 NHWC (B,20,36,64)
__device__ float g_col2[184320 * 576];       // conv2 im2col
__device__ float g_wt2 [576 * 64];
__device__ float g_y2  [184320 * 64];        // conv2 out NHWC (B,20,36,64)
__device__ float g_x   [46080 * 64];         // tokens / residual stream (B,180,64)
__device__ float g_h   [46080 * 64];         // LN output (ln2 only now)
__device__ float g_ao  [46080 * 768];        // attention output (B,180,768)
__device__ float g_ff  [46080 * 256];        // MLP hidden
__device__ float g_col3[8192 * 576];         // pcaps im2col
__device__ float g_wtp [576 * 256];
__device__ float g_pc  [8192 * 256];         // pcaps out NHWC (B,4,8,256)
__device__ float g_caps[256 * 1024 * 8];
__device__ float g_u   [256 * 1024 * 48];

// ---------------- im2col kernels ----------------
__global__ void im2col1_k(const float* __restrict__ x, float* __restrict__ col) {
    long idx = (long)blockIdx.x * blockDim.x + threadIdx.x;
    const long total = (long)737280 * 28;
    if (idx >= total) return;
    int kk = (int)(idx % 28);
    long m = idx / 28;
    if (kk == 27) { col[idx] = 0.f; return; }
    int ow = (int)(m % 72);
    int t  = (int)(m / 72);
    int oh = t % 40;
    int b  = t / 40;
    int kw = kk % 3, kh = (kk / 3) % 3, ci = kk / 9;
    int ih = oh + kh - 1, iw = ow + kw - 1;
    float v = 0.f;
    if (ih >= 0 && ih < 40 && iw >= 0 && iw < 72)
        v = x[(((long)b * 3 + ci) * 40 + ih) * 72 + iw];
    col[idx] = v;
}

__global__ void im2col2_k(const float* __restrict__ p1, float* __restrict__ col) {
    long idx = (long)blockIdx.x * blockDim.x + threadIdx.x;
    const long total = (long)184320 * 576;
    if (idx >= total) return;
    int kk = (int)(idx % 576);
    long m = idx / 576;
    int ow = (int)(m % 36);
    int t  = (int)(m / 36);
    int oh = t % 20;
    int b  = t / 20;
    int ci = kk % 64;
    int kw = (kk / 64) % 3;
    int kh = kk / 192;
    int ih = oh + kh - 1, iw = ow + kw - 1;
    float v = 0.f;
    if (ih >= 0 && ih < 20 && iw >= 0 && iw < 36)
        v = p1[(((long)b * 20 + ih) * 36 + iw) * 64 + ci];
    col[idx] = v;
}

// pcaps: input tokens g_x viewed as (B, 10, 18, 64); conv k3 s2 p0 -> (B,4,8,*)
__global__ void im2col3_k(const float* __restrict__ tk, float* __restrict__ col) {
    long idx = (long)blockIdx.x * blockDim.x + threadIdx.x;
    const long total = (long)8192 * 576;
    if (idx >= total) return;
    int kk = (int)(idx % 576);
    long m = idx / 576;
    int ow = (int)(m % 8);
    int t  = (int)(m / 8);
    int oh = t % 4;
    int b  = t / 4;
    int ci = kk % 64;
    int kw = (kk / 64) % 3;
    int kh = kk / 192;
    int ih = oh * 2 + kh, iw = ow * 2 + kw;
    col[idx] = tk[((long)b * 180 + ih * 18 + iw) * 64 + ci];
}

// ---------------- weight transposes ----------------
__global__ void wtrans1(const float* __restrict__ w, float* __restrict__ wt) {
    int i = blockIdx.x * blockDim.x + threadIdx.x;
    if (i >= 64 * 28) return;
    int o = i / 28, k = i % 28;
    wt[k * 64 + o] = (k < 27) ? w[o * 27 + k] : 0.f;
}
__global__ void wtrans_hwc(const float* __restrict__ w, float* __restrict__ wt, int O, int CI) {
    int K = CI * 9;
    int i = blockIdx.x * blockDim.x + threadIdx.x;
    if (i >= O * K) return;
    int o = i / K, r = i % K;
    int ci = r / 9, kh = (r % 9) / 3, kw = r % 3;
    wt[((kh * 3 + kw) * CI + ci) * O + o] = w[i];
}

// ---------------- tf32 helpers ----------------
__device__ __forceinline__ float f2tf(float f) {
    uint32_t r;
    asm("cvt.rna.tf32.f32 %0, %1;" : "=r"(r) : "f"(f));
    return __uint_as_float(r);
}
__device__ __forceinline__ void mma_tf32(float d[4], const uint32_t a[4], const uint32_t b[2],
                                         const float c[4]) {
    asm("mma.sync.aligned.m16n8k8.row.col.f32.tf32.tf32.f32 "
        "{%0,%1,%2,%3},{%4,%5,%6,%7},{%8,%9},{%10,%11,%12,%13};"
        : "=f"(d[0]), "=f"(d[1]), "=f"(d[2]), "=f"(d[3])
        : "r"(a[0]), "r"(a[1]), "r"(a[2]), "r"(a[3]), "r"(b[0]), "r"(b[1]),
          "f"(c[0]), "f"(c[1]), "f"(c[2]), "f"(c[3]));
}

// ---------------- tf32 tensor-core GEMM: 128x64 tile, 256 threads ----------------
// C[M,N] = epilogue(A[M,K] @ B[K,N]); EPI: 0 none, 1 relu, 2 +bias, 3 +bias gelu, 4 +bias +res
template <int EPI>
__global__ void __launch_bounds__(256) tgemm_k(const float* __restrict__ A, const float* __restrict__ Bm,
                                               const float* __restrict__ bias, const float* __restrict__ res,
                                               float* __restrict__ C, int M, int N, int K) {
    __shared__ float As[128 * 36];   // [m][k], stride 36
    __shared__ float Bs[32 * 68];    // [k][n], stride 68
    const int bm = blockIdx.y * 128, bn = blockIdx.x * 64;
    const int tid = threadIdx.x, lane = tid & 31, w = tid >> 5;
    const int g4 = lane >> 2, c4 = lane & 3;
    const int wm = (w & 3) * 32, wn = (w >> 2) * 32;

    float acc[2][4][4];
#pragma unroll
    for (int mt = 0; mt < 2; mt++)
#pragma unroll
        for (int nt = 0; nt < 4; nt++)
#pragma unroll
            for (int i = 0; i < 4; i++) acc[mt][nt][i] = 0.f;

    const int ar = tid >> 1, akb = (tid & 1) * 16;           // A load: row, k-block
    const int bk = tid >> 3, bn0 = (tid & 7) * 8;            // B load: k-row, n-offset
    const float* Arow = A + (long)(bm + ar) * K;

    for (int k0 = 0; k0 < K; k0 += 32) {
        float4 av[4], bv[2];
#pragma unroll
        for (int i = 0; i < 4; i++) {
            int gk = k0 + akb + 4 * i;
            av[i] = (gk + 4 <= K) ? *(const float4*)(Arow + gk) : make_float4(0.f, 0.f, 0.f, 0.f);
        }
        {
            int gk = k0 + bk;
            if (gk < K) {
                bv[0] = *(const float4*)(Bm + (long)gk * N + bn + bn0);
                bv[1] = *(const float4*)(Bm + (long)gk * N + bn + bn0 + 4);
            } else {
                bv[0] = make_float4(0.f, 0.f, 0.f, 0.f);
                bv[1] = bv[0];
            }
        }
        __syncthreads();
#pragma unroll
        for (int i = 0; i < 4; i++) {
            float* p = &As[ar * 36 + akb + 4 * i];
            p[0] = f2tf(av[i].x); p[1] = f2tf(av[i].y); p[2] = f2tf(av[i].z); p[3] = f2tf(av[i].w);
        }
        {
            float* p = &Bs[bk * 68 + bn0];
            p[0] = f2tf(bv[0].x); p[1] = f2tf(bv[0].y); p[2] = f2tf(bv[0].z); p[3] = f2tf(bv[0].w);
            p[4] = f2tf(bv[1].x); p[5] = f2tf(bv[1].y); p[6] = f2tf(bv[1].z); p[7] = f2tf(bv[1].w);
        }
        __syncthreads();
#pragma unroll
        for (int ks = 0; ks < 4; ks++) {
            uint32_t bfr[4][2], afr[2][4];
#pragma unroll
            for (int nt = 0; nt < 4; nt++) {
                int col = wn + nt * 8 + g4;
                bfr[nt][0] = __float_as_uint(Bs[(ks * 8 + c4) * 68 + col]);
                bfr[nt][1] = __float_as_uint(Bs[(ks * 8 + c4 + 4) * 68 + col]);
            }
#pragma unroll
            for (int mt = 0; mt < 2; mt++) {
                int base = (wm + mt * 16 + g4) * 36 + ks * 8 + c4;
                afr[mt][0] = __float_as_uint(As[base]);
                afr[mt][1] = __float_as_uint(As[base + 8 * 36]);
                afr[mt][2] = __float_as_uint(As[base + 4]);
                afr[mt][3] = __float_as_uint(As[base + 8 * 36 + 4]);
            }
#pragma unroll
            for (int mt = 0; mt < 2; mt++)
#pragma unroll
                for (int nt = 0; nt < 4; nt++)
                    mma_tf32(acc[mt][nt], afr[mt], bfr[nt], acc[mt][nt]);
        }
        __syncthreads();
    }

    // ---- epilogue ----
#pragma unroll
    for (int nt = 0; nt < 4; nt++) {
        int col = bn + wn + nt * 8 + 2 * c4;
        float b0 = 0.f, b1 = 0.f;
        if (EPI >= 2) { b0 = bias[col]; b1 = bias[col + 1]; }
#pragma unroll
        for (int mt = 0; mt < 2; mt++) {
#pragma unroll
            for (int half = 0; half < 2; half++) {
                long row = bm + wm + mt * 16 + g4 + 8 * half;
                float v0 = acc[mt][nt][2 * half], v1 = acc[mt][nt][2 * half + 1];
                if (EPI == 1) { v0 = fmaxf(v0, 0.f); v1 = fmaxf(v1, 0.f); }
                if (EPI >= 2) { v0 += b0; v1 += b1; }
                if (EPI == 3) {
                    v0 = 0.5f * v0 * (1.f + erff(v0 * 0.70710678118654752f));
                    v1 = 0.5f * v1 * (1.f + erff(v1 * 0.70710678118654752f));
                }
                if (EPI == 4) {
                    float2 r = *(const float2*)(res + row * N + col);
                    v0 += r.x; v1 += r.y;
                }
                *(float2*)(C + row * N + col) = make_float2(v0, v1);
            }
        }
    }
}

// ---------------- maxpool 3x3 s2 p1 on NHWC (+ optional pos-emb add) ----------------
__global__ void maxpool_k(const float* __restrict__ in, float* __restrict__ out,
                          int Bn, int IH, int IW, int C, int OH, int OW,
                          const float* __restrict__ pos) {
    long idx = (long)blockIdx.x * blockDim.x + threadIdx.x;
    long total = (long)Bn * OH * OW * C;
    if (idx >= total) return;
    int c = (int)(idx % C);
    long r = idx / C;
    int ow = (int)(r % OW); r /= OW;
    int oh = (int)(r % OH);
    int b  = (int)(r / OH);
    float m = -1e30f;
#pragma unroll
    for (int kh = 0; kh < 3; kh++) {
        int ih = oh * 2 - 1 + kh;
        if (ih < 0 || ih >= IH) continue;
#pragma unroll
        for (int kw = 0; kw < 3; kw++) {
            int iw = ow * 2 - 1 + kw;
            if (iw < 0 || iw >= IW) continue;
            m = fmaxf(m, in[(((long)b * IH + ih) * IW + iw) * C + c]);
        }
    }
    if (pos) m += pos[(oh * OW + ow) * C + c];
    out[idx] = m;
}

// ---------------- LayerNorm over last dim (64), one warp per token ----------------
__global__ void ln64_k(const float* __restrict__ x, const float* __restrict__ g,
                       const float* __restrict__ bta, float* __restrict__ out, int ntok) {
    int warp = (blockIdx.x * blockDim.x + threadIdx.x) >> 5;
    int lane = threadIdx.x & 31;
    if (warp >= ntok) return;
    float v0 = x[(long)warp * 64 + lane];
    float v1 = x[(long)warp * 64 + 32 + lane];
    float s = v0 + v1;
#pragma unroll
    for (int o = 16; o; o >>= 1) s += __shfl_xor_sync(0xffffffffu, s, o);
    float mean = s * (1.f / 64.f);
    float d0 = v0 - mean, d1 = v1 - mean;
    float q = d0 * d0 + d1 * d1;
#pragma unroll
    for (int o = 16; o; o >>= 1) q += __shfl_xor_sync(0xffffffffu, q, o);
    float rstd = rsqrtf(q * (1.f / 64.f) + 1e-5f);
    out[(long)warp * 64 + lane]      = d0 * rstd * g[lane] + bta[lane];
    out[(long)warp * 64 + 32 + lane] = d1 * rstd * g[lane + 32] + bta[lane + 32];
}

// ---------------- fully fused LN1 + QKV + attention: one block per (b, head) ----------------
// smem floats:
//   Qs [192][68]  tokens x d    (13056)
//   Ks [192][68]                (13056)
//   Vs [192][72]                (13824)
//   tail region (18048): phase1 = Hs[192][68] (13056) + Ws[64][68] (4352)
//                        phase2 = Ss[96][188]
#define AQ_OFF 0
#define AK_OFF (192 * 68)
#define AV_OFF (AK_OFF + 192 * 68)
#define ATAIL  (AV_OFF + 192 * 72)
#define AW_OFF (ATAIL + 192 * 68)
#define ATTN3_SMEM ((ATAIL + 18048) * 4)

__global__ void __launch_bounds__(256) attn_fused_k(const float* __restrict__ x,
                                                    const float* __restrict__ qw,
                                                    const float* __restrict__ lng,
                                                    const float* __restrict__ lnb,
                                                    float* __restrict__ out) {
    extern __shared__ float sm[];
    float* Qs = sm + AQ_OFF;
    float* Ks = sm + AK_OFF;
    float* Vs = sm + AV_OFF;
    float* Hs = sm + ATAIL;
    float* Ws = sm + AW_OFF;
    float* Ss = sm + ATAIL;

    int b = blockIdx.x / 12, h = blockIdx.x % 12;
    int tid = threadIdx.x, lane = tid & 31, w = tid >> 5;
    int g4 = lane >> 2, c4 = lane & 3;

    // ---- load raw residual tokens ----
    const float* xb = x + (long)b * 180 * 64;
    for (int i = tid; i < 180 * 16; i += 256) {
        int n = i >> 4, d = (i & 15) << 2;
        *(float4*)&Hs[n * 68 + d] = *(const float4*)(xb + n * 64 + d);
    }
    for (int i = tid; i < 12 * 68; i += 256) Hs[180 * 68 + i] = 0.f;
    __syncthreads();

    // ---- LN in place (fp32 stats, tf32 output) ----
    {
        float ga = lng[lane], gb = lng[lane + 32];
        float ba = lnb[lane], bb2 = lnb[lane + 32];
        for (int r = w; r < 180; r += 8) {
            float v0 = Hs[r * 68 + lane], v1 = Hs[r * 68 + 32 + lane];
            float s = v0 + v1;
#pragma unroll
            for (int o = 16; o; o >>= 1) s += __shfl_xor_sync(0xffffffffu, s, o);
            float mean = s * (1.f / 64.f);
            float d0 = v0 - mean, d1 = v1 - mean;
            float q = d0 * d0 + d1 * d1;
#pragma unroll
            for (int o = 16; o; o >>= 1) q += __shfl_xor_sync(0xffffffffu, q, o);
            float rstd = rsqrtf(q * (1.f / 64.f) + 1e-5f);
            Hs[r * 68 + lane]      = f2tf(d0 * rstd * ga + ba);
            Hs[r * 68 + 32 + lane] = f2tf(d1 * rstd * gb + bb2);
        }
    }

    // ---- QKV projections via MMA: order K, V, Q (Wbuf reused) ----
    const float* wbase = qw + h * 64;
#pragma unroll
    for (int m3 = 0; m3 < 3; m3++) {
        const int offs = (m3 == 0) ? 768 : (m3 == 1) ? 1536 : 0;
        float* dst = (m3 == 0) ? Ks : (m3 == 1) ? Vs : Qs;
        const int str = (m3 == 1) ? 72 : 68;
        __syncthreads();   // Wbuf free / Hs ready
        for (int i = tid; i < 64 * 16; i += 256) {
            int k = i >> 4, n0 = (i & 15) << 2;
            float4 t = *(const float4*)(wbase + offs + (long)k * 2304 + n0);
            float* p = &Ws[k * 68 + n0];
            p[0] = f2tf(t.x); p[1] = f2tf(t.y); p[2] = f2tf(t.z); p[3] = f2tf(t.w);
        }
        __syncthreads();
        uint32_t bf[8][2];
#pragma unroll
        for (int ks = 0; ks < 8; ks++) {
            bf[ks][0] = __float_as_uint(Ws[(ks * 8 + c4) * 68 + w * 8 + g4]);
            bf[ks][1] = __float_as_uint(Ws[(ks * 8 + c4 + 4) * 68 + w * 8 + g4]);
        }
#pragma unroll
        for (int mt = 0; mt < 12; mt++) {
            int arow = mt * 16 + g4;
            float acc[4] = {0.f, 0.f, 0.f, 0.f};
#pragma unroll
            for (int ks = 0; ks < 8; ks++) {
                uint32_t a[4];
                int k0 = ks * 8 + c4;
                a[0] = __float_as_uint(Hs[arow * 68 + k0]);
                a[1] = __float_as_uint(Hs[(arow + 8) * 68 + k0]);
                a[2] = __float_as_uint(Hs[arow * 68 + k0 + 4]);
                a[3] = __float_as_uint(Hs[(arow + 8) * 68 + k0 + 4]);
                mma_tf32(acc, a, bf[ks], acc);
            }
            int col = w * 8 + 2 * c4;
            *(float2*)&dst[(mt * 16 + g4) * str + col]     = make_float2(f2tf(acc[0]), f2tf(acc[1]));
            *(float2*)&dst[(mt * 16 + g4 + 8) * str + col] = make_float2(f2tf(acc[2]), f2tf(acc[3]));
        }
    }
    __syncthreads();   // Hs/Ws dead; Q/K/V ready

    float* outb = out + (long)b * 180 * 768 + h * 64;

    for (int half = 0; half < 2; half++) {
        int row0 = half * 96;
        if (half) __syncthreads();   // Ss reuse between halves

        // ---- stage 1: S = (Q K^T) * 0.125, warp w owns n-tiles {3w..3w+2} ----
        {
            uint32_t bf[3][8][2];
#pragma unroll
            for (int nn = 0; nn < 3; nn++) {
                int brow = (w * 3 + nn) * 8 + g4;
#pragma unroll
                for (int ks = 0; ks < 8; ks++) {
                    int k0 = ks * 8 + c4;
                    bf[nn][ks][0] = __float_as_uint(Ks[brow * 68 + k0]);
                    bf[nn][ks][1] = __float_as_uint(Ks[brow * 68 + k0 + 4]);
                }
            }
            for (int mt = 0; mt < 6; mt++) {
                uint32_t af[8][4];
                int arow = row0 + mt * 16 + g4;
#pragma unroll
                for (int ks = 0; ks < 8; ks++) {
                    int k0 = ks * 8 + c4;
                    af[ks][0] = __float_as_uint(Qs[arow * 68 + k0]);
                    af[ks][1] = __float_as_uint(Qs[(arow + 8) * 68 + k0]);
                    af[ks][2] = __float_as_uint(Qs[arow * 68 + k0 + 4]);
                    af[ks][3] = __float_as_uint(Qs[(arow + 8) * 68 + k0 + 4]);
                }
#pragma unroll
                for (int nn = 0; nn < 3; nn++) {
                    float acc[4] = {0.f, 0.f, 0.f, 0.f};
#pragma unroll
                    for (int ks = 0; ks < 8; ks++) mma_tf32(acc, af[ks], bf[nn][ks], acc);
                    int srow = mt * 16 + g4;
                    int scol = (w * 3 + nn) * 8 + 2 * c4;
                    if (scol < 188) {
                        *(float2*)&Ss[srow * 188 + scol]       = make_float2(acc[0] * 0.125f, acc[1] * 0.125f);
                        *(float2*)&Ss[(srow + 8) * 188 + scol] = make_float2(acc[2] * 0.125f, acc[3] * 0.125f);
                    }
                }
            }
        }
        __syncthreads();

        // ---- stage 2: softmax rows (warp w handles rows w, w+8, ...) ----
        for (int r = 0; r < 12; r++) {
            int row = w + 8 * r;
            float s[6];
            float mx = -1e30f;
#pragma unroll
            for (int c = 0; c < 6; c++) {
                int col = lane + 32 * c;
                s[c] = (col < 180) ? Ss[row * 188 + col] : -1e30f;
                mx = fmaxf(mx, s[c]);
            }
#pragma unroll
            for (int o = 16; o; o >>= 1) mx = fmaxf(mx, __shfl_xor_sync(0xffffffffu, mx, o));
            float sum = 0.f;
#pragma unroll
            for (int c = 0; c < 6; c++) {
                int col = lane + 32 * c;
                s[c] = (col < 180) ? __expf(s[c] - mx) : 0.f;
                sum += s[c];
            }
#pragma unroll
            for (int o = 16; o; o >>= 1) sum += __shfl_xor_sync(0xffffffffu, sum, o);
            float inv = 1.f / sum;
#pragma unroll
            for (int c = 0; c < 6; c++) {
                int col = lane + 32 * c;
                if (col < 188) Ss[row * 188 + col] = f2tf(s[c] * inv);
            }
        }
        __syncthreads();

        // ---- stage 3: O = P V (23 k-steps cover j<184; cols 180..187 are 0) ----
        {
            int ncol = w * 8;
            uint32_t bf[23][2];
#pragma unroll
            for (int ks = 0; ks < 23; ks++) {
                int k0 = ks * 8 + c4;
                bf[ks][0] = __float_as_uint(Vs[k0 * 72 + ncol + g4]);
                bf[ks][1] = __float_as_uint(Vs[(k0 + 4) * 72 + ncol + g4]);
            }
            for (int mt = 0; mt < 6; mt++) {
                float acc[4] = {0.f, 0.f, 0.f, 0.f};
                int arow = mt * 16 + g4;
#pragma unroll
                for (int ks = 0; ks < 23; ks++) {
                    uint32_t a[4];
                    int k0 = ks * 8 + c4;
                    a[0] = __float_as_uint(Ss[arow * 188 + k0]);
                    a[1] = __float_as_uint(Ss[(arow + 8) * 188 + k0]);
                    a[2] = __float_as_uint(Ss[arow * 188 + k0 + 4]);
                    a[3] = __float_as_uint(Ss[(arow + 8) * 188 + k0 + 4]);
                    mma_tf32(acc, a, bf[ks], acc);
                }
                int grow = row0 + mt * 16 + g4;
                long gcol = ncol + 2 * c4;
                if (grow < 180)
                    *(float2*)(outb + (long)grow * 768 + gcol) = make_float2(acc[0], acc[1]);
                if (grow + 8 < 180)
                    *(float2*)(outb + (long)(grow + 8) * 768 + gcol) = make_float2(acc[2], acc[3]);
            }
        }
    }
}

// ---------------- primary caps: gather + squash ----------------
__global__ void caps_squash_k(const float* __restrict__ pc, float* __restrict__ caps) {
    int idx = blockIdx.x * blockDim.x + threadIdx.x; // b*1024 + i
    if (idx >= 256 * 1024) return;
    int i = idx & 1023, b = idx >> 10;
    int i32 = i >> 5, y = (i >> 3) & 3, xq = i & 7;
    const float* src = pc + (((long)b * 4 + y) * 8 + xq) * 256 + i32 * 8;
    float t[8];
    float l2 = 0.f;
#pragma unroll
    for (int e = 0; e < 8; e++) { t[e] = src[e]; l2 += t[e] * t[e]; }
    float sc = sqrtf(l2) / (1.f + l2);
#pragma unroll
    for (int e = 0; e < 8; e++) caps[(long)idx * 8 + e] = t[e] * sc;
}

// ---------------- capsule predictions u[b,i,:] ----------------
__global__ void caps_u_k(const float* __restrict__ caps, const float* __restrict__ cw,
                         float* __restrict__ u) {
    __shared__ float w_s[8 * 48];
    int i = blockIdx.x;
    for (int t = threadIdx.x; t < 384; t += 256) w_s[t] = cw[(long)i * 384 + t];
    __syncthreads();
    int b = threadIdx.x;
    float ce[8];
    const float* cp = caps + ((long)b * 1024 + i) * 8;
#pragma unroll
    for (int e = 0; e < 8; e++) ce[e] = cp[e];
    float* up = u + ((long)b * 1024 + i) * 48;
#pragma unroll 4
    for (int o = 0; o < 48; o++) {
        float s = 0.f;
#pragma unroll
        for (int e = 0; e < 8; e++) s = fmaf(ce[e], w_s[e * 48 + o], s);
        up[o] = s;
    }
}

// ---------------- dynamic routing, one block per batch element ----------------
__global__ void __launch_bounds__(256) routing_k(const float* __restrict__ u,
                                                 const float* __restrict__ br,
                                                 float* __restrict__ out) {
    __shared__ float bb[1024 * 3];
    __shared__ float S[48];
    __shared__ float v[48];
    int b = blockIdx.x, tid = threadIdx.x, lane = tid & 31;
    for (int i = tid; i < 3072; i += 256) bb[i] = br[i];
    __syncthreads();
    const float* ub = u + (long)b * 1024 * 48;

    for (int it = 0; it < 4; it++) {
        if (tid < 48) S[tid] = 0.f;
        __syncthreads();
        float acc[48];
#pragma unroll
        for (int o = 0; o < 48; o++) acc[o] = 0.f;
        for (int i = tid; i < 1024; i += 256) {
            float b0 = bb[i * 3], b1 = bb[i * 3 + 1], b2 = bb[i * 3 + 2];
            float m = fmaxf(b0, fmaxf(b1, b2));
            float e0 = expf(b0 - m), e1 = expf(b1 - m), e2 = expf(b2 - m);
            float inv = 1.f / (e0 + e1 + e2);
            float c[3] = {e0 * inv, e1 * inv, e2 * inv};
            const float* up = ub + (long)i * 48;
#pragma unroll
            for (int j = 0; j < 3; j++)
#pragma unroll
                for (int o = 0; o < 16; o++)
                    acc[j * 16 + o] = fmaf(c[j], up[j * 16 + o], acc[j * 16 + o]);
        }
#pragma unroll
        for (int o = 0; o < 48; o++) {
            float s = acc[o];
#pragma unroll
            for (int d = 16; d; d >>= 1) s += __shfl_xor_sync(0xffffffffu, s, d);
            if (lane == 0) atomicAdd(&S[o], s);
        }
        __syncthreads();
        if (tid < 3) {
            float l2 = 0.f;
            for (int o = 0; o < 16; o++) { float t = S[tid * 16 + o]; l2 += t * t; }
            float sc = sqrtf(l2) / (1.f + l2);
            for (int o = 0; o < 16; o++) v[tid * 16 + o] = S[tid * 16 + o] * sc;
            if (it == 3) out[b * 3 + tid] = l2 / (1.f + l2);  // |v| = l2/(1+l2)
        }
        __syncthreads();
        if (it < 3) {
            for (int i = tid; i < 1024; i += 256) {
                const float* up = ub + (long)i * 48;
#pragma unroll
                for (int j = 0; j < 3; j++) {
                    float s = 0.f;
#pragma unroll
                    for (int o = 0; o < 16; o++) s = fmaf(up[j * 16 + o], v[j * 16 + o], s);
                    bb[i * 3 + j] += s;
                }
            }
            __syncthreads();
        }
    }
}

// ---------------- host ----------------
extern "C" void kernel_launch(void* const* d_in, const int* in_sizes, int n_in,
                              void* d_out, int out_size) {
    const float* x_in    = (const float*)d_in[0];
    const float* conv1_w = (const float*)d_in[1];
    const float* conv2_w = (const float*)d_in[2];
    const float* pos_emb = (const float*)d_in[3];
    const float* ln1_g   = (const float*)d_in[4];
    const float* ln1_b   = (const float*)d_in[5];
    const float* qkv_w   = (const float*)d_in[6];
    const float* out_w   = (const float*)d_in[7];
    const float* out_b   = (const float*)d_in[8];
    const float* ln2_g   = (const float*)d_in[9];
    const float* ln2_b   = (const float*)d_in[10];
    const float* ff1_w   = (const float*)d_in[11];
    const float* ff1_b   = (const float*)d_in[12];
    const float* ff2_w   = (const float*)d_in[13];
    const float* ff2_b   = (const float*)d_in[14];
    const float* pcaps_w = (const float*)d_in[15];
    const float* pcaps_b = (const float*)d_in[16];
    const float* caps_w  = (const float*)d_in[17];
    const float* b_route = (const float*)d_in[18];
    float* out = (float*)d_out;

    float *col1, *wt1, *y1, *p1, *col2, *wt2, *y2, *xb, *hb, *ao, *ff, *col3, *wtp, *pc, *caps, *u;
    cudaGetSymbolAddress((void**)&col1, g_col1);
    cudaGetSymbolAddress((void**)&wt1,  g_wt1);
    cudaGetSymbolAddress((void**)&y1,   g_y1);
    cudaGetSymbolAddress((void**)&p1,   g_p1);
    cudaGetSymbolAddress((void**)&col2, g_col2);
    cudaGetSymbolAddress((void**)&wt2,  g_wt2);
    cudaGetSymbolAddress((void**)&y2,   g_y2);
    cudaGetSymbolAddress((void**)&xb,   g_x);
    cudaGetSymbolAddress((void**)&hb,   g_h);
    cudaGetSymbolAddress((void**)&ao,   g_ao);
    cudaGetSymbolAddress((void**)&ff,   g_ff);
    cudaGetSymbolAddress((void**)&col3, g_col3);
    cudaGetSymbolAddress((void**)&wtp,  g_wtp);
    cudaGetSymbolAddress((void**)&pc,   g_pc);
    cudaGetSymbolAddress((void**)&caps, g_caps);
    cudaGetSymbolAddress((void**)&u,    g_u);

    cudaFuncSetAttribute(attn_fused_k, cudaFuncAttributeMaxDynamicSharedMemorySize, ATTN3_SMEM);

    // ---- ConvEmbed ----
    im2col1_k<<<(int)CDIV((long)737280 * 28, 256), 256>>>(x_in, col1);
    wtrans1<<<CDIV(64 * 28, 256), 256>>>(conv1_w, wt1);
    tgemm_k<1><<<dim3(1, 737280 / 128), 256>>>(col1, wt1, nullptr, nullptr, y1, 737280, 64, 28);
    maxpool_k<<<(int)CDIV((long)256 * 20 * 36 * 64, 256), 256>>>(y1, p1, 256, 40, 72, 64, 20, 36, nullptr);
    im2col2_k<<<(int)CDIV((long)184320 * 576, 256), 256>>>(p1, col2);
    wtrans_hwc<<<CDIV(64 * 576, 256), 256>>>(conv2_w, wt2, 64, 64);
    tgemm_k<1><<<dim3(1, 184320 / 128), 256>>>(col2, wt2, nullptr, nullptr, y2, 184320, 64, 576);
    maxpool_k<<<(int)CDIV((long)256 * 10 * 18 * 64, 256), 256>>>(y2, xb, 256, 20, 36, 64, 10, 18, pos_emb);

    // ---- Transformer: 12 shared layers applied twice ----
    const int M = 46080;
    for (int pass = 0; pass < 2; pass++) {
        for (int l = 0; l < 12; l++) {
            const float* qw  = qkv_w + (long)l * 64 * 2304;
            const float* ow  = out_w + (long)l * 768 * 64;
            const float* ob  = out_b + (long)l * 64;
            const float* f1w = ff1_w + (long)l * 64 * 256;
            const float* f1b = ff1_b + (long)l * 256;
            const float* f2w = ff2_w + (long)l * 256 * 64;
            const float* f2b = ff2_b + (long)l * 64;

            attn_fused_k<<<256 * 12, 256, ATTN3_SMEM>>>(xb, qw, ln1_g + l * 64, ln1_b + l * 64, ao);
            tgemm_k<4><<<dim3(1, M / 128), 256>>>(ao, ow, ob, xb, xb, M, 64, 768);
            ln64_k<<<M / 8, 256>>>(xb, ln2_g + l * 64, ln2_b + l * 64, hb, M);
            tgemm_k<3><<<dim3(256 / 64, M / 128), 256>>>(hb, f1w, f1b, nullptr, ff, M, 256, 64);
            tgemm_k<4><<<dim3(1, M / 128), 256>>>(ff, f2w, f2b, xb, xb, M, 64, 256);
        }
    }

    // ---- PrimaryCaps + routing ----
    im2col3_k<<<(int)CDIV((long)8192 * 576, 256), 256>>>(xb, col3);
    wtrans_hwc<<<CDIV(256 * 576, 256), 256>>>(pcaps_w, wtp, 256, 64);
    tgemm_k<2><<<dim3(256 / 64, 8192 / 128), 256>>>(col3, wtp, pcaps_b, nullptr, pc, 8192, 256, 576);
    caps_squash_k<<<CDIV(256 * 1024, 256), 256>>>(pc, caps);
    caps_u_k<<<1024, 256>>>(caps, caps_w, u);
    routing_k<<<256, 256>>>(u, b_route, out);
}

// round 6
// speedup vs baseline: 2.3184x; 1.0558x over previous
#include <cuda_runtime.h>
#include <math.h>
#include <stdint.h>

#define CDIV(a,b) (((a)+(b)-1)/(b))

// ---------------- static scratch (no allocations allowed) ----------------
__device__ float g_col1[737280 * 28];        // conv1 im2col (K padded 27->28)
__device__ float g_wt1 [28 * 64];
__device__ float g_y1  [737280 * 64];        // conv1 out NHWC (B,40,72,64)
__device__ float g_p1  [184320 * 64];        // pool1 NHWC (B,20,36,64)
__device__ float g_col2[184320 * 576];       // conv2 im2col
__device__ float g_wt2 [576 * 64];
__device__ float g_y2  [184320 * 64];        // conv2 out NHWC (B,20,36,64)
__device__ float g_x   [46080 * 64];         // tokens / residual stream (B,180,64)
__device__ float g_ao  [46080 * 768];        // attention output (B,180,768)
__device__ float g_col3[8192 * 576];         // pcaps im2col
__device__ float g_wtp [576 * 256];
__device__ float g_pc  [8192 * 256];         // pcaps out NHWC (B,4,8,256)
__device__ float g_caps[256 * 1024 * 8];
__device__ float g_u   [256 * 1024 * 48];

// ---------------- im2col kernels ----------------
__global__ void im2col1_k(const float* __restrict__ x, float* __restrict__ col) {
    long idx = (long)blockIdx.x * blockDim.x + threadIdx.x;
    const long total = (long)737280 * 28;
    if (idx >= total) return;
    int kk = (int)(idx % 28);
    long m = idx / 28;
    if (kk == 27) { col[idx] = 0.f; return; }
    int ow = (int)(m % 72);
    int t  = (int)(m / 72);
    int oh = t % 40;
    int b  = t / 40;
    int kw = kk % 3, kh = (kk / 3) % 3, ci = kk / 9;
    int ih = oh + kh - 1, iw = ow + kw - 1;
    float v = 0.f;
    if (ih >= 0 && ih < 40 && iw >= 0 && iw < 72)
        v = x[(((long)b * 3 + ci) * 40 + ih) * 72 + iw];
    col[idx] = v;
}

__global__ void im2col2_k(const float* __restrict__ p1, float* __restrict__ col) {
    long idx = (long)blockIdx.x * blockDim.x + threadIdx.x;
    const long total = (long)184320 * 576;
    if (idx >= total) return;
    int kk = (int)(idx % 576);
    long m = idx / 576;
    int ow = (int)(m % 36);
    int t  = (int)(m / 36);
    int oh = t % 20;
    int b  = t / 20;
    int ci = kk % 64;
    int kw = (kk / 64) % 3;
    int kh = kk / 192;
    int ih = oh + kh - 1, iw = ow + kw - 1;
    float v = 0.f;
    if (ih >= 0 && ih < 20 && iw >= 0 && iw < 36)
        v = p1[(((long)b * 20 + ih) * 36 + iw) * 64 + ci];
    col[idx] = v;
}

// pcaps: input tokens g_x viewed as (B, 10, 18, 64); conv k3 s2 p0 -> (B,4,8,*)
__global__ void im2col3_k(const float* __restrict__ tk, float* __restrict__ col) {
    long idx = (long)blockIdx.x * blockDim.x + threadIdx.x;
    const long total = (long)8192 * 576;
    if (idx >= total) return;
    int kk = (int)(idx % 576);
    long m = idx / 576;
    int ow = (int)(m % 8);
    int t  = (int)(m / 8);
    int oh = t % 4;
    int b  = t / 4;
    int ci = kk % 64;
    int kw = (kk / 64) % 3;
    int kh = kk / 192;
    int ih = oh * 2 + kh, iw = ow * 2 + kw;
    col[idx] = tk[((long)b * 180 + ih * 18 + iw) * 64 + ci];
}

// ---------------- weight transposes ----------------
__global__ void wtrans1(const float* __restrict__ w, float* __restrict__ wt) {
    int i = blockIdx.x * blockDim.x + threadIdx.x;
    if (i >= 64 * 28) return;
    int o = i / 28, k = i % 28;
    wt[k * 64 + o] = (k < 27) ? w[o * 27 + k] : 0.f;
}
__global__ void wtrans_hwc(const float* __restrict__ w, float* __restrict__ wt, int O, int CI) {
    int K = CI * 9;
    int i = blockIdx.x * blockDim.x + threadIdx.x;
    if (i >= O * K) return;
    int o = i / K, r = i % K;
    int ci = r / 9, kh = (r % 9) / 3, kw = r % 3;
    wt[((kh * 3 + kw) * CI + ci) * O + o] = w[i];
}

// ---------------- tf32 helpers ----------------
__device__ __forceinline__ float f2tf(float f) {
    uint32_t r;
    asm("cvt.rna.tf32.f32 %0, %1;" : "=r"(r) : "f"(f));
    return __uint_as_float(r);
}
__device__ __forceinline__ uint32_t f2tfu(float f) {
    uint32_t r;
    asm("cvt.rna.tf32.f32 %0, %1;" : "=r"(r) : "f"(f));
    return r;
}
__device__ __forceinline__ void mma_tf32(float d[4], const uint32_t a[4], const uint32_t b[2],
                                         const float c[4]) {
    asm("mma.sync.aligned.m16n8k8.row.col.f32.tf32.tf32.f32 "
        "{%0,%1,%2,%3},{%4,%5,%6,%7},{%8,%9},{%10,%11,%12,%13};"
        : "=f"(d[0]), "=f"(d[1]), "=f"(d[2]), "=f"(d[3])
        : "r"(a[0]), "r"(a[1]), "r"(a[2]), "r"(a[3]), "r"(b[0]), "r"(b[1]),
          "f"(c[0]), "f"(c[1]), "f"(c[2]), "f"(c[3]));
}

// ---------------- tf32 tensor-core GEMM: 128x64 tile, 256 threads ----------------
// EPI: 0 none, 1 relu, 2 +bias, 3 +bias gelu, 4 +bias +res
template <int EPI>
__global__ void __launch_bounds__(256) tgemm_k(const float* __restrict__ A, const float* __restrict__ Bm,
                                               const float* __restrict__ bias, const float* __restrict__ res,
                                               float* __restrict__ C, int M, int N, int K) {
    __shared__ float As[128 * 36];   // [m][k], stride 36
    __shared__ float Bs[32 * 68];    // [k][n], stride 68
    const int bm = blockIdx.y * 128, bn = blockIdx.x * 64;
    const int tid = threadIdx.x, lane = tid & 31, w = tid >> 5;
    const int g4 = lane >> 2, c4 = lane & 3;
    const int wm = (w & 3) * 32, wn = (w >> 2) * 32;

    float acc[2][4][4];
#pragma unroll
    for (int mt = 0; mt < 2; mt++)
#pragma unroll
        for (int nt = 0; nt < 4; nt++)
#pragma unroll
            for (int i = 0; i < 4; i++) acc[mt][nt][i] = 0.f;

    const int ar = tid >> 1, akb = (tid & 1) * 16;
    const int bk = tid >> 3, bn0 = (tid & 7) * 8;
    const float* Arow = A + (long)(bm + ar) * K;

    for (int k0 = 0; k0 < K; k0 += 32) {
        float4 av[4], bv[2];
#pragma unroll
        for (int i = 0; i < 4; i++) {
            int gk = k0 + akb + 4 * i;
            av[i] = (gk + 4 <= K) ? *(const float4*)(Arow + gk) : make_float4(0.f, 0.f, 0.f, 0.f);
        }
        {
            int gk = k0 + bk;
            if (gk < K) {
                bv[0] = *(const float4*)(Bm + (long)gk * N + bn + bn0);
                bv[1] = *(const float4*)(Bm + (long)gk * N + bn + bn0 + 4);
            } else {
                bv[0] = make_float4(0.f, 0.f, 0.f, 0.f);
                bv[1] = bv[0];
            }
        }
        __syncthreads();
#pragma unroll
        for (int i = 0; i < 4; i++) {
            float* p = &As[ar * 36 + akb + 4 * i];
            p[0] = f2tf(av[i].x); p[1] = f2tf(av[i].y); p[2] = f2tf(av[i].z); p[3] = f2tf(av[i].w);
        }
        {
            float* p = &Bs[bk * 68 + bn0];
            p[0] = f2tf(bv[0].x); p[1] = f2tf(bv[0].y); p[2] = f2tf(bv[0].z); p[3] = f2tf(bv[0].w);
            p[4] = f2tf(bv[1].x); p[5] = f2tf(bv[1].y); p[6] = f2tf(bv[1].z); p[7] = f2tf(bv[1].w);
        }
        __syncthreads();
#pragma unroll
        for (int ks = 0; ks < 4; ks++) {
            uint32_t bfr[4][2], afr[2][4];
#pragma unroll
            for (int nt = 0; nt < 4; nt++) {
                int col = wn + nt * 8 + g4;
                bfr[nt][0] = __float_as_uint(Bs[(ks * 8 + c4) * 68 + col]);
                bfr[nt][1] = __float_as_uint(Bs[(ks * 8 + c4 + 4) * 68 + col]);
            }
#pragma unroll
            for (int mt = 0; mt < 2; mt++) {
                int base = (wm + mt * 16 + g4) * 36 + ks * 8 + c4;
                afr[mt][0] = __float_as_uint(As[base]);
                afr[mt][1] = __float_as_uint(As[base + 8 * 36]);
                afr[mt][2] = __float_as_uint(As[base + 4]);
                afr[mt][3] = __float_as_uint(As[base + 8 * 36 + 4]);
            }
#pragma unroll
            for (int mt = 0; mt < 2; mt++)
#pragma unroll
                for (int nt = 0; nt < 4; nt++)
                    mma_tf32(acc[mt][nt], afr[mt], bfr[nt], acc[mt][nt]);
        }
        __syncthreads();
    }

#pragma unroll
    for (int nt = 0; nt < 4; nt++) {
        int col = bn + wn + nt * 8 + 2 * c4;
        float b0 = 0.f, b1 = 0.f;
        if (EPI >= 2) { b0 = bias[col]; b1 = bias[col + 1]; }
#pragma unroll
        for (int mt = 0; mt < 2; mt++) {
#pragma unroll
            for (int half = 0; half < 2; half++) {
                long row = bm + wm + mt * 16 + g4 + 8 * half;
                float v0 = acc[mt][nt][2 * half], v1 = acc[mt][nt][2 * half + 1];
                if (EPI == 1) { v0 = fmaxf(v0, 0.f); v1 = fmaxf(v1, 0.f); }
                if (EPI >= 2) { v0 += b0; v1 += b1; }
                if (EPI == 3) {
                    v0 = 0.5f * v0 * (1.f + erff(v0 * 0.70710678118654752f));
                    v1 = 0.5f * v1 * (1.f + erff(v1 * 0.70710678118654752f));
                }
                if (EPI == 4) {
                    float2 r = *(const float2*)(res + row * N + col);
                    v0 += r.x; v1 += r.y;
                }
                *(float2*)(C + row * N + col) = make_float2(v0, v1);
            }
        }
    }
}

// ---------------- maxpool 3x3 s2 p1 on NHWC (+ optional pos-emb add) ----------------
__global__ void maxpool_k(const float* __restrict__ in, float* __restrict__ out,
                          int Bn, int IH, int IW, int C, int OH, int OW,
                          const float* __restrict__ pos) {
    long idx = (long)blockIdx.x * blockDim.x + threadIdx.x;
    long total = (long)Bn * OH * OW * C;
    if (idx >= total) return;
    int c = (int)(idx % C);
    long r = idx / C;
    int ow = (int)(r % OW); r /= OW;
    int oh = (int)(r % OH);
    int b  = (int)(r / OH);
    float m = -1e30f;
#pragma unroll
    for (int kh = 0; kh < 3; kh++) {
        int ih = oh * 2 - 1 + kh;
        if (ih < 0 || ih >= IH) continue;
#pragma unroll
        for (int kw = 0; kw < 3; kw++) {
            int iw = ow * 2 - 1 + kw;
            if (iw < 0 || iw >= IW) continue;
            m = fmaxf(m, in[(((long)b * IH + ih) * IW + iw) * C + c]);
        }
    }
    if (pos) m += pos[(oh * OW + ow) * C + c];
    out[idx] = m;
}

// ---------------- fused LN1 + QKV + attention v2 ----------------
// smem floats: Qs[192][68], Ks[192][68], Vs[192][68],
//   tail: phase1 Hs[192][68] (13056), phase2 Ss[96][188] (18048)
#define AQ_OFF 0
#define AK_OFF (192 * 68)
#define AV_OFF (2 * 192 * 68)
#define ATAIL  (3 * 192 * 68)
#define ATTN3_SMEM ((ATAIL + 96 * 188) * 4)

__global__ void __launch_bounds__(256) attn_fused_k(const float* __restrict__ x,
                                                    const float* __restrict__ qw,
                                                    const float* __restrict__ lng,
                                                    const float* __restrict__ lnb,
                                                    float* __restrict__ out) {
    extern __shared__ float sm[];
    float* Qs = sm + AQ_OFF;
    float* Ks = sm + AK_OFF;
    float* Vs = sm + AV_OFF;
    float* Hs = sm + ATAIL;
    float* Ss = sm + ATAIL;

    int b = blockIdx.x / 12, h = blockIdx.x % 12;
    int tid = threadIdx.x, lane = tid & 31, w = tid >> 5;
    int g4 = lane >> 2, c4 = lane & 3;

    // ---- prefetch W for K (m3=0) straight from gmem (L2-hot) ----
    const float* wcol = qw + h * 64 + w * 8 + g4;   // fixed column for this thread
    float wraw[16];
#pragma unroll
    for (int i = 0; i < 16; i++) {
        int row = (i >> 1) * 8 + c4 + (i & 1) * 4;
        wraw[i] = __ldg(wcol + 768 + (long)row * 2304);
    }

    // ---- load raw residual tokens ----
    const float* xb = x + (long)b * 180 * 64;
    for (int i = tid; i < 180 * 16; i += 256) {
        int n = i >> 4, d = (i & 15) << 2;
        *(float4*)&Hs[n * 68 + d] = *(const float4*)(xb + n * 64 + d);
    }
    for (int i = tid; i < 12 * 68; i += 256) Hs[180 * 68 + i] = 0.f;
    __syncthreads();

    // ---- LN in place (fp32 stats, tf32 output) ----
    {
        float ga = lng[lane], gb = lng[lane + 32];
        float ba = lnb[lane], bb2 = lnb[lane + 32];
        for (int r = w; r < 180; r += 8) {
            float v0 = Hs[r * 68 + lane], v1 = Hs[r * 68 + 32 + lane];
            float s = v0 + v1;
#pragma unroll
            for (int o = 16; o; o >>= 1) s += __shfl_xor_sync(0xffffffffu, s, o);
            float mean = s * (1.f / 64.f);
            float d0 = v0 - mean, d1 = v1 - mean;
            float q = d0 * d0 + d1 * d1;
#pragma unroll
            for (int o = 16; o; o >>= 1) q += __shfl_xor_sync(0xffffffffu, q, o);
            float rstd = rsqrtf(q * (1.f / 64.f) + 1e-5f);
            Hs[r * 68 + lane]      = f2tf(d0 * rstd * ga + ba);
            Hs[r * 68 + 32 + lane] = f2tf(d1 * rstd * gb + bb2);
        }
    }
    __syncthreads();

    // ---- QKV projections: K, V, Q back-to-back, no intervening syncs ----
#pragma unroll
    for (int m3 = 0; m3 < 3; m3++) {
        uint32_t bf[8][2];
#pragma unroll
        for (int i = 0; i < 16; i++) bf[i >> 1][i & 1] = f2tfu(wraw[i]);
        if (m3 < 2) {
            int offs = (m3 == 0) ? 1536 : 0;   // next: V then Q
#pragma unroll
            for (int i = 0; i < 16; i++) {
                int row = (i >> 1) * 8 + c4 + (i & 1) * 4;
                wraw[i] = __ldg(wcol + offs + (long)row * 2304);
            }
        }
        float* dst = (m3 == 0) ? Ks : (m3 == 1) ? Vs : Qs;
#pragma unroll
        for (int mt = 0; mt < 12; mt++) {
            int arow = mt * 16 + g4;
            float acc[4] = {0.f, 0.f, 0.f, 0.f};
#pragma unroll
            for (int ks = 0; ks < 8; ks++) {
                uint32_t a[4];
                int k0 = ks * 8 + c4;
                a[0] = __float_as_uint(Hs[arow * 68 + k0]);
                a[1] = __float_as_uint(Hs[(arow + 8) * 68 + k0]);
                a[2] = __float_as_uint(Hs[arow * 68 + k0 + 4]);
                a[3] = __float_as_uint(Hs[(arow + 8) * 68 + k0 + 4]);
                mma_tf32(acc, a, bf[ks], acc);
            }
            int col = w * 8 + 2 * c4;
            *(float2*)&dst[(mt * 16 + g4) * 68 + col]     = make_float2(f2tf(acc[0]), f2tf(acc[1]));
            *(float2*)&dst[(mt * 16 + g4 + 8) * 68 + col] = make_float2(f2tf(acc[2]), f2tf(acc[3]));
        }
    }
    __syncthreads();   // Hs dead; Q/K/V ready

    float* outb = out + (long)b * 180 * 768 + h * 64;

    for (int half = 0; half < 2; half++) {
        int row0 = half * 96;
        if (half) __syncthreads();   // Ss reuse between halves

        // ---- stage 1: S = (Q K^T) * 0.125 ----
        {
            uint32_t bf[3][8][2];
#pragma unroll
            for (int nn = 0; nn < 3; nn++) {
                int brow = (w * 3 + nn) * 8 + g4;
#pragma unroll
                for (int ks = 0; ks < 8; ks++) {
                    int k0 = ks * 8 + c4;
                    bf[nn][ks][0] = __float_as_uint(Ks[brow * 68 + k0]);
                    bf[nn][ks][1] = __float_as_uint(Ks[brow * 68 + k0 + 4]);
                }
            }
            for (int mt = 0; mt < 6; mt++) {
                uint32_t af[8][4];
                int arow = row0 + mt * 16 + g4;
#pragma unroll
                for (int ks = 0; ks < 8; ks++) {
                    int k0 = ks * 8 + c4;
                    af[ks][0] = __float_as_uint(Qs[arow * 68 + k0]);
                    af[ks][1] = __float_as_uint(Qs[(arow + 8) * 68 + k0]);
                    af[ks][2] = __float_as_uint(Qs[arow * 68 + k0 + 4]);
                    af[ks][3] = __float_as_uint(Qs[(arow + 8) * 68 + k0 + 4]);
                }
#pragma unroll
                for (int nn = 0; nn < 3; nn++) {
                    float acc[4] = {0.f, 0.f, 0.f, 0.f};
#pragma unroll
                    for (int ks = 0; ks < 8; ks++) mma_tf32(acc, af[ks], bf[nn][ks], acc);
                    int srow = mt * 16 + g4;
                    int scol = (w * 3 + nn) * 8 + 2 * c4;
                    if (scol < 188) {
                        *(float2*)&Ss[srow * 188 + scol]       = make_float2(acc[0] * 0.125f, acc[1] * 0.125f);
                        *(float2*)&Ss[(srow + 8) * 188 + scol] = make_float2(acc[2] * 0.125f, acc[3] * 0.125f);
                    }
                }
            }
        }
        __syncthreads();

        // ---- stage 2: softmax ----
        for (int r = 0; r < 12; r++) {
            int row = w + 8 * r;
            float s[6];
            float mx = -1e30f;
#pragma unroll
            for (int c = 0; c < 6; c++) {
                int col = lane + 32 * c;
                s[c] = (col < 180) ? Ss[row * 188 + col] : -1e30f;
                mx = fmaxf(mx, s[c]);
            }
#pragma unroll
            for (int o = 16; o; o >>= 1) mx = fmaxf(mx, __shfl_xor_sync(0xffffffffu, mx, o));
            float sum = 0.f;
#pragma unroll
            for (int c = 0; c < 6; c++) {
                int col = lane + 32 * c;
                s[c] = (col < 180) ? __expf(s[c] - mx) : 0.f;
                sum += s[c];
            }
#pragma unroll
            for (int o = 16; o; o >>= 1) sum += __shfl_xor_sync(0xffffffffu, sum, o);
            float inv = 1.f / sum;
#pragma unroll
            for (int c = 0; c < 6; c++) {
                int col = lane + 32 * c;
                if (col < 188) Ss[row * 188 + col] = f2tf(s[c] * inv);
            }
        }
        __syncthreads();

        // ---- stage 3: O = P V ----
        {
            int ncol = w * 8;
            uint32_t bf[23][2];
#pragma unroll
            for (int ks = 0; ks < 23; ks++) {
                int k0 = ks * 8 + c4;
                bf[ks][0] = __float_as_uint(Vs[k0 * 68 + ncol + g4]);
                bf[ks][1] = __float_as_uint(Vs[(k0 + 4) * 68 + ncol + g4]);
            }
            for (int mt = 0; mt < 6; mt++) {
                float acc[4] = {0.f, 0.f, 0.f, 0.f};
                int arow = mt * 16 + g4;
#pragma unroll
                for (int ks = 0; ks < 23; ks++) {
                    uint32_t a[4];
                    int k0 = ks * 8 + c4;
                    a[0] = __float_as_uint(Ss[arow * 188 + k0]);
                    a[1] = __float_as_uint(Ss[(arow + 8) * 188 + k0]);
                    a[2] = __float_as_uint(Ss[arow * 188 + k0 + 4]);
                    a[3] = __float_as_uint(Ss[(arow + 8) * 188 + k0 + 4]);
                    mma_tf32(acc, a, bf[ks], acc);
                }
                int grow = row0 + mt * 16 + g4;
                long gcol = ncol + 2 * c4;
                if (grow < 180)
                    *(float2*)(outb + (long)grow * 768 + gcol) = make_float2(acc[0], acc[1]);
                if (grow + 8 < 180)
                    *(float2*)(outb + (long)(grow + 8) * 768 + gcol) = make_float2(acc[2], acc[3]);
            }
        }
    }
}

// ---------------- fused MLP: LN2 + ff1 + GELU + ff2 + bias + residual ----------------
// 64 tokens per block. smem: Hs[64][68], W1s[64][260], Gs[64][260], W2s[256][68]
#define MH_OFF 0
#define MW1_OFF (64 * 68)
#define MG_OFF  (MW1_OFF + 64 * 260)
#define MW2_OFF (MG_OFF + 64 * 260)
#define MLP_SMEM ((MW2_OFF + 256 * 68) * 4)

__global__ void __launch_bounds__(256) mlp_fused_k(const float* __restrict__ x,
                                                   const float* __restrict__ w1,
                                                   const float* __restrict__ b1,
                                                   const float* __restrict__ w2,
                                                   const float* __restrict__ b2,
                                                   const float* __restrict__ lng,
                                                   const float* __restrict__ lnb,
                                                   float* __restrict__ outx) {
    extern __shared__ float sm[];
    float* Hs  = sm + MH_OFF;
    float* W1s = sm + MW1_OFF;
    float* Gs  = sm + MG_OFF;
    float* W2s = sm + MW2_OFF;

    int tid = threadIdx.x, lane = tid & 31, w = tid >> 5;
    int g4 = lane >> 2, c4 = lane & 3;
    long t0 = (long)blockIdx.x * 64;

    // ---- load W1 [64][256] and W2 [256][64] (tf32) ----
    for (int i = tid; i < 64 * 64; i += 256) {
        int k = i >> 6, n4 = (i & 63) << 2;
        float4 t = *(const float4*)(w1 + (long)k * 256 + n4);
        float* p = &W1s[k * 260 + n4];
        p[0] = f2tf(t.x); p[1] = f2tf(t.y); p[2] = f2tf(t.z); p[3] = f2tf(t.w);
    }
    for (int i = tid; i < 256 * 16; i += 256) {
        int k = i >> 4, n4 = (i & 15) << 2;
        float4 t = *(const float4*)(w2 + (long)k * 64 + n4);
        float* p = &W2s[k * 68 + n4];
        p[0] = f2tf(t.x); p[1] = f2tf(t.y); p[2] = f2tf(t.z); p[3] = f2tf(t.w);
    }

    // ---- LN from gmem into Hs (tf32) ----
    {
        float ga = lng[lane], gb = lng[lane + 32];
        float ba = lnb[lane], bb2 = lnb[lane + 32];
        for (int r = w; r < 64; r += 8) {
            float v0 = x[(t0 + r) * 64 + lane];
            float v1 = x[(t0 + r) * 64 + 32 + lane];
            float s = v0 + v1;
#pragma unroll
            for (int o = 16; o; o >>= 1) s += __shfl_xor_sync(0xffffffffu, s, o);
            float mean = s * (1.f / 64.f);
            float d0 = v0 - mean, d1 = v1 - mean;
            float q = d0 * d0 + d1 * d1;
#pragma unroll
            for (int o = 16; o; o >>= 1) q += __shfl_xor_sync(0xffffffffu, q, o);
            float rstd = rsqrtf(q * (1.f / 64.f) + 1e-5f);
            Hs[r * 68 + lane]      = f2tf(d0 * rstd * ga + ba);
            Hs[r * 68 + 32 + lane] = f2tf(d1 * rstd * gb + bb2);
        }
    }
    __syncthreads();

    // ---- ff1: G = gelu(H @ W1 + b1); warp w owns cols [32w, 32w+32) ----
    {
        int wn = w * 32;
        float acc[4][4][4];
#pragma unroll
        for (int mt = 0; mt < 4; mt++)
#pragma unroll
            for (int nt = 0; nt < 4; nt++)
#pragma unroll
                for (int i = 0; i < 4; i++) acc[mt][nt][i] = 0.f;
#pragma unroll
        for (int ks = 0; ks < 8; ks++) {
            int k0 = ks * 8 + c4;
            uint32_t bfr[4][2], afr[4][4];
#pragma unroll
            for (int nt = 0; nt < 4; nt++) {
                int col = wn + nt * 8 + g4;
                bfr[nt][0] = __float_as_uint(W1s[k0 * 260 + col]);
                bfr[nt][1] = __float_as_uint(W1s[(k0 + 4) * 260 + col]);
            }
#pragma unroll
            for (int mt = 0; mt < 4; mt++) {
                int base = (mt * 16 + g4) * 68 + k0;
                afr[mt][0] = __float_as_uint(Hs[base]);
                afr[mt][1] = __float_as_uint(Hs[base + 8 * 68]);
                afr[mt][2] = __float_as_uint(Hs[base + 4]);
                afr[mt][3] = __float_as_uint(Hs[base + 8 * 68 + 4]);
            }
#pragma unroll
            for (int mt = 0; mt < 4; mt++)
#pragma unroll
                for (int nt = 0; nt < 4; nt++)
                    mma_tf32(acc[mt][nt], afr[mt], bfr[nt], acc[mt][nt]);
        }
#pragma unroll
        for (int nt = 0; nt < 4; nt++) {
            int col = wn + nt * 8 + 2 * c4;
            float bb0 = b1[col], bb1 = b1[col + 1];
#pragma unroll
            for (int mt = 0; mt < 4; mt++) {
#pragma unroll
                for (int half = 0; half < 2; half++) {
                    int row = mt * 16 + g4 + 8 * half;
                    float v0 = acc[mt][nt][2 * half] + bb0;
                    float v1 = acc[mt][nt][2 * half + 1] + bb1;
                    v0 = 0.5f * v0 * (1.f + erff(v0 * 0.70710678118654752f));
                    v1 = 0.5f * v1 * (1.f + erff(v1 * 0.70710678118654752f));
                    Gs[row * 260 + col]     = f2tf(v0);
                    Gs[row * 260 + col + 1] = f2tf(v1);
                }
            }
        }
    }
    __syncthreads();

    // ---- ff2: out = G @ W2 + b2 + x; warp w owns cols [8w, 8w+8) ----
    {
        int ncol = w * 8;
        float acc[4][4];
#pragma unroll
        for (int mt = 0; mt < 4; mt++)
#pragma unroll
            for (int i = 0; i < 4; i++) acc[mt][i] = 0.f;
#pragma unroll
        for (int ks = 0; ks < 32; ks++) {
            int k0 = ks * 8 + c4;
            uint32_t bfr[2];
            bfr[0] = __float_as_uint(W2s[k0 * 68 + ncol + g4]);
            bfr[1] = __float_as_uint(W2s[(k0 + 4) * 68 + ncol + g4]);
#pragma unroll
            for (int mt = 0; mt < 4; mt++) {
                uint32_t a[4];
                int base = (mt * 16 + g4) * 260 + k0;
                a[0] = __float_as_uint(Gs[base]);
                a[1] = __float_as_uint(Gs[base + 8 * 260]);
                a[2] = __float_as_uint(Gs[base + 4]);
                a[3] = __float_as_uint(Gs[base + 8 * 260 + 4]);
                mma_tf32(acc[mt], a, bfr, acc[mt]);
            }
        }
        int col = ncol + 2 * c4;
        float bb0 = b2[col], bb1 = b2[col + 1];
#pragma unroll
        for (int mt = 0; mt < 4; mt++) {
#pragma unroll
            for (int half = 0; half < 2; half++) {
                long row = t0 + mt * 16 + g4 + 8 * half;
                float2 r = *(const float2*)(x + row * 64 + col);
                float v0 = acc[mt][2 * half] + bb0 + r.x;
                float v1 = acc[mt][2 * half + 1] + bb1 + r.y;
                *(float2*)(outx + row * 64 + col) = make_float2(v0, v1);
            }
        }
    }
}

// ---------------- primary caps: gather + squash ----------------
__global__ void caps_squash_k(const float* __restrict__ pc, float* __restrict__ caps) {
    int idx = blockIdx.x * blockDim.x + threadIdx.x; // b*1024 + i
    if (idx >= 256 * 1024) return;
    int i = idx & 1023, b = idx >> 10;
    int i32 = i >> 5, y = (i >> 3) & 3, xq = i & 7;
    const float* src = pc + (((long)b * 4 + y) * 8 + xq) * 256 + i32 * 8;
    float t[8];
    float l2 = 0.f;
#pragma unroll
    for (int e = 0; e < 8; e++) { t[e] = src[e]; l2 += t[e] * t[e]; }
    float sc = sqrtf(l2) / (1.f + l2);
#pragma unroll
    for (int e = 0; e < 8; e++) caps[(long)idx * 8 + e] = t[e] * sc;
}

// ---------------- capsule predictions u[b,i,:] ----------------
__global__ void caps_u_k(const float* __restrict__ caps, const float* __restrict__ cw,
                         float* __restrict__ u) {
    __shared__ float w_s[8 * 48];
    int i = blockIdx.x;
    for (int t = threadIdx.x; t < 384; t += 256) w_s[t] = cw[(long)i * 384 + t];
    __syncthreads();
    int b = threadIdx.x;
    float ce[8];
    const float* cp = caps + ((long)b * 1024 + i) * 8;
#pragma unroll
    for (int e = 0; e < 8; e++) ce[e] = cp[e];
    float* up = u + ((long)b * 1024 + i) * 48;
#pragma unroll 4
    for (int o = 0; o < 48; o++) {
        float s = 0.f;
#pragma unroll
        for (int e = 0; e < 8; e++) s = fmaf(ce[e], w_s[e * 48 + o], s);
        up[o] = s;
    }
}

// ---------------- dynamic routing, one block per batch element ----------------
__global__ void __launch_bounds__(256) routing_k(const float* __restrict__ u,
                                                 const float* __restrict__ br,
                                                 float* __restrict__ out) {
    __shared__ float bb[1024 * 3];
    __shared__ float S[48];
    __shared__ float v[48];
    int b = blockIdx.x, tid = threadIdx.x, lane = tid & 31;
    for (int i = tid; i < 3072; i += 256) bb[i] = br[i];
    __syncthreads();
    const float* ub = u + (long)b * 1024 * 48;

    for (int it = 0; it < 4; it++) {
        if (tid < 48) S[tid] = 0.f;
        __syncthreads();
        float acc[48];
#pragma unroll
        for (int o = 0; o < 48; o++) acc[o] = 0.f;
        for (int i = tid; i < 1024; i += 256) {
            float b0 = bb[i * 3], b1 = bb[i * 3 + 1], b2 = bb[i * 3 + 2];
            float m = fmaxf(b0, fmaxf(b1, b2));
            float e0 = expf(b0 - m), e1 = expf(b1 - m), e2 = expf(b2 - m);
            float inv = 1.f / (e0 + e1 + e2);
            float c[3] = {e0 * inv, e1 * inv, e2 * inv};
            const float* up = ub + (long)i * 48;
#pragma unroll
            for (int j = 0; j < 3; j++)
#pragma unroll
                for (int o = 0; o < 16; o++)
                    acc[j * 16 + o] = fmaf(c[j], up[j * 16 + o], acc[j * 16 + o]);
        }
#pragma unroll
        for (int o = 0; o < 48; o++) {
            float s = acc[o];
#pragma unroll
            for (int d = 16; d; d >>= 1) s += __shfl_xor_sync(0xffffffffu, s, d);
            if (lane == 0) atomicAdd(&S[o], s);
        }
        __syncthreads();
        if (tid < 3) {
            float l2 = 0.f;
            for (int o = 0; o < 16; o++) { float t = S[tid * 16 + o]; l2 += t * t; }
            float sc = sqrtf(l2) / (1.f + l2);
            for (int o = 0; o < 16; o++) v[tid * 16 + o] = S[tid * 16 + o] * sc;
            if (it == 3) out[b * 3 + tid] = l2 / (1.f + l2);  // |v| = l2/(1+l2)
        }
        __syncthreads();
        if (it < 3) {
            for (int i = tid; i < 1024; i += 256) {
                const float* up = ub + (long)i * 48;
#pragma unroll
                for (int j = 0; j < 3; j++) {
                    float s = 0.f;
#pragma unroll
                    for (int o = 0; o < 16; o++) s = fmaf(up[j * 16 + o], v[j * 16 + o], s);
                    bb[i * 3 + j] += s;
                }
            }
            __syncthreads();
        }
    }
}

// ---------------- host ----------------
extern "C" void kernel_launch(void* const* d_in, const int* in_sizes, int n_in,
                              void* d_out, int out_size) {
    const float* x_in    = (const float*)d_in[0];
    const float* conv1_w = (const float*)d_in[1];
    const float* conv2_w = (const float*)d_in[2];
    const float* pos_emb = (const float*)d_in[3];
    const float* ln1_g   = (const float*)d_in[4];
    const float* ln1_b   = (const float*)d_in[5];
    const float* qkv_w   = (const float*)d_in[6];
    const float* out_w   = (const float*)d_in[7];
    const float* out_b   = (const float*)d_in[8];
    const float* ln2_g   = (const float*)d_in[9];
    const float* ln2_b   = (const float*)d_in[10];
    const float* ff1_w   = (const float*)d_in[11];
    const float* ff1_b   = (const float*)d_in[12];
    const float* ff2_w   = (const float*)d_in[13];
    const float* ff2_b   = (const float*)d_in[14];
    const float* pcaps_w = (const float*)d_in[15];
    const float* pcaps_b = (const float*)d_in[16];
    const float* caps_w  = (const float*)d_in[17];
    const float* b_route = (const float*)d_in[18];
    float* out = (float*)d_out;

    float *col1, *wt1, *y1, *p1, *col2, *wt2, *y2, *xb, *ao, *col3, *wtp, *pc, *caps, *u;
    cudaGetSymbolAddress((void**)&col1, g_col1);
    cudaGetSymbolAddress((void**)&wt1,  g_wt1);
    cudaGetSymbolAddress((void**)&y1,   g_y1);
    cudaGetSymbolAddress((void**)&p1,   g_p1);
    cudaGetSymbolAddress((void**)&col2, g_col2);
    cudaGetSymbolAddress((void**)&wt2,  g_wt2);
    cudaGetSymbolAddress((void**)&y2,   g_y2);
    cudaGetSymbolAddress((void**)&xb,   g_x);
    cudaGetSymbolAddress((void**)&ao,   g_ao);
    cudaGetSymbolAddress((void**)&col3, g_col3);
    cudaGetSymbolAddress((void**)&wtp,  g_wtp);
    cudaGetSymbolAddress((void**)&pc,   g_pc);
    cudaGetSymbolAddress((void**)&caps, g_caps);
    cudaGetSymbolAddress((void**)&u,    g_u);

    cudaFuncSetAttribute(attn_fused_k, cudaFuncAttributeMaxDynamicSharedMemorySize, ATTN3_SMEM);
    cudaFuncSetAttribute(mlp_fused_k,  cudaFuncAttributeMaxDynamicSharedMemorySize, MLP_SMEM);

    // ---- ConvEmbed ----
    im2col1_k<<<(int)CDIV((long)737280 * 28, 256), 256>>>(x_in, col1);
    wtrans1<<<CDIV(64 * 28, 256), 256>>>(conv1_w, wt1);
    tgemm_k<1><<<dim3(1, 737280 / 128), 256>>>(col1, wt1, nullptr, nullptr, y1, 737280, 64, 28);
    maxpool_k<<<(int)CDIV((long)256 * 20 * 36 * 64, 256), 256>>>(y1, p1, 256, 40, 72, 64, 20, 36, nullptr);
    im2col2_k<<<(int)CDIV((long)184320 * 576, 256), 256>>>(p1, col2);
    wtrans_hwc<<<CDIV(64 * 576, 256), 256>>>(conv2_w, wt2, 64, 64);
    tgemm_k<1><<<dim3(1, 184320 / 128), 256>>>(col2, wt2, nullptr, nullptr, y2, 184320, 64, 576);
    maxpool_k<<<(int)CDIV((long)256 * 10 * 18 * 64, 256), 256>>>(y2, xb, 256, 20, 36, 64, 10, 18, pos_emb);

    // ---- Transformer: 12 shared layers applied twice ----
    const int M = 46080;
    for (int pass = 0; pass < 2; pass++) {
        for (int l = 0; l < 12; l++) {
            const float* qw  = qkv_w + (long)l * 64 * 2304;
            const float* ow  = out_w + (long)l * 768 * 64;
            const float* ob  = out_b + (long)l * 64;
            const float* f1w = ff1_w + (long)l * 64 * 256;
            const float* f1b = ff1_b + (long)l * 256;
            const float* f2w = ff2_w + (long)l * 256 * 64;
            const float* f2b = ff2_b + (long)l * 64;

            attn_fused_k<<<256 * 12, 256, ATTN3_SMEM>>>(xb, qw, ln1_g + l * 64, ln1_b + l * 64, ao);
            tgemm_k<4><<<dim3(1, M / 128), 256>>>(ao, ow, ob, xb, xb, M, 64, 768);
            mlp_fused_k<<<M / 64, 256, MLP_SMEM>>>(xb, f1w, f1b, f2w, f2b,
                                                   ln2_g + l * 64, ln2_b + l * 64, xb);
        }
    }

    // ---- PrimaryCaps + routing ----
    im2col3_k<<<(int)CDIV((long)8192 * 576, 256), 256>>>(xb, col3);
    wtrans_hwc<<<CDIV(256 * 576, 256), 256>>>(pcaps_w, wtp, 256, 64);
    tgemm_k<2><<<dim3(256 / 64, 8192 / 128), 256>>>(col3, wtp, pcaps_b, nullptr, pc, 8192, 256, 576);
    caps_squash_k<<<CDIV(256 * 1024, 256), 256>>>(pc, caps);
    caps_u_k<<<1024, 256>>>(caps, caps_w, u);
    routing_k<<<256, 256>>>(u, b_route, out);
}

// round 7
// speedup vs baseline: 2.7000x; 1.1646x over previous
#include <cuda_runtime.h>
#include <cuda_fp16.h>
#include <math.h>
#include <stdint.h>

#define CDIV(a,b) (((a)+(b)-1)/(b))

// ---------------- static scratch (no allocations allowed) ----------------
__device__ float g_col1[737280 * 28];        // conv1 im2col (K padded 27->28)
__device__ float g_wt1 [28 * 64];
__device__ float g_y1  [737280 * 64];        // conv1 out NHWC (B,40,72,64)
__device__ float g_p1  [184320 * 64];        // pool1 NHWC (B,20,36,64)
__device__ float g_col2[184320 * 576];       // conv2 im2col
__device__ float g_wt2 [576 * 64];
__device__ float g_y2  [184320 * 64];        // conv2 out NHWC (B,20,36,64)
__device__ float g_x   [46080 * 64];         // tokens / residual stream (B,180,64)
__device__ float g_ao  [46080 * 768];        // attention output (B,180,768)
__device__ float g_col3[8192 * 576];         // pcaps im2col
__device__ float g_wtp [576 * 256];
__device__ float g_pc  [8192 * 256];         // pcaps out NHWC (B,4,8,256)
__device__ float g_caps[256 * 1024 * 8];
__device__ float g_u   [256 * 1024 * 48];

// ---------------- im2col kernels ----------------
__global__ void im2col1_k(const float* __restrict__ x, float* __restrict__ col) {
    long idx = (long)blockIdx.x * blockDim.x + threadIdx.x;
    const long total = (long)737280 * 28;
    if (idx >= total) return;
    int kk = (int)(idx % 28);
    long m = idx / 28;
    if (kk == 27) { col[idx] = 0.f; return; }
    int ow = (int)(m % 72);
    int t  = (int)(m / 72);
    int oh = t % 40;
    int b  = t / 40;
    int kw = kk % 3, kh = (kk / 3) % 3, ci = kk / 9;
    int ih = oh + kh - 1, iw = ow + kw - 1;
    float v = 0.f;
    if (ih >= 0 && ih < 40 && iw >= 0 && iw < 72)
        v = x[(((long)b * 3 + ci) * 40 + ih) * 72 + iw];
    col[idx] = v;
}

__global__ void im2col2_k(const float* __restrict__ p1, float* __restrict__ col) {
    long idx = (long)blockIdx.x * blockDim.x + threadIdx.x;
    const long total = (long)184320 * 576;
    if (idx >= total) return;
    int kk = (int)(idx % 576);
    long m = idx / 576;
    int ow = (int)(m % 36);
    int t  = (int)(m / 36);
    int oh = t % 20;
    int b  = t / 20;
    int ci = kk % 64;
    int kw = (kk / 64) % 3;
    int kh = kk / 192;
    int ih = oh + kh - 1, iw = ow + kw - 1;
    float v = 0.f;
    if (ih >= 0 && ih < 20 && iw >= 0 && iw < 36)
        v = p1[(((long)b * 20 + ih) * 36 + iw) * 64 + ci];
    col[idx] = v;
}

// pcaps: input tokens g_x viewed as (B, 10, 18, 64); conv k3 s2 p0 -> (B,4,8,*)
__global__ void im2col3_k(const float* __restrict__ tk, float* __restrict__ col) {
    long idx = (long)blockIdx.x * blockDim.x + threadIdx.x;
    const long total = (long)8192 * 576;
    if (idx >= total) return;
    int kk = (int)(idx % 576);
    long m = idx / 576;
    int ow = (int)(m % 8);
    int t  = (int)(m / 8);
    int oh = t % 4;
    int b  = t / 4;
    int ci = kk % 64;
    int kw = (kk / 64) % 3;
    int kh = kk / 192;
    int ih = oh * 2 + kh, iw = ow * 2 + kw;
    col[idx] = tk[((long)b * 180 + ih * 18 + iw) * 64 + ci];
}

// ---------------- weight transposes ----------------
__global__ void wtrans1(const float* __restrict__ w, float* __restrict__ wt) {
    int i = blockIdx.x * blockDim.x + threadIdx.x;
    if (i >= 64 * 28) return;
    int o = i / 28, k = i % 28;
    wt[k * 64 + o] = (k < 27) ? w[o * 27 + k] : 0.f;
}
__global__ void wtrans_hwc(const float* __restrict__ w, float* __restrict__ wt, int O, int CI) {
    int K = CI * 9;
    int i = blockIdx.x * blockDim.x + threadIdx.x;
    if (i >= O * K) return;
    int o = i / K, r = i % K;
    int ci = r / 9, kh = (r % 9) / 3, kw = r % 3;
    wt[((kh * 3 + kw) * CI + ci) * O + o] = w[i];
}

// ---------------- tf32 helpers ----------------
__device__ __forceinline__ float f2tf(float f) {
    uint32_t r;
    asm("cvt.rna.tf32.f32 %0, %1;" : "=r"(r) : "f"(f));
    return __uint_as_float(r);
}
__device__ __forceinline__ void mma_tf32(float d[4], const uint32_t a[4], const uint32_t b[2],
                                         const float c[4]) {
    asm("mma.sync.aligned.m16n8k8.row.col.f32.tf32.tf32.f32 "
        "{%0,%1,%2,%3},{%4,%5,%6,%7},{%8,%9},{%10,%11,%12,%13};"
        : "=f"(d[0]), "=f"(d[1]), "=f"(d[2]), "=f"(d[3])
        : "r"(a[0]), "r"(a[1]), "r"(a[2]), "r"(a[3]), "r"(b[0]), "r"(b[1]),
          "f"(c[0]), "f"(c[1]), "f"(c[2]), "f"(c[3]));
}

// ---------------- fp16 mma helpers ----------------
__device__ __forceinline__ uint32_t smem_u32(const void* p) {
    return (uint32_t)__cvta_generic_to_shared(p);
}
__device__ __forceinline__ void ldsm_x4(uint32_t r[4], uint32_t addr) {
    asm volatile("ldmatrix.sync.aligned.m8n8.x4.shared.b16 {%0,%1,%2,%3}, [%4];"
        : "=r"(r[0]), "=r"(r[1]), "=r"(r[2]), "=r"(r[3]) : "r"(addr));
}
__device__ __forceinline__ void ldsm_x2(uint32_t r[2], uint32_t addr) {
    asm volatile("ldmatrix.sync.aligned.m8n8.x2.shared.b16 {%0,%1}, [%2];"
        : "=r"(r[0]), "=r"(r[1]) : "r"(addr));
}
__device__ __forceinline__ void ldsm_x2_t(uint32_t r[2], uint32_t addr) {
    asm volatile("ldmatrix.sync.aligned.m8n8.x2.trans.shared.b16 {%0,%1}, [%2];"
        : "=r"(r[0]), "=r"(r[1]) : "r"(addr));
}
__device__ __forceinline__ void mma_f16(float d[4], const uint32_t a[4], const uint32_t b[2],
                                        const float c[4]) {
    asm volatile("mma.sync.aligned.m16n8k16.row.col.f32.f16.f16.f32 "
        "{%0,%1,%2,%3},{%4,%5,%6,%7},{%8,%9},{%10,%11,%12,%13};"
        : "=f"(d[0]), "=f"(d[1]), "=f"(d[2]), "=f"(d[3])
        : "r"(a[0]), "r"(a[1]), "r"(a[2]), "r"(a[3]), "r"(b[0]), "r"(b[1]),
          "f"(c[0]), "f"(c[1]), "f"(c[2]), "f"(c[3]));
}
__device__ __forceinline__ uint32_t packh2(float a, float b) {
    __half2 h = __floats2half2_rn(a, b);
    return *(uint32_t*)&h;
}

// ---------------- tf32 tensor-core GEMM: 128x64 tile, 256 threads ----------------
// EPI: 0 none, 1 relu, 2 +bias, 3 +bias gelu, 4 +bias +res
template <int EPI>
__global__ void __launch_bounds__(256) tgemm_k(const float* __restrict__ A, const float* __restrict__ Bm,
                                               const float* __restrict__ bias, const float* __restrict__ res,
                                               float* __restrict__ C, int M, int N, int K) {
    __shared__ float As[128 * 36];   // [m][k], stride 36
    __shared__ float Bs[32 * 68];    // [k][n], stride 68
    const int bm = blockIdx.y * 128, bn = blockIdx.x * 64;
    const int tid = threadIdx.x, lane = tid & 31, w = tid >> 5;
    const int g4 = lane >> 2, c4 = lane & 3;
    const int wm = (w & 3) * 32, wn = (w >> 2) * 32;

    float acc[2][4][4];
#pragma unroll
    for (int mt = 0; mt < 2; mt++)
#pragma unroll
        for (int nt = 0; nt < 4; nt++)
#pragma unroll
            for (int i = 0; i < 4; i++) acc[mt][nt][i] = 0.f;

    const int ar = tid >> 1, akb = (tid & 1) * 16;
    const int bk = tid >> 3, bn0 = (tid & 7) * 8;
    const float* Arow = A + (long)(bm + ar) * K;

    for (int k0 = 0; k0 < K; k0 += 32) {
        float4 av[4], bv[2];
#pragma unroll
        for (int i = 0; i < 4; i++) {
            int gk = k0 + akb + 4 * i;
            av[i] = (gk + 4 <= K) ? *(const float4*)(Arow + gk) : make_float4(0.f, 0.f, 0.f, 0.f);
        }
        {
            int gk = k0 + bk;
            if (gk < K) {
                bv[0] = *(const float4*)(Bm + (long)gk * N + bn + bn0);
                bv[1] = *(const float4*)(Bm + (long)gk * N + bn + bn0 + 4);
            } else {
                bv[0] = make_float4(0.f, 0.f, 0.f, 0.f);
                bv[1] = bv[0];
            }
        }
        __syncthreads();
#pragma unroll
        for (int i = 0; i < 4; i++) {
            float* p = &As[ar * 36 + akb + 4 * i];
            p[0] = f2tf(av[i].x); p[1] = f2tf(av[i].y); p[2] = f2tf(av[i].z); p[3] = f2tf(av[i].w);
        }
        {
            float* p = &Bs[bk * 68 + bn0];
            p[0] = f2tf(bv[0].x); p[1] = f2tf(bv[0].y); p[2] = f2tf(bv[0].z); p[3] = f2tf(bv[0].w);
            p[4] = f2tf(bv[1].x); p[5] = f2tf(bv[1].y); p[6] = f2tf(bv[1].z); p[7] = f2tf(bv[1].w);
        }
        __syncthreads();
#pragma unroll
        for (int ks = 0; ks < 4; ks++) {
            uint32_t bfr[4][2], afr[2][4];
#pragma unroll
            for (int nt = 0; nt < 4; nt++) {
                int col = wn + nt * 8 + g4;
                bfr[nt][0] = __float_as_uint(Bs[(ks * 8 + c4) * 68 + col]);
                bfr[nt][1] = __float_as_uint(Bs[(ks * 8 + c4 + 4) * 68 + col]);
            }
#pragma unroll
            for (int mt = 0; mt < 2; mt++) {
                int base = (wm + mt * 16 + g4) * 36 + ks * 8 + c4;
                afr[mt][0] = __float_as_uint(As[base]);
                afr[mt][1] = __float_as_uint(As[base + 8 * 36]);
                afr[mt][2] = __float_as_uint(As[base + 4]);
                afr[mt][3] = __float_as_uint(As[base + 8 * 36 + 4]);
            }
#pragma unroll
            for (int mt = 0; mt < 2; mt++)
#pragma unroll
                for (int nt = 0; nt < 4; nt++)
                    mma_tf32(acc[mt][nt], afr[mt], bfr[nt], acc[mt][nt]);
        }
        __syncthreads();
    }

#pragma unroll
    for (int nt = 0; nt < 4; nt++) {
        int col = bn + wn + nt * 8 + 2 * c4;
        float b0 = 0.f, b1 = 0.f;
        if (EPI >= 2) { b0 = bias[col]; b1 = bias[col + 1]; }
#pragma unroll
        for (int mt = 0; mt < 2; mt++) {
#pragma unroll
            for (int half = 0; half < 2; half++) {
                long row = bm + wm + mt * 16 + g4 + 8 * half;
                float v0 = acc[mt][nt][2 * half], v1 = acc[mt][nt][2 * half + 1];
                if (EPI == 1) { v0 = fmaxf(v0, 0.f); v1 = fmaxf(v1, 0.f); }
                if (EPI >= 2) { v0 += b0; v1 += b1; }
                if (EPI == 3) {
                    v0 = 0.5f * v0 * (1.f + erff(v0 * 0.70710678118654752f));
                    v1 = 0.5f * v1 * (1.f + erff(v1 * 0.70710678118654752f));
                }
                if (EPI == 4) {
                    float2 r = *(const float2*)(res + row * N + col);
                    v0 += r.x; v1 += r.y;
                }
                *(float2*)(C + row * N + col) = make_float2(v0, v1);
            }
        }
    }
}

// ---------------- maxpool 3x3 s2 p1 on NHWC (+ optional pos-emb add) ----------------
__global__ void maxpool_k(const float* __restrict__ in, float* __restrict__ out,
                          int Bn, int IH, int IW, int C, int OH, int OW,
                          const float* __restrict__ pos) {
    long idx = (long)blockIdx.x * blockDim.x + threadIdx.x;
    long total = (long)Bn * OH * OW * C;
    if (idx >= total) return;
    int c = (int)(idx % C);
    long r = idx / C;
    int ow = (int)(r % OW); r /= OW;
    int oh = (int)(r % OH);
    int b  = (int)(r / OH);
    float m = -1e30f;
#pragma unroll
    for (int kh = 0; kh < 3; kh++) {
        int ih = oh * 2 - 1 + kh;
        if (ih < 0 || ih >= IH) continue;
#pragma unroll
        for (int kw = 0; kw < 3; kw++) {
            int iw = ow * 2 - 1 + kw;
            if (iw < 0 || iw >= IW) continue;
            m = fmaxf(m, in[(((long)b * IH + ih) * IW + iw) * C + c]);
        }
    }
    if (pos) m += pos[(oh * OW + ow) * C + c];
    out[idx] = m;
}

// ---------------- fused LN1 + QKV + attention, fp16 tensor cores ----------------
// smem bytes:
//   Q16 [192][72] half @ 0       (27648)
//   K16 [192][72] half @ 27648   (27648)
//   V16 [192][72] half @ 55296   (27648)
//   Ss32 [96][196] float @ 82944 (75264)
//   S16/H16 [96][200] half @ 158208 (38400; H16 uses [192][72] = 27648)
#define ATTNH_SMEM 196608

__global__ void __launch_bounds__(256) attn_fused_k(const float* __restrict__ x,
                                                    const float* __restrict__ qw,
                                                    const float* __restrict__ lng,
                                                    const float* __restrict__ lnb,
                                                    float* __restrict__ out) {
    extern __shared__ char smc[];
    __half* Q16 = (__half*)(smc);
    __half* K16 = (__half*)(smc + 27648);
    __half* V16 = (__half*)(smc + 55296);
    float*  Ss  = (float*)(smc + 82944);
    __half* S16 = (__half*)(smc + 158208);
    __half* H16 = S16;   // overlay: H16 only used before S16

    int b = blockIdx.x / 12, h = blockIdx.x % 12;
    int tid = threadIdx.x, lane = tid & 31, w = tid >> 5;
    int g4 = lane >> 2, c4 = lane & 3;
    int lmrow = lane & 15, lmk = (lane >> 4) * 8;   // ldmatrix x4 addressing
    int b2row = lane & 7, b2k = ((lane >> 3) & 1) * 8;  // ldmatrix x2 addressing

    // ---- prefetch W for K projection (per-thread column, L2-hot) ----
    const float* wbase = qw + h * 64 + w * 8 + g4;
    float wraw[16];
#pragma unroll
    for (int ks = 0; ks < 4; ks++) {
        int r = ks * 16 + 2 * c4;
        wraw[ks * 4 + 0] = __ldg(wbase + 768 + (long)r * 2304);
        wraw[ks * 4 + 1] = __ldg(wbase + 768 + (long)(r + 1) * 2304);
        wraw[ks * 4 + 2] = __ldg(wbase + 768 + (long)(r + 8) * 2304);
        wraw[ks * 4 + 3] = __ldg(wbase + 768 + (long)(r + 9) * 2304);
    }

    // ---- LN: read residual from gmem, write fp16 H ----
    {
        const float* xb = x + (long)b * 180 * 64;
        float ga = lng[lane], gb = lng[lane + 32];
        float ba = lnb[lane], bb2 = lnb[lane + 32];
        for (int r = w; r < 180; r += 8) {
            float v0 = xb[r * 64 + lane], v1 = xb[r * 64 + 32 + lane];
            float s = v0 + v1;
#pragma unroll
            for (int o = 16; o; o >>= 1) s += __shfl_xor_sync(0xffffffffu, s, o);
            float mean = s * (1.f / 64.f);
            float d0 = v0 - mean, d1 = v1 - mean;
            float q = d0 * d0 + d1 * d1;
#pragma unroll
            for (int o = 16; o; o >>= 1) q += __shfl_xor_sync(0xffffffffu, q, o);
            float rstd = rsqrtf(q * (1.f / 64.f) + 1e-5f);
            H16[r * 72 + lane]      = __float2half(d0 * rstd * ga + ba);
            H16[r * 72 + 32 + lane] = __float2half(d1 * rstd * gb + bb2);
        }
        for (int i = tid; i < 12 * 72; i += 256) H16[180 * 72 + i] = __float2half(0.f);
    }
    __syncthreads();

    // ---- QKV projections: K, V, Q; fp16 mma, A via ldmatrix, B from gmem regs ----
#pragma unroll
    for (int m3 = 0; m3 < 3; m3++) {
        uint32_t bf[4][2];
#pragma unroll
        for (int ks = 0; ks < 4; ks++) {
            bf[ks][0] = packh2(wraw[ks * 4 + 0], wraw[ks * 4 + 1]);
            bf[ks][1] = packh2(wraw[ks * 4 + 2], wraw[ks * 4 + 3]);
        }
        if (m3 < 2) {
            int offs = (m3 == 0) ? 1536 : 0;   // next: V then Q
#pragma unroll
            for (int ks = 0; ks < 4; ks++) {
                int r = ks * 16 + 2 * c4;
                wraw[ks * 4 + 0] = __ldg(wbase + offs + (long)r * 2304);
                wraw[ks * 4 + 1] = __ldg(wbase + offs + (long)(r + 1) * 2304);
                wraw[ks * 4 + 2] = __ldg(wbase + offs + (long)(r + 8) * 2304);
                wraw[ks * 4 + 3] = __ldg(wbase + offs + (long)(r + 9) * 2304);
            }
        }
        __half* dst = (m3 == 0) ? K16 : (m3 == 1) ? V16 : Q16;
#pragma unroll
        for (int mp = 0; mp < 6; mp++) {
            int r0 = mp * 32, r1 = r0 + 16;
            float acc0[4] = {0.f, 0.f, 0.f, 0.f}, acc1[4] = {0.f, 0.f, 0.f, 0.f};
#pragma unroll
            for (int ks = 0; ks < 4; ks++) {
                uint32_t a0[4], a1[4];
                ldsm_x4(a0, smem_u32(&H16[(r0 + lmrow) * 72 + ks * 16 + lmk]));
                ldsm_x4(a1, smem_u32(&H16[(r1 + lmrow) * 72 + ks * 16 + lmk]));
                mma_f16(acc0, a0, bf[ks], acc0);
                mma_f16(acc1, a1, bf[ks], acc1);
            }
            int col = w * 8 + 2 * c4;
            *(uint32_t*)&dst[(r0 + g4) * 72 + col]     = packh2(acc0[0], acc0[1]);
            *(uint32_t*)&dst[(r0 + g4 + 8) * 72 + col] = packh2(acc0[2], acc0[3]);
            *(uint32_t*)&dst[(r1 + g4) * 72 + col]     = packh2(acc1[0], acc1[1]);
            *(uint32_t*)&dst[(r1 + g4 + 8) * 72 + col] = packh2(acc1[2], acc1[3]);
        }
    }
    __syncthreads();   // H16 dead; Q/K/V ready

    float* outb = out + (long)b * 180 * 768 + h * 64;

    for (int half = 0; half < 2; half++) {
        int row0 = half * 96;

        // ---- stage 1: S = (Q K^T) * 0.125; warp owns n-tiles {3w..3w+2} ----
        {
            uint32_t bq[3][4][2];
#pragma unroll
            for (int nn = 0; nn < 3; nn++) {
                int nbase = (w * 3 + nn) * 8;
#pragma unroll
                for (int ks = 0; ks < 4; ks++)
                    ldsm_x2(bq[nn][ks], smem_u32(&K16[(nbase + b2row) * 72 + ks * 16 + b2k]));
            }
#pragma unroll
            for (int mp = 0; mp < 3; mp++) {
                int r0 = row0 + mp * 32, r1 = r0 + 16;
                float acc0[3][4], acc1[3][4];
#pragma unroll
                for (int nn = 0; nn < 3; nn++)
#pragma unroll
                    for (int i = 0; i < 4; i++) { acc0[nn][i] = 0.f; acc1[nn][i] = 0.f; }
#pragma unroll
                for (int ks = 0; ks < 4; ks++) {
                    uint32_t a0[4], a1[4];
                    ldsm_x4(a0, smem_u32(&Q16[(r0 + lmrow) * 72 + ks * 16 + lmk]));
                    ldsm_x4(a1, smem_u32(&Q16[(r1 + lmrow) * 72 + ks * 16 + lmk]));
#pragma unroll
                    for (int nn = 0; nn < 3; nn++) {
                        mma_f16(acc0[nn], a0, bq[nn][ks], acc0[nn]);
                        mma_f16(acc1[nn], a1, bq[nn][ks], acc1[nn]);
                    }
                }
#pragma unroll
                for (int nn = 0; nn < 3; nn++) {
                    int scol = (w * 3 + nn) * 8 + 2 * c4;
                    int s0 = mp * 32 + g4, s1 = s0 + 16;
                    *(float2*)&Ss[s0 * 196 + scol]        = make_float2(acc0[nn][0] * 0.125f, acc0[nn][1] * 0.125f);
                    *(float2*)&Ss[(s0 + 8) * 196 + scol]  = make_float2(acc0[nn][2] * 0.125f, acc0[nn][3] * 0.125f);
                    *(float2*)&Ss[s1 * 196 + scol]        = make_float2(acc1[nn][0] * 0.125f, acc1[nn][1] * 0.125f);
                    *(float2*)&Ss[(s1 + 8) * 196 + scol]  = make_float2(acc1[nn][2] * 0.125f, acc1[nn][3] * 0.125f);
                }
            }
        }
        __syncthreads();

        // ---- stage 2: softmax (fp32 scores -> fp16 P) ----
        for (int r = 0; r < 12; r++) {
            int row = w + 8 * r;
            float s[6];
            float mx = -1e30f;
#pragma unroll
            for (int c = 0; c < 6; c++) {
                int col = lane + 32 * c;
                s[c] = (col < 180) ? Ss[row * 196 + col] : -1e30f;
                mx = fmaxf(mx, s[c]);
            }
#pragma unroll
            for (int o = 16; o; o >>= 1) mx = fmaxf(mx, __shfl_xor_sync(0xffffffffu, mx, o));
            float sum = 0.f;
#pragma unroll
            for (int c = 0; c < 6; c++) {
                int col = lane + 32 * c;
                s[c] = (col < 180) ? __expf(s[c] - mx) : 0.f;
                sum += s[c];
            }
#pragma unroll
            for (int o = 16; o; o >>= 1) sum += __shfl_xor_sync(0xffffffffu, sum, o);
            float inv = 1.f / sum;
#pragma unroll
            for (int c = 0; c < 6; c++) {
                int col = lane + 32 * c;   // covers 0..191
                S16[row * 200 + col] = __float2half((col < 180) ? s[c] * inv : 0.f);
            }
        }
        __syncthreads();

        // ---- stage 3: O = P V; warp owns output cols [8w, 8w+8) ----
        {
            int ncol = w * 8;
            uint32_t bv[12][2];
#pragma unroll
            for (int ks = 0; ks < 12; ks++)
                ldsm_x2_t(bv[ks], smem_u32(&V16[(ks * 16 + lmrow) * 72 + ncol]));
#pragma unroll
            for (int mp = 0; mp < 3; mp++) {
                int s0 = mp * 32, s1 = s0 + 16;
                float acc0[4] = {0.f, 0.f, 0.f, 0.f}, acc1[4] = {0.f, 0.f, 0.f, 0.f};
#pragma unroll
                for (int ks = 0; ks < 12; ks++) {
                    uint32_t a0[4], a1[4];
                    ldsm_x4(a0, smem_u32(&S16[(s0 + lmrow) * 200 + ks * 16 + lmk]));
                    ldsm_x4(a1, smem_u32(&S16[(s1 + lmrow) * 200 + ks * 16 + lmk]));
                    mma_f16(acc0, a0, bv[ks], acc0);
                    mma_f16(acc1, a1, bv[ks], acc1);
                }
                long gcol = ncol + 2 * c4;
#pragma unroll
                for (int pi = 0; pi < 2; pi++) {
                    float* ac = pi ? acc1 : acc0;
                    int base = row0 + (pi ? s1 : s0) + g4;
                    if (base < 180)
                        *(float2*)(outb + (long)base * 768 + gcol) = make_float2(ac[0], ac[1]);
                    if (base + 8 < 180)
                        *(float2*)(outb + (long)(base + 8) * 768 + gcol) = make_float2(ac[2], ac[3]);
                }
            }
        }
        if (half == 0) __syncthreads();   // protect Ss/S16 reuse
    }
}

// ---------------- fused MLP: LN2 + ff1 + GELU + ff2 + bias + residual ----------------
#define MH_OFF 0
#define MW1_OFF (64 * 68)
#define MG_OFF  (MW1_OFF + 64 * 260)
#define MW2_OFF (MG_OFF + 64 * 260)
#define MLP_SMEM ((MW2_OFF + 256 * 68) * 4)

__global__ void __launch_bounds__(256) mlp_fused_k(const float* __restrict__ x,
                                                   const float* __restrict__ w1,
                                                   const float* __restrict__ b1,
                                                   const float* __restrict__ w2,
                                                   const float* __restrict__ b2,
                                                   const float* __restrict__ lng,
                                                   const float* __restrict__ lnb,
                                                   float* __restrict__ outx) {
    extern __shared__ float sm[];
    float* Hs  = sm + MH_OFF;
    float* W1s = sm + MW1_OFF;
    float* Gs  = sm + MG_OFF;
    float* W2s = sm + MW2_OFF;

    int tid = threadIdx.x, lane = tid & 31, w = tid >> 5;
    int g4 = lane >> 2, c4 = lane & 3;
    long t0 = (long)blockIdx.x * 64;

    for (int i = tid; i < 64 * 64; i += 256) {
        int k = i >> 6, n4 = (i & 63) << 2;
        float4 t = *(const float4*)(w1 + (long)k * 256 + n4);
        float* p = &W1s[k * 260 + n4];
        p[0] = f2tf(t.x); p[1] = f2tf(t.y); p[2] = f2tf(t.z); p[3] = f2tf(t.w);
    }
    for (int i = tid; i < 256 * 16; i += 256) {
        int k = i >> 4, n4 = (i & 15) << 2;
        float4 t = *(const float4*)(w2 + (long)k * 64 + n4);
        float* p = &W2s[k * 68 + n4];
        p[0] = f2tf(t.x); p[1] = f2tf(t.y); p[2] = f2tf(t.z); p[3] = f2tf(t.w);
    }

    {
        float ga = lng[lane], gb = lng[lane + 32];
        float ba = lnb[lane], bb2 = lnb[lane + 32];
        for (int r = w; r < 64; r += 8) {
            float v0 = x[(t0 + r) * 64 + lane];
            float v1 = x[(t0 + r) * 64 + 32 + lane];
            float s = v0 + v1;
#pragma unroll
            for (int o = 16; o; o >>= 1) s += __shfl_xor_sync(0xffffffffu, s, o);
            float mean = s * (1.f / 64.f);
            float d0 = v0 - mean, d1 = v1 - mean;
            float q = d0 * d0 + d1 * d1;
#pragma unroll
            for (int o = 16; o; o >>= 1) q += __shfl_xor_sync(0xffffffffu, q, o);
            float rstd = rsqrtf(q * (1.f / 64.f) + 1e-5f);
            Hs[r * 68 + lane]      = f2tf(d0 * rstd * ga + ba);
            Hs[r * 68 + 32 + lane] = f2tf(d1 * rstd * gb + bb2);
        }
    }
    __syncthreads();

    {
        int wn = w * 32;
        float acc[4][4][4];
#pragma unroll
        for (int mt = 0; mt < 4; mt++)
#pragma unroll
            for (int nt = 0; nt < 4; nt++)
#pragma unroll
                for (int i = 0; i < 4; i++) acc[mt][nt][i] = 0.f;
#pragma unroll
        for (int ks = 0; ks < 8; ks++) {
            int k0 = ks * 8 + c4;
            uint32_t bfr[4][2], afr[4][4];
#pragma unroll
            for (int nt = 0; nt < 4; nt++) {
                int col = wn + nt * 8 + g4;
                bfr[nt][0] = __float_as_uint(W1s[k0 * 260 + col]);
                bfr[nt][1] = __float_as_uint(W1s[(k0 + 4) * 260 + col]);
            }
#pragma unroll
            for (int mt = 0; mt < 4; mt++) {
                int base = (mt * 16 + g4) * 68 + k0;
                afr[mt][0] = __float_as_uint(Hs[base]);
                afr[mt][1] = __float_as_uint(Hs[base + 8 * 68]);
                afr[mt][2] = __float_as_uint(Hs[base + 4]);
                afr[mt][3] = __float_as_uint(Hs[base + 8 * 68 + 4]);
            }
#pragma unroll
            for (int mt = 0; mt < 4; mt++)
#pragma unroll
                for (int nt = 0; nt < 4; nt++)
                    mma_tf32(acc[mt][nt], afr[mt], bfr[nt], acc[mt][nt]);
        }
#pragma unroll
        for (int nt = 0; nt < 4; nt++) {
            int col = wn + nt * 8 + 2 * c4;
            float bb0 = b1[col], bb1 = b1[col + 1];
#pragma unroll
            for (int mt = 0; mt < 4; mt++) {
#pragma unroll
                for (int half = 0; half < 2; half++) {
                    int row = mt * 16 + g4 + 8 * half;
                    float v0 = acc[mt][nt][2 * half] + bb0;
                    float v1 = acc[mt][nt][2 * half + 1] + bb1;
                    v0 = 0.5f * v0 * (1.f + erff(v0 * 0.70710678118654752f));
                    v1 = 0.5f * v1 * (1.f + erff(v1 * 0.70710678118654752f));
                    Gs[row * 260 + col]     = f2tf(v0);
                    Gs[row * 260 + col + 1] = f2tf(v1);
                }
            }
        }
    }
    __syncthreads();

    {
        int ncol = w * 8;
        float acc[4][4];
#pragma unroll
        for (int mt = 0; mt < 4; mt++)
#pragma unroll
            for (int i = 0; i < 4; i++) acc[mt][i] = 0.f;
#pragma unroll
        for (int ks = 0; ks < 32; ks++) {
            int k0 = ks * 8 + c4;
            uint32_t bfr[2];
            bfr[0] = __float_as_uint(W2s[k0 * 68 + ncol + g4]);
            bfr[1] = __float_as_uint(W2s[(k0 + 4) * 68 + ncol + g4]);
#pragma unroll
            for (int mt = 0; mt < 4; mt++) {
                uint32_t a[4];
                int base = (mt * 16 + g4) * 260 + k0;
                a[0] = __float_as_uint(Gs[base]);
                a[1] = __float_as_uint(Gs[base + 8 * 260]);
                a[2] = __float_as_uint(Gs[base + 4]);
                a[3] = __float_as_uint(Gs[base + 8 * 260 + 4]);
                mma_tf32(acc[mt], a, bfr, acc[mt]);
            }
        }
        int col = ncol + 2 * c4;
        float bb0 = b2[col], bb1 = b2[col + 1];
#pragma unroll
        for (int mt = 0; mt < 4; mt++) {
#pragma unroll
            for (int half = 0; half < 2; half++) {
                long row = t0 + mt * 16 + g4 + 8 * half;
                float2 r = *(const float2*)(x + row * 64 + col);
                float v0 = acc[mt][2 * half] + bb0 + r.x;
                float v1 = acc[mt][2 * half + 1] + bb1 + r.y;
                *(float2*)(outx + row * 64 + col) = make_float2(v0, v1);
            }
        }
    }
}

// ---------------- primary caps: gather + squash ----------------
__global__ void caps_squash_k(const float* __restrict__ pc, float* __restrict__ caps) {
    int idx = blockIdx.x * blockDim.x + threadIdx.x; // b*1024 + i
    if (idx >= 256 * 1024) return;
    int i = idx & 1023, b = idx >> 10;
    int i32 = i >> 5, y = (i >> 3) & 3, xq = i & 7;
    const float* src = pc + (((long)b * 4 + y) * 8 + xq) * 256 + i32 * 8;
    float t[8];
    float l2 = 0.f;
#pragma unroll
    for (int e = 0; e < 8; e++) { t[e] = src[e]; l2 += t[e] * t[e]; }
    float sc = sqrtf(l2) / (1.f + l2);
#pragma unroll
    for (int e = 0; e < 8; e++) caps[(long)idx * 8 + e] = t[e] * sc;
}

// ---------------- capsule predictions u[b,i,:] ----------------
__global__ void caps_u_k(const float* __restrict__ caps, const float* __restrict__ cw,
                         float* __restrict__ u) {
    __shared__ float w_s[8 * 48];
    int i = blockIdx.x;
    for (int t = threadIdx.x; t < 384; t += 256) w_s[t] = cw[(long)i * 384 + t];
    __syncthreads();
    int b = threadIdx.x;
    float ce[8];
    const float* cp = caps + ((long)b * 1024 + i) * 8;
#pragma unroll
    for (int e = 0; e < 8; e++) ce[e] = cp[e];
    float* up = u + ((long)b * 1024 + i) * 48;
#pragma unroll 4
    for (int o = 0; o < 48; o++) {
        float s = 0.f;
#pragma unroll
        for (int e = 0; e < 8; e++) s = fmaf(ce[e], w_s[e * 48 + o], s);
        up[o] = s;
    }
}

// ---------------- dynamic routing, one block per batch element ----------------
__global__ void __launch_bounds__(256) routing_k(const float* __restrict__ u,
                                                 const float* __restrict__ br,
                                                 float* __restrict__ out) {
    __shared__ float bb[1024 * 3];
    __shared__ float S[48];
    __shared__ float v[48];
    int b = blockIdx.x, tid = threadIdx.x, lane = tid & 31;
    for (int i = tid; i < 3072; i += 256) bb[i] = br[i];
    __syncthreads();
    const float* ub = u + (long)b * 1024 * 48;

    for (int it = 0; it < 4; it++) {
        if (tid < 48) S[tid] = 0.f;
        __syncthreads();
        float acc[48];
#pragma unroll
        for (int o = 0; o < 48; o++) acc[o] = 0.f;
        for (int i = tid; i < 1024; i += 256) {
            float b0 = bb[i * 3], b1 = bb[i * 3 + 1], b2 = bb[i * 3 + 2];
            float m = fmaxf(b0, fmaxf(b1, b2));
            float e0 = expf(b0 - m), e1 = expf(b1 - m), e2 = expf(b2 - m);
            float inv = 1.f / (e0 + e1 + e2);
            float c[3] = {e0 * inv, e1 * inv, e2 * inv};
            const float* up = ub + (long)i * 48;
#pragma unroll
            for (int j = 0; j < 3; j++)
#pragma unroll
                for (int o = 0; o < 16; o++)
                    acc[j * 16 + o] = fmaf(c[j], up[j * 16 + o], acc[j * 16 + o]);
        }
#pragma unroll
        for (int o = 0; o < 48; o++) {
            float s = acc[o];
#pragma unroll
            for (int d = 16; d; d >>= 1) s += __shfl_xor_sync(0xffffffffu, s, d);
            if (lane == 0) atomicAdd(&S[o], s);
        }
        __syncthreads();
        if (tid < 3) {
            float l2 = 0.f;
            for (int o = 0; o < 16; o++) { float t = S[tid * 16 + o]; l2 += t * t; }
            float sc = sqrtf(l2) / (1.f + l2);
            for (int o = 0; o < 16; o++) v[tid * 16 + o] = S[tid * 16 + o] * sc;
            if (it == 3) out[b * 3 + tid] = l2 / (1.f + l2);  // |v| = l2/(1+l2)
        }
        __syncthreads();
        if (it < 3) {
            for (int i = tid; i < 1024; i += 256) {
                const float* up = ub + (long)i * 48;
#pragma unroll
                for (int j = 0; j < 3; j++) {
                    float s = 0.f;
#pragma unroll
                    for (int o = 0; o < 16; o++) s = fmaf(up[j * 16 + o], v[j * 16 + o], s);
                    bb[i * 3 + j] += s;
                }
            }
            __syncthreads();
        }
    }
}

// ---------------- host ----------------
extern "C" void kernel_launch(void* const* d_in, const int* in_sizes, int n_in,
                              void* d_out, int out_size) {
    const float* x_in    = (const float*)d_in[0];
    const float* conv1_w = (const float*)d_in[1];
    const float* conv2_w = (const float*)d_in[2];
    const float* pos_emb = (const float*)d_in[3];
    const float* ln1_g   = (const float*)d_in[4];
    const float* ln1_b   = (const float*)d_in[5];
    const float* qkv_w   = (const float*)d_in[6];
    const float* out_w   = (const float*)d_in[7];
    const float* out_b   = (const float*)d_in[8];
    const float* ln2_g   = (const float*)d_in[9];
    const float* ln2_b   = (const float*)d_in[10];
    const float* ff1_w   = (const float*)d_in[11];
    const float* ff1_b   = (const float*)d_in[12];
    const float* ff2_w   = (const float*)d_in[13];
    const float* ff2_b   = (const float*)d_in[14];
    const float* pcaps_w = (const float*)d_in[15];
    const float* pcaps_b = (const float*)d_in[16];
    const float* caps_w  = (const float*)d_in[17];
    const float* b_route = (const float*)d_in[18];
    float* out = (float*)d_out;

    float *col1, *wt1, *y1, *p1, *col2, *wt2, *y2, *xb, *ao, *col3, *wtp, *pc, *caps, *u;
    cudaGetSymbolAddress((void**)&col1, g_col1);
    cudaGetSymbolAddress((void**)&wt1,  g_wt1);
    cudaGetSymbolAddress((void**)&y1,   g_y1);
    cudaGetSymbolAddress((void**)&p1,   g_p1);
    cudaGetSymbolAddress((void**)&col2, g_col2);
    cudaGetSymbolAddress((void**)&wt2,  g_wt2);
    cudaGetSymbolAddress((void**)&y2,   g_y2);
    cudaGetSymbolAddress((void**)&xb,   g_x);
    cudaGetSymbolAddress((void**)&ao,   g_ao);
    cudaGetSymbolAddress((void**)&col3, g_col3);
    cudaGetSymbolAddress((void**)&wtp,  g_wtp);
    cudaGetSymbolAddress((void**)&pc,   g_pc);
    cudaGetSymbolAddress((void**)&caps, g_caps);
    cudaGetSymbolAddress((void**)&u,    g_u);

    cudaFuncSetAttribute(attn_fused_k, cudaFuncAttributeMaxDynamicSharedMemorySize, ATTNH_SMEM);
    cudaFuncSetAttribute(mlp_fused_k,  cudaFuncAttributeMaxDynamicSharedMemorySize, MLP_SMEM);

    // ---- ConvEmbed ----
    im2col1_k<<<(int)CDIV((long)737280 * 28, 256), 256>>>(x_in, col1);
    wtrans1<<<CDIV(64 * 28, 256), 256>>>(conv1_w, wt1);
    tgemm_k<1><<<dim3(1, 737280 / 128), 256>>>(col1, wt1, nullptr, nullptr, y1, 737280, 64, 28);
    maxpool_k<<<(int)CDIV((long)256 * 20 * 36 * 64, 256), 256>>>(y1, p1, 256, 40, 72, 64, 20, 36, nullptr);
    im2col2_k<<<(int)CDIV((long)184320 * 576, 256), 256>>>(p1, col2);
    wtrans_hwc<<<CDIV(64 * 576, 256), 256>>>(conv2_w, wt2, 64, 64);
    tgemm_k<1><<<dim3(1, 184320 / 128), 256>>>(col2, wt2, nullptr, nullptr, y2, 184320, 64, 576);
    maxpool_k<<<(int)CDIV((long)256 * 10 * 18 * 64, 256), 256>>>(y2, xb, 256, 20, 36, 64, 10, 18, pos_emb);

    // ---- Transformer: 12 shared layers applied twice ----
    const int M = 46080;
    for (int pass = 0; pass < 2; pass++) {
        for (int l = 0; l < 12; l++) {
            const float* qw  = qkv_w + (long)l * 64 * 2304;
            const float* ow  = out_w + (long)l * 768 * 64;
            const float* ob  = out_b + (long)l * 64;
            const float* f1w = ff1_w + (long)l * 64 * 256;
            const float* f1b = ff1_b + (long)l * 256;
            const float* f2w = ff2_w + (long)l * 256 * 64;
            const float* f2b = ff2_b + (long)l * 64;

            attn_fused_k<<<256 * 12, 256, ATTNH_SMEM>>>(xb, qw, ln1_g + l * 64, ln1_b + l * 64, ao);
            tgemm_k<4><<<dim3(1, M / 128), 256>>>(ao, ow, ob, xb, xb, M, 64, 768);
            mlp_fused_k<<<M / 64, 256, MLP_SMEM>>>(xb, f1w, f1b, f2w, f2b,
                                                   ln2_g + l * 64, ln2_b + l * 64, xb);
        }
    }

    // ---- PrimaryCaps + routing ----
    im2col3_k<<<(int)CDIV((long)8192 * 576, 256), 256>>>(xb, col3);
    wtrans_hwc<<<CDIV(256 * 576, 256), 256>>>(pcaps_w, wtp, 256, 64);
    tgemm_k<2><<<dim3(256 / 64, 8192 / 128), 256>>>(col3, wtp, pcaps_b, nullptr, pc, 8192, 256, 576);
    caps_squash_k<<<CDIV(256 * 1024, 256), 256>>>(pc, caps);
    caps_u_k<<<1024, 256>>>(caps, caps_w, u);
    routing_k<<<256, 256>>>(u, b_route, out);
}

// round 8
// speedup vs baseline: 3.7085x; 1.3735x over previous
#include <cuda_runtime.h>
#include <cuda_fp16.h>
#include <math.h>
#include <stdint.h>

#define CDIV(a,b) (((a)+(b)-1)/(b))

// ---------------- static scratch (no allocations allowed) ----------------
__device__ float g_col1[737280 * 28];        // conv1 im2col (K padded 27->28)
__device__ float g_wt1 [28 * 64];
__device__ float g_y1  [737280 * 64];        // conv1 out NHWC (B,40,72,64)
__device__ float g_p1  [184320 * 64];        // pool1 NHWC (B,20,36,64)
__device__ float g_col2[184320 * 576];       // conv2 im2col
__device__ float g_wt2 [576 * 64];
__device__ float g_y2  [184320 * 64];        // conv2 out NHWC (B,20,36,64)
__device__ float g_x   [46080 * 64];         // tokens / residual stream (B,180,64)
__device__ float g_ao  [46080 * 768];        // attention output (B,180,768)
__device__ float g_col3[8192 * 576];         // pcaps im2col
__device__ float g_wtp [576 * 256];
__device__ float g_pc  [8192 * 256];         // pcaps out NHWC (B,4,8,256)
__device__ float g_caps[256 * 1024 * 8];
__device__ float g_u   [256 * 1024 * 48];

// ---------------- im2col kernels ----------------
__global__ void im2col1_k(const float* __restrict__ x, float* __restrict__ col) {
    long idx = (long)blockIdx.x * blockDim.x + threadIdx.x;
    const long total = (long)737280 * 28;
    if (idx >= total) return;
    int kk = (int)(idx % 28);
    long m = idx / 28;
    if (kk == 27) { col[idx] = 0.f; return; }
    int ow = (int)(m % 72);
    int t  = (int)(m / 72);
    int oh = t % 40;
    int b  = t / 40;
    int kw = kk % 3, kh = (kk / 3) % 3, ci = kk / 9;
    int ih = oh + kh - 1, iw = ow + kw - 1;
    float v = 0.f;
    if (ih >= 0 && ih < 40 && iw >= 0 && iw < 72)
        v = x[(((long)b * 3 + ci) * 40 + ih) * 72 + iw];
    col[idx] = v;
}

__global__ void im2col2_k(const float* __restrict__ p1, float* __restrict__ col) {
    long idx = (long)blockIdx.x * blockDim.x + threadIdx.x;
    const long total = (long)184320 * 576;
    if (idx >= total) return;
    int kk = (int)(idx % 576);
    long m = idx / 576;
    int ow = (int)(m % 36);
    int t  = (int)(m / 36);
    int oh = t % 20;
    int b  = t / 20;
    int ci = kk % 64;
    int kw = (kk / 64) % 3;
    int kh = kk / 192;
    int ih = oh + kh - 1, iw = ow + kw - 1;
    float v = 0.f;
    if (ih >= 0 && ih < 20 && iw >= 0 && iw < 36)
        v = p1[(((long)b * 20 + ih) * 36 + iw) * 64 + ci];
    col[idx] = v;
}

// pcaps: input tokens g_x viewed as (B, 10, 18, 64); conv k3 s2 p0 -> (B,4,8,*)
__global__ void im2col3_k(const float* __restrict__ tk, float* __restrict__ col) {
    long idx = (long)blockIdx.x * blockDim.x + threadIdx.x;
    const long total = (long)8192 * 576;
    if (idx >= total) return;
    int kk = (int)(idx % 576);
    long m = idx / 576;
    int ow = (int)(m % 8);
    int t  = (int)(m / 8);
    int oh = t % 4;
    int b  = t / 4;
    int ci = kk % 64;
    int kw = (kk / 64) % 3;
    int kh = kk / 192;
    int ih = oh * 2 + kh, iw = ow * 2 + kw;
    col[idx] = tk[((long)b * 180 + ih * 18 + iw) * 64 + ci];
}

// ---------------- weight transposes ----------------
__global__ void wtrans1(const float* __restrict__ w, float* __restrict__ wt) {
    int i = blockIdx.x * blockDim.x + threadIdx.x;
    if (i >= 64 * 28) return;
    int o = i / 28, k = i % 28;
    wt[k * 64 + o] = (k < 27) ? w[o * 27 + k] : 0.f;
}
__global__ void wtrans_hwc(const float* __restrict__ w, float* __restrict__ wt, int O, int CI) {
    int K = CI * 9;
    int i = blockIdx.x * blockDim.x + threadIdx.x;
    if (i >= O * K) return;
    int o = i / K, r = i % K;
    int ci = r / 9, kh = (r % 9) / 3, kw = r % 3;
    wt[((kh * 3 + kw) * CI + ci) * O + o] = w[i];
}

// ---------------- tf32 helpers ----------------
__device__ __forceinline__ float f2tf(float f) {
    uint32_t r;
    asm("cvt.rna.tf32.f32 %0, %1;" : "=r"(r) : "f"(f));
    return __uint_as_float(r);
}
__device__ __forceinline__ void mma_tf32(float d[4], const uint32_t a[4], const uint32_t b[2],
                                         const float c[4]) {
    asm("mma.sync.aligned.m16n8k8.row.col.f32.tf32.tf32.f32 "
        "{%0,%1,%2,%3},{%4,%5,%6,%7},{%8,%9},{%10,%11,%12,%13};"
        : "=f"(d[0]), "=f"(d[1]), "=f"(d[2]), "=f"(d[3])
        : "r"(a[0]), "r"(a[1]), "r"(a[2]), "r"(a[3]), "r"(b[0]), "r"(b[1]),
          "f"(c[0]), "f"(c[1]), "f"(c[2]), "f"(c[3]));
}

// ---------------- fp16 mma helpers ----------------
__device__ __forceinline__ uint32_t smem_u32(const void* p) {
    return (uint32_t)__cvta_generic_to_shared(p);
}
__device__ __forceinline__ void ldsm_x4(uint32_t r[4], uint32_t addr) {
    asm volatile("ldmatrix.sync.aligned.m8n8.x4.shared.b16 {%0,%1,%2,%3}, [%4];"
        : "=r"(r[0]), "=r"(r[1]), "=r"(r[2]), "=r"(r[3]) : "r"(addr));
}
__device__ __forceinline__ void ldsm_x2(uint32_t r[2], uint32_t addr) {
    asm volatile("ldmatrix.sync.aligned.m8n8.x2.shared.b16 {%0,%1}, [%2];"
        : "=r"(r[0]), "=r"(r[1]) : "r"(addr));
}
__device__ __forceinline__ void ldsm_x2_t(uint32_t r[2], uint32_t addr) {
    asm volatile("ldmatrix.sync.aligned.m8n8.x2.trans.shared.b16 {%0,%1}, [%2];"
        : "=r"(r[0]), "=r"(r[1]) : "r"(addr));
}
__device__ __forceinline__ void mma_f16(float d[4], const uint32_t a[4], const uint32_t b[2],
                                        const float c[4]) {
    asm volatile("mma.sync.aligned.m16n8k16.row.col.f32.f16.f16.f32 "
        "{%0,%1,%2,%3},{%4,%5,%6,%7},{%8,%9},{%10,%11,%12,%13};"
        : "=f"(d[0]), "=f"(d[1]), "=f"(d[2]), "=f"(d[3])
        : "r"(a[0]), "r"(a[1]), "r"(a[2]), "r"(a[3]), "r"(b[0]), "r"(b[1]),
          "f"(c[0]), "f"(c[1]), "f"(c[2]), "f"(c[3]));
}
__device__ __forceinline__ uint32_t packh2(float a, float b) {
    __half2 h = __floats2half2_rn(a, b);
    return *(uint32_t*)&h;
}

// ---------------- tf32 tensor-core GEMM: 128x64 tile, 256 threads ----------------
// EPI: 0 none, 1 relu, 2 +bias, 3 +bias gelu, 4 +bias +res
template <int EPI>
__global__ void __launch_bounds__(256) tgemm_k(const float* __restrict__ A, const float* __restrict__ Bm,
                                               const float* __restrict__ bias, const float* __restrict__ res,
                                               float* __restrict__ C, int M, int N, int K) {
    __shared__ float As[128 * 36];   // [m][k], stride 36
    __shared__ float Bs[32 * 68];    // [k][n], stride 68
    const int bm = blockIdx.y * 128, bn = blockIdx.x * 64;
    const int tid = threadIdx.x, lane = tid & 31, w = tid >> 5;
    const int g4 = lane >> 2, c4 = lane & 3;
    const int wm = (w & 3) * 32, wn = (w >> 2) * 32;

    float acc[2][4][4];
#pragma unroll
    for (int mt = 0; mt < 2; mt++)
#pragma unroll
        for (int nt = 0; nt < 4; nt++)
#pragma unroll
            for (int i = 0; i < 4; i++) acc[mt][nt][i] = 0.f;

    const int ar = tid >> 1, akb = (tid & 1) * 16;
    const int bk = tid >> 3, bn0 = (tid & 7) * 8;
    const float* Arow = A + (long)(bm + ar) * K;

    for (int k0 = 0; k0 < K; k0 += 32) {
        float4 av[4], bv[2];
#pragma unroll
        for (int i = 0; i < 4; i++) {
            int gk = k0 + akb + 4 * i;
            av[i] = (gk + 4 <= K) ? *(const float4*)(Arow + gk) : make_float4(0.f, 0.f, 0.f, 0.f);
        }
        {
            int gk = k0 + bk;
            if (gk < K) {
                bv[0] = *(const float4*)(Bm + (long)gk * N + bn + bn0);
                bv[1] = *(const float4*)(Bm + (long)gk * N + bn + bn0 + 4);
            } else {
                bv[0] = make_float4(0.f, 0.f, 0.f, 0.f);
                bv[1] = bv[0];
            }
        }
        __syncthreads();
#pragma unroll
        for (int i = 0; i < 4; i++) {
            float* p = &As[ar * 36 + akb + 4 * i];
            p[0] = f2tf(av[i].x); p[1] = f2tf(av[i].y); p[2] = f2tf(av[i].z); p[3] = f2tf(av[i].w);
        }
        {
            float* p = &Bs[bk * 68 + bn0];
            p[0] = f2tf(bv[0].x); p[1] = f2tf(bv[0].y); p[2] = f2tf(bv[0].z); p[3] = f2tf(bv[0].w);
            p[4] = f2tf(bv[1].x); p[5] = f2tf(bv[1].y); p[6] = f2tf(bv[1].z); p[7] = f2tf(bv[1].w);
        }
        __syncthreads();
#pragma unroll
        for (int ks = 0; ks < 4; ks++) {
            uint32_t bfr[4][2], afr[2][4];
#pragma unroll
            for (int nt = 0; nt < 4; nt++) {
                int col = wn + nt * 8 + g4;
                bfr[nt][0] = __float_as_uint(Bs[(ks * 8 + c4) * 68 + col]);
                bfr[nt][1] = __float_as_uint(Bs[(ks * 8 + c4 + 4) * 68 + col]);
            }
#pragma unroll
            for (int mt = 0; mt < 2; mt++) {
                int base = (wm + mt * 16 + g4) * 36 + ks * 8 + c4;
                afr[mt][0] = __float_as_uint(As[base]);
                afr[mt][1] = __float_as_uint(As[base + 8 * 36]);
                afr[mt][2] = __float_as_uint(As[base + 4]);
                afr[mt][3] = __float_as_uint(As[base + 8 * 36 + 4]);
            }
#pragma unroll
            for (int mt = 0; mt < 2; mt++)
#pragma unroll
                for (int nt = 0; nt < 4; nt++)
                    mma_tf32(acc[mt][nt], afr[mt], bfr[nt], acc[mt][nt]);
        }
        __syncthreads();
    }

#pragma unroll
    for (int nt = 0; nt < 4; nt++) {
        int col = bn + wn + nt * 8 + 2 * c4;
        float b0 = 0.f, b1 = 0.f;
        if (EPI >= 2) { b0 = bias[col]; b1 = bias[col + 1]; }
#pragma unroll
        for (int mt = 0; mt < 2; mt++) {
#pragma unroll
            for (int half = 0; half < 2; half++) {
                long row = bm + wm + mt * 16 + g4 + 8 * half;
                float v0 = acc[mt][nt][2 * half], v1 = acc[mt][nt][2 * half + 1];
                if (EPI == 1) { v0 = fmaxf(v0, 0.f); v1 = fmaxf(v1, 0.f); }
                if (EPI >= 2) { v0 += b0; v1 += b1; }
                if (EPI == 3) {
                    v0 = 0.5f * v0 * (1.f + erff(v0 * 0.70710678118654752f));
                    v1 = 0.5f * v1 * (1.f + erff(v1 * 0.70710678118654752f));
                }
                if (EPI == 4) {
                    float2 r = *(const float2*)(res + row * N + col);
                    v0 += r.x; v1 += r.y;
                }
                *(float2*)(C + row * N + col) = make_float2(v0, v1);
            }
        }
    }
}

// ---------------- maxpool 3x3 s2 p1 on NHWC (+ optional pos-emb add) ----------------
__global__ void maxpool_k(const float* __restrict__ in, float* __restrict__ out,
                          int Bn, int IH, int IW, int C, int OH, int OW,
                          const float* __restrict__ pos) {
    long idx = (long)blockIdx.x * blockDim.x + threadIdx.x;
    long total = (long)Bn * OH * OW * C;
    if (idx >= total) return;
    int c = (int)(idx % C);
    long r = idx / C;
    int ow = (int)(r % OW); r /= OW;
    int oh = (int)(r % OH);
    int b  = (int)(r / OH);
    float m = -1e30f;
#pragma unroll
    for (int kh = 0; kh < 3; kh++) {
        int ih = oh * 2 - 1 + kh;
        if (ih < 0 || ih >= IH) continue;
#pragma unroll
        for (int kw = 0; kw < 3; kw++) {
            int iw = ow * 2 - 1 + kw;
            if (iw < 0 || iw >= IW) continue;
            m = fmaxf(m, in[(((long)b * IH + ih) * IW + iw) * C + c]);
        }
    }
    if (pos) m += pos[(oh * OW + ow) * C + c];
    out[idx] = m;
}

// ---------------- fully-fused attention v3: scores in registers ----------------
// 384 threads (12 warps); warp w owns row tile [16w, 16w+16).
// smem halfs: H16[192][72] @0, K16[192][72] @13824, V16[192][72] @27648, W16[3][64][72] @41472
#define ATTNH_SMEM ((3 * 192 * 72 + 3 * 64 * 72) * 2)

__global__ void __launch_bounds__(384, 1) attn_fused_k(const float* __restrict__ x,
                                                       const float* __restrict__ qw,
                                                       const float* __restrict__ lng,
                                                       const float* __restrict__ lnb,
                                                       float* __restrict__ out) {
    extern __shared__ __half smh[];
    __half* H16 = smh;
    __half* K16 = smh + 192 * 72;
    __half* V16 = smh + 2 * 192 * 72;
    __half* W16 = smh + 3 * 192 * 72;   // [mat][64][72], mat: 0=K,1=V,2=Q

    int b = blockIdx.x / 12, h = blockIdx.x % 12;
    int tid = threadIdx.x, lane = tid & 31, w = tid >> 5;
    int g4 = lane >> 2, c4 = lane & 3;
    int lmrow = lane & 15, lmk = (lane >> 4) * 8;   // ldmatrix x4 addressing
    int b2row = lane & 7, b2k = ((lane >> 3) & 1) * 8;  // ldmatrix x2 addressing
    const int r0 = w * 16;

    // ---- stage W16 (K, V, Q weight slices for this head), fp16, [n][k] ----
    for (int idx = tid; idx < 3 * 64 * 16; idx += 384) {
        int mat = idx >> 10;
        int rem = idx & 1023;
        int k = rem >> 4, n4 = (rem & 15) << 2;
        int moff = (mat == 0) ? 768 : (mat == 1) ? 1536 : 0;
        float4 t = *(const float4*)(qw + (long)k * 2304 + moff + h * 64 + n4);
        __half* Wm = W16 + mat * 64 * 72;
        Wm[(n4 + 0) * 72 + k] = __float2half(t.x);
        Wm[(n4 + 1) * 72 + k] = __float2half(t.y);
        Wm[(n4 + 2) * 72 + k] = __float2half(t.z);
        Wm[(n4 + 3) * 72 + k] = __float2half(t.w);
    }

    // ---- LN: residual from gmem -> fp16 H ----
    {
        const float* xb = x + (long)b * 180 * 64;
        float ga = lng[lane], gb = lng[lane + 32];
        float ba = lnb[lane], bb2 = lnb[lane + 32];
        for (int r = w; r < 180; r += 12) {
            float v0 = xb[r * 64 + lane], v1 = xb[r * 64 + 32 + lane];
            float s = v0 + v1;
#pragma unroll
            for (int o = 16; o; o >>= 1) s += __shfl_xor_sync(0xffffffffu, s, o);
            float mean = s * (1.f / 64.f);
            float d0 = v0 - mean, d1 = v1 - mean;
            float q = d0 * d0 + d1 * d1;
#pragma unroll
            for (int o = 16; o; o >>= 1) q += __shfl_xor_sync(0xffffffffu, q, o);
            float rstd = rsqrtf(q * (1.f / 64.f) + 1e-5f);
            H16[r * 72 + lane]      = __float2half(d0 * rstd * ga + ba);
            H16[r * 72 + 32 + lane] = __float2half(d1 * rstd * gb + bb2);
        }
        for (int i = tid; i < 12 * 72; i += 384) H16[180 * 72 + i] = __float2half(0.f);
    }
    __syncthreads();

    // ---- A fragments of H for this warp's row tile (reused for K, V, Q proj) ----
    uint32_t afr[4][4];
#pragma unroll
    for (int ks = 0; ks < 4; ks++)
        ldsm_x4(afr[ks], smem_u32(&H16[(r0 + lmrow) * 72 + ks * 16 + lmk]));

    // ---- K, V projections -> smem ----
#pragma unroll
    for (int mat = 0; mat < 2; mat++) {
        const __half* Wm = W16 + mat * 64 * 72;
        __half* dst = mat ? V16 : K16;
#pragma unroll
        for (int nt = 0; nt < 8; nt++) {
            float acc[4] = {0.f, 0.f, 0.f, 0.f};
#pragma unroll
            for (int ks = 0; ks < 4; ks++) {
                uint32_t bf[2];
                ldsm_x2(bf, smem_u32(&Wm[(nt * 8 + b2row) * 72 + ks * 16 + b2k]));
                mma_f16(acc, afr[ks], bf, acc);
            }
            int col = nt * 8 + 2 * c4;
            *(uint32_t*)&dst[(r0 + g4) * 72 + col]     = packh2(acc[0], acc[1]);
            *(uint32_t*)&dst[(r0 + g4 + 8) * 72 + col] = packh2(acc[2], acc[3]);
        }
    }

    // ---- Q projection -> registers (D-fragments repacked as A-fragments) ----
    uint32_t afq[4][4];
    {
        const __half* Wm = W16 + 2 * 64 * 72;
        float qacc[8][4];
#pragma unroll
        for (int nt = 0; nt < 8; nt++) {
#pragma unroll
            for (int i = 0; i < 4; i++) qacc[nt][i] = 0.f;
#pragma unroll
            for (int ks = 0; ks < 4; ks++) {
                uint32_t bf[2];
                ldsm_x2(bf, smem_u32(&Wm[(nt * 8 + b2row) * 72 + ks * 16 + b2k]));
                mma_f16(qacc[nt], afr[ks], bf, qacc[nt]);
            }
        }
#pragma unroll
        for (int kt = 0; kt < 4; kt++) {
            afq[kt][0] = packh2(qacc[2 * kt][0],     qacc[2 * kt][1]);
            afq[kt][1] = packh2(qacc[2 * kt][2],     qacc[2 * kt][3]);
            afq[kt][2] = packh2(qacc[2 * kt + 1][0], qacc[2 * kt + 1][1]);
            afq[kt][3] = packh2(qacc[2 * kt + 1][2], qacc[2 * kt + 1][3]);
        }
    }
    __syncthreads();   // K16/V16 visible to all warps

    // ---- S = (Q K^T) * 0.125, entirely in registers ----
    float S[24][4];
#pragma unroll
    for (int nt = 0; nt < 24; nt++) {
        float acc[4] = {0.f, 0.f, 0.f, 0.f};
#pragma unroll
        for (int ks = 0; ks < 4; ks++) {
            uint32_t bf[2];
            ldsm_x2(bf, smem_u32(&K16[(nt * 8 + b2row) * 72 + ks * 16 + b2k]));
            mma_f16(acc, afq[ks], bf, acc);
        }
#pragma unroll
        for (int i = 0; i < 4; i++) S[nt][i] = acc[i] * 0.125f;
    }

    // ---- softmax in registers (rows g4 and g4+8 of this warp's tile) ----
    {
        float mx0 = -1e30f, mx1 = -1e30f;
#pragma unroll
        for (int nt = 0; nt < 24; nt++) {
#pragma unroll
            for (int j = 0; j < 2; j++) {
                int col = nt * 8 + 2 * c4 + j;
                if (col < 180) {
                    mx0 = fmaxf(mx0, S[nt][j]);
                    mx1 = fmaxf(mx1, S[nt][2 + j]);
                }
            }
        }
        mx0 = fmaxf(mx0, __shfl_xor_sync(0xffffffffu, mx0, 1));
        mx0 = fmaxf(mx0, __shfl_xor_sync(0xffffffffu, mx0, 2));
        mx1 = fmaxf(mx1, __shfl_xor_sync(0xffffffffu, mx1, 1));
        mx1 = fmaxf(mx1, __shfl_xor_sync(0xffffffffu, mx1, 2));
        float sum0 = 0.f, sum1 = 0.f;
#pragma unroll
        for (int nt = 0; nt < 24; nt++) {
#pragma unroll
            for (int j = 0; j < 2; j++) {
                int col = nt * 8 + 2 * c4 + j;
                float e0 = (col < 180) ? __expf(S[nt][j] - mx0) : 0.f;
                float e1 = (col < 180) ? __expf(S[nt][2 + j] - mx1) : 0.f;
                S[nt][j] = e0; S[nt][2 + j] = e1;
                sum0 += e0; sum1 += e1;
            }
        }
        sum0 += __shfl_xor_sync(0xffffffffu, sum0, 1);
        sum0 += __shfl_xor_sync(0xffffffffu, sum0, 2);
        sum1 += __shfl_xor_sync(0xffffffffu, sum1, 1);
        sum1 += __shfl_xor_sync(0xffffffffu, sum1, 2);
        float inv0 = 1.f / sum0, inv1 = 1.f / sum1;
#pragma unroll
        for (int nt = 0; nt < 24; nt++) {
            S[nt][0] *= inv0; S[nt][1] *= inv0;
            S[nt][2] *= inv1; S[nt][3] *= inv1;
        }
    }

    // ---- pack P into A-fragments ----
    uint32_t P[12][4];
#pragma unroll
    for (int kt = 0; kt < 12; kt++) {
        P[kt][0] = packh2(S[2 * kt][0],     S[2 * kt][1]);
        P[kt][1] = packh2(S[2 * kt][2],     S[2 * kt][3]);
        P[kt][2] = packh2(S[2 * kt + 1][0], S[2 * kt + 1][1]);
        P[kt][3] = packh2(S[2 * kt + 1][2], S[2 * kt + 1][3]);
    }

    // ---- O = P V, write to gmem ----
    {
        float* outb = out + (long)b * 180 * 768 + h * 64;
#pragma unroll
        for (int nt = 0; nt < 8; nt++) {
            float acc[4] = {0.f, 0.f, 0.f, 0.f};
#pragma unroll
            for (int kt = 0; kt < 12; kt++) {
                uint32_t bv[2];
                ldsm_x2_t(bv, smem_u32(&V16[(kt * 16 + lmrow) * 72 + nt * 8]));
                mma_f16(acc, P[kt], bv, acc);
            }
            int row = r0 + g4;
            long col = nt * 8 + 2 * c4;
            if (row < 180)
                *(float2*)(outb + (long)row * 768 + col) = make_float2(acc[0], acc[1]);
            if (row + 8 < 180)
                *(float2*)(outb + (long)(row + 8) * 768 + col) = make_float2(acc[2], acc[3]);
        }
    }
}

// ---------------- fused MLP: LN2 + ff1 + GELU + ff2 + bias + residual ----------------
#define MH_OFF 0
#define MW1_OFF (64 * 68)
#define MG_OFF  (MW1_OFF + 64 * 260)
#define MW2_OFF (MG_OFF + 64 * 260)
#define MLP_SMEM ((MW2_OFF + 256 * 68) * 4)

__global__ void __launch_bounds__(256) mlp_fused_k(const float* __restrict__ x,
                                                   const float* __restrict__ w1,
                                                   const float* __restrict__ b1,
                                                   const float* __restrict__ w2,
                                                   const float* __restrict__ b2,
                                                   const float* __restrict__ lng,
                                                   const float* __restrict__ lnb,
                                                   float* __restrict__ outx) {
    extern __shared__ float sm[];
    float* Hs  = sm + MH_OFF;
    float* W1s = sm + MW1_OFF;
    float* Gs  = sm + MG_OFF;
    float* W2s = sm + MW2_OFF;

    int tid = threadIdx.x, lane = tid & 31, w = tid >> 5;
    int g4 = lane >> 2, c4 = lane & 3;
    long t0 = (long)blockIdx.x * 64;

    for (int i = tid; i < 64 * 64; i += 256) {
        int k = i >> 6, n4 = (i & 63) << 2;
        float4 t = *(const float4*)(w1 + (long)k * 256 + n4);
        float* p = &W1s[k * 260 + n4];
        p[0] = f2tf(t.x); p[1] = f2tf(t.y); p[2] = f2tf(t.z); p[3] = f2tf(t.w);
    }
    for (int i = tid; i < 256 * 16; i += 256) {
        int k = i >> 4, n4 = (i & 15) << 2;
        float4 t = *(const float4*)(w2 + (long)k * 64 + n4);
        float* p = &W2s[k * 68 + n4];
        p[0] = f2tf(t.x); p[1] = f2tf(t.y); p[2] = f2tf(t.z); p[3] = f2tf(t.w);
    }

    {
        float ga = lng[lane], gb = lng[lane + 32];
        float ba = lnb[lane], bb2 = lnb[lane + 32];
        for (int r = w; r < 64; r += 8) {
            float v0 = x[(t0 + r) * 64 + lane];
            float v1 = x[(t0 + r) * 64 + 32 + lane];
            float s = v0 + v1;
#pragma unroll
            for (int o = 16; o; o >>= 1) s += __shfl_xor_sync(0xffffffffu, s, o);
            float mean = s * (1.f / 64.f);
            float d0 = v0 - mean, d1 = v1 - mean;
            float q = d0 * d0 + d1 * d1;
#pragma unroll
            for (int o = 16; o; o >>= 1) q += __shfl_xor_sync(0xffffffffu, q, o);
            float rstd = rsqrtf(q * (1.f / 64.f) + 1e-5f);
            Hs[r * 68 + lane]      = f2tf(d0 * rstd * ga + ba);
            Hs[r * 68 + 32 + lane] = f2tf(d1 * rstd * gb + bb2);
        }
    }
    __syncthreads();

    {
        int wn = w * 32;
        float acc[4][4][4];
#pragma unroll
        for (int mt = 0; mt < 4; mt++)
#pragma unroll
            for (int nt = 0; nt < 4; nt++)
#pragma unroll
                for (int i = 0; i < 4; i++) acc[mt][nt][i] = 0.f;
#pragma unroll
        for (int ks = 0; ks < 8; ks++) {
            int k0 = ks * 8 + c4;
            uint32_t bfr[4][2], afr[4][4];
#pragma unroll
            for (int nt = 0; nt < 4; nt++) {
                int col = wn + nt * 8 + g4;
                bfr[nt][0] = __float_as_uint(W1s[k0 * 260 + col]);
                bfr[nt][1] = __float_as_uint(W1s[(k0 + 4) * 260 + col]);
            }
#pragma unroll
            for (int mt = 0; mt < 4; mt++) {
                int base = (mt * 16 + g4) * 68 + k0;
                afr[mt][0] = __float_as_uint(Hs[base]);
                afr[mt][1] = __float_as_uint(Hs[base + 8 * 68]);
                afr[mt][2] = __float_as_uint(Hs[base + 4]);
                afr[mt][3] = __float_as_uint(Hs[base + 8 * 68 + 4]);
            }
#pragma unroll
            for (int mt = 0; mt < 4; mt++)
#pragma unroll
                for (int nt = 0; nt < 4; nt++)
                    mma_tf32(acc[mt][nt], afr[mt], bfr[nt], acc[mt][nt]);
        }
#pragma unroll
        for (int nt = 0; nt < 4; nt++) {
            int col = wn + nt * 8 + 2 * c4;
            float bb0 = b1[col], bb1 = b1[col + 1];
#pragma unroll
            for (int mt = 0; mt < 4; mt++) {
#pragma unroll
                for (int half = 0; half < 2; half++) {
                    int row = mt * 16 + g4 + 8 * half;
                    float v0 = acc[mt][nt][2 * half] + bb0;
                    float v1 = acc[mt][nt][2 * half + 1] + bb1;
                    v0 = 0.5f * v0 * (1.f + erff(v0 * 0.70710678118654752f));
                    v1 = 0.5f * v1 * (1.f + erff(v1 * 0.70710678118654752f));
                    Gs[row * 260 + col]     = f2tf(v0);
                    Gs[row * 260 + col + 1] = f2tf(v1);
                }
            }
        }
    }
    __syncthreads();

    {
        int ncol = w * 8;
        float acc[4][4];
#pragma unroll
        for (int mt = 0; mt < 4; mt++)
#pragma unroll
            for (int i = 0; i < 4; i++) acc[mt][i] = 0.f;
#pragma unroll
        for (int ks = 0; ks < 32; ks++) {
            int k0 = ks * 8 + c4;
            uint32_t bfr[2];
            bfr[0] = __float_as_uint(W2s[k0 * 68 + ncol + g4]);
            bfr[1] = __float_as_uint(W2s[(k0 + 4) * 68 + ncol + g4]);
#pragma unroll
            for (int mt = 0; mt < 4; mt++) {
                uint32_t a[4];
                int base = (mt * 16 + g4) * 260 + k0;
                a[0] = __float_as_uint(Gs[base]);
                a[1] = __float_as_uint(Gs[base + 8 * 260]);
                a[2] = __float_as_uint(Gs[base + 4]);
                a[3] = __float_as_uint(Gs[base + 8 * 260 + 4]);
                mma_tf32(acc[mt], a, bfr, acc[mt]);
            }
        }
        int col = ncol + 2 * c4;
        float bb0 = b2[col], bb1 = b2[col + 1];
#pragma unroll
        for (int mt = 0; mt < 4; mt++) {
#pragma unroll
            for (int half = 0; half < 2; half++) {
                long row = t0 + mt * 16 + g4 + 8 * half;
                float2 r = *(const float2*)(x + row * 64 + col);
                float v0 = acc[mt][2 * half] + bb0 + r.x;
                float v1 = acc[mt][2 * half + 1] + bb1 + r.y;
                *(float2*)(outx + row * 64 + col) = make_float2(v0, v1);
            }
        }
    }
}

// ---------------- primary caps: gather + squash ----------------
__global__ void caps_squash_k(const float* __restrict__ pc, float* __restrict__ caps) {
    int idx = blockIdx.x * blockDim.x + threadIdx.x; // b*1024 + i
    if (idx >= 256 * 1024) return;
    int i = idx & 1023, b = idx >> 10;
    int i32 = i >> 5, y = (i >> 3) & 3, xq = i & 7;
    const float* src = pc + (((long)b * 4 + y) * 8 + xq) * 256 + i32 * 8;
    float t[8];
    float l2 = 0.f;
#pragma unroll
    for (int e = 0; e < 8; e++) { t[e] = src[e]; l2 += t[e] * t[e]; }
    float sc = sqrtf(l2) / (1.f + l2);
#pragma unroll
    for (int e = 0; e < 8; e++) caps[(long)idx * 8 + e] = t[e] * sc;
}

// ---------------- capsule predictions u[b,i,:] ----------------
__global__ void caps_u_k(const float* __restrict__ caps, const float* __restrict__ cw,
                         float* __restrict__ u) {
    __shared__ float w_s[8 * 48];
    int i = blockIdx.x;
    for (int t = threadIdx.x; t < 384; t += 256) w_s[t] = cw[(long)i * 384 + t];
    __syncthreads();
    int b = threadIdx.x;
    float ce[8];
    const float* cp = caps + ((long)b * 1024 + i) * 8;
#pragma unroll
    for (int e = 0; e < 8; e++) ce[e] = cp[e];
    float* up = u + ((long)b * 1024 + i) * 48;
#pragma unroll 4
    for (int o = 0; o < 48; o++) {
        float s = 0.f;
#pragma unroll
        for (int e = 0; e < 8; e++) s = fmaf(ce[e], w_s[e * 48 + o], s);
        up[o] = s;
    }
}

// ---------------- dynamic routing, one block per batch element ----------------
__global__ void __launch_bounds__(256) routing_k(const float* __restrict__ u,
                                                 const float* __restrict__ br,
                                                 float* __restrict__ out) {
    __shared__ float bb[1024 * 3];
    __shared__ float S[48];
    __shared__ float v[48];
    int b = blockIdx.x, tid = threadIdx.x, lane = tid & 31;
    for (int i = tid; i < 3072; i += 256) bb[i] = br[i];
    __syncthreads();
    const float* ub = u + (long)b * 1024 * 48;

    for (int it = 0; it < 4; it++) {
        if (tid < 48) S[tid] = 0.f;
        __syncthreads();
        float acc[48];
#pragma unroll
        for (int o = 0; o < 48; o++) acc[o] = 0.f;
        for (int i = tid; i < 1024; i += 256) {
            float b0 = bb[i * 3], b1 = bb[i * 3 + 1], b2 = bb[i * 3 + 2];
            float m = fmaxf(b0, fmaxf(b1, b2));
            float e0 = expf(b0 - m), e1 = expf(b1 - m), e2 = expf(b2 - m);
            float inv = 1.f / (e0 + e1 + e2);
            float c[3] = {e0 * inv, e1 * inv, e2 * inv};
            const float* up = ub + (long)i * 48;
#pragma unroll
            for (int j = 0; j < 3; j++)
#pragma unroll
                for (int o = 0; o < 16; o++)
                    acc[j * 16 + o] = fmaf(c[j], up[j * 16 + o], acc[j * 16 + o]);
        }
#pragma unroll
        for (int o = 0; o < 48; o++) {
            float s = acc[o];
#pragma unroll
            for (int d = 16; d; d >>= 1) s += __shfl_xor_sync(0xffffffffu, s, d);
            if (lane == 0) atomicAdd(&S[o], s);
        }
        __syncthreads();
        if (tid < 3) {
            float l2 = 0.f;
            for (int o = 0; o < 16; o++) { float t = S[tid * 16 + o]; l2 += t * t; }
            float sc = sqrtf(l2) / (1.f + l2);
            for (int o = 0; o < 16; o++) v[tid * 16 + o] = S[tid * 16 + o] * sc;
            if (it == 3) out[b * 3 + tid] = l2 / (1.f + l2);  // |v| = l2/(1+l2)
        }
        __syncthreads();
        if (it < 3) {
            for (int i = tid; i < 1024; i += 256) {
                const float* up = ub + (long)i * 48;
#pragma unroll
                for (int j = 0; j < 3; j++) {
                    float s = 0.f;
#pragma unroll
                    for (int o = 0; o < 16; o++) s = fmaf(up[j * 16 + o], v[j * 16 + o], s);
                    bb[i * 3 + j] += s;
                }
            }
            __syncthreads();
        }
    }
}

// ---------------- host ----------------
extern "C" void kernel_launch(void* const* d_in, const int* in_sizes, int n_in,
                              void* d_out, int out_size) {
    const float* x_in    = (const float*)d_in[0];
    const float* conv1_w = (const float*)d_in[1];
    const float* conv2_w = (const float*)d_in[2];
    const float* pos_emb = (const float*)d_in[3];
    const float* ln1_g   = (const float*)d_in[4];
    const float* ln1_b   = (const float*)d_in[5];
    const float* qkv_w   = (const float*)d_in[6];
    const float* out_w   = (const float*)d_in[7];
    const float* out_b   = (const float*)d_in[8];
    const float* ln2_g   = (const float*)d_in[9];
    const float* ln2_b   = (const float*)d_in[10];
    const float* ff1_w   = (const float*)d_in[11];
    const float* ff1_b   = (const float*)d_in[12];
    const float* ff2_w   = (const float*)d_in[13];
    const float* ff2_b   = (const float*)d_in[14];
    const float* pcaps_w = (const float*)d_in[15];
    const float* pcaps_b = (const float*)d_in[16];
    const float* caps_w  = (const float*)d_in[17];
    const float* b_route = (const float*)d_in[18];
    float* out = (float*)d_out;

    float *col1, *wt1, *y1, *p1, *col2, *wt2, *y2, *xb, *ao, *col3, *wtp, *pc, *caps, *u;
    cudaGetSymbolAddress((void**)&col1, g_col1);
    cudaGetSymbolAddress((void**)&wt1,  g_wt1);
    cudaGetSymbolAddress((void**)&y1,   g_y1);
    cudaGetSymbolAddress((void**)&p1,   g_p1);
    cudaGetSymbolAddress((void**)&col2, g_col2);
    cudaGetSymbolAddress((void**)&wt2,  g_wt2);
    cudaGetSymbolAddress((void**)&y2,   g_y2);
    cudaGetSymbolAddress((void**)&xb,   g_x);
    cudaGetSymbolAddress((void**)&ao,   g_ao);
    cudaGetSymbolAddress((void**)&col3, g_col3);
    cudaGetSymbolAddress((void**)&wtp,  g_wtp);
    cudaGetSymbolAddress((void**)&pc,   g_pc);
    cudaGetSymbolAddress((void**)&caps, g_caps);
    cudaGetSymbolAddress((void**)&u,    g_u);

    cudaFuncSetAttribute(attn_fused_k, cudaFuncAttributeMaxDynamicSharedMemorySize, ATTNH_SMEM);
    cudaFuncSetAttribute(mlp_fused_k,  cudaFuncAttributeMaxDynamicSharedMemorySize, MLP_SMEM);

    // ---- ConvEmbed ----
    im2col1_k<<<(int)CDIV((long)737280 * 28, 256), 256>>>(x_in, col1);
    wtrans1<<<CDIV(64 * 28, 256), 256>>>(conv1_w, wt1);
    tgemm_k<1><<<dim3(1, 737280 / 128), 256>>>(col1, wt1, nullptr, nullptr, y1, 737280, 64, 28);
    maxpool_k<<<(int)CDIV((long)256 * 20 * 36 * 64, 256), 256>>>(y1, p1, 256, 40, 72, 64, 20, 36, nullptr);
    im2col2_k<<<(int)CDIV((long)184320 * 576, 256), 256>>>(p1, col2);
    wtrans_hwc<<<CDIV(64 * 576, 256), 256>>>(conv2_w, wt2, 64, 64);
    tgemm_k<1><<<dim3(1, 184320 / 128), 256>>>(col2, wt2, nullptr, nullptr, y2, 184320, 64, 576);
    maxpool_k<<<(int)CDIV((long)256 * 10 * 18 * 64, 256), 256>>>(y2, xb, 256, 20, 36, 64, 10, 18, pos_emb);

    // ---- Transformer: 12 shared layers applied twice ----
    const int M = 46080;
    for (int pass = 0; pass < 2; pass++) {
        for (int l = 0; l < 12; l++) {
            const float* qw  = qkv_w + (long)l * 64 * 2304;
            const float* ow  = out_w + (long)l * 768 * 64;
            const float* ob  = out_b + (long)l * 64;
            const float* f1w = ff1_w + (long)l * 64 * 256;
            const float* f1b = ff1_b + (long)l * 256;
            const float* f2w = ff2_w + (long)l * 256 * 64;
            const float* f2b = ff2_b + (long)l * 64;

            attn_fused_k<<<256 * 12, 384, ATTNH_SMEM>>>(xb, qw, ln1_g + l * 64, ln1_b + l * 64, ao);
            tgemm_k<4><<<dim3(1, M / 128), 256>>>(ao, ow, ob, xb, xb, M, 64, 768);
            mlp_fused_k<<<M / 64, 256, MLP_SMEM>>>(xb, f1w, f1b, f2w, f2b,
                                                   ln2_g + l * 64, ln2_b + l * 64, xb);
        }
    }

    // ---- PrimaryCaps + routing ----
    im2col3_k<<<(int)CDIV((long)8192 * 576, 256), 256>>>(xb, col3);
    wtrans_hwc<<<CDIV(256 * 576, 256), 256>>>(pcaps_w, wtp, 256, 64);
    tgemm_k<2><<<dim3(256 / 64, 8192 / 128), 256>>>(col3, wtp, pcaps_b, nullptr, pc, 8192, 256, 576);
    caps_squash_k<<<CDIV(256 * 1024, 256), 256>>>(pc, caps);
    caps_u_k<<<1024, 256>>>(caps, caps_w, u);
    routing_k<<<256, 256>>>(u, b_route, out);
}

// round 9
// speedup vs baseline: 4.1196x; 1.1109x over previous
#include <cuda_runtime.h>
#include <cuda_fp16.h>
#include <math.h>
#include <stdint.h>

#define CDIV(a,b) (((a)+(b)-1)/(b))

// ---------------- static scratch (no allocations allowed) ----------------
__device__ float g_col1[737280 * 28];        // conv1 im2col (K padded 27->28)
__device__ float g_wt1 [28 * 64];
__device__ float g_y1  [737280 * 64];        // conv1 out NHWC (B,40,72,64)
__device__ float g_p1  [184320 * 64];        // pool1 NHWC (B,20,36,64)
__device__ float g_col2[184320 * 576];       // conv2 im2col
__device__ float g_wt2 [576 * 64];
__device__ float g_y2  [184320 * 64];        // conv2 out NHWC (B,20,36,64)
__device__ float g_x   [46080 * 64];         // tokens / residual stream (B,180,64)
__device__ __half g_aoh[46080 * 768];        // attention output fp16 (B,180,768)
__device__ float g_col3[8192 * 576];         // pcaps im2col
__device__ float g_wtp [576 * 256];
__device__ float g_pc  [8192 * 256];         // pcaps out NHWC (B,4,8,256)
__device__ float g_caps[256 * 1024 * 8];
__device__ float g_u   [256 * 1024 * 48];

// ---------------- im2col kernels ----------------
__global__ void im2col1_k(const float* __restrict__ x, float* __restrict__ col) {
    long idx = (long)blockIdx.x * blockDim.x + threadIdx.x;
    const long total = (long)737280 * 28;
    if (idx >= total) return;
    int kk = (int)(idx % 28);
    long m = idx / 28;
    if (kk == 27) { col[idx] = 0.f; return; }
    int ow = (int)(m % 72);
    int t  = (int)(m / 72);
    int oh = t % 40;
    int b  = t / 40;
    int kw = kk % 3, kh = (kk / 3) % 3, ci = kk / 9;
    int ih = oh + kh - 1, iw = ow + kw - 1;
    float v = 0.f;
    if (ih >= 0 && ih < 40 && iw >= 0 && iw < 72)
        v = x[(((long)b * 3 + ci) * 40 + ih) * 72 + iw];
    col[idx] = v;
}

__global__ void im2col2_k(const float* __restrict__ p1, float* __restrict__ col) {
    long idx = (long)blockIdx.x * blockDim.x + threadIdx.x;
    const long total = (long)184320 * 576;
    if (idx >= total) return;
    int kk = (int)(idx % 576);
    long m = idx / 576;
    int ow = (int)(m % 36);
    int t  = (int)(m / 36);
    int oh = t % 20;
    int b  = t / 20;
    int ci = kk % 64;
    int kw = (kk / 64) % 3;
    int kh = kk / 192;
    int ih = oh + kh - 1, iw = ow + kw - 1;
    float v = 0.f;
    if (ih >= 0 && ih < 20 && iw >= 0 && iw < 36)
        v = p1[(((long)b * 20 + ih) * 36 + iw) * 64 + ci];
    col[idx] = v;
}

// pcaps: input tokens g_x viewed as (B, 10, 18, 64); conv k3 s2 p0 -> (B,4,8,*)
__global__ void im2col3_k(const float* __restrict__ tk, float* __restrict__ col) {
    long idx = (long)blockIdx.x * blockDim.x + threadIdx.x;
    const long total = (long)8192 * 576;
    if (idx >= total) return;
    int kk = (int)(idx % 576);
    long m = idx / 576;
    int ow = (int)(m % 8);
    int t  = (int)(m / 8);
    int oh = t % 4;
    int b  = t / 4;
    int ci = kk % 64;
    int kw = (kk / 64) % 3;
    int kh = kk / 192;
    int ih = oh * 2 + kh, iw = ow * 2 + kw;
    col[idx] = tk[((long)b * 180 + ih * 18 + iw) * 64 + ci];
}

// ---------------- weight transposes ----------------
__global__ void wtrans1(const float* __restrict__ w, float* __restrict__ wt) {
    int i = blockIdx.x * blockDim.x + threadIdx.x;
    if (i >= 64 * 28) return;
    int o = i / 28, k = i % 28;
    wt[k * 64 + o] = (k < 27) ? w[o * 27 + k] : 0.f;
}
__global__ void wtrans_hwc(const float* __restrict__ w, float* __restrict__ wt, int O, int CI) {
    int K = CI * 9;
    int i = blockIdx.x * blockDim.x + threadIdx.x;
    if (i >= O * K) return;
    int o = i / K, r = i % K;
    int ci = r / 9, kh = (r % 9) / 3, kw = r % 3;
    wt[((kh * 3 + kw) * CI + ci) * O + o] = w[i];
}

// ---------------- tf32 helpers ----------------
__device__ __forceinline__ float f2tf(float f) {
    uint32_t r;
    asm("cvt.rna.tf32.f32 %0, %1;" : "=r"(r) : "f"(f));
    return __uint_as_float(r);
}
__device__ __forceinline__ void mma_tf32(float d[4], const uint32_t a[4], const uint32_t b[2],
                                         const float c[4]) {
    asm("mma.sync.aligned.m16n8k8.row.col.f32.tf32.tf32.f32 "
        "{%0,%1,%2,%3},{%4,%5,%6,%7},{%8,%9},{%10,%11,%12,%13};"
        : "=f"(d[0]), "=f"(d[1]), "=f"(d[2]), "=f"(d[3])
        : "r"(a[0]), "r"(a[1]), "r"(a[2]), "r"(a[3]), "r"(b[0]), "r"(b[1]),
          "f"(c[0]), "f"(c[1]), "f"(c[2]), "f"(c[3]));
}

// ---------------- fp16 mma helpers ----------------
__device__ __forceinline__ uint32_t smem_u32(const void* p) {
    return (uint32_t)__cvta_generic_to_shared(p);
}
__device__ __forceinline__ void ldsm_x4(uint32_t r[4], uint32_t addr) {
    asm volatile("ldmatrix.sync.aligned.m8n8.x4.shared.b16 {%0,%1,%2,%3}, [%4];"
        : "=r"(r[0]), "=r"(r[1]), "=r"(r[2]), "=r"(r[3]) : "r"(addr));
}
__device__ __forceinline__ void ldsm_x2(uint32_t r[2], uint32_t addr) {
    asm volatile("ldmatrix.sync.aligned.m8n8.x2.shared.b16 {%0,%1}, [%2];"
        : "=r"(r[0]), "=r"(r[1]) : "r"(addr));
}
__device__ __forceinline__ void ldsm_x2_t(uint32_t r[2], uint32_t addr) {
    asm volatile("ldmatrix.sync.aligned.m8n8.x2.trans.shared.b16 {%0,%1}, [%2];"
        : "=r"(r[0]), "=r"(r[1]) : "r"(addr));
}
__device__ __forceinline__ void mma_f16(float d[4], const uint32_t a[4], const uint32_t b[2],
                                        const float c[4]) {
    asm volatile("mma.sync.aligned.m16n8k16.row.col.f32.f16.f16.f32 "
        "{%0,%1,%2,%3},{%4,%5,%6,%7},{%8,%9},{%10,%11,%12,%13};"
        : "=f"(d[0]), "=f"(d[1]), "=f"(d[2]), "=f"(d[3])
        : "r"(a[0]), "r"(a[1]), "r"(a[2]), "r"(a[3]), "r"(b[0]), "r"(b[1]),
          "f"(c[0]), "f"(c[1]), "f"(c[2]), "f"(c[3]));
}
__device__ __forceinline__ uint32_t packh2(float a, float b) {
    __half2 h = __floats2half2_rn(a, b);
    return *(uint32_t*)&h;
}

// ---------------- tf32 tensor-core GEMM (convs / pcaps) ----------------
// EPI: 0 none, 1 relu, 2 +bias
template <int EPI>
__global__ void __launch_bounds__(256) tgemm_k(const float* __restrict__ A, const float* __restrict__ Bm,
                                               const float* __restrict__ bias, const float* __restrict__ res,
                                               float* __restrict__ C, int M, int N, int K) {
    __shared__ float As[128 * 36];
    __shared__ float Bs[32 * 68];
    const int bm = blockIdx.y * 128, bn = blockIdx.x * 64;
    const int tid = threadIdx.x, lane = tid & 31, w = tid >> 5;
    const int g4 = lane >> 2, c4 = lane & 3;
    const int wm = (w & 3) * 32, wn = (w >> 2) * 32;

    float acc[2][4][4];
#pragma unroll
    for (int mt = 0; mt < 2; mt++)
#pragma unroll
        for (int nt = 0; nt < 4; nt++)
#pragma unroll
            for (int i = 0; i < 4; i++) acc[mt][nt][i] = 0.f;

    const int ar = tid >> 1, akb = (tid & 1) * 16;
    const int bk = tid >> 3, bn0 = (tid & 7) * 8;
    const float* Arow = A + (long)(bm + ar) * K;

    for (int k0 = 0; k0 < K; k0 += 32) {
        float4 av[4], bv[2];
#pragma unroll
        for (int i = 0; i < 4; i++) {
            int gk = k0 + akb + 4 * i;
            av[i] = (gk + 4 <= K) ? *(const float4*)(Arow + gk) : make_float4(0.f, 0.f, 0.f, 0.f);
        }
        {
            int gk = k0 + bk;
            if (gk < K) {
                bv[0] = *(const float4*)(Bm + (long)gk * N + bn + bn0);
                bv[1] = *(const float4*)(Bm + (long)gk * N + bn + bn0 + 4);
            } else {
                bv[0] = make_float4(0.f, 0.f, 0.f, 0.f);
                bv[1] = bv[0];
            }
        }
        __syncthreads();
#pragma unroll
        for (int i = 0; i < 4; i++) {
            float* p = &As[ar * 36 + akb + 4 * i];
            p[0] = f2tf(av[i].x); p[1] = f2tf(av[i].y); p[2] = f2tf(av[i].z); p[3] = f2tf(av[i].w);
        }
        {
            float* p = &Bs[bk * 68 + bn0];
            p[0] = f2tf(bv[0].x); p[1] = f2tf(bv[0].y); p[2] = f2tf(bv[0].z); p[3] = f2tf(bv[0].w);
            p[4] = f2tf(bv[1].x); p[5] = f2tf(bv[1].y); p[6] = f2tf(bv[1].z); p[7] = f2tf(bv[1].w);
        }
        __syncthreads();
#pragma unroll
        for (int ks = 0; ks < 4; ks++) {
            uint32_t bfr[4][2], afr[2][4];
#pragma unroll
            for (int nt = 0; nt < 4; nt++) {
                int col = wn + nt * 8 + g4;
                bfr[nt][0] = __float_as_uint(Bs[(ks * 8 + c4) * 68 + col]);
                bfr[nt][1] = __float_as_uint(Bs[(ks * 8 + c4 + 4) * 68 + col]);
            }
#pragma unroll
            for (int mt = 0; mt < 2; mt++) {
                int base = (wm + mt * 16 + g4) * 36 + ks * 8 + c4;
                afr[mt][0] = __float_as_uint(As[base]);
                afr[mt][1] = __float_as_uint(As[base + 8 * 36]);
                afr[mt][2] = __float_as_uint(As[base + 4]);
                afr[mt][3] = __float_as_uint(As[base + 8 * 36 + 4]);
            }
#pragma unroll
            for (int mt = 0; mt < 2; mt++)
#pragma unroll
                for (int nt = 0; nt < 4; nt++)
                    mma_tf32(acc[mt][nt], afr[mt], bfr[nt], acc[mt][nt]);
        }
        __syncthreads();
    }

#pragma unroll
    for (int nt = 0; nt < 4; nt++) {
        int col = bn + wn + nt * 8 + 2 * c4;
        float b0 = 0.f, b1 = 0.f;
        if (EPI >= 2) { b0 = bias[col]; b1 = bias[col + 1]; }
#pragma unroll
        for (int mt = 0; mt < 2; mt++) {
#pragma unroll
            for (int half = 0; half < 2; half++) {
                long row = bm + wm + mt * 16 + g4 + 8 * half;
                float v0 = acc[mt][nt][2 * half], v1 = acc[mt][nt][2 * half + 1];
                if (EPI == 1) { v0 = fmaxf(v0, 0.f); v1 = fmaxf(v1, 0.f); }
                if (EPI >= 2) { v0 += b0; v1 += b1; }
                *(float2*)(C + row * N + col) = make_float2(v0, v1);
            }
        }
    }
}

// ---------------- maxpool 3x3 s2 p1 on NHWC (+ optional pos-emb add) ----------------
__global__ void maxpool_k(const float* __restrict__ in, float* __restrict__ out,
                          int Bn, int IH, int IW, int C, int OH, int OW,
                          const float* __restrict__ pos) {
    long idx = (long)blockIdx.x * blockDim.x + threadIdx.x;
    long total = (long)Bn * OH * OW * C;
    if (idx >= total) return;
    int c = (int)(idx % C);
    long r = idx / C;
    int ow = (int)(r % OW); r /= OW;
    int oh = (int)(r % OH);
    int b  = (int)(r / OH);
    float m = -1e30f;
#pragma unroll
    for (int kh = 0; kh < 3; kh++) {
        int ih = oh * 2 - 1 + kh;
        if (ih < 0 || ih >= IH) continue;
#pragma unroll
        for (int kw = 0; kw < 3; kw++) {
            int iw = ow * 2 - 1 + kw;
            if (iw < 0 || iw >= IW) continue;
            m = fmaxf(m, in[(((long)b * IH + ih) * IW + iw) * C + c]);
        }
    }
    if (pos) m += pos[(oh * OW + ow) * C + c];
    out[idx] = m;
}

// ---------------- fully-fused attention: scores in registers, fp16 out ----------------
// 384 threads (12 warps); warp w owns row tile [16w, 16w+16).
#define ATTNH_SMEM ((3 * 192 * 72 + 3 * 64 * 72) * 2)

__global__ void __launch_bounds__(384, 1) attn_fused_k(const float* __restrict__ x,
                                                       const float* __restrict__ qw,
                                                       const float* __restrict__ lng,
                                                       const float* __restrict__ lnb,
                                                       __half* __restrict__ out) {
    extern __shared__ __half smh[];
    __half* H16 = smh;
    __half* K16 = smh + 192 * 72;
    __half* V16 = smh + 2 * 192 * 72;
    __half* W16 = smh + 3 * 192 * 72;   // [mat][64][72], mat: 0=K,1=V,2=Q

    int b = blockIdx.x / 12, h = blockIdx.x % 12;
    int tid = threadIdx.x, lane = tid & 31, w = tid >> 5;
    int g4 = lane >> 2, c4 = lane & 3;
    int lmrow = lane & 15, lmk = (lane >> 4) * 8;
    int b2row = lane & 7, b2k = ((lane >> 3) & 1) * 8;
    const int r0 = w * 16;

    // ---- stage W16 (K, V, Q weight slices for this head), fp16, [n][k] ----
    for (int idx = tid; idx < 3 * 64 * 16; idx += 384) {
        int mat = idx >> 10;
        int rem = idx & 1023;
        int k = rem >> 4, n4 = (rem & 15) << 2;
        int moff = (mat == 0) ? 768 : (mat == 1) ? 1536 : 0;
        float4 t = *(const float4*)(qw + (long)k * 2304 + moff + h * 64 + n4);
        __half* Wm = W16 + mat * 64 * 72;
        Wm[(n4 + 0) * 72 + k] = __float2half(t.x);
        Wm[(n4 + 1) * 72 + k] = __float2half(t.y);
        Wm[(n4 + 2) * 72 + k] = __float2half(t.z);
        Wm[(n4 + 3) * 72 + k] = __float2half(t.w);
    }

    // ---- LN: residual from gmem -> fp16 H ----
    {
        const float* xb = x + (long)b * 180 * 64;
        float ga = lng[lane], gb = lng[lane + 32];
        float ba = lnb[lane], bb2 = lnb[lane + 32];
        for (int r = w; r < 180; r += 12) {
            float v0 = xb[r * 64 + lane], v1 = xb[r * 64 + 32 + lane];
            float s = v0 + v1;
#pragma unroll
            for (int o = 16; o; o >>= 1) s += __shfl_xor_sync(0xffffffffu, s, o);
            float mean = s * (1.f / 64.f);
            float d0 = v0 - mean, d1 = v1 - mean;
            float q = d0 * d0 + d1 * d1;
#pragma unroll
            for (int o = 16; o; o >>= 1) q += __shfl_xor_sync(0xffffffffu, q, o);
            float rstd = rsqrtf(q * (1.f / 64.f) + 1e-5f);
            H16[r * 72 + lane]      = __float2half(d0 * rstd * ga + ba);
            H16[r * 72 + 32 + lane] = __float2half(d1 * rstd * gb + bb2);
        }
        for (int i = tid; i < 12 * 72; i += 384) H16[180 * 72 + i] = __float2half(0.f);
    }
    __syncthreads();

    // ---- A fragments of H for this warp's row tile ----
    uint32_t afr[4][4];
#pragma unroll
    for (int ks = 0; ks < 4; ks++)
        ldsm_x4(afr[ks], smem_u32(&H16[(r0 + lmrow) * 72 + ks * 16 + lmk]));

    // ---- K, V projections -> smem ----
#pragma unroll
    for (int mat = 0; mat < 2; mat++) {
        const __half* Wm = W16 + mat * 64 * 72;
        __half* dst = mat ? V16 : K16;
#pragma unroll
        for (int nt = 0; nt < 8; nt++) {
            float acc[4] = {0.f, 0.f, 0.f, 0.f};
#pragma unroll
            for (int ks = 0; ks < 4; ks++) {
                uint32_t bf[2];
                ldsm_x2(bf, smem_u32(&Wm[(nt * 8 + b2row) * 72 + ks * 16 + b2k]));
                mma_f16(acc, afr[ks], bf, acc);
            }
            int col = nt * 8 + 2 * c4;
            *(uint32_t*)&dst[(r0 + g4) * 72 + col]     = packh2(acc[0], acc[1]);
            *(uint32_t*)&dst[(r0 + g4 + 8) * 72 + col] = packh2(acc[2], acc[3]);
        }
    }

    // ---- Q projection -> registers (repack D-frag -> A-frag) ----
    uint32_t afq[4][4];
    {
        const __half* Wm = W16 + 2 * 64 * 72;
        float qacc[8][4];
#pragma unroll
        for (int nt = 0; nt < 8; nt++) {
#pragma unroll
            for (int i = 0; i < 4; i++) qacc[nt][i] = 0.f;
#pragma unroll
            for (int ks = 0; ks < 4; ks++) {
                uint32_t bf[2];
                ldsm_x2(bf, smem_u32(&Wm[(nt * 8 + b2row) * 72 + ks * 16 + b2k]));
                mma_f16(qacc[nt], afr[ks], bf, qacc[nt]);
            }
        }
#pragma unroll
        for (int kt = 0; kt < 4; kt++) {
            afq[kt][0] = packh2(qacc[2 * kt][0],     qacc[2 * kt][1]);
            afq[kt][1] = packh2(qacc[2 * kt][2],     qacc[2 * kt][3]);
            afq[kt][2] = packh2(qacc[2 * kt + 1][0], qacc[2 * kt + 1][1]);
            afq[kt][3] = packh2(qacc[2 * kt + 1][2], qacc[2 * kt + 1][3]);
        }
    }
    __syncthreads();

    // ---- S = (Q K^T) * 0.125, in registers ----
    float S[24][4];
#pragma unroll
    for (int nt = 0; nt < 24; nt++) {
        float acc[4] = {0.f, 0.f, 0.f, 0.f};
#pragma unroll
        for (int ks = 0; ks < 4; ks++) {
            uint32_t bf[2];
            ldsm_x2(bf, smem_u32(&K16[(nt * 8 + b2row) * 72 + ks * 16 + b2k]));
            mma_f16(acc, afq[ks], bf, acc);
        }
#pragma unroll
        for (int i = 0; i < 4; i++) S[nt][i] = acc[i] * 0.125f;
    }

    // ---- softmax in registers ----
    {
        float mx0 = -1e30f, mx1 = -1e30f;
#pragma unroll
        for (int nt = 0; nt < 24; nt++) {
#pragma unroll
            for (int j = 0; j < 2; j++) {
                int col = nt * 8 + 2 * c4 + j;
                if (col < 180) {
                    mx0 = fmaxf(mx0, S[nt][j]);
                    mx1 = fmaxf(mx1, S[nt][2 + j]);
                }
            }
        }
        mx0 = fmaxf(mx0, __shfl_xor_sync(0xffffffffu, mx0, 1));
        mx0 = fmaxf(mx0, __shfl_xor_sync(0xffffffffu, mx0, 2));
        mx1 = fmaxf(mx1, __shfl_xor_sync(0xffffffffu, mx1, 1));
        mx1 = fmaxf(mx1, __shfl_xor_sync(0xffffffffu, mx1, 2));
        float sum0 = 0.f, sum1 = 0.f;
#pragma unroll
        for (int nt = 0; nt < 24; nt++) {
#pragma unroll
            for (int j = 0; j < 2; j++) {
                int col = nt * 8 + 2 * c4 + j;
                float e0 = (col < 180) ? __expf(S[nt][j] - mx0) : 0.f;
                float e1 = (col < 180) ? __expf(S[nt][2 + j] - mx1) : 0.f;
                S[nt][j] = e0; S[nt][2 + j] = e1;
                sum0 += e0; sum1 += e1;
            }
        }
        sum0 += __shfl_xor_sync(0xffffffffu, sum0, 1);
        sum0 += __shfl_xor_sync(0xffffffffu, sum0, 2);
        sum1 += __shfl_xor_sync(0xffffffffu, sum1, 1);
        sum1 += __shfl_xor_sync(0xffffffffu, sum1, 2);
        float inv0 = 1.f / sum0, inv1 = 1.f / sum1;
#pragma unroll
        for (int nt = 0; nt < 24; nt++) {
            S[nt][0] *= inv0; S[nt][1] *= inv0;
            S[nt][2] *= inv1; S[nt][3] *= inv1;
        }
    }

    // ---- pack P into A-fragments ----
    uint32_t P[12][4];
#pragma unroll
    for (int kt = 0; kt < 12; kt++) {
        P[kt][0] = packh2(S[2 * kt][0],     S[2 * kt][1]);
        P[kt][1] = packh2(S[2 * kt][2],     S[2 * kt][3]);
        P[kt][2] = packh2(S[2 * kt + 1][0], S[2 * kt + 1][1]);
        P[kt][3] = packh2(S[2 * kt + 1][2], S[2 * kt + 1][3]);
    }

    // ---- O = P V, write fp16 to gmem ----
    {
        __half* outb = out + (long)b * 180 * 768 + h * 64;
#pragma unroll
        for (int nt = 0; nt < 8; nt++) {
            float acc[4] = {0.f, 0.f, 0.f, 0.f};
#pragma unroll
            for (int kt = 0; kt < 12; kt++) {
                uint32_t bv[2];
                ldsm_x2_t(bv, smem_u32(&V16[(kt * 16 + lmrow) * 72 + nt * 8]));
                mma_f16(acc, P[kt], bv, acc);
            }
            int row = r0 + g4;
            long col = nt * 8 + 2 * c4;
            if (row < 180)
                *(uint32_t*)(outb + (long)row * 768 + col) = packh2(acc[0], acc[1]);
            if (row + 8 < 180)
                *(uint32_t*)(outb + (long)(row + 8) * 768 + col) = packh2(acc[2], acc[3]);
        }
    }
}

// ---------------- out-projection: fp16 GEMM, +bias +residual ----------------
// C[M,64] = ao[M,768] @ ow[768,64] + ob + res. 128 rows/block, 256 threads.
#define OUTP_SMEM (64 * 776 * 2 + 128 * 72 * 2)
__global__ void __launch_bounds__(256) outproj_k(const __half* __restrict__ ao,
                                                 const float* __restrict__ ow,
                                                 const float* __restrict__ ob,
                                                 float* __restrict__ xio) {
    extern __shared__ __half smo[];
    __half* Ws = smo;                 // [64 n][776 k]
    __half* As = smo + 64 * 776;      // [128 m][72 k-chunk]

    const int bm = blockIdx.x * 128;
    const int tid = threadIdx.x, lane = tid & 31, w = tid >> 5;
    const int g4 = lane >> 2, c4 = lane & 3;
    const int lmrow = lane & 15, lmk = (lane >> 4) * 8;
    const int b2row = lane & 7, b2k = ((lane >> 3) & 1) * 8;
    const int r0 = w * 16;

    // stage W: Ws[n][k] = ow[k*64 + n]
    for (int idx = tid; idx < 768 * 16; idx += 256) {
        int k = idx >> 4, n4 = (idx & 15) << 2;
        float4 t = *(const float4*)(ow + (long)k * 64 + n4);
        Ws[(n4 + 0) * 776 + k] = __float2half(t.x);
        Ws[(n4 + 1) * 776 + k] = __float2half(t.y);
        Ws[(n4 + 2) * 776 + k] = __float2half(t.z);
        Ws[(n4 + 3) * 776 + k] = __float2half(t.w);
    }

    float acc[8][4];
#pragma unroll
    for (int nt = 0; nt < 8; nt++)
#pragma unroll
        for (int i = 0; i < 4; i++) acc[nt][i] = 0.f;

    const int ar = tid >> 1, apart = (tid & 1) * 32;
    for (int kc = 0; kc < 12; kc++) {
        __syncthreads();
        // stage A chunk [128][64] fp16
        {
            const uint4* src = (const uint4*)(ao + (long)(bm + ar) * 768 + kc * 64 + apart);
            uint4* dst = (uint4*)&As[ar * 72 + apart];
            dst[0] = src[0]; dst[1] = src[1]; dst[2] = src[2]; dst[3] = src[3];
        }
        __syncthreads();
        uint32_t afr[4][4];
#pragma unroll
        for (int ks = 0; ks < 4; ks++)
            ldsm_x4(afr[ks], smem_u32(&As[(r0 + lmrow) * 72 + ks * 16 + lmk]));
#pragma unroll
        for (int nt = 0; nt < 8; nt++) {
#pragma unroll
            for (int ks = 0; ks < 4; ks++) {
                uint32_t bf[2];
                ldsm_x2(bf, smem_u32(&Ws[(nt * 8 + b2row) * 776 + kc * 64 + ks * 16 + b2k]));
                mma_f16(acc[nt], afr[ks], bf, acc[nt]);
            }
        }
    }

    // epilogue: + bias + residual, write fp32
#pragma unroll
    for (int nt = 0; nt < 8; nt++) {
        int col = nt * 8 + 2 * c4;
        float b0 = ob[col], b1 = ob[col + 1];
#pragma unroll
        for (int half = 0; half < 2; half++) {
            long row = bm + r0 + g4 + 8 * half;
            float2 r = *(const float2*)(xio + row * 64 + col);
            float v0 = acc[nt][2 * half] + b0 + r.x;
            float v1 = acc[nt][2 * half + 1] + b1 + r.y;
            *(float2*)(xio + row * 64 + col) = make_float2(v0, v1);
        }
    }
}

// ---------------- fused MLP fp16: LN2 + ff1 + GELU + ff2 + bias + residual ----------------
// 128 tokens/block, 256 threads (8 warps), warp owns 16 rows.
// smem halfs: Hs[128][72] @0, W1s[256][72] @9216, Gs[128][264] @27648, W2s[64][264] @61440
#define MLPH_SMEM ((128 * 72 + 256 * 72 + 128 * 264 + 64 * 264) * 2)

__global__ void __launch_bounds__(256) mlp_fused_k(const float* __restrict__ x,
                                                   const float* __restrict__ w1,
                                                   const float* __restrict__ b1,
                                                   const float* __restrict__ w2,
                                                   const float* __restrict__ b2,
                                                   const float* __restrict__ lng,
                                                   const float* __restrict__ lnb,
                                                   float* __restrict__ outx) {
    extern __shared__ __half smm[];
    __half* Hs  = smm;
    __half* W1s = smm + 128 * 72;
    __half* Gs  = smm + 128 * 72 + 256 * 72;
    __half* W2s = Gs + 128 * 264;

    int tid = threadIdx.x, lane = tid & 31, w = tid >> 5;
    int g4 = lane >> 2, c4 = lane & 3;
    int lmrow = lane & 15, lmk = (lane >> 4) * 8;
    int b2row = lane & 7, b2k = ((lane >> 3) & 1) * 8;
    const int r0 = w * 16;
    long t0 = (long)blockIdx.x * 128;

    // stage W1 [256 n][72 k]: W1s[n][k] = w1[k*256+n]
    for (int idx = tid; idx < 64 * 64; idx += 256) {
        int k = idx >> 6, n4 = (idx & 63) << 2;
        float4 t = *(const float4*)(w1 + (long)k * 256 + n4);
        W1s[(n4 + 0) * 72 + k] = __float2half(t.x);
        W1s[(n4 + 1) * 72 + k] = __float2half(t.y);
        W1s[(n4 + 2) * 72 + k] = __float2half(t.z);
        W1s[(n4 + 3) * 72 + k] = __float2half(t.w);
    }
    // stage W2 [64 n][264 k]: W2s[n][k] = w2[k*64+n]
    for (int idx = tid; idx < 256 * 16; idx += 256) {
        int k = idx >> 4, n4 = (idx & 15) << 2;
        float4 t = *(const float4*)(w2 + (long)k * 64 + n4);
        W2s[(n4 + 0) * 264 + k] = __float2half(t.x);
        W2s[(n4 + 1) * 264 + k] = __float2half(t.y);
        W2s[(n4 + 2) * 264 + k] = __float2half(t.z);
        W2s[(n4 + 3) * 264 + k] = __float2half(t.w);
    }

    // LN -> Hs fp16
    {
        float ga = lng[lane], gb = lng[lane + 32];
        float ba = lnb[lane], bb2 = lnb[lane + 32];
        for (int r = w; r < 128; r += 8) {
            float v0 = x[(t0 + r) * 64 + lane];
            float v1 = x[(t0 + r) * 64 + 32 + lane];
            float s = v0 + v1;
#pragma unroll
            for (int o = 16; o; o >>= 1) s += __shfl_xor_sync(0xffffffffu, s, o);
            float mean = s * (1.f / 64.f);
            float d0 = v0 - mean, d1 = v1 - mean;
            float q = d0 * d0 + d1 * d1;
#pragma unroll
            for (int o = 16; o; o >>= 1) q += __shfl_xor_sync(0xffffffffu, q, o);
            float rstd = rsqrtf(q * (1.f / 64.f) + 1e-5f);
            Hs[r * 72 + lane]      = __float2half(d0 * rstd * ga + ba);
            Hs[r * 72 + 32 + lane] = __float2half(d1 * rstd * gb + bb2);
        }
    }
    __syncthreads();

    // ff1: G = gelu(H @ W1 + b1)
    {
        uint32_t afr[4][4];
#pragma unroll
        for (int ks = 0; ks < 4; ks++)
            ldsm_x4(afr[ks], smem_u32(&Hs[(r0 + lmrow) * 72 + ks * 16 + lmk]));
#pragma unroll
        for (int nt = 0; nt < 32; nt++) {
            float acc[4] = {0.f, 0.f, 0.f, 0.f};
#pragma unroll
            for (int ks = 0; ks < 4; ks++) {
                uint32_t bf[2];
                ldsm_x2(bf, smem_u32(&W1s[(nt * 8 + b2row) * 72 + ks * 16 + b2k]));
                mma_f16(acc, afr[ks], bf, acc);
            }
            int col = nt * 8 + 2 * c4;
            float bb0 = b1[col], bb1 = b1[col + 1];
            float v0 = acc[0] + bb0, v1 = acc[1] + bb1;
            float v2 = acc[2] + bb0, v3 = acc[3] + bb1;
            v0 = 0.5f * v0 * (1.f + erff(v0 * 0.70710678118654752f));
            v1 = 0.5f * v1 * (1.f + erff(v1 * 0.70710678118654752f));
            v2 = 0.5f * v2 * (1.f + erff(v2 * 0.70710678118654752f));
            v3 = 0.5f * v3 * (1.f + erff(v3 * 0.70710678118654752f));
            *(uint32_t*)&Gs[(r0 + g4) * 264 + col]     = packh2(v0, v1);
            *(uint32_t*)&Gs[(r0 + g4 + 8) * 264 + col] = packh2(v2, v3);
        }
    }
    __syncthreads();

    // ff2: out = G @ W2 + b2 + x
    {
        uint32_t afg[16][4];
#pragma unroll
        for (int kt = 0; kt < 16; kt++)
            ldsm_x4(afg[kt], smem_u32(&Gs[(r0 + lmrow) * 264 + kt * 16 + lmk]));
#pragma unroll
        for (int nt = 0; nt < 8; nt++) {
            float acc[4] = {0.f, 0.f, 0.f, 0.f};
#pragma unroll
            for (int kt = 0; kt < 16; kt++) {
                uint32_t bf[2];
                ldsm_x2(bf, smem_u32(&W2s[(nt * 8 + b2row) * 264 + kt * 16 + b2k]));
                mma_f16(acc, afg[kt], bf, acc);
            }
            int col = nt * 8 + 2 * c4;
            float bb0 = b2[col], bb1 = b2[col + 1];
#pragma unroll
            for (int half = 0; half < 2; half++) {
                long row = t0 + r0 + g4 + 8 * half;
                float2 r = *(const float2*)(x + row * 64 + col);
                float v0 = acc[2 * half] + bb0 + r.x;
                float v1 = acc[2 * half + 1] + bb1 + r.y;
                *(float2*)(outx + row * 64 + col) = make_float2(v0, v1);
            }
        }
    }
}

// ---------------- primary caps: gather + squash ----------------
__global__ void caps_squash_k(const float* __restrict__ pc, float* __restrict__ caps) {
    int idx = blockIdx.x * blockDim.x + threadIdx.x; // b*1024 + i
    if (idx >= 256 * 1024) return;
    int i = idx & 1023, b = idx >> 10;
    int i32 = i >> 5, y = (i >> 3) & 3, xq = i & 7;
    const float* src = pc + (((long)b * 4 + y) * 8 + xq) * 256 + i32 * 8;
    float t[8];
    float l2 = 0.f;
#pragma unroll
    for (int e = 0; e < 8; e++) { t[e] = src[e]; l2 += t[e] * t[e]; }
    float sc = sqrtf(l2) / (1.f + l2);
#pragma unroll
    for (int e = 0; e < 8; e++) caps[(long)idx * 8 + e] = t[e] * sc;
}

// ---------------- capsule predictions u[b,i,:] ----------------
__global__ void caps_u_k(const float* __restrict__ caps, const float* __restrict__ cw,
                         float* __restrict__ u) {
    __shared__ float w_s[8 * 48];
    int i = blockIdx.x;
    for (int t = threadIdx.x; t < 384; t += 256) w_s[t] = cw[(long)i * 384 + t];
    __syncthreads();
    int b = threadIdx.x;
    float ce[8];
    const float* cp = caps + ((long)b * 1024 + i) * 8;
#pragma unroll
    for (int e = 0; e < 8; e++) ce[e] = cp[e];
    float* up = u + ((long)b * 1024 + i) * 48;
#pragma unroll 4
    for (int o = 0; o < 48; o++) {
        float s = 0.f;
#pragma unroll
        for (int e = 0; e < 8; e++) s = fmaf(ce[e], w_s[e * 48 + o], s);
        up[o] = s;
    }
}

// ---------------- dynamic routing, one block per batch element ----------------
__global__ void __launch_bounds__(256) routing_k(const float* __restrict__ u,
                                                 const float* __restrict__ br,
                                                 float* __restrict__ out) {
    __shared__ float bb[1024 * 3];
    __shared__ float S[48];
    __shared__ float v[48];
    int b = blockIdx.x, tid = threadIdx.x, lane = tid & 31;
    for (int i = tid; i < 3072; i += 256) bb[i] = br[i];
    __syncthreads();
    const float* ub = u + (long)b * 1024 * 48;

    for (int it = 0; it < 4; it++) {
        if (tid < 48) S[tid] = 0.f;
        __syncthreads();
        float acc[48];
#pragma unroll
        for (int o = 0; o < 48; o++) acc[o] = 0.f;
        for (int i = tid; i < 1024; i += 256) {
            float b0 = bb[i * 3], b1 = bb[i * 3 + 1], b2 = bb[i * 3 + 2];
            float m = fmaxf(b0, fmaxf(b1, b2));
            float e0 = expf(b0 - m), e1 = expf(b1 - m), e2 = expf(b2 - m);
            float inv = 1.f / (e0 + e1 + e2);
            float c[3] = {e0 * inv, e1 * inv, e2 * inv};
            const float* up = ub + (long)i * 48;
#pragma unroll
            for (int j = 0; j < 3; j++)
#pragma unroll
                for (int o = 0; o < 16; o++)
                    acc[j * 16 + o] = fmaf(c[j], up[j * 16 + o], acc[j * 16 + o]);
        }
#pragma unroll
        for (int o = 0; o < 48; o++) {
            float s = acc[o];
#pragma unroll
            for (int d = 16; d; d >>= 1) s += __shfl_xor_sync(0xffffffffu, s, d);
            if (lane == 0) atomicAdd(&S[o], s);
        }
        __syncthreads();
        if (tid < 3) {
            float l2 = 0.f;
            for (int o = 0; o < 16; o++) { float t = S[tid * 16 + o]; l2 += t * t; }
            float sc = sqrtf(l2) / (1.f + l2);
            for (int o = 0; o < 16; o++) v[tid * 16 + o] = S[tid * 16 + o] * sc;
            if (it == 3) out[b * 3 + tid] = l2 / (1.f + l2);  // |v| = l2/(1+l2)
        }
        __syncthreads();
        if (it < 3) {
            for (int i = tid; i < 1024; i += 256) {
                const float* up = ub + (long)i * 48;
#pragma unroll
                for (int j = 0; j < 3; j++) {
                    float s = 0.f;
#pragma unroll
                    for (int o = 0; o < 16; o++) s = fmaf(up[j * 16 + o], v[j * 16 + o], s);
                    bb[i * 3 + j] += s;
                }
            }
            __syncthreads();
        }
    }
}

// ---------------- host ----------------
extern "C" void kernel_launch(void* const* d_in, const int* in_sizes, int n_in,
                              void* d_out, int out_size) {
    const float* x_in    = (const float*)d_in[0];
    const float* conv1_w = (const float*)d_in[1];
    const float* conv2_w = (const float*)d_in[2];
    const float* pos_emb = (const float*)d_in[3];
    const float* ln1_g   = (const float*)d_in[4];
    const float* ln1_b   = (const float*)d_in[5];
    const float* qkv_w   = (const float*)d_in[6];
    const float* out_w   = (const float*)d_in[7];
    const float* out_b   = (const float*)d_in[8];
    const float* ln2_g   = (const float*)d_in[9];
    const float* ln2_b   = (const float*)d_in[10];
    const float* ff1_w   = (const float*)d_in[11];
    const float* ff1_b   = (const float*)d_in[12];
    const float* ff2_w   = (const float*)d_in[13];
    const float* ff2_b   = (const float*)d_in[14];
    const float* pcaps_w = (const float*)d_in[15];
    const float* pcaps_b = (const float*)d_in[16];
    const float* caps_w  = (const float*)d_in[17];
    const float* b_route = (const float*)d_in[18];
    float* out = (float*)d_out;

    float *col1, *wt1, *y1, *p1, *col2, *wt2, *y2, *xb, *col3, *wtp, *pc, *caps, *u;
    __half* aoh;
    cudaGetSymbolAddress((void**)&col1, g_col1);
    cudaGetSymbolAddress((void**)&wt1,  g_wt1);
    cudaGetSymbolAddress((void**)&y1,   g_y1);
    cudaGetSymbolAddress((void**)&p1,   g_p1);
    cudaGetSymbolAddress((void**)&col2, g_col2);
    cudaGetSymbolAddress((void**)&wt2,  g_wt2);
    cudaGetSymbolAddress((void**)&y2,   g_y2);
    cudaGetSymbolAddress((void**)&xb,   g_x);
    cudaGetSymbolAddress((void**)&aoh,  g_aoh);
    cudaGetSymbolAddress((void**)&col3, g_col3);
    cudaGetSymbolAddress((void**)&wtp,  g_wtp);
    cudaGetSymbolAddress((void**)&pc,   g_pc);
    cudaGetSymbolAddress((void**)&caps, g_caps);
    cudaGetSymbolAddress((void**)&u,    g_u);

    cudaFuncSetAttribute(attn_fused_k, cudaFuncAttributeMaxDynamicSharedMemorySize, ATTNH_SMEM);
    cudaFuncSetAttribute(outproj_k,    cudaFuncAttributeMaxDynamicSharedMemorySize, OUTP_SMEM);
    cudaFuncSetAttribute(mlp_fused_k,  cudaFuncAttributeMaxDynamicSharedMemorySize, MLPH_SMEM);

    // ---- ConvEmbed ----
    im2col1_k<<<(int)CDIV((long)737280 * 28, 256), 256>>>(x_in, col1);
    wtrans1<<<CDIV(64 * 28, 256), 256>>>(conv1_w, wt1);
    tgemm_k<1><<<dim3(1, 737280 / 128), 256>>>(col1, wt1, nullptr, nullptr, y1, 737280, 64, 28);
    maxpool_k<<<(int)CDIV((long)256 * 20 * 36 * 64, 256), 256>>>(y1, p1, 256, 40, 72, 64, 20, 36, nullptr);
    im2col2_k<<<(int)CDIV((long)184320 * 576, 256), 256>>>(p1, col2);
    wtrans_hwc<<<CDIV(64 * 576, 256), 256>>>(conv2_w, wt2, 64, 64);
    tgemm_k<1><<<dim3(1, 184320 / 128), 256>>>(col2, wt2, nullptr, nullptr, y2, 184320, 64, 576);
    maxpool_k<<<(int)CDIV((long)256 * 10 * 18 * 64, 256), 256>>>(y2, xb, 256, 20, 36, 64, 10, 18, pos_emb);

    // ---- Transformer: 12 shared layers applied twice ----
    const int M = 46080;
    for (int pass = 0; pass < 2; pass++) {
        for (int l = 0; l < 12; l++) {
            const float* qw  = qkv_w + (long)l * 64 * 2304;
            const float* ow  = out_w + (long)l * 768 * 64;
            const float* ob  = out_b + (long)l * 64;
            const float* f1w = ff1_w + (long)l * 64 * 256;
            const float* f1b = ff1_b + (long)l * 256;
            const float* f2w = ff2_w + (long)l * 256 * 64;
            const float* f2b = ff2_b + (long)l * 64;

            attn_fused_k<<<256 * 12, 384, ATTNH_SMEM>>>(xb, qw, ln1_g + l * 64, ln1_b + l * 64, aoh);
            outproj_k<<<M / 128, 256, OUTP_SMEM>>>(aoh, ow, ob, xb);
            mlp_fused_k<<<M / 128, 256, MLPH_SMEM>>>(xb, f1w, f1b, f2w, f2b,
                                                     ln2_g + l * 64, ln2_b + l * 64, xb);
        }
    }

    // ---- PrimaryCaps + routing ----
    im2col3_k<<<(int)CDIV((long)8192 * 576, 256), 256>>>(xb, col3);
    wtrans_hwc<<<CDIV(256 * 576, 256), 256>>>(pcaps_w, wtp, 256, 64);
    tgemm_k<2><<<dim3(256 / 64, 8192 / 128), 256>>>(col3, wtp, pcaps_b, nullptr, pc, 8192, 256, 576);
    caps_squash_k<<<CDIV(256 * 1024, 256), 256>>>(pc, caps);
    caps_u_k<<<1024, 256>>>(caps, caps_w, u);
    routing_k<<<256, 256>>>(u, b_route, out);
}

// round 10
// speedup vs baseline: 4.3087x; 1.0459x over previous
#include <cuda_runtime.h>
#include <cuda_fp16.h>
#include <math.h>
#include <stdint.h>

#define CDIV(a,b) (((a)+(b)-1)/(b))

// ---------------- static scratch (no allocations allowed) ----------------
__device__ float  g_col1[737280 * 28];       // conv1 im2col (K padded 27->28)
__device__ float  g_wt1 [28 * 64];
__device__ float  g_y1  [737280 * 64];       // conv1 out NHWC (B,40,72,64)
__device__ float  g_p1  [184320 * 64];       // pool1 NHWC (B,20,36,64)
__device__ __half g_col2h[184320 * 576];     // conv2 im2col (fp16)
__device__ float  g_wt2 [576 * 64];
__device__ float  g_y2  [184320 * 64];       // conv2 out NHWC (B,20,36,64)
__device__ float  g_x   [46080 * 64];        // tokens / residual stream (B,180,64)
__device__ __half g_aoh [46080 * 768];       // attention output fp16 (B,180,768)
__device__ float  g_col3[8192 * 576];        // pcaps im2col
__device__ float  g_wtp [576 * 256];
__device__ float  g_pc  [8192 * 256];        // pcaps out NHWC (B,4,8,256)
__device__ float  g_caps[256 * 1024 * 8];
__device__ float  g_u   [256 * 1024 * 48];

// ---------------- im2col kernels ----------------
__global__ void im2col1_k(const float* __restrict__ x, float* __restrict__ col) {
    long idx = (long)blockIdx.x * blockDim.x + threadIdx.x;
    const long total = (long)737280 * 28;
    if (idx >= total) return;
    int kk = (int)(idx % 28);
    long m = idx / 28;
    if (kk == 27) { col[idx] = 0.f; return; }
    int ow = (int)(m % 72);
    int t  = (int)(m / 72);
    int oh = t % 40;
    int b  = t / 40;
    int kw = kk % 3, kh = (kk / 3) % 3, ci = kk / 9;
    int ih = oh + kh - 1, iw = ow + kw - 1;
    float v = 0.f;
    if (ih >= 0 && ih < 40 && iw >= 0 && iw < 72)
        v = x[(((long)b * 3 + ci) * 40 + ih) * 72 + iw];
    col[idx] = v;
}

__global__ void im2col2h_k(const float* __restrict__ p1, __half* __restrict__ col) {
    long idx = (long)blockIdx.x * blockDim.x + threadIdx.x;
    const long total = (long)184320 * 576;
    if (idx >= total) return;
    int kk = (int)(idx % 576);
    long m = idx / 576;
    int ow = (int)(m % 36);
    int t  = (int)(m / 36);
    int oh = t % 20;
    int b  = t / 20;
    int ci = kk % 64;
    int kw = (kk / 64) % 3;
    int kh = kk / 192;
    int ih = oh + kh - 1, iw = ow + kw - 1;
    float v = 0.f;
    if (ih >= 0 && ih < 20 && iw >= 0 && iw < 36)
        v = p1[(((long)b * 20 + ih) * 36 + iw) * 64 + ci];
    col[idx] = __float2half(v);
}

// pcaps: input tokens g_x viewed as (B, 10, 18, 64); conv k3 s2 p0 -> (B,4,8,*)
__global__ void im2col3_k(const float* __restrict__ tk, float* __restrict__ col) {
    long idx = (long)blockIdx.x * blockDim.x + threadIdx.x;
    const long total = (long)8192 * 576;
    if (idx >= total) return;
    int kk = (int)(idx % 576);
    long m = idx / 576;
    int ow = (int)(m % 8);
    int t  = (int)(m / 8);
    int oh = t % 4;
    int b  = t / 4;
    int ci = kk % 64;
    int kw = (kk / 64) % 3;
    int kh = kk / 192;
    int ih = oh * 2 + kh, iw = ow * 2 + kw;
    col[idx] = tk[((long)b * 180 + ih * 18 + iw) * 64 + ci];
}

// ---------------- weight transposes ----------------
__global__ void wtrans1(const float* __restrict__ w, float* __restrict__ wt) {
    int i = blockIdx.x * blockDim.x + threadIdx.x;
    if (i >= 64 * 28) return;
    int o = i / 28, k = i % 28;
    wt[k * 64 + o] = (k < 27) ? w[o * 27 + k] : 0.f;
}
__global__ void wtrans_hwc(const float* __restrict__ w, float* __restrict__ wt, int O, int CI) {
    int K = CI * 9;
    int i = blockIdx.x * blockDim.x + threadIdx.x;
    if (i >= O * K) return;
    int o = i / K, r = i % K;
    int ci = r / 9, kh = (r % 9) / 3, kw = r % 3;
    wt[((kh * 3 + kw) * CI + ci) * O + o] = w[i];
}

// ---------------- tf32 helpers ----------------
__device__ __forceinline__ float f2tf(float f) {
    uint32_t r;
    asm("cvt.rna.tf32.f32 %0, %1;" : "=r"(r) : "f"(f));
    return __uint_as_float(r);
}
__device__ __forceinline__ void mma_tf32(float d[4], const uint32_t a[4], const uint32_t b[2],
                                         const float c[4]) {
    asm("mma.sync.aligned.m16n8k8.row.col.f32.tf32.tf32.f32 "
        "{%0,%1,%2,%3},{%4,%5,%6,%7},{%8,%9},{%10,%11,%12,%13};"
        : "=f"(d[0]), "=f"(d[1]), "=f"(d[2]), "=f"(d[3])
        : "r"(a[0]), "r"(a[1]), "r"(a[2]), "r"(a[3]), "r"(b[0]), "r"(b[1]),
          "f"(c[0]), "f"(c[1]), "f"(c[2]), "f"(c[3]));
}

// ---------------- fp16 mma helpers ----------------
__device__ __forceinline__ uint32_t smem_u32(const void* p) {
    return (uint32_t)__cvta_generic_to_shared(p);
}
__device__ __forceinline__ void ldsm_x4(uint32_t r[4], uint32_t addr) {
    asm volatile("ldmatrix.sync.aligned.m8n8.x4.shared.b16 {%0,%1,%2,%3}, [%4];"
        : "=r"(r[0]), "=r"(r[1]), "=r"(r[2]), "=r"(r[3]) : "r"(addr));
}
__device__ __forceinline__ void ldsm_x2(uint32_t r[2], uint32_t addr) {
    asm volatile("ldmatrix.sync.aligned.m8n8.x2.shared.b16 {%0,%1}, [%2];"
        : "=r"(r[0]), "=r"(r[1]) : "r"(addr));
}
__device__ __forceinline__ void ldsm_x2_t(uint32_t r[2], uint32_t addr) {
    asm volatile("ldmatrix.sync.aligned.m8n8.x2.trans.shared.b16 {%0,%1}, [%2];"
        : "=r"(r[0]), "=r"(r[1]) : "r"(addr));
}
__device__ __forceinline__ void mma_f16(float d[4], const uint32_t a[4], const uint32_t b[2],
                                        const float c[4]) {
    asm volatile("mma.sync.aligned.m16n8k16.row.col.f32.f16.f16.f32 "
        "{%0,%1,%2,%3},{%4,%5,%6,%7},{%8,%9},{%10,%11,%12,%13};"
        : "=f"(d[0]), "=f"(d[1]), "=f"(d[2]), "=f"(d[3])
        : "r"(a[0]), "r"(a[1]), "r"(a[2]), "r"(a[3]), "r"(b[0]), "r"(b[1]),
          "f"(c[0]), "f"(c[1]), "f"(c[2]), "f"(c[3]));
}
__device__ __forceinline__ uint32_t packh2(float a, float b) {
    __half2 h = __floats2half2_rn(a, b);
    return *(uint32_t*)&h;
}

// ---------------- tf32 tensor-core GEMM (conv1 / pcaps) ----------------
// EPI: 0 none, 1 relu, 2 +bias
template <int EPI>
__global__ void __launch_bounds__(256) tgemm_k(const float* __restrict__ A, const float* __restrict__ Bm,
                                               const float* __restrict__ bias, const float* __restrict__ res,
                                               float* __restrict__ C, int M, int N, int K) {
    __shared__ float As[128 * 36];
    __shared__ float Bs[32 * 68];
    const int bm = blockIdx.y * 128, bn = blockIdx.x * 64;
    const int tid = threadIdx.x, lane = tid & 31, w = tid >> 5;
    const int g4 = lane >> 2, c4 = lane & 3;
    const int wm = (w & 3) * 32, wn = (w >> 2) * 32;

    float acc[2][4][4];
#pragma unroll
    for (int mt = 0; mt < 2; mt++)
#pragma unroll
        for (int nt = 0; nt < 4; nt++)
#pragma unroll
            for (int i = 0; i < 4; i++) acc[mt][nt][i] = 0.f;

    const int ar = tid >> 1, akb = (tid & 1) * 16;
    const int bk = tid >> 3, bn0 = (tid & 7) * 8;
    const float* Arow = A + (long)(bm + ar) * K;

    for (int k0 = 0; k0 < K; k0 += 32) {
        float4 av[4], bv[2];
#pragma unroll
        for (int i = 0; i < 4; i++) {
            int gk = k0 + akb + 4 * i;
            av[i] = (gk + 4 <= K) ? *(const float4*)(Arow + gk) : make_float4(0.f, 0.f, 0.f, 0.f);
        }
        {
            int gk = k0 + bk;
            if (gk < K) {
                bv[0] = *(const float4*)(Bm + (long)gk * N + bn + bn0);
                bv[1] = *(const float4*)(Bm + (long)gk * N + bn + bn0 + 4);
            } else {
                bv[0] = make_float4(0.f, 0.f, 0.f, 0.f);
                bv[1] = bv[0];
            }
        }
        __syncthreads();
#pragma unroll
        for (int i = 0; i < 4; i++) {
            float* p = &As[ar * 36 + akb + 4 * i];
            p[0] = f2tf(av[i].x); p[1] = f2tf(av[i].y); p[2] = f2tf(av[i].z); p[3] = f2tf(av[i].w);
        }
        {
            float* p = &Bs[bk * 68 + bn0];
            p[0] = f2tf(bv[0].x); p[1] = f2tf(bv[0].y); p[2] = f2tf(bv[0].z); p[3] = f2tf(bv[0].w);
            p[4] = f2tf(bv[1].x); p[5] = f2tf(bv[1].y); p[6] = f2tf(bv[1].z); p[7] = f2tf(bv[1].w);
        }
        __syncthreads();
#pragma unroll
        for (int ks = 0; ks < 4; ks++) {
            uint32_t bfr[4][2], afr[2][4];
#pragma unroll
            for (int nt = 0; nt < 4; nt++) {
                int col = wn + nt * 8 + g4;
                bfr[nt][0] = __float_as_uint(Bs[(ks * 8 + c4) * 68 + col]);
                bfr[nt][1] = __float_as_uint(Bs[(ks * 8 + c4 + 4) * 68 + col]);
            }
#pragma unroll
            for (int mt = 0; mt < 2; mt++) {
                int base = (wm + mt * 16 + g4) * 36 + ks * 8 + c4;
                afr[mt][0] = __float_as_uint(As[base]);
                afr[mt][1] = __float_as_uint(As[base + 8 * 36]);
                afr[mt][2] = __float_as_uint(As[base + 4]);
                afr[mt][3] = __float_as_uint(As[base + 8 * 36 + 4]);
            }
#pragma unroll
            for (int mt = 0; mt < 2; mt++)
#pragma unroll
                for (int nt = 0; nt < 4; nt++)
                    mma_tf32(acc[mt][nt], afr[mt], bfr[nt], acc[mt][nt]);
        }
        __syncthreads();
    }

#pragma unroll
    for (int nt = 0; nt < 4; nt++) {
        int col = bn + wn + nt * 8 + 2 * c4;
        float b0 = 0.f, b1 = 0.f;
        if (EPI >= 2) { b0 = bias[col]; b1 = bias[col + 1]; }
#pragma unroll
        for (int mt = 0; mt < 2; mt++) {
#pragma unroll
            for (int half = 0; half < 2; half++) {
                long row = bm + wm + mt * 16 + g4 + 8 * half;
                float v0 = acc[mt][nt][2 * half], v1 = acc[mt][nt][2 * half + 1];
                if (EPI == 1) { v0 = fmaxf(v0, 0.f); v1 = fmaxf(v1, 0.f); }
                if (EPI >= 2) { v0 += b0; v1 += b1; }
                *(float2*)(C + row * N + col) = make_float2(v0, v1);
            }
        }
    }
}

// ---------------- fp16 conv GEMM: C[M,64] = relu(A16[M,K] @ Wf[K,64]) ----------------
// 128 rows/block, 256 threads; K % 64 == 0, K <= 776.
#define HCONV_SMEM (64 * 776 * 2 + 128 * 72 * 2)
__global__ void __launch_bounds__(256) hconv_k(const __half* __restrict__ A,
                                               const float* __restrict__ Wf,
                                               float* __restrict__ C, int K) {
    extern __shared__ __half smo[];
    __half* Ws = smo;                 // [64 n][776 k]
    __half* As = smo + 64 * 776;      // [128 m][72 k-chunk]

    const int bm = blockIdx.x * 128;
    const int tid = threadIdx.x, lane = tid & 31, w = tid >> 5;
    const int g4 = lane >> 2, c4 = lane & 3;
    const int lmrow = lane & 15, lmk = (lane >> 4) * 8;
    const int b2row = lane & 7, b2k = ((lane >> 3) & 1) * 8;
    const int r0 = w * 16;

    for (int idx = tid; idx < K * 16; idx += 256) {
        int k = idx >> 4, n4 = (idx & 15) << 2;
        float4 t = *(const float4*)(Wf + (long)k * 64 + n4);
        Ws[(n4 + 0) * 776 + k] = __float2half(t.x);
        Ws[(n4 + 1) * 776 + k] = __float2half(t.y);
        Ws[(n4 + 2) * 776 + k] = __float2half(t.z);
        Ws[(n4 + 3) * 776 + k] = __float2half(t.w);
    }

    float acc[8][4];
#pragma unroll
    for (int nt = 0; nt < 8; nt++)
#pragma unroll
        for (int i = 0; i < 4; i++) acc[nt][i] = 0.f;

    const int ar = tid >> 1, apart = (tid & 1) * 32;
    const int nchunk = K >> 6;
    for (int kc = 0; kc < nchunk; kc++) {
        __syncthreads();
        {
            const uint4* src = (const uint4*)(A + (long)(bm + ar) * K + kc * 64 + apart);
            uint4* dst = (uint4*)&As[ar * 72 + apart];
            dst[0] = src[0]; dst[1] = src[1]; dst[2] = src[2]; dst[3] = src[3];
        }
        __syncthreads();
        uint32_t afr[4][4];
#pragma unroll
        for (int ks = 0; ks < 4; ks++)
            ldsm_x4(afr[ks], smem_u32(&As[(r0 + lmrow) * 72 + ks * 16 + lmk]));
#pragma unroll
        for (int nt = 0; nt < 8; nt++) {
#pragma unroll
            for (int ks = 0; ks < 4; ks++) {
                uint32_t bf[2];
                ldsm_x2(bf, smem_u32(&Ws[(nt * 8 + b2row) * 776 + kc * 64 + ks * 16 + b2k]));
                mma_f16(acc[nt], afr[ks], bf, acc[nt]);
            }
        }
    }

#pragma unroll
    for (int nt = 0; nt < 8; nt++) {
        int col = nt * 8 + 2 * c4;
#pragma unroll
        for (int half = 0; half < 2; half++) {
            long row = bm + r0 + g4 + 8 * half;
            float v0 = fmaxf(acc[nt][2 * half], 0.f);
            float v1 = fmaxf(acc[nt][2 * half + 1], 0.f);
            *(float2*)(C + row * 64 + col) = make_float2(v0, v1);
        }
    }
}

// ---------------- maxpool 3x3 s2 p1 on NHWC (+ optional pos-emb add) ----------------
__global__ void maxpool_k(const float* __restrict__ in, float* __restrict__ out,
                          int Bn, int IH, int IW, int C, int OH, int OW,
                          const float* __restrict__ pos) {
    long idx = (long)blockIdx.x * blockDim.x + threadIdx.x;
    long total = (long)Bn * OH * OW * C;
    if (idx >= total) return;
    int c = (int)(idx % C);
    long r = idx / C;
    int ow = (int)(r % OW); r /= OW;
    int oh = (int)(r % OH);
    int b  = (int)(r / OH);
    float m = -1e30f;
#pragma unroll
    for (int kh = 0; kh < 3; kh++) {
        int ih = oh * 2 - 1 + kh;
        if (ih < 0 || ih >= IH) continue;
#pragma unroll
        for (int kw = 0; kw < 3; kw++) {
            int iw = ow * 2 - 1 + kw;
            if (iw < 0 || iw >= IW) continue;
            m = fmaxf(m, in[(((long)b * IH + ih) * IW + iw) * C + c]);
        }
    }
    if (pos) m += pos[(oh * OW + ow) * C + c];
    out[idx] = m;
}

// ---------------- fully-fused attention: scores in registers, fp16 out ----------------
#define ATTNH_SMEM ((3 * 192 * 72 + 3 * 64 * 72) * 2)

__global__ void __launch_bounds__(384, 1) attn_fused_k(const float* __restrict__ x,
                                                       const float* __restrict__ qw,
                                                       const float* __restrict__ lng,
                                                       const float* __restrict__ lnb,
                                                       __half* __restrict__ out) {
    extern __shared__ __half smh[];
    __half* H16 = smh;
    __half* K16 = smh + 192 * 72;
    __half* V16 = smh + 2 * 192 * 72;
    __half* W16 = smh + 3 * 192 * 72;

    int b = blockIdx.x / 12, h = blockIdx.x % 12;
    int tid = threadIdx.x, lane = tid & 31, w = tid >> 5;
    int g4 = lane >> 2, c4 = lane & 3;
    int lmrow = lane & 15, lmk = (lane >> 4) * 8;
    int b2row = lane & 7, b2k = ((lane >> 3) & 1) * 8;
    const int r0 = w * 16;

    for (int idx = tid; idx < 3 * 64 * 16; idx += 384) {
        int mat = idx >> 10;
        int rem = idx & 1023;
        int k = rem >> 4, n4 = (rem & 15) << 2;
        int moff = (mat == 0) ? 768 : (mat == 1) ? 1536 : 0;
        float4 t = *(const float4*)(qw + (long)k * 2304 + moff + h * 64 + n4);
        __half* Wm = W16 + mat * 64 * 72;
        Wm[(n4 + 0) * 72 + k] = __float2half(t.x);
        Wm[(n4 + 1) * 72 + k] = __float2half(t.y);
        Wm[(n4 + 2) * 72 + k] = __float2half(t.z);
        Wm[(n4 + 3) * 72 + k] = __float2half(t.w);
    }

    {
        const float* xb = x + (long)b * 180 * 64;
        float ga = lng[lane], gb = lng[lane + 32];
        float ba = lnb[lane], bb2 = lnb[lane + 32];
        for (int r = w; r < 180; r += 12) {
            float v0 = xb[r * 64 + lane], v1 = xb[r * 64 + 32 + lane];
            float s = v0 + v1;
#pragma unroll
            for (int o = 16; o; o >>= 1) s += __shfl_xor_sync(0xffffffffu, s, o);
            float mean = s * (1.f / 64.f);
            float d0 = v0 - mean, d1 = v1 - mean;
            float q = d0 * d0 + d1 * d1;
#pragma unroll
            for (int o = 16; o; o >>= 1) q += __shfl_xor_sync(0xffffffffu, q, o);
            float rstd = rsqrtf(q * (1.f / 64.f) + 1e-5f);
            H16[r * 72 + lane]      = __float2half(d0 * rstd * ga + ba);
            H16[r * 72 + 32 + lane] = __float2half(d1 * rstd * gb + bb2);
        }
        for (int i = tid; i < 12 * 72; i += 384) H16[180 * 72 + i] = __float2half(0.f);
    }
    __syncthreads();

    uint32_t afr[4][4];
#pragma unroll
    for (int ks = 0; ks < 4; ks++)
        ldsm_x4(afr[ks], smem_u32(&H16[(r0 + lmrow) * 72 + ks * 16 + lmk]));

#pragma unroll
    for (int mat = 0; mat < 2; mat++) {
        const __half* Wm = W16 + mat * 64 * 72;
        __half* dst = mat ? V16 : K16;
#pragma unroll
        for (int nt = 0; nt < 8; nt++) {
            float acc[4] = {0.f, 0.f, 0.f, 0.f};
#pragma unroll
            for (int ks = 0; ks < 4; ks++) {
                uint32_t bf[2];
                ldsm_x2(bf, smem_u32(&Wm[(nt * 8 + b2row) * 72 + ks * 16 + b2k]));
                mma_f16(acc, afr[ks], bf, acc);
            }
            int col = nt * 8 + 2 * c4;
            *(uint32_t*)&dst[(r0 + g4) * 72 + col]     = packh2(acc[0], acc[1]);
            *(uint32_t*)&dst[(r0 + g4 + 8) * 72 + col] = packh2(acc[2], acc[3]);
        }
    }

    uint32_t afq[4][4];
    {
        const __half* Wm = W16 + 2 * 64 * 72;
        float qacc[8][4];
#pragma unroll
        for (int nt = 0; nt < 8; nt++) {
#pragma unroll
            for (int i = 0; i < 4; i++) qacc[nt][i] = 0.f;
#pragma unroll
            for (int ks = 0; ks < 4; ks++) {
                uint32_t bf[2];
                ldsm_x2(bf, smem_u32(&Wm[(nt * 8 + b2row) * 72 + ks * 16 + b2k]));
                mma_f16(qacc[nt], afr[ks], bf, qacc[nt]);
            }
        }
#pragma unroll
        for (int kt = 0; kt < 4; kt++) {
            afq[kt][0] = packh2(qacc[2 * kt][0],     qacc[2 * kt][1]);
            afq[kt][1] = packh2(qacc[2 * kt][2],     qacc[2 * kt][3]);
            afq[kt][2] = packh2(qacc[2 * kt + 1][0], qacc[2 * kt + 1][1]);
            afq[kt][3] = packh2(qacc[2 * kt + 1][2], qacc[2 * kt + 1][3]);
        }
    }
    __syncthreads();

    float S[24][4];
#pragma unroll
    for (int nt = 0; nt < 24; nt++) {
        float acc[4] = {0.f, 0.f, 0.f, 0.f};
#pragma unroll
        for (int ks = 0; ks < 4; ks++) {
            uint32_t bf[2];
            ldsm_x2(bf, smem_u32(&K16[(nt * 8 + b2row) * 72 + ks * 16 + b2k]));
            mma_f16(acc, afq[ks], bf, acc);
        }
#pragma unroll
        for (int i = 0; i < 4; i++) S[nt][i] = acc[i] * 0.125f;
    }

    {
        float mx0 = -1e30f, mx1 = -1e30f;
#pragma unroll
        for (int nt = 0; nt < 24; nt++) {
#pragma unroll
            for (int j = 0; j < 2; j++) {
                int col = nt * 8 + 2 * c4 + j;
                if (col < 180) {
                    mx0 = fmaxf(mx0, S[nt][j]);
                    mx1 = fmaxf(mx1, S[nt][2 + j]);
                }
            }
        }
        mx0 = fmaxf(mx0, __shfl_xor_sync(0xffffffffu, mx0, 1));
        mx0 = fmaxf(mx0, __shfl_xor_sync(0xffffffffu, mx0, 2));
        mx1 = fmaxf(mx1, __shfl_xor_sync(0xffffffffu, mx1, 1));
        mx1 = fmaxf(mx1, __shfl_xor_sync(0xffffffffu, mx1, 2));
        float sum0 = 0.f, sum1 = 0.f;
#pragma unroll
        for (int nt = 0; nt < 24; nt++) {
#pragma unroll
            for (int j = 0; j < 2; j++) {
                int col = nt * 8 + 2 * c4 + j;
                float e0 = (col < 180) ? __expf(S[nt][j] - mx0) : 0.f;
                float e1 = (col < 180) ? __expf(S[nt][2 + j] - mx1) : 0.f;
                S[nt][j] = e0; S[nt][2 + j] = e1;
                sum0 += e0; sum1 += e1;
            }
        }
        sum0 += __shfl_xor_sync(0xffffffffu, sum0, 1);
        sum0 += __shfl_xor_sync(0xffffffffu, sum0, 2);
        sum1 += __shfl_xor_sync(0xffffffffu, sum1, 1);
        sum1 += __shfl_xor_sync(0xffffffffu, sum1, 2);
        float inv0 = 1.f / sum0, inv1 = 1.f / sum1;
#pragma unroll
        for (int nt = 0; nt < 24; nt++) {
            S[nt][0] *= inv0; S[nt][1] *= inv0;
            S[nt][2] *= inv1; S[nt][3] *= inv1;
        }
    }

    uint32_t P[12][4];
#pragma unroll
    for (int kt = 0; kt < 12; kt++) {
        P[kt][0] = packh2(S[2 * kt][0],     S[2 * kt][1]);
        P[kt][1] = packh2(S[2 * kt][2],     S[2 * kt][3]);
        P[kt][2] = packh2(S[2 * kt + 1][0], S[2 * kt + 1][1]);
        P[kt][3] = packh2(S[2 * kt + 1][2], S[2 * kt + 1][3]);
    }

    {
        __half* outb = out + (long)b * 180 * 768 + h * 64;
#pragma unroll
        for (int nt = 0; nt < 8; nt++) {
            float acc[4] = {0.f, 0.f, 0.f, 0.f};
#pragma unroll
            for (int kt = 0; kt < 12; kt++) {
                uint32_t bv[2];
                ldsm_x2_t(bv, smem_u32(&V16[(kt * 16 + lmrow) * 72 + nt * 8]));
                mma_f16(acc, P[kt], bv, acc);
            }
            int row = r0 + g4;
            long col = nt * 8 + 2 * c4;
            if (row < 180)
                *(uint32_t*)(outb + (long)row * 768 + col) = packh2(acc[0], acc[1]);
            if (row + 8 < 180)
                *(uint32_t*)(outb + (long)(row + 8) * 768 + col) = packh2(acc[2], acc[3]);
        }
    }
}

// ---------------- fused tail: outproj + bias + residual + LN2 + MLP + residual ----------------
// 128 tokens/block, 256 threads (8 warps), warp owns rows [16w,16w+16).
// smem (halfs): GsWs @0 (49664: Ws phase1 / Gs phase2), AsHs @49664 (9216),
//               W1s @58880 (18432), W2s @77312 (16896). total 94208 halfs = 188416 B
#define T_GSWS 0
#define T_ASHS 49664
#define T_W1S  58880
#define T_W2S  77312
#define TAIL_SMEM 188416

__global__ void __launch_bounds__(256) tail_fused_k(const __half* __restrict__ ao,
                                                    const float* __restrict__ ow,
                                                    const float* __restrict__ ob,
                                                    const float* __restrict__ x,
                                                    const float* __restrict__ w1,
                                                    const float* __restrict__ b1,
                                                    const float* __restrict__ w2,
                                                    const float* __restrict__ b2,
                                                    const float* __restrict__ lng,
                                                    const float* __restrict__ lnb,
                                                    float* __restrict__ outx) {
    extern __shared__ __half smt[];
    __half* Ws  = smt + T_GSWS;   // [64 n][776 k]   (phase 1)
    __half* Gs  = smt + T_GSWS;   // [128 m][264]    (phase 2)
    __half* As  = smt + T_ASHS;   // [128 m][72]     (phase 1)
    __half* Hs  = smt + T_ASHS;   // [128 m][72]     (phase 2)
    __half* W1s = smt + T_W1S;    // [256 n][72]
    __half* W2s = smt + T_W2S;    // [64 n][264]

    const int tid = threadIdx.x, lane = tid & 31, w = tid >> 5;
    const int g4 = lane >> 2, c4 = lane & 3;
    const int lmrow = lane & 15, lmk = (lane >> 4) * 8;
    const int b2row = lane & 7, b2k = ((lane >> 3) & 1) * 8;
    const int r0 = w * 16;
    const long bm = (long)blockIdx.x * 128;

    // ---- stage Wo, W1, W2 (disjoint regions) ----
    for (int idx = tid; idx < 768 * 16; idx += 256) {
        int k = idx >> 4, n4 = (idx & 15) << 2;
        float4 t = *(const float4*)(ow + (long)k * 64 + n4);
        Ws[(n4 + 0) * 776 + k] = __float2half(t.x);
        Ws[(n4 + 1) * 776 + k] = __float2half(t.y);
        Ws[(n4 + 2) * 776 + k] = __float2half(t.z);
        Ws[(n4 + 3) * 776 + k] = __float2half(t.w);
    }
    for (int idx = tid; idx < 64 * 64; idx += 256) {
        int k = idx >> 6, n4 = (idx & 63) << 2;
        float4 t = *(const float4*)(w1 + (long)k * 256 + n4);
        W1s[(n4 + 0) * 72 + k] = __float2half(t.x);
        W1s[(n4 + 1) * 72 + k] = __float2half(t.y);
        W1s[(n4 + 2) * 72 + k] = __float2half(t.z);
        W1s[(n4 + 3) * 72 + k] = __float2half(t.w);
    }
    for (int idx = tid; idx < 256 * 16; idx += 256) {
        int k = idx >> 4, n4 = (idx & 15) << 2;
        float4 t = *(const float4*)(w2 + (long)k * 64 + n4);
        W2s[(n4 + 0) * 264 + k] = __float2half(t.x);
        W2s[(n4 + 1) * 264 + k] = __float2half(t.y);
        W2s[(n4 + 2) * 264 + k] = __float2half(t.z);
        W2s[(n4 + 3) * 264 + k] = __float2half(t.w);
    }

    // ---- phase 1: out-projection over 12 k-chunks ----
    float acc[8][4];
#pragma unroll
    for (int nt = 0; nt < 8; nt++)
#pragma unroll
        for (int i = 0; i < 4; i++) acc[nt][i] = 0.f;

    const int ar = tid >> 1, apart = (tid & 1) * 32;
    for (int kc = 0; kc < 12; kc++) {
        __syncthreads();
        {
            const uint4* src = (const uint4*)(ao + (bm + ar) * 768 + kc * 64 + apart);
            uint4* dst = (uint4*)&As[ar * 72 + apart];
            dst[0] = src[0]; dst[1] = src[1]; dst[2] = src[2]; dst[3] = src[3];
        }
        __syncthreads();
        uint32_t afr[4][4];
#pragma unroll
        for (int ks = 0; ks < 4; ks++)
            ldsm_x4(afr[ks], smem_u32(&As[(r0 + lmrow) * 72 + ks * 16 + lmk]));
#pragma unroll
        for (int nt = 0; nt < 8; nt++) {
#pragma unroll
            for (int ks = 0; ks < 4; ks++) {
                uint32_t bf[2];
                ldsm_x2(bf, smem_u32(&Ws[(nt * 8 + b2row) * 776 + kc * 64 + ks * 16 + b2k]));
                mma_f16(acc[nt], afr[ks], bf, acc[nt]);
            }
        }
    }

    // ---- epilogue 1: +ob +residual -> xres regs; LN2 via quad shuffles -> Hs ----
    float xres[8][4];
    {
#pragma unroll
        for (int nt = 0; nt < 8; nt++) {
            int col = nt * 8 + 2 * c4;
            float b0 = ob[col], b1 = ob[col + 1];
#pragma unroll
            for (int half = 0; half < 2; half++) {
                long row = bm + r0 + g4 + 8 * half;
                float2 r = *(const float2*)(x + row * 64 + col);
                xres[nt][2 * half]     = acc[nt][2 * half] + b0 + r.x;
                xres[nt][2 * half + 1] = acc[nt][2 * half + 1] + b1 + r.y;
            }
        }
        // LN stats: row (r0+g4) over [nt][0..1], row (r0+g4+8) over [nt][2..3]
        float s0 = 0.f, s1 = 0.f;
#pragma unroll
        for (int nt = 0; nt < 8; nt++) {
            s0 += xres[nt][0] + xres[nt][1];
            s1 += xres[nt][2] + xres[nt][3];
        }
        s0 += __shfl_xor_sync(0xffffffffu, s0, 1);
        s0 += __shfl_xor_sync(0xffffffffu, s0, 2);
        s1 += __shfl_xor_sync(0xffffffffu, s1, 1);
        s1 += __shfl_xor_sync(0xffffffffu, s1, 2);
        float m0 = s0 * (1.f / 64.f), m1 = s1 * (1.f / 64.f);
        float q0 = 0.f, q1 = 0.f;
#pragma unroll
        for (int nt = 0; nt < 8; nt++) {
            float d0 = xres[nt][0] - m0, d1 = xres[nt][1] - m0;
            float d2 = xres[nt][2] - m1, d3 = xres[nt][3] - m1;
            q0 += d0 * d0 + d1 * d1;
            q1 += d2 * d2 + d3 * d3;
        }
        q0 += __shfl_xor_sync(0xffffffffu, q0, 1);
        q0 += __shfl_xor_sync(0xffffffffu, q0, 2);
        q1 += __shfl_xor_sync(0xffffffffu, q1, 1);
        q1 += __shfl_xor_sync(0xffffffffu, q1, 2);
        float rs0 = rsqrtf(q0 * (1.f / 64.f) + 1e-5f);
        float rs1 = rsqrtf(q1 * (1.f / 64.f) + 1e-5f);
        __syncthreads();   // As (chunk 11) fully consumed -> safe to write Hs
#pragma unroll
        for (int nt = 0; nt < 8; nt++) {
            int col = nt * 8 + 2 * c4;
            float g0 = lng[col], g1 = lng[col + 1];
            float be0 = lnb[col], be1 = lnb[col + 1];
            float h0 = (xres[nt][0] - m0) * rs0 * g0 + be0;
            float h1 = (xres[nt][1] - m0) * rs0 * g1 + be1;
            float h2 = (xres[nt][2] - m1) * rs1 * g0 + be0;
            float h3 = (xres[nt][3] - m1) * rs1 * g1 + be1;
            *(uint32_t*)&Hs[(r0 + g4) * 72 + col]     = packh2(h0, h1);
            *(uint32_t*)&Hs[(r0 + g4 + 8) * 72 + col] = packh2(h2, h3);
        }
    }
    __syncthreads();   // Hs ready; Ws dead (Gs region free)

    // ---- ff1: G = gelu(H @ W1 + b1) ----
    {
        uint32_t afr[4][4];
#pragma unroll
        for (int ks = 0; ks < 4; ks++)
            ldsm_x4(afr[ks], smem_u32(&Hs[(r0 + lmrow) * 72 + ks * 16 + lmk]));
#pragma unroll
        for (int nt = 0; nt < 32; nt++) {
            float a2[4] = {0.f, 0.f, 0.f, 0.f};
#pragma unroll
            for (int ks = 0; ks < 4; ks++) {
                uint32_t bf[2];
                ldsm_x2(bf, smem_u32(&W1s[(nt * 8 + b2row) * 72 + ks * 16 + b2k]));
                mma_f16(a2, afr[ks], bf, a2);
            }
            int col = nt * 8 + 2 * c4;
            float bb0 = b1[col], bb1 = b1[col + 1];
            float v0 = a2[0] + bb0, v1 = a2[1] + bb1;
            float v2 = a2[2] + bb0, v3 = a2[3] + bb1;
            v0 = 0.5f * v0 * (1.f + erff(v0 * 0.70710678118654752f));
            v1 = 0.5f * v1 * (1.f + erff(v1 * 0.70710678118654752f));
            v2 = 0.5f * v2 * (1.f + erff(v2 * 0.70710678118654752f));
            v3 = 0.5f * v3 * (1.f + erff(v3 * 0.70710678118654752f));
            *(uint32_t*)&Gs[(r0 + g4) * 264 + col]     = packh2(v0, v1);
            *(uint32_t*)&Gs[(r0 + g4 + 8) * 264 + col] = packh2(v2, v3);
        }
    }
    __syncthreads();

    // ---- ff2: out = G @ W2 + b2 + xres ----
    {
        uint32_t afg[16][4];
#pragma unroll
        for (int kt = 0; kt < 16; kt++)
            ldsm_x4(afg[kt], smem_u32(&Gs[(r0 + lmrow) * 264 + kt * 16 + lmk]));
#pragma unroll
        for (int nt = 0; nt < 8; nt++) {
            float a2[4] = {0.f, 0.f, 0.f, 0.f};
#pragma unroll
            for (int kt = 0; kt < 16; kt++) {
                uint32_t bf[2];
                ldsm_x2(bf, smem_u32(&W2s[(nt * 8 + b2row) * 264 + kt * 16 + b2k]));
                mma_f16(a2, afg[kt], bf, a2);
            }
            int col = nt * 8 + 2 * c4;
            float bb0 = b2[col], bb1 = b2[col + 1];
#pragma unroll
            for (int half = 0; half < 2; half++) {
                long row = bm + r0 + g4 + 8 * half;
                float v0 = a2[2 * half] + bb0 + xres[nt][2 * half];
                float v1 = a2[2 * half + 1] + bb1 + xres[nt][2 * half + 1];
                *(float2*)(outx + row * 64 + col) = make_float2(v0, v1);
            }
        }
    }
}

// ---------------- primary caps: gather + squash ----------------
__global__ void caps_squash_k(const float* __restrict__ pc, float* __restrict__ caps) {
    int idx = blockIdx.x * blockDim.x + threadIdx.x;
    if (idx >= 256 * 1024) return;
    int i = idx & 1023, b = idx >> 10;
    int i32 = i >> 5, y = (i >> 3) & 3, xq = i & 7;
    const float* src = pc + (((long)b * 4 + y) * 8 + xq) * 256 + i32 * 8;
    float t[8];
    float l2 = 0.f;
#pragma unroll
    for (int e = 0; e < 8; e++) { t[e] = src[e]; l2 += t[e] * t[e]; }
    float sc = sqrtf(l2) / (1.f + l2);
#pragma unroll
    for (int e = 0; e < 8; e++) caps[(long)idx * 8 + e] = t[e] * sc;
}

// ---------------- capsule predictions u[b,i,:] ----------------
__global__ void caps_u_k(const float* __restrict__ caps, const float* __restrict__ cw,
                         float* __restrict__ u) {
    __shared__ float w_s[8 * 48];
    int i = blockIdx.x;
    for (int t = threadIdx.x; t < 384; t += 256) w_s[t] = cw[(long)i * 384 + t];
    __syncthreads();
    int b = threadIdx.x;
    float ce[8];
    const float* cp = caps + ((long)b * 1024 + i) * 8;
#pragma unroll
    for (int e = 0; e < 8; e++) ce[e] = cp[e];
    float* up = u + ((long)b * 1024 + i) * 48;
#pragma unroll 4
    for (int o = 0; o < 48; o++) {
        float s = 0.f;
#pragma unroll
        for (int e = 0; e < 8; e++) s = fmaf(ce[e], w_s[e * 48 + o], s);
        up[o] = s;
    }
}

// ---------------- dynamic routing, one block per batch element, u in smem ----------------
#define ROUT_SMEM ((49152 + 3072 + 96) * 4)
__global__ void __launch_bounds__(256) routing_k(const float* __restrict__ u,
                                                 const float* __restrict__ br,
                                                 float* __restrict__ out) {
    extern __shared__ float smr[];
    float* us = smr;                 // [1024*48]
    float* bb = smr + 49152;         // [1024*3]
    float* S  = bb + 3072;           // [48]
    float* v  = S + 48;              // [48]
    int b = blockIdx.x, tid = threadIdx.x, lane = tid & 31;
    const float* ub = u + (long)b * 1024 * 48;
    for (int i = tid; i < 49152; i += 256) us[i] = ub[i];
    for (int i = tid; i < 3072; i += 256) bb[i] = br[i];
    __syncthreads();

    for (int it = 0; it < 4; it++) {
        if (tid < 48) S[tid] = 0.f;
        __syncthreads();
        float acc[48];
#pragma unroll
        for (int o = 0; o < 48; o++) acc[o] = 0.f;
        for (int i = tid; i < 1024; i += 256) {
            float b0 = bb[i * 3], b1 = bb[i * 3 + 1], b2 = bb[i * 3 + 2];
            float m = fmaxf(b0, fmaxf(b1, b2));
            float e0 = expf(b0 - m), e1 = expf(b1 - m), e2 = expf(b2 - m);
            float inv = 1.f / (e0 + e1 + e2);
            float c[3] = {e0 * inv, e1 * inv, e2 * inv};
            const float* up = &us[i * 48];
#pragma unroll
            for (int j = 0; j < 3; j++)
#pragma unroll
                for (int o = 0; o < 16; o++)
                    acc[j * 16 + o] = fmaf(c[j], up[j * 16 + o], acc[j * 16 + o]);
        }
#pragma unroll
        for (int o = 0; o < 48; o++) {
            float s = acc[o];
#pragma unroll
            for (int d = 16; d; d >>= 1) s += __shfl_xor_sync(0xffffffffu, s, d);
            if (lane == 0) atomicAdd(&S[o], s);
        }
        __syncthreads();
        if (tid < 3) {
            float l2 = 0.f;
            for (int o = 0; o < 16; o++) { float t = S[tid * 16 + o]; l2 += t * t; }
            float sc = sqrtf(l2) / (1.f + l2);
            for (int o = 0; o < 16; o++) v[tid * 16 + o] = S[tid * 16 + o] * sc;
            if (it == 3) out[b * 3 + tid] = l2 / (1.f + l2);
        }
        __syncthreads();
        if (it < 3) {
            for (int i = tid; i < 1024; i += 256) {
                const float* up = &us[i * 48];
#pragma unroll
                for (int j = 0; j < 3; j++) {
                    float s = 0.f;
#pragma unroll
                    for (int o = 0; o < 16; o++) s = fmaf(up[j * 16 + o], v[j * 16 + o], s);
                    bb[i * 3 + j] += s;
                }
            }
            __syncthreads();
        }
    }
}

// ---------------- host ----------------
extern "C" void kernel_launch(void* const* d_in, const int* in_sizes, int n_in,
                              void* d_out, int out_size) {
    const float* x_in    = (const float*)d_in[0];
    const float* conv1_w = (const float*)d_in[1];
    const float* conv2_w = (const float*)d_in[2];
    const float* pos_emb = (const float*)d_in[3];
    const float* ln1_g   = (const float*)d_in[4];
    const float* ln1_b   = (const float*)d_in[5];
    const float* qkv_w   = (const float*)d_in[6];
    const float* out_w   = (const float*)d_in[7];
    const float* out_b   = (const float*)d_in[8];
    const float* ln2_g   = (const float*)d_in[9];
    const float* ln2_b   = (const float*)d_in[10];
    const float* ff1_w   = (const float*)d_in[11];
    const float* ff1_b   = (const float*)d_in[12];
    const float* ff2_w   = (const float*)d_in[13];
    const float* ff2_b   = (const float*)d_in[14];
    const float* pcaps_w = (const float*)d_in[15];
    const float* pcaps_b = (const float*)d_in[16];
    const float* caps_w  = (const float*)d_in[17];
    const float* b_route = (const float*)d_in[18];
    float* out = (float*)d_out;

    float *col1, *wt1, *y1, *p1, *wt2, *y2, *xb, *col3, *wtp, *pc, *caps, *u;
    __half *aoh, *col2h;
    cudaGetSymbolAddress((void**)&col1, g_col1);
    cudaGetSymbolAddress((void**)&wt1,  g_wt1);
    cudaGetSymbolAddress((void**)&y1,   g_y1);
    cudaGetSymbolAddress((void**)&p1,   g_p1);
    cudaGetSymbolAddress((void**)&col2h, g_col2h);
    cudaGetSymbolAddress((void**)&wt2,  g_wt2);
    cudaGetSymbolAddress((void**)&y2,   g_y2);
    cudaGetSymbolAddress((void**)&xb,   g_x);
    cudaGetSymbolAddress((void**)&aoh,  g_aoh);
    cudaGetSymbolAddress((void**)&col3, g_col3);
    cudaGetSymbolAddress((void**)&wtp,  g_wtp);
    cudaGetSymbolAddress((void**)&pc,   g_pc);
    cudaGetSymbolAddress((void**)&caps, g_caps);
    cudaGetSymbolAddress((void**)&u,    g_u);

    cudaFuncSetAttribute(attn_fused_k, cudaFuncAttributeMaxDynamicSharedMemorySize, ATTNH_SMEM);
    cudaFuncSetAttribute(tail_fused_k, cudaFuncAttributeMaxDynamicSharedMemorySize, TAIL_SMEM);
    cudaFuncSetAttribute(hconv_k,      cudaFuncAttributeMaxDynamicSharedMemorySize, HCONV_SMEM);
    cudaFuncSetAttribute(routing_k,    cudaFuncAttributeMaxDynamicSharedMemorySize, ROUT_SMEM);

    // ---- ConvEmbed ----
    im2col1_k<<<(int)CDIV((long)737280 * 28, 256), 256>>>(x_in, col1);
    wtrans1<<<CDIV(64 * 28, 256), 256>>>(conv1_w, wt1);
    tgemm_k<1><<<dim3(1, 737280 / 128), 256>>>(col1, wt1, nullptr, nullptr, y1, 737280, 64, 28);
    maxpool_k<<<(int)CDIV((long)256 * 20 * 36 * 64, 256), 256>>>(y1, p1, 256, 40, 72, 64, 20, 36, nullptr);
    im2col2h_k<<<(int)CDIV((long)184320 * 576, 256), 256>>>(p1, col2h);
    wtrans_hwc<<<CDIV(64 * 576, 256), 256>>>(conv2_w, wt2, 64, 64);
    hconv_k<<<184320 / 128, 256, HCONV_SMEM>>>(col2h, wt2, y2, 576);
    maxpool_k<<<(int)CDIV((long)256 * 10 * 18 * 64, 256), 256>>>(y2, xb, 256, 20, 36, 64, 10, 18, pos_emb);

    // ---- Transformer: 12 shared layers applied twice ----
    const int M = 46080;
    for (int pass = 0; pass < 2; pass++) {
        for (int l = 0; l < 12; l++) {
            const float* qw  = qkv_w + (long)l * 64 * 2304;
            const float* ow  = out_w + (long)l * 768 * 64;
            const float* ob  = out_b + (long)l * 64;
            const float* f1w = ff1_w + (long)l * 64 * 256;
            const float* f1b = ff1_b + (long)l * 256;
            const float* f2w = ff2_w + (long)l * 256 * 64;
            const float* f2b = ff2_b + (long)l * 64;

            attn_fused_k<<<256 * 12, 384, ATTNH_SMEM>>>(xb, qw, ln1_g + l * 64, ln1_b + l * 64, aoh);
            tail_fused_k<<<M / 128, 256, TAIL_SMEM>>>(aoh, ow, ob, xb, f1w, f1b, f2w, f2b,
                                                      ln2_g + l * 64, ln2_b + l * 64, xb);
        }
    }

    // ---- PrimaryCaps + routing ----
    im2col3_k<<<(int)CDIV((long)8192 * 576, 256), 256>>>(xb, col3);
    wtrans_hwc<<<CDIV(256 * 576, 256), 256>>>(pcaps_w, wtp, 256, 64);
    tgemm_k<2><<<dim3(256 / 64, 8192 / 128), 256>>>(col3, wtp, pcaps_b, nullptr, pc, 8192, 256, 576);
    caps_squash_k<<<CDIV(256 * 1024, 256), 256>>>(pc, caps);
    caps_u_k<<<1024, 256>>>(caps, caps_w, u);
    routing_k<<<256, 256, ROUT_SMEM>>>(u, b_route, out);
}

// round 11
// speedup vs baseline: 5.0378x; 1.1692x over previous
#include <cuda_runtime.h>
#include <cuda_fp16.h>
#include <math.h>
#include <stdint.h>

#define CDIV(a,b) (((a)+(b)-1)/(b))

// ---------------- static scratch (no allocations allowed) ----------------
__device__ float  g_col1[737280 * 28];       // conv1 im2col (K padded 27->28)
__device__ float  g_wt1 [28 * 64];
__device__ __half g_y1h [737280 * 64];       // conv1 out NHWC fp16
__device__ __half g_p1h [184320 * 64];       // pool1 NHWC fp16
__device__ __half g_y2h [184320 * 64];       // conv2 out NHWC fp16
__device__ float  g_x   [46080 * 64];        // tokens / residual stream (B,180,64)
__device__ __half g_aoh [46080 * 768];       // attention output fp16
__device__ float  g_col3[8192 * 576];        // pcaps im2col
__device__ float  g_wtp [576 * 256];
__device__ float  g_pc  [8192 * 256];        // pcaps out NHWC (B,4,8,256)
__device__ float  g_caps[256 * 1024 * 8];
__device__ float  g_u   [256 * 1024 * 48];
// pre-transposed fp16 weights
__device__ __half g_qh  [12 * 12 * 3 * 64 * 64];  // [l][h][mat(K,V,Q)][n][k]
__device__ __half g_owh [12 * 64 * 768];          // [l][n][k]
__device__ __half g_w1h [12 * 256 * 64];          // [l][n][k]
__device__ __half g_w2h [12 * 64 * 256];          // [l][n][k]
__device__ __half g_cw2h[64 * 576];               // conv2 w [n][k=(kh,kw,ci)]

// ---------------- weight prep (fp32 -> fp16, transposed) ----------------
__global__ void prep_qkv_k(const float* __restrict__ qw, __half* __restrict__ qh) {
    int idx = blockIdx.x * 256 + threadIdx.x;
    if (idx >= 12 * 12 * 3 * 4096) return;
    int k = idx & 63, n = (idx >> 6) & 63;
    int rest = idx >> 12;
    int mat = rest % 3; rest /= 3;
    int h = rest % 12, l = rest / 12;
    int moff = (mat == 0) ? 768 : (mat == 1) ? 1536 : 0;
    qh[idx] = __float2half(qw[(long)l * 64 * 2304 + (long)k * 2304 + moff + h * 64 + n]);
}
__global__ void prep_ow_k(const float* __restrict__ ow, __half* __restrict__ oh) {
    int idx = blockIdx.x * 256 + threadIdx.x;
    if (idx >= 12 * 64 * 768) return;
    int k = idx % 768, n = (idx / 768) % 64, l = idx / 49152;
    oh[idx] = __float2half(ow[(long)l * 49152 + (long)k * 64 + n]);
}
__global__ void prep_w1_k(const float* __restrict__ w1, __half* __restrict__ o) {
    int idx = blockIdx.x * 256 + threadIdx.x;
    if (idx >= 12 * 256 * 64) return;
    int k = idx & 63, n = (idx >> 6) & 255, l = idx >> 14;
    o[idx] = __float2half(w1[(long)l * 16384 + (long)k * 256 + n]);
}
__global__ void prep_w2_k(const float* __restrict__ w2, __half* __restrict__ o) {
    int idx = blockIdx.x * 256 + threadIdx.x;
    if (idx >= 12 * 64 * 256) return;
    int k = idx & 255, n = (idx >> 8) & 63, l = idx >> 14;
    o[idx] = __float2half(w2[(long)l * 16384 + (long)k * 64 + n]);
}
__global__ void prep_cw2_k(const float* __restrict__ w, __half* __restrict__ o) {
    int idx = blockIdx.x * 256 + threadIdx.x;   // n*576 + (kh*3+kw)*64+ci
    if (idx >= 64 * 576) return;
    int kk = idx % 576, n = idx / 576;
    int ci = kk & 63, tap = kk >> 6;
    o[idx] = __float2half(w[n * 576 + ci * 9 + tap]);
}

// ---------------- im2col kernels ----------------
__global__ void im2col1_k(const float* __restrict__ x, float* __restrict__ col) {
    long idx = (long)blockIdx.x * blockDim.x + threadIdx.x;
    const long total = (long)737280 * 28;
    if (idx >= total) return;
    int kk = (int)(idx % 28);
    long m = idx / 28;
    if (kk == 27) { col[idx] = 0.f; return; }
    int ow = (int)(m % 72);
    int t  = (int)(m / 72);
    int oh = t % 40;
    int b  = t / 40;
    int kw = kk % 3, kh = (kk / 3) % 3, ci = kk / 9;
    int ih = oh + kh - 1, iw = ow + kw - 1;
    float v = 0.f;
    if (ih >= 0 && ih < 40 && iw >= 0 && iw < 72)
        v = x[(((long)b * 3 + ci) * 40 + ih) * 72 + iw];
    col[idx] = v;
}

__global__ void im2col3_k(const float* __restrict__ tk, float* __restrict__ col) {
    long idx = (long)blockIdx.x * blockDim.x + threadIdx.x;
    const long total = (long)8192 * 576;
    if (idx >= total) return;
    int kk = (int)(idx % 576);
    long m = idx / 576;
    int ow = (int)(m % 8);
    int t  = (int)(m / 8);
    int oh = t % 4;
    int b  = t / 4;
    int ci = kk % 64;
    int kw = (kk / 64) % 3;
    int kh = kk / 192;
    int ih = oh * 2 + kh, iw = ow * 2 + kw;
    col[idx] = tk[((long)b * 180 + ih * 18 + iw) * 64 + ci];
}

// ---------------- weight transposes (fp32 paths) ----------------
__global__ void wtrans1(const float* __restrict__ w, float* __restrict__ wt) {
    int i = blockIdx.x * blockDim.x + threadIdx.x;
    if (i >= 64 * 28) return;
    int o = i / 28, k = i % 28;
    wt[k * 64 + o] = (k < 27) ? w[o * 27 + k] : 0.f;
}
__global__ void wtrans_hwc(const float* __restrict__ w, float* __restrict__ wt, int O, int CI) {
    int K = CI * 9;
    int i = blockIdx.x * blockDim.x + threadIdx.x;
    if (i >= O * K) return;
    int o = i / K, r = i % K;
    int ci = r / 9, kh = (r % 9) / 3, kw = r % 3;
    wt[((kh * 3 + kw) * CI + ci) * O + o] = w[i];
}

// ---------------- tf32 helpers ----------------
__device__ __forceinline__ float f2tf(float f) {
    uint32_t r;
    asm("cvt.rna.tf32.f32 %0, %1;" : "=r"(r) : "f"(f));
    return __uint_as_float(r);
}
__device__ __forceinline__ void mma_tf32(float d[4], const uint32_t a[4], const uint32_t b[2],
                                         const float c[4]) {
    asm("mma.sync.aligned.m16n8k8.row.col.f32.tf32.tf32.f32 "
        "{%0,%1,%2,%3},{%4,%5,%6,%7},{%8,%9},{%10,%11,%12,%13};"
        : "=f"(d[0]), "=f"(d[1]), "=f"(d[2]), "=f"(d[3])
        : "r"(a[0]), "r"(a[1]), "r"(a[2]), "r"(a[3]), "r"(b[0]), "r"(b[1]),
          "f"(c[0]), "f"(c[1]), "f"(c[2]), "f"(c[3]));
}

// ---------------- fp16 mma helpers ----------------
__device__ __forceinline__ uint32_t smem_u32(const void* p) {
    return (uint32_t)__cvta_generic_to_shared(p);
}
__device__ __forceinline__ void ldsm_x4(uint32_t r[4], uint32_t addr) {
    asm volatile("ldmatrix.sync.aligned.m8n8.x4.shared.b16 {%0,%1,%2,%3}, [%4];"
        : "=r"(r[0]), "=r"(r[1]), "=r"(r[2]), "=r"(r[3]) : "r"(addr));
}
__device__ __forceinline__ void ldsm_x2(uint32_t r[2], uint32_t addr) {
    asm volatile("ldmatrix.sync.aligned.m8n8.x2.shared.b16 {%0,%1}, [%2];"
        : "=r"(r[0]), "=r"(r[1]) : "r"(addr));
}
__device__ __forceinline__ void ldsm_x2_t(uint32_t r[2], uint32_t addr) {
    asm volatile("ldmatrix.sync.aligned.m8n8.x2.trans.shared.b16 {%0,%1}, [%2];"
        : "=r"(r[0]), "=r"(r[1]) : "r"(addr));
}
__device__ __forceinline__ void mma_f16(float d[4], const uint32_t a[4], const uint32_t b[2],
                                        const float c[4]) {
    asm volatile("mma.sync.aligned.m16n8k16.row.col.f32.f16.f16.f32 "
        "{%0,%1,%2,%3},{%4,%5,%6,%7},{%8,%9},{%10,%11,%12,%13};"
        : "=f"(d[0]), "=f"(d[1]), "=f"(d[2]), "=f"(d[3])
        : "r"(a[0]), "r"(a[1]), "r"(a[2]), "r"(a[3]), "r"(b[0]), "r"(b[1]),
          "f"(c[0]), "f"(c[1]), "f"(c[2]), "f"(c[3]));
}
__device__ __forceinline__ uint32_t packh2(float a, float b) {
    __half2 h = __floats2half2_rn(a, b);
    return *(uint32_t*)&h;
}

// ---------------- tf32 tensor-core GEMM (conv1 / pcaps) ----------------
// EPI: 1 relu, 2 +bias. OUTH: write fp16.
template <int EPI, bool OUTH>
__global__ void __launch_bounds__(256) tgemm_k(const float* __restrict__ A, const float* __restrict__ Bm,
                                               const float* __restrict__ bias,
                                               void* __restrict__ C, int M, int N, int K) {
    __shared__ float As[128 * 36];
    __shared__ float Bs[32 * 68];
    const int bm = blockIdx.y * 128, bn = blockIdx.x * 64;
    const int tid = threadIdx.x, lane = tid & 31, w = tid >> 5;
    const int g4 = lane >> 2, c4 = lane & 3;
    const int wm = (w & 3) * 32, wn = (w >> 2) * 32;

    float acc[2][4][4];
#pragma unroll
    for (int mt = 0; mt < 2; mt++)
#pragma unroll
        for (int nt = 0; nt < 4; nt++)
#pragma unroll
            for (int i = 0; i < 4; i++) acc[mt][nt][i] = 0.f;

    const int ar = tid >> 1, akb = (tid & 1) * 16;
    const int bk = tid >> 3, bn0 = (tid & 7) * 8;
    const float* Arow = A + (long)(bm + ar) * K;

    for (int k0 = 0; k0 < K; k0 += 32) {
        float4 av[4], bv[2];
#pragma unroll
        for (int i = 0; i < 4; i++) {
            int gk = k0 + akb + 4 * i;
            av[i] = (gk + 4 <= K) ? *(const float4*)(Arow + gk) : make_float4(0.f, 0.f, 0.f, 0.f);
        }
        {
            int gk = k0 + bk;
            if (gk < K) {
                bv[0] = *(const float4*)(Bm + (long)gk * N + bn + bn0);
                bv[1] = *(const float4*)(Bm + (long)gk * N + bn + bn0 + 4);
            } else {
                bv[0] = make_float4(0.f, 0.f, 0.f, 0.f);
                bv[1] = bv[0];
            }
        }
        __syncthreads();
#pragma unroll
        for (int i = 0; i < 4; i++) {
            float* p = &As[ar * 36 + akb + 4 * i];
            p[0] = f2tf(av[i].x); p[1] = f2tf(av[i].y); p[2] = f2tf(av[i].z); p[3] = f2tf(av[i].w);
        }
        {
            float* p = &Bs[bk * 68 + bn0];
            p[0] = f2tf(bv[0].x); p[1] = f2tf(bv[0].y); p[2] = f2tf(bv[0].z); p[3] = f2tf(bv[0].w);
            p[4] = f2tf(bv[1].x); p[5] = f2tf(bv[1].y); p[6] = f2tf(bv[1].z); p[7] = f2tf(bv[1].w);
        }
        __syncthreads();
#pragma unroll
        for (int ks = 0; ks < 4; ks++) {
            uint32_t bfr[4][2], afr[2][4];
#pragma unroll
            for (int nt = 0; nt < 4; nt++) {
                int col = wn + nt * 8 + g4;
                bfr[nt][0] = __float_as_uint(Bs[(ks * 8 + c4) * 68 + col]);
                bfr[nt][1] = __float_as_uint(Bs[(ks * 8 + c4 + 4) * 68 + col]);
            }
#pragma unroll
            for (int mt = 0; mt < 2; mt++) {
                int base = (wm + mt * 16 + g4) * 36 + ks * 8 + c4;
                afr[mt][0] = __float_as_uint(As[base]);
                afr[mt][1] = __float_as_uint(As[base + 8 * 36]);
                afr[mt][2] = __float_as_uint(As[base + 4]);
                afr[mt][3] = __float_as_uint(As[base + 8 * 36 + 4]);
            }
#pragma unroll
            for (int mt = 0; mt < 2; mt++)
#pragma unroll
                for (int nt = 0; nt < 4; nt++)
                    mma_tf32(acc[mt][nt], afr[mt], bfr[nt], acc[mt][nt]);
        }
        __syncthreads();
    }

#pragma unroll
    for (int nt = 0; nt < 4; nt++) {
        int col = bn + wn + nt * 8 + 2 * c4;
        float b0 = 0.f, b1 = 0.f;
        if (EPI >= 2) { b0 = bias[col]; b1 = bias[col + 1]; }
#pragma unroll
        for (int mt = 0; mt < 2; mt++) {
#pragma unroll
            for (int half = 0; half < 2; half++) {
                long row = bm + wm + mt * 16 + g4 + 8 * half;
                float v0 = acc[mt][nt][2 * half], v1 = acc[mt][nt][2 * half + 1];
                if (EPI == 1) { v0 = fmaxf(v0, 0.f); v1 = fmaxf(v1, 0.f); }
                if (EPI >= 2) { v0 += b0; v1 += b1; }
                if (OUTH)
                    *(uint32_t*)((__half*)C + row * N + col) = packh2(v0, v1);
                else
                    *(float2*)((float*)C + row * N + col) = make_float2(v0, v1);
            }
        }
    }
}

// ---------------- conv2 direct (fused im2col): y2 = relu(p1 (*) w), fp16 ----------------
#define HC2_SMEM (64 * 584 * 2 + 128 * 72 * 2)
__global__ void __launch_bounds__(256) hconv2_k(const __half* __restrict__ p1,
                                                const __half* __restrict__ wch,
                                                __half* __restrict__ y2) {
    extern __shared__ __half smc[];
    __half* Ws = smc;                 // [64 n][584 k]
    __half* As = smc + 64 * 584;      // [128 m][72]

    const int bm = blockIdx.x * 128;
    const int tid = threadIdx.x, lane = tid & 31, w = tid >> 5;
    const int g4 = lane >> 2, c4 = lane & 3;
    const int lmrow = lane & 15, lmk = (lane >> 4) * 8;
    const int b2row = lane & 7, b2k = ((lane >> 3) & 1) * 8;
    const int r0 = w * 16;

    for (int idx = tid; idx < 64 * 72; idx += 256) {
        int n = idx / 72, q = idx % 72;
        *(uint4*)&Ws[n * 584 + q * 8] = *(const uint4*)(wch + n * 576 + q * 8);
    }
    __syncthreads();

    float acc[8][4];
#pragma unroll
    for (int nt = 0; nt < 8; nt++)
#pragma unroll
        for (int i = 0; i < 4; i++) acc[nt][i] = 0.f;

    const int ar = tid >> 1, apart = (tid & 1) * 32;
    const int m = bm + ar;
    const int bidx = m / 720, rem = m % 720;
    const int oh = rem / 36, owp = rem % 36;

#pragma unroll
    for (int kc = 0; kc < 9; kc++) {
        int kh = kc / 3, kw = kc % 3;
        int ih = oh + kh - 1, iw = owp + kw - 1;
        uint4 v[4];
        if ((unsigned)ih < 20u && (unsigned)iw < 36u) {
            const uint4* src = (const uint4*)(p1 + (((long)(bidx * 20 + ih)) * 36 + iw) * 64 + apart);
            v[0] = src[0]; v[1] = src[1]; v[2] = src[2]; v[3] = src[3];
        } else {
            v[0] = make_uint4(0, 0, 0, 0); v[1] = v[0]; v[2] = v[0]; v[3] = v[0];
        }
        uint4* dst = (uint4*)&As[ar * 72 + apart];
        dst[0] = v[0]; dst[1] = v[1]; dst[2] = v[2]; dst[3] = v[3];
        __syncwarp();
        uint32_t afr[4][4];
#pragma unroll
        for (int ks = 0; ks < 4; ks++)
            ldsm_x4(afr[ks], smem_u32(&As[(r0 + lmrow) * 72 + ks * 16 + lmk]));
#pragma unroll
        for (int nt = 0; nt < 8; nt++) {
#pragma unroll
            for (int ks = 0; ks < 4; ks++) {
                uint32_t bf[2];
                ldsm_x2(bf, smem_u32(&Ws[(nt * 8 + b2row) * 584 + kc * 64 + ks * 16 + b2k]));
                mma_f16(acc[nt], afr[ks], bf, acc[nt]);
            }
        }
        __syncwarp();
    }

#pragma unroll
    for (int nt = 0; nt < 8; nt++) {
        int col = nt * 8 + 2 * c4;
#pragma unroll
        for (int half = 0; half < 2; half++) {
            long row = bm + r0 + g4 + 8 * half;
            *(uint32_t*)(y2 + row * 64 + col) =
                packh2(fmaxf(acc[nt][2 * half], 0.f), fmaxf(acc[nt][2 * half + 1], 0.f));
        }
    }
}

// ---------------- maxpool 3x3 s2 p1 on NHWC (+ optional pos-emb add) ----------------
template <typename Ti, typename To>
__global__ void maxpool_k(const Ti* __restrict__ in, To* __restrict__ out,
                          int Bn, int IH, int IW, int C, int OH, int OW,
                          const float* __restrict__ pos) {
    long idx = (long)blockIdx.x * blockDim.x + threadIdx.x;
    long total = (long)Bn * OH * OW * C;
    if (idx >= total) return;
    int c = (int)(idx % C);
    long r = idx / C;
    int ow = (int)(r % OW); r /= OW;
    int oh = (int)(r % OH);
    int b  = (int)(r / OH);
    float m = -1e30f;
#pragma unroll
    for (int kh = 0; kh < 3; kh++) {
        int ih = oh * 2 - 1 + kh;
        if (ih < 0 || ih >= IH) continue;
#pragma unroll
        for (int kw = 0; kw < 3; kw++) {
            int iw = ow * 2 - 1 + kw;
            if (iw < 0 || iw >= IW) continue;
            m = fmaxf(m, (float)in[(((long)b * IH + ih) * IW + iw) * C + c]);
        }
    }
    if (pos) m += pos[(oh * OW + ow) * C + c];
    out[idx] = (To)m;
}

// ---------------- fully-fused attention: scores in registers, fp16 out ----------------
#define ATTNH_SMEM ((3 * 192 * 72 + 3 * 64 * 72) * 2)

__global__ void __launch_bounds__(384, 1) attn_fused_k(const float* __restrict__ x,
                                                       const __half* __restrict__ qh,
                                                       const float* __restrict__ lng,
                                                       const float* __restrict__ lnb,
                                                       __half* __restrict__ out) {
    extern __shared__ __half smh[];
    __half* H16 = smh;
    __half* K16 = smh + 192 * 72;
    __half* V16 = smh + 2 * 192 * 72;
    __half* W16 = smh + 3 * 192 * 72;

    int b = blockIdx.x / 12, h = blockIdx.x % 12;
    int tid = threadIdx.x, lane = tid & 31, w = tid >> 5;
    int g4 = lane >> 2, c4 = lane & 3;
    int lmrow = lane & 15, lmk = (lane >> 4) * 8;
    int b2row = lane & 7, b2k = ((lane >> 3) & 1) * 8;
    const int r0 = w * 16;

    // ---- stage W16 from pre-transposed fp16 (vector copies) ----
    {
        const __half* qsrc = qh + (long)h * 12288;
        for (int idx = tid; idx < 192 * 8; idx += 384) {
            int row = idx >> 3, q = idx & 7;
            *(uint4*)&W16[row * 72 + q * 8] = *(const uint4*)(qsrc + row * 64 + q * 8);
        }
    }

    // ---- LN: residual from gmem -> fp16 H ----
    {
        const float* xb = x + (long)b * 180 * 64;
        float ga = lng[lane], gb = lng[lane + 32];
        float ba = lnb[lane], bb2 = lnb[lane + 32];
        for (int r = w; r < 180; r += 12) {
            float v0 = xb[r * 64 + lane], v1 = xb[r * 64 + 32 + lane];
            float s = v0 + v1;
#pragma unroll
            for (int o = 16; o; o >>= 1) s += __shfl_xor_sync(0xffffffffu, s, o);
            float mean = s * (1.f / 64.f);
            float d0 = v0 - mean, d1 = v1 - mean;
            float q = d0 * d0 + d1 * d1;
#pragma unroll
            for (int o = 16; o; o >>= 1) q += __shfl_xor_sync(0xffffffffu, q, o);
            float rstd = rsqrtf(q * (1.f / 64.f) + 1e-5f);
            H16[r * 72 + lane]      = __float2half(d0 * rstd * ga + ba);
            H16[r * 72 + 32 + lane] = __float2half(d1 * rstd * gb + bb2);
        }
        for (int i = tid; i < 12 * 72; i += 384) H16[180 * 72 + i] = __float2half(0.f);
    }
    __syncthreads();

    uint32_t afr[4][4];
#pragma unroll
    for (int ks = 0; ks < 4; ks++)
        ldsm_x4(afr[ks], smem_u32(&H16[(r0 + lmrow) * 72 + ks * 16 + lmk]));

#pragma unroll
    for (int mat = 0; mat < 2; mat++) {
        const __half* Wm = W16 + mat * 64 * 72;
        __half* dst = mat ? V16 : K16;
#pragma unroll
        for (int nt = 0; nt < 8; nt++) {
            float acc[4] = {0.f, 0.f, 0.f, 0.f};
#pragma unroll
            for (int ks = 0; ks < 4; ks++) {
                uint32_t bf[2];
                ldsm_x2(bf, smem_u32(&Wm[(nt * 8 + b2row) * 72 + ks * 16 + b2k]));
                mma_f16(acc, afr[ks], bf, acc);
            }
            int col = nt * 8 + 2 * c4;
            *(uint32_t*)&dst[(r0 + g4) * 72 + col]     = packh2(acc[0], acc[1]);
            *(uint32_t*)&dst[(r0 + g4 + 8) * 72 + col] = packh2(acc[2], acc[3]);
        }
    }

    uint32_t afq[4][4];
    {
        const __half* Wm = W16 + 2 * 64 * 72;
        float qacc[8][4];
#pragma unroll
        for (int nt = 0; nt < 8; nt++) {
#pragma unroll
            for (int i = 0; i < 4; i++) qacc[nt][i] = 0.f;
#pragma unroll
            for (int ks = 0; ks < 4; ks++) {
                uint32_t bf[2];
                ldsm_x2(bf, smem_u32(&Wm[(nt * 8 + b2row) * 72 + ks * 16 + b2k]));
                mma_f16(qacc[nt], afr[ks], bf, qacc[nt]);
            }
        }
#pragma unroll
        for (int kt = 0; kt < 4; kt++) {
            afq[kt][0] = packh2(qacc[2 * kt][0],     qacc[2 * kt][1]);
            afq[kt][1] = packh2(qacc[2 * kt][2],     qacc[2 * kt][3]);
            afq[kt][2] = packh2(qacc[2 * kt + 1][0], qacc[2 * kt + 1][1]);
            afq[kt][3] = packh2(qacc[2 * kt + 1][2], qacc[2 * kt + 1][3]);
        }
    }
    __syncthreads();

    float S[24][4];
#pragma unroll
    for (int nt = 0; nt < 24; nt++) {
        float acc[4] = {0.f, 0.f, 0.f, 0.f};
#pragma unroll
        for (int ks = 0; ks < 4; ks++) {
            uint32_t bf[2];
            ldsm_x2(bf, smem_u32(&K16[(nt * 8 + b2row) * 72 + ks * 16 + b2k]));
            mma_f16(acc, afq[ks], bf, acc);
        }
#pragma unroll
        for (int i = 0; i < 4; i++) S[nt][i] = acc[i] * 0.125f;
    }

    {
        float mx0 = -1e30f, mx1 = -1e30f;
#pragma unroll
        for (int nt = 0; nt < 24; nt++) {
#pragma unroll
            for (int j = 0; j < 2; j++) {
                int col = nt * 8 + 2 * c4 + j;
                if (col < 180) {
                    mx0 = fmaxf(mx0, S[nt][j]);
                    mx1 = fmaxf(mx1, S[nt][2 + j]);
                }
            }
        }
        mx0 = fmaxf(mx0, __shfl_xor_sync(0xffffffffu, mx0, 1));
        mx0 = fmaxf(mx0, __shfl_xor_sync(0xffffffffu, mx0, 2));
        mx1 = fmaxf(mx1, __shfl_xor_sync(0xffffffffu, mx1, 1));
        mx1 = fmaxf(mx1, __shfl_xor_sync(0xffffffffu, mx1, 2));
        float sum0 = 0.f, sum1 = 0.f;
#pragma unroll
        for (int nt = 0; nt < 24; nt++) {
#pragma unroll
            for (int j = 0; j < 2; j++) {
                int col = nt * 8 + 2 * c4 + j;
                float e0 = (col < 180) ? __expf(S[nt][j] - mx0) : 0.f;
                float e1 = (col < 180) ? __expf(S[nt][2 + j] - mx1) : 0.f;
                S[nt][j] = e0; S[nt][2 + j] = e1;
                sum0 += e0; sum1 += e1;
            }
        }
        sum0 += __shfl_xor_sync(0xffffffffu, sum0, 1);
        sum0 += __shfl_xor_sync(0xffffffffu, sum0, 2);
        sum1 += __shfl_xor_sync(0xffffffffu, sum1, 1);
        sum1 += __shfl_xor_sync(0xffffffffu, sum1, 2);
        float inv0 = 1.f / sum0, inv1 = 1.f / sum1;
#pragma unroll
        for (int nt = 0; nt < 24; nt++) {
            S[nt][0] *= inv0; S[nt][1] *= inv0;
            S[nt][2] *= inv1; S[nt][3] *= inv1;
        }
    }

    uint32_t P[12][4];
#pragma unroll
    for (int kt = 0; kt < 12; kt++) {
        P[kt][0] = packh2(S[2 * kt][0],     S[2 * kt][1]);
        P[kt][1] = packh2(S[2 * kt][2],     S[2 * kt][3]);
        P[kt][2] = packh2(S[2 * kt + 1][0], S[2 * kt + 1][1]);
        P[kt][3] = packh2(S[2 * kt + 1][2], S[2 * kt + 1][3]);
    }

    {
        __half* outb = out + (long)b * 180 * 768 + h * 64;
#pragma unroll
        for (int nt = 0; nt < 8; nt++) {
            float acc[4] = {0.f, 0.f, 0.f, 0.f};
#pragma unroll
            for (int kt = 0; kt < 12; kt++) {
                uint32_t bv[2];
                ldsm_x2_t(bv, smem_u32(&V16[(kt * 16 + lmrow) * 72 + nt * 8]));
                mma_f16(acc, P[kt], bv, acc);
            }
            int row = r0 + g4;
            long col = nt * 8 + 2 * c4;
            if (row < 180)
                *(uint32_t*)(outb + (long)row * 768 + col) = packh2(acc[0], acc[1]);
            if (row + 8 < 180)
                *(uint32_t*)(outb + (long)(row + 8) * 768 + col) = packh2(acc[2], acc[3]);
        }
    }
}

// ---------------- fused tail v2: outproj + LN2 + MLP, G in registers, 2 chunks/block ----------------
// smem halfs: Ws 64x776 @0 (49664), As/Hs 128x72 @49664 (9216),
//             W1s 256x72 @58880 (18432), W2s 64x264 @77312 (16896)
#define T_WS   0
#define T_ASHS 49664
#define T_W1S  58880
#define T_W2S  77312
#define TAIL_SMEM 188416

__global__ void __launch_bounds__(256) tail_fused_k(const __half* __restrict__ ao,
                                                    const __half* __restrict__ owh,
                                                    const float* __restrict__ ob,
                                                    const float* __restrict__ x,
                                                    const __half* __restrict__ w1h,
                                                    const float* __restrict__ b1,
                                                    const __half* __restrict__ w2h,
                                                    const float* __restrict__ b2,
                                                    const float* __restrict__ lng,
                                                    const float* __restrict__ lnb,
                                                    float* __restrict__ outx) {
    extern __shared__ __half smt[];
    __half* Ws  = smt + T_WS;
    __half* As  = smt + T_ASHS;   // also Hs
    __half* W1s = smt + T_W1S;
    __half* W2s = smt + T_W2S;

    const int tid = threadIdx.x, lane = tid & 31, w = tid >> 5;
    const int g4 = lane >> 2, c4 = lane & 3;
    const int lmrow = lane & 15, lmk = (lane >> 4) * 8;
    const int b2row = lane & 7, b2k = ((lane >> 3) & 1) * 8;
    const int r0 = w * 16;

    // ---- stage all weights once (vector copies from fp16 globals) ----
    for (int idx = tid; idx < 64 * 96; idx += 256) {
        int n = idx / 96, q = idx % 96;
        *(uint4*)&Ws[n * 776 + q * 8] = *(const uint4*)(owh + n * 768 + q * 8);
    }
    for (int idx = tid; idx < 256 * 8; idx += 256) {
        int n = idx >> 3, q = idx & 7;
        *(uint4*)&W1s[n * 72 + q * 8] = *(const uint4*)(w1h + n * 64 + q * 8);
    }
    for (int idx = tid; idx < 64 * 32; idx += 256) {
        int n = idx >> 5, q = idx & 31;
        *(uint4*)&W2s[n * 264 + q * 8] = *(const uint4*)(w2h + n * 256 + q * 8);
    }
    __syncthreads();

    const int ar = tid >> 1, apart = (tid & 1) * 32;

    for (int c = 0; c < 2; c++) {
        const long bm = ((long)blockIdx.x * 2 + c) * 128;

        // ---- phase 1: out-projection over 12 k-chunks (warp-local As) ----
        float acc[8][4];
#pragma unroll
        for (int nt = 0; nt < 8; nt++)
#pragma unroll
            for (int i = 0; i < 4; i++) acc[nt][i] = 0.f;

        for (int kc = 0; kc < 12; kc++) {
            {
                const uint4* src = (const uint4*)(ao + (bm + ar) * 768 + kc * 64 + apart);
                uint4* dst = (uint4*)&As[ar * 72 + apart];
                dst[0] = src[0]; dst[1] = src[1]; dst[2] = src[2]; dst[3] = src[3];
            }
            __syncwarp();
            uint32_t afr[4][4];
#pragma unroll
            for (int ks = 0; ks < 4; ks++)
                ldsm_x4(afr[ks], smem_u32(&As[(r0 + lmrow) * 72 + ks * 16 + lmk]));
#pragma unroll
            for (int nt = 0; nt < 8; nt++) {
#pragma unroll
                for (int ks = 0; ks < 4; ks++) {
                    uint32_t bf[2];
                    ldsm_x2(bf, smem_u32(&Ws[(nt * 8 + b2row) * 776 + kc * 64 + ks * 16 + b2k]));
                    mma_f16(acc[nt], afr[ks], bf, acc[nt]);
                }
            }
            __syncwarp();
        }

        // ---- epilogue 1: +ob +residual -> xres; LN2 via quad shuffles -> Hs ----
        float xres[8][4];
#pragma unroll
        for (int nt = 0; nt < 8; nt++) {
            int col = nt * 8 + 2 * c4;
            float b0 = ob[col], b1 = ob[col + 1];
#pragma unroll
            for (int half = 0; half < 2; half++) {
                long row = bm + r0 + g4 + 8 * half;
                float2 r = *(const float2*)(x + row * 64 + col);
                xres[nt][2 * half]     = acc[nt][2 * half] + b0 + r.x;
                xres[nt][2 * half + 1] = acc[nt][2 * half + 1] + b1 + r.y;
            }
        }
        {
            float s0 = 0.f, s1 = 0.f;
#pragma unroll
            for (int nt = 0; nt < 8; nt++) {
                s0 += xres[nt][0] + xres[nt][1];
                s1 += xres[nt][2] + xres[nt][3];
            }
            s0 += __shfl_xor_sync(0xffffffffu, s0, 1);
            s0 += __shfl_xor_sync(0xffffffffu, s0, 2);
            s1 += __shfl_xor_sync(0xffffffffu, s1, 1);
            s1 += __shfl_xor_sync(0xffffffffu, s1, 2);
            float m0 = s0 * (1.f / 64.f), m1 = s1 * (1.f / 64.f);
            float q0 = 0.f, q1 = 0.f;
#pragma unroll
            for (int nt = 0; nt < 8; nt++) {
                float d0 = xres[nt][0] - m0, d1 = xres[nt][1] - m0;
                float d2 = xres[nt][2] - m1, d3 = xres[nt][3] - m1;
                q0 += d0 * d0 + d1 * d1;
                q1 += d2 * d2 + d3 * d3;
            }
            q0 += __shfl_xor_sync(0xffffffffu, q0, 1);
            q0 += __shfl_xor_sync(0xffffffffu, q0, 2);
            q1 += __shfl_xor_sync(0xffffffffu, q1, 1);
            q1 += __shfl_xor_sync(0xffffffffu, q1, 2);
            float rs0 = rsqrtf(q0 * (1.f / 64.f) + 1e-5f);
            float rs1 = rsqrtf(q1 * (1.f / 64.f) + 1e-5f);
#pragma unroll
            for (int nt = 0; nt < 8; nt++) {
                int col = nt * 8 + 2 * c4;
                float g0 = lng[col], g1 = lng[col + 1];
                float be0 = lnb[col], be1 = lnb[col + 1];
                float h0 = (xres[nt][0] - m0) * rs0 * g0 + be0;
                float h1 = (xres[nt][1] - m0) * rs0 * g1 + be1;
                float h2 = (xres[nt][2] - m1) * rs1 * g0 + be0;
                float h3 = (xres[nt][3] - m1) * rs1 * g1 + be1;
                *(uint32_t*)&As[(r0 + g4) * 72 + col]     = packh2(h0, h1);
                *(uint32_t*)&As[(r0 + g4 + 8) * 72 + col] = packh2(h2, h3);
            }
        }
        __syncwarp();

        // ---- ff1 streamed: D-frags -> GELU -> A-frags (registers only) ----
        uint32_t afg[16][4];
        {
            uint32_t afr[4][4];
#pragma unroll
            for (int ks = 0; ks < 4; ks++)
                ldsm_x4(afr[ks], smem_u32(&As[(r0 + lmrow) * 72 + ks * 16 + lmk]));
#pragma unroll
            for (int kt = 0; kt < 16; kt++) {
                float d0[4] = {0.f, 0.f, 0.f, 0.f}, d1[4] = {0.f, 0.f, 0.f, 0.f};
#pragma unroll
                for (int ks = 0; ks < 4; ks++) {
                    uint32_t bf[2];
                    ldsm_x2(bf, smem_u32(&W1s[((2 * kt) * 8 + b2row) * 72 + ks * 16 + b2k]));
                    mma_f16(d0, afr[ks], bf, d0);
                    ldsm_x2(bf, smem_u32(&W1s[((2 * kt + 1) * 8 + b2row) * 72 + ks * 16 + b2k]));
                    mma_f16(d1, afr[ks], bf, d1);
                }
                int col0 = (2 * kt) * 8 + 2 * c4, col1 = (2 * kt + 1) * 8 + 2 * c4;
                float a0 = d0[0] + b1[col0],     a1 = d0[1] + b1[col0 + 1];
                float a2 = d0[2] + b1[col0],     a3 = d0[3] + b1[col0 + 1];
                float a4 = d1[0] + b1[col1],     a5 = d1[1] + b1[col1 + 1];
                float a6 = d1[2] + b1[col1],     a7 = d1[3] + b1[col1 + 1];
                a0 = 0.5f * a0 * (1.f + erff(a0 * 0.70710678118654752f));
                a1 = 0.5f * a1 * (1.f + erff(a1 * 0.70710678118654752f));
                a2 = 0.5f * a2 * (1.f + erff(a2 * 0.70710678118654752f));
                a3 = 0.5f * a3 * (1.f + erff(a3 * 0.70710678118654752f));
                a4 = 0.5f * a4 * (1.f + erff(a4 * 0.70710678118654752f));
                a5 = 0.5f * a5 * (1.f + erff(a5 * 0.70710678118654752f));
                a6 = 0.5f * a6 * (1.f + erff(a6 * 0.70710678118654752f));
                a7 = 0.5f * a7 * (1.f + erff(a7 * 0.70710678118654752f));
                afg[kt][0] = packh2(a0, a1);
                afg[kt][1] = packh2(a2, a3);
                afg[kt][2] = packh2(a4, a5);
                afg[kt][3] = packh2(a6, a7);
            }
        }

        // ---- ff2: out = G @ W2 + b2 + xres ----
#pragma unroll
        for (int nt = 0; nt < 8; nt++) {
            float a2c[4] = {0.f, 0.f, 0.f, 0.f};
#pragma unroll
            for (int kt = 0; kt < 16; kt++) {
                uint32_t bf[2];
                ldsm_x2(bf, smem_u32(&W2s[(nt * 8 + b2row) * 264 + kt * 16 + b2k]));
                mma_f16(a2c, afg[kt], bf, a2c);
            }
            int col = nt * 8 + 2 * c4;
            float bb0 = b2[col], bb1 = b2[col + 1];
#pragma unroll
            for (int half = 0; half < 2; half++) {
                long row = bm + r0 + g4 + 8 * half;
                float v0 = a2c[2 * half] + bb0 + xres[nt][2 * half];
                float v1 = a2c[2 * half + 1] + bb1 + xres[nt][2 * half + 1];
                *(float2*)(outx + row * 64 + col) = make_float2(v0, v1);
            }
        }
        __syncwarp();
    }
}

// ---------------- primary caps: gather + squash ----------------
__global__ void caps_squash_k(const float* __restrict__ pc, float* __restrict__ caps) {
    int idx = blockIdx.x * blockDim.x + threadIdx.x;
    if (idx >= 256 * 1024) return;
    int i = idx & 1023, b = idx >> 10;
    int i32 = i >> 5, y = (i >> 3) & 3, xq = i & 7;
    const float* src = pc + (((long)b * 4 + y) * 8 + xq) * 256 + i32 * 8;
    float t[8];
    float l2 = 0.f;
#pragma unroll
    for (int e = 0; e < 8; e++) { t[e] = src[e]; l2 += t[e] * t[e]; }
    float sc = sqrtf(l2) / (1.f + l2);
#pragma unroll
    for (int e = 0; e < 8; e++) caps[(long)idx * 8 + e] = t[e] * sc;
}

// ---------------- capsule predictions u[b,i,:] ----------------
__global__ void caps_u_k(const float* __restrict__ caps, const float* __restrict__ cw,
                         float* __restrict__ u) {
    __shared__ float w_s[8 * 48];
    int i = blockIdx.x;
    for (int t = threadIdx.x; t < 384; t += 256) w_s[t] = cw[(long)i * 384 + t];
    __syncthreads();
    int b = threadIdx.x;
    float ce[8];
    const float* cp = caps + ((long)b * 1024 + i) * 8;
#pragma unroll
    for (int e = 0; e < 8; e++) ce[e] = cp[e];
    float* up = u + ((long)b * 1024 + i) * 48;
#pragma unroll 4
    for (int o = 0; o < 48; o++) {
        float s = 0.f;
#pragma unroll
        for (int e = 0; e < 8; e++) s = fmaf(ce[e], w_s[e * 48 + o], s);
        up[o] = s;
    }
}

// ---------------- dynamic routing, u staged in smem ----------------
#define ROUT_SMEM ((49152 + 3072 + 96) * 4)
__global__ void __launch_bounds__(256) routing_k(const float* __restrict__ u,
                                                 const float* __restrict__ br,
                                                 float* __restrict__ out) {
    extern __shared__ float smr[];
    float* us = smr;
    float* bb = smr + 49152;
    float* S  = bb + 3072;
    float* v  = S + 48;
    int b = blockIdx.x, tid = threadIdx.x, lane = tid & 31;
    const float* ub = u + (long)b * 1024 * 48;
    for (int i = tid; i < 49152; i += 256) us[i] = ub[i];
    for (int i = tid; i < 3072; i += 256) bb[i] = br[i];
    __syncthreads();

    for (int it = 0; it < 4; it++) {
        if (tid < 48) S[tid] = 0.f;
        __syncthreads();
        float acc[48];
#pragma unroll
        for (int o = 0; o < 48; o++) acc[o] = 0.f;
        for (int i = tid; i < 1024; i += 256) {
            float b0 = bb[i * 3], b1 = bb[i * 3 + 1], b2 = bb[i * 3 + 2];
            float m = fmaxf(b0, fmaxf(b1, b2));
            float e0 = expf(b0 - m), e1 = expf(b1 - m), e2 = expf(b2 - m);
            float inv = 1.f / (e0 + e1 + e2);
            float c[3] = {e0 * inv, e1 * inv, e2 * inv};
            const float* up = &us[i * 48];
#pragma unroll
            for (int j = 0; j < 3; j++)
#pragma unroll
                for (int o = 0; o < 16; o++)
                    acc[j * 16 + o] = fmaf(c[j], up[j * 16 + o], acc[j * 16 + o]);
        }
#pragma unroll
        for (int o = 0; o < 48; o++) {
            float s = acc[o];
#pragma unroll
            for (int d = 16; d; d >>= 1) s += __shfl_xor_sync(0xffffffffu, s, d);
            if (lane == 0) atomicAdd(&S[o], s);
        }
        __syncthreads();
        if (tid < 3) {
            float l2 = 0.f;
            for (int o = 0; o < 16; o++) { float t = S[tid * 16 + o]; l2 += t * t; }
            float sc = sqrtf(l2) / (1.f + l2);
            for (int o = 0; o < 16; o++) v[tid * 16 + o] = S[tid * 16 + o] * sc;
            if (it == 3) out[b * 3 + tid] = l2 / (1.f + l2);
        }
        __syncthreads();
        if (it < 3) {
            for (int i = tid; i < 1024; i += 256) {
                const float* up = &us[i * 48];
#pragma unroll
                for (int j = 0; j < 3; j++) {
                    float s = 0.f;
#pragma unroll
                    for (int o = 0; o < 16; o++) s = fmaf(up[j * 16 + o], v[j * 16 + o], s);
                    bb[i * 3 + j] += s;
                }
            }
            __syncthreads();
        }
    }
}

// ---------------- host ----------------
extern "C" void kernel_launch(void* const* d_in, const int* in_sizes, int n_in,
                              void* d_out, int out_size) {
    const float* x_in    = (const float*)d_in[0];
    const float* conv1_w = (const float*)d_in[1];
    const float* conv2_w = (const float*)d_in[2];
    const float* pos_emb = (const float*)d_in[3];
    const float* ln1_g   = (const float*)d_in[4];
    const float* ln1_b   = (const float*)d_in[5];
    const float* qkv_w   = (const float*)d_in[6];
    const float* out_w   = (const float*)d_in[7];
    const float* out_b   = (const float*)d_in[8];
    const float* ln2_g   = (const float*)d_in[9];
    const float* ln2_b   = (const float*)d_in[10];
    const float* ff1_w   = (const float*)d_in[11];
    const float* ff1_b   = (const float*)d_in[12];
    const float* ff2_w   = (const float*)d_in[13];
    const float* ff2_b   = (const float*)d_in[14];
    const float* pcaps_w = (const float*)d_in[15];
    const float* pcaps_b = (const float*)d_in[16];
    const float* caps_w  = (const float*)d_in[17];
    const float* b_route = (const float*)d_in[18];
    float* out = (float*)d_out;

    float *col1, *wt1, *xb, *col3, *wtp, *pc, *caps, *u;
    __half *y1h, *p1h, *y2h, *aoh, *qh, *owh, *w1h, *w2h, *cw2h;
    cudaGetSymbolAddress((void**)&col1, g_col1);
    cudaGetSymbolAddress((void**)&wt1,  g_wt1);
    cudaGetSymbolAddress((void**)&y1h,  g_y1h);
    cudaGetSymbolAddress((void**)&p1h,  g_p1h);
    cudaGetSymbolAddress((void**)&y2h,  g_y2h);
    cudaGetSymbolAddress((void**)&xb,   g_x);
    cudaGetSymbolAddress((void**)&aoh,  g_aoh);
    cudaGetSymbolAddress((void**)&col3, g_col3);
    cudaGetSymbolAddress((void**)&wtp,  g_wtp);
    cudaGetSymbolAddress((void**)&pc,   g_pc);
    cudaGetSymbolAddress((void**)&caps, g_caps);
    cudaGetSymbolAddress((void**)&u,    g_u);
    cudaGetSymbolAddress((void**)&qh,   g_qh);
    cudaGetSymbolAddress((void**)&owh,  g_owh);
    cudaGetSymbolAddress((void**)&w1h,  g_w1h);
    cudaGetSymbolAddress((void**)&w2h,  g_w2h);
    cudaGetSymbolAddress((void**)&cw2h, g_cw2h);

    cudaFuncSetAttribute(attn_fused_k, cudaFuncAttributeMaxDynamicSharedMemorySize, ATTNH_SMEM);
    cudaFuncSetAttribute(tail_fused_k, cudaFuncAttributeMaxDynamicSharedMemorySize, TAIL_SMEM);
    cudaFuncSetAttribute(hconv2_k,     cudaFuncAttributeMaxDynamicSharedMemorySize, HC2_SMEM);
    cudaFuncSetAttribute(routing_k,    cudaFuncAttributeMaxDynamicSharedMemorySize, ROUT_SMEM);

    // ---- weight prep (fp16, pre-transposed) ----
    prep_qkv_k<<<CDIV(12 * 12 * 3 * 4096, 256), 256>>>(qkv_w, qh);
    prep_ow_k <<<CDIV(12 * 64 * 768, 256), 256>>>(out_w, owh);
    prep_w1_k <<<CDIV(12 * 256 * 64, 256), 256>>>(ff1_w, w1h);
    prep_w2_k <<<CDIV(12 * 64 * 256, 256), 256>>>(ff2_w, w2h);
    prep_cw2_k<<<CDIV(64 * 576, 256), 256>>>(conv2_w, cw2h);

    // ---- ConvEmbed ----
    im2col1_k<<<(int)CDIV((long)737280 * 28, 256), 256>>>(x_in, col1);
    wtrans1<<<CDIV(64 * 28, 256), 256>>>(conv1_w, wt1);
    tgemm_k<1, true><<<dim3(1, 737280 / 128), 256>>>(col1, wt1, nullptr, y1h, 737280, 64, 28);
    maxpool_k<__half, __half><<<(int)CDIV((long)256 * 20 * 36 * 64, 256), 256>>>(
        y1h, p1h, 256, 40, 72, 64, 20, 36, nullptr);
    hconv2_k<<<184320 / 128, 256, HC2_SMEM>>>(p1h, cw2h, y2h);
    maxpool_k<__half, float><<<(int)CDIV((long)256 * 10 * 18 * 64, 256), 256>>>(
        y2h, xb, 256, 20, 36, 64, 10, 18, pos_emb);

    // ---- Transformer: 12 shared layers applied twice ----
    for (int pass = 0; pass < 2; pass++) {
        for (int l = 0; l < 12; l++) {
            attn_fused_k<<<256 * 12, 384, ATTNH_SMEM>>>(xb, qh + (long)l * 147456,
                                                        ln1_g + l * 64, ln1_b + l * 64, aoh);
            tail_fused_k<<<180, 256, TAIL_SMEM>>>(aoh, owh + (long)l * 49152, out_b + l * 64,
                                                  xb, w1h + (long)l * 16384, ff1_b + l * 256,
                                                  w2h + (long)l * 16384, ff2_b + l * 64,
                                                  ln2_g + l * 64, ln2_b + l * 64, xb);
        }
    }

    // ---- PrimaryCaps + routing ----
    im2col3_k<<<(int)CDIV((long)8192 * 576, 256), 256>>>(xb, col3);
    wtrans_hwc<<<CDIV(256 * 576, 256), 256>>>(pcaps_w, wtp, 256, 64);
    tgemm_k<2, false><<<dim3(256 / 64, 8192 / 128), 256>>>(col3, wtp, pcaps_b, pc, 8192, 256, 576);
    caps_squash_k<<<CDIV(256 * 1024, 256), 256>>>(pc, caps);
    caps_u_k<<<1024, 256>>>(caps, caps_w, u);
    routing_k<<<256, 256, ROUT_SMEM>>>(u, b_route, out);
}

// round 12
// speedup vs baseline: 7.2453x; 1.4382x over previous
#include <cuda_runtime.h>
#include <cuda_fp16.h>
#include <math.h>
#include <stdint.h>

#define CDIV(a,b) (((a)+(b)-1)/(b))

// ---------------- static scratch (no allocations allowed) ----------------
__device__ __half g_col1h[737280 * 32];      // conv1 im2col fp16 (K padded 27->32)
__device__ __half g_y1h [737280 * 64];       // conv1 out NHWC fp16
__device__ __half g_p1h [184320 * 64];       // pool1 NHWC fp16
__device__ __half g_y2h [184320 * 64];       // conv2 out NHWC fp16
__device__ float  g_x   [46080 * 64];        // tokens / residual stream (B,180,64)
__device__ __half g_h16 [46080 * 64];        // LN1 output fp16
__device__ __half g_aoh [46080 * 768];       // attention output fp16
__device__ float  g_col3[8192 * 576];        // pcaps im2col
__device__ float  g_wtp [576 * 256];
__device__ float  g_pc  [8192 * 256];        // pcaps out NHWC (B,4,8,256)
__device__ float  g_caps[256 * 1024 * 8];
__device__ float  g_u   [256 * 1024 * 48];
// pre-transposed fp16 weights
__device__ __half g_qh  [12 * 12 * 3 * 64 * 64];  // [l][h][mat(K,V,Q)][n][k]
__device__ __half g_owh [12 * 64 * 768];          // [l][n][k]
__device__ __half g_w1h [12 * 256 * 64];          // [l][n][k]
__device__ __half g_w2h [12 * 64 * 256];          // [l][n][k]
__device__ __half g_cw1h[64 * 32];                // conv1 w [n][k] (k=(ci,kh,kw), pad 32)
__device__ __half g_cw2h[64 * 576];               // conv2 w [n][k=(kh,kw,ci)]

// ---------------- weight prep (fp32 -> fp16, transposed) ----------------
__global__ void prep_qkv_k(const float* __restrict__ qw, __half* __restrict__ qh) {
    int idx = blockIdx.x * 256 + threadIdx.x;
    if (idx >= 12 * 12 * 3 * 4096) return;
    int k = idx & 63, n = (idx >> 6) & 63;
    int rest = idx >> 12;
    int mat = rest % 3; rest /= 3;
    int h = rest % 12, l = rest / 12;
    int moff = (mat == 0) ? 768 : (mat == 1) ? 1536 : 0;
    qh[idx] = __float2half(qw[(long)l * 64 * 2304 + (long)k * 2304 + moff + h * 64 + n]);
}
__global__ void prep_ow_k(const float* __restrict__ ow, __half* __restrict__ oh) {
    int idx = blockIdx.x * 256 + threadIdx.x;
    if (idx >= 12 * 64 * 768) return;
    int k = idx % 768, n = (idx / 768) % 64, l = idx / 49152;
    oh[idx] = __float2half(ow[(long)l * 49152 + (long)k * 64 + n]);
}
__global__ void prep_w1_k(const float* __restrict__ w1, __half* __restrict__ o) {
    int idx = blockIdx.x * 256 + threadIdx.x;
    if (idx >= 12 * 256 * 64) return;
    int k = idx & 63, n = (idx >> 6) & 255, l = idx >> 14;
    o[idx] = __float2half(w1[(long)l * 16384 + (long)k * 256 + n]);
}
__global__ void prep_w2_k(const float* __restrict__ w2, __half* __restrict__ o) {
    int idx = blockIdx.x * 256 + threadIdx.x;
    if (idx >= 12 * 64 * 256) return;
    int k = idx & 255, n = (idx >> 8) & 63, l = idx >> 14;
    o[idx] = __float2half(w2[(long)l * 16384 + (long)k * 64 + n]);
}
__global__ void prep_cw1_k(const float* __restrict__ w, __half* __restrict__ o) {
    int idx = blockIdx.x * 256 + threadIdx.x;
    if (idx >= 64 * 32) return;
    int k = idx & 31, n = idx >> 5;
    o[idx] = __float2half(k < 27 ? w[n * 27 + k] : 0.f);
}
__global__ void prep_cw2_k(const float* __restrict__ w, __half* __restrict__ o) {
    int idx = blockIdx.x * 256 + threadIdx.x;   // n*576 + (kh*3+kw)*64+ci
    if (idx >= 64 * 576) return;
    int kk = idx % 576, n = idx / 576;
    int ci = kk & 63, tap = kk >> 6;
    o[idx] = __float2half(w[n * 576 + ci * 9 + tap]);
}

// ---------------- im2col kernels ----------------
__global__ void im2col1h_k(const float* __restrict__ x, __half* __restrict__ col) {
    long idx = (long)blockIdx.x * blockDim.x + threadIdx.x;
    const long total = (long)737280 * 32;
    if (idx >= total) return;
    int kk = (int)(idx & 31);
    long m = idx >> 5;
    if (kk >= 27) { col[idx] = __float2half(0.f); return; }
    int ow = (int)(m % 72);
    int t  = (int)(m / 72);
    int oh = t % 40;
    int b  = t / 40;
    int kw = kk % 3, kh = (kk / 3) % 3, ci = kk / 9;
    int ih = oh + kh - 1, iw = ow + kw - 1;
    float v = 0.f;
    if (ih >= 0 && ih < 40 && iw >= 0 && iw < 72)
        v = x[(((long)b * 3 + ci) * 40 + ih) * 72 + iw];
    col[idx] = __float2half(v);
}

__global__ void im2col3_k(const float* __restrict__ tk, float* __restrict__ col) {
    long idx = (long)blockIdx.x * blockDim.x + threadIdx.x;
    const long total = (long)8192 * 576;
    if (idx >= total) return;
    int kk = (int)(idx % 576);
    long m = idx / 576;
    int ow = (int)(m % 8);
    int t  = (int)(m / 8);
    int oh = t % 4;
    int b  = t / 4;
    int ci = kk % 64;
    int kw = (kk / 64) % 3;
    int kh = kk / 192;
    int ih = oh * 2 + kh, iw = ow * 2 + kw;
    col[idx] = tk[((long)b * 180 + ih * 18 + iw) * 64 + ci];
}

// ---------------- weight transpose (pcaps, fp32) ----------------
__global__ void wtrans_hwc(const float* __restrict__ w, float* __restrict__ wt, int O, int CI) {
    int K = CI * 9;
    int i = blockIdx.x * blockDim.x + threadIdx.x;
    if (i >= O * K) return;
    int o = i / K, r = i % K;
    int ci = r / 9, kh = (r % 9) / 3, kw = r % 3;
    wt[((kh * 3 + kw) * CI + ci) * O + o] = w[i];
}

// ---------------- tf32 helpers ----------------
__device__ __forceinline__ float f2tf(float f) {
    uint32_t r;
    asm("cvt.rna.tf32.f32 %0, %1;" : "=r"(r) : "f"(f));
    return __uint_as_float(r);
}
__device__ __forceinline__ void mma_tf32(float d[4], const uint32_t a[4], const uint32_t b[2],
                                         const float c[4]) {
    asm("mma.sync.aligned.m16n8k8.row.col.f32.tf32.tf32.f32 "
        "{%0,%1,%2,%3},{%4,%5,%6,%7},{%8,%9},{%10,%11,%12,%13};"
        : "=f"(d[0]), "=f"(d[1]), "=f"(d[2]), "=f"(d[3])
        : "r"(a[0]), "r"(a[1]), "r"(a[2]), "r"(a[3]), "r"(b[0]), "r"(b[1]),
          "f"(c[0]), "f"(c[1]), "f"(c[2]), "f"(c[3]));
}

// ---------------- fp16 mma helpers ----------------
__device__ __forceinline__ uint32_t smem_u32(const void* p) {
    return (uint32_t)__cvta_generic_to_shared(p);
}
__device__ __forceinline__ void ldsm_x4(uint32_t r[4], uint32_t addr) {
    asm volatile("ldmatrix.sync.aligned.m8n8.x4.shared.b16 {%0,%1,%2,%3}, [%4];"
        : "=r"(r[0]), "=r"(r[1]), "=r"(r[2]), "=r"(r[3]) : "r"(addr));
}
__device__ __forceinline__ void ldsm_x2(uint32_t r[2], uint32_t addr) {
    asm volatile("ldmatrix.sync.aligned.m8n8.x2.shared.b16 {%0,%1}, [%2];"
        : "=r"(r[0]), "=r"(r[1]) : "r"(addr));
}
__device__ __forceinline__ void ldsm_x2_t(uint32_t r[2], uint32_t addr) {
    asm volatile("ldmatrix.sync.aligned.m8n8.x2.trans.shared.b16 {%0,%1}, [%2];"
        : "=r"(r[0]), "=r"(r[1]) : "r"(addr));
}
__device__ __forceinline__ void mma_f16(float d[4], const uint32_t a[4], const uint32_t b[2],
                                        const float c[4]) {
    asm volatile("mma.sync.aligned.m16n8k16.row.col.f32.f16.f16.f32 "
        "{%0,%1,%2,%3},{%4,%5,%6,%7},{%8,%9},{%10,%11,%12,%13};"
        : "=f"(d[0]), "=f"(d[1]), "=f"(d[2]), "=f"(d[3])
        : "r"(a[0]), "r"(a[1]), "r"(a[2]), "r"(a[3]), "r"(b[0]), "r"(b[1]),
          "f"(c[0]), "f"(c[1]), "f"(c[2]), "f"(c[3]));
}
__device__ __forceinline__ uint32_t packh2(float a, float b) {
    __half2 h = __floats2half2_rn(a, b);
    return *(uint32_t*)&h;
}

// ---------------- tf32 tensor-core GEMM (pcaps) ----------------
template <int EPI>
__global__ void __launch_bounds__(256) tgemm_k(const float* __restrict__ A, const float* __restrict__ Bm,
                                               const float* __restrict__ bias,
                                               float* __restrict__ C, int M, int N, int K) {
    __shared__ float As[128 * 36];
    __shared__ float Bs[32 * 68];
    const int bm = blockIdx.y * 128, bn = blockIdx.x * 64;
    const int tid = threadIdx.x, lane = tid & 31, w = tid >> 5;
    const int g4 = lane >> 2, c4 = lane & 3;
    const int wm = (w & 3) * 32, wn = (w >> 2) * 32;

    float acc[2][4][4];
#pragma unroll
    for (int mt = 0; mt < 2; mt++)
#pragma unroll
        for (int nt = 0; nt < 4; nt++)
#pragma unroll
            for (int i = 0; i < 4; i++) acc[mt][nt][i] = 0.f;

    const int ar = tid >> 1, akb = (tid & 1) * 16;
    const int bk = tid >> 3, bn0 = (tid & 7) * 8;
    const float* Arow = A + (long)(bm + ar) * K;

    for (int k0 = 0; k0 < K; k0 += 32) {
        float4 av[4], bv[2];
#pragma unroll
        for (int i = 0; i < 4; i++) {
            int gk = k0 + akb + 4 * i;
            av[i] = (gk + 4 <= K) ? *(const float4*)(Arow + gk) : make_float4(0.f, 0.f, 0.f, 0.f);
        }
        {
            int gk = k0 + bk;
            if (gk < K) {
                bv[0] = *(const float4*)(Bm + (long)gk * N + bn + bn0);
                bv[1] = *(const float4*)(Bm + (long)gk * N + bn + bn0 + 4);
            } else {
                bv[0] = make_float4(0.f, 0.f, 0.f, 0.f);
                bv[1] = bv[0];
            }
        }
        __syncthreads();
#pragma unroll
        for (int i = 0; i < 4; i++) {
            float* p = &As[ar * 36 + akb + 4 * i];
            p[0] = f2tf(av[i].x); p[1] = f2tf(av[i].y); p[2] = f2tf(av[i].z); p[3] = f2tf(av[i].w);
        }
        {
            float* p = &Bs[bk * 68 + bn0];
            p[0] = f2tf(bv[0].x); p[1] = f2tf(bv[0].y); p[2] = f2tf(bv[0].z); p[3] = f2tf(bv[0].w);
            p[4] = f2tf(bv[1].x); p[5] = f2tf(bv[1].y); p[6] = f2tf(bv[1].z); p[7] = f2tf(bv[1].w);
        }
        __syncthreads();
#pragma unroll
        for (int ks = 0; ks < 4; ks++) {
            uint32_t bfr[4][2], afr[2][4];
#pragma unroll
            for (int nt = 0; nt < 4; nt++) {
                int col = wn + nt * 8 + g4;
                bfr[nt][0] = __float_as_uint(Bs[(ks * 8 + c4) * 68 + col]);
                bfr[nt][1] = __float_as_uint(Bs[(ks * 8 + c4 + 4) * 68 + col]);
            }
#pragma unroll
            for (int mt = 0; mt < 2; mt++) {
                int base = (wm + mt * 16 + g4) * 36 + ks * 8 + c4;
                afr[mt][0] = __float_as_uint(As[base]);
                afr[mt][1] = __float_as_uint(As[base + 8 * 36]);
                afr[mt][2] = __float_as_uint(As[base + 4]);
                afr[mt][3] = __float_as_uint(As[base + 8 * 36 + 4]);
            }
#pragma unroll
            for (int mt = 0; mt < 2; mt++)
#pragma unroll
                for (int nt = 0; nt < 4; nt++)
                    mma_tf32(acc[mt][nt], afr[mt], bfr[nt], acc[mt][nt]);
        }
        __syncthreads();
    }

#pragma unroll
    for (int nt = 0; nt < 4; nt++) {
        int col = bn + wn + nt * 8 + 2 * c4;
        float b0 = 0.f, b1 = 0.f;
        if (EPI >= 2) { b0 = bias[col]; b1 = bias[col + 1]; }
#pragma unroll
        for (int mt = 0; mt < 2; mt++) {
#pragma unroll
            for (int half = 0; half < 2; half++) {
                long row = bm + wm + mt * 16 + g4 + 8 * half;
                float v0 = acc[mt][nt][2 * half], v1 = acc[mt][nt][2 * half + 1];
                if (EPI == 1) { v0 = fmaxf(v0, 0.f); v1 = fmaxf(v1, 0.f); }
                if (EPI >= 2) { v0 += b0; v1 += b1; }
                *(float2*)(C + row * N + col) = make_float2(v0, v1);
            }
        }
    }
}

// ---------------- conv1 fp16 GEMM: y1 = relu(col1h[M,32] @ W[32,64]) ----------------
#define HC1_SMEM ((64 * 40 + 128 * 40) * 2)
__global__ void __launch_bounds__(256) hconv1_k(const __half* __restrict__ col,
                                                const __half* __restrict__ wch,
                                                __half* __restrict__ y1) {
    extern __shared__ __half sm1[];
    __half* Ws = sm1;               // [64 n][40 k]
    __half* As = sm1 + 64 * 40;     // [128 m][40 k]

    const int bm = blockIdx.x * 128;
    const int tid = threadIdx.x, lane = tid & 31, w = tid >> 5;
    const int g4 = lane >> 2, c4 = lane & 3;
    const int lmrow = lane & 15, lmk = (lane >> 4) * 8;
    const int b2row = lane & 7, b2k = ((lane >> 3) & 1) * 8;
    const int r0 = w * 16;

    for (int idx = tid; idx < 64 * 4; idx += 256) {
        int n = idx >> 2, q = idx & 3;
        *(uint4*)&Ws[n * 40 + q * 8] = *(const uint4*)(wch + n * 32 + q * 8);
    }
    __syncthreads();

    const int ar = tid >> 1, apart = (tid & 1) * 16;
    {
        const uint4* src = (const uint4*)(col + (long)(bm + ar) * 32 + apart);
        uint4* dst = (uint4*)&As[ar * 40 + apart];
        dst[0] = src[0]; dst[1] = src[1];
    }
    __syncwarp();

    uint32_t afr[2][4];
#pragma unroll
    for (int ks = 0; ks < 2; ks++)
        ldsm_x4(afr[ks], smem_u32(&As[(r0 + lmrow) * 40 + ks * 16 + lmk]));

#pragma unroll
    for (int nt = 0; nt < 8; nt++) {
        float acc[4] = {0.f, 0.f, 0.f, 0.f};
#pragma unroll
        for (int ks = 0; ks < 2; ks++) {
            uint32_t bf[2];
            ldsm_x2(bf, smem_u32(&Ws[(nt * 8 + b2row) * 40 + ks * 16 + b2k]));
            mma_f16(acc, afr[ks], bf, acc);
        }
        int coln = nt * 8 + 2 * c4;
#pragma unroll
        for (int half = 0; half < 2; half++) {
            long row = bm + r0 + g4 + 8 * half;
            *(uint32_t*)(y1 + row * 64 + coln) =
                packh2(fmaxf(acc[2 * half], 0.f), fmaxf(acc[2 * half + 1], 0.f));
        }
    }
}

// ---------------- conv2 direct (fused im2col): y2 = relu(p1 (*) w), fp16 ----------------
#define HC2_SMEM (64 * 584 * 2 + 128 * 72 * 2)
__global__ void __launch_bounds__(256) hconv2_k(const __half* __restrict__ p1,
                                                const __half* __restrict__ wch,
                                                __half* __restrict__ y2) {
    extern __shared__ __half smc[];
    __half* Ws = smc;                 // [64 n][584 k]
    __half* As = smc + 64 * 584;      // [128 m][72]

    const int bm = blockIdx.x * 128;
    const int tid = threadIdx.x, lane = tid & 31, w = tid >> 5;
    const int g4 = lane >> 2, c4 = lane & 3;
    const int lmrow = lane & 15, lmk = (lane >> 4) * 8;
    const int b2row = lane & 7, b2k = ((lane >> 3) & 1) * 8;
    const int r0 = w * 16;

    for (int idx = tid; idx < 64 * 72; idx += 256) {
        int n = idx / 72, q = idx % 72;
        *(uint4*)&Ws[n * 584 + q * 8] = *(const uint4*)(wch + n * 576 + q * 8);
    }
    __syncthreads();

    float acc[8][4];
#pragma unroll
    for (int nt = 0; nt < 8; nt++)
#pragma unroll
        for (int i = 0; i < 4; i++) acc[nt][i] = 0.f;

    const int ar = tid >> 1, apart = (tid & 1) * 32;
    const int m = bm + ar;
    const int bidx = m / 720, rem = m % 720;
    const int oh = rem / 36, owp = rem % 36;

#pragma unroll
    for (int kc = 0; kc < 9; kc++) {
        int kh = kc / 3, kw = kc % 3;
        int ih = oh + kh - 1, iw = owp + kw - 1;
        uint4 v[4];
        if ((unsigned)ih < 20u && (unsigned)iw < 36u) {
            const uint4* src = (const uint4*)(p1 + (((long)(bidx * 20 + ih)) * 36 + iw) * 64 + apart);
            v[0] = src[0]; v[1] = src[1]; v[2] = src[2]; v[3] = src[3];
        } else {
            v[0] = make_uint4(0, 0, 0, 0); v[1] = v[0]; v[2] = v[0]; v[3] = v[0];
        }
        uint4* dst = (uint4*)&As[ar * 72 + apart];
        dst[0] = v[0]; dst[1] = v[1]; dst[2] = v[2]; dst[3] = v[3];
        __syncwarp();
        uint32_t afr[4][4];
#pragma unroll
        for (int ks = 0; ks < 4; ks++)
            ldsm_x4(afr[ks], smem_u32(&As[(r0 + lmrow) * 72 + ks * 16 + lmk]));
#pragma unroll
        for (int nt = 0; nt < 8; nt++) {
#pragma unroll
            for (int ks = 0; ks < 4; ks++) {
                uint32_t bf[2];
                ldsm_x2(bf, smem_u32(&Ws[(nt * 8 + b2row) * 584 + kc * 64 + ks * 16 + b2k]));
                mma_f16(acc[nt], afr[ks], bf, acc[nt]);
            }
        }
        __syncwarp();
    }

#pragma unroll
    for (int nt = 0; nt < 8; nt++) {
        int col = nt * 8 + 2 * c4;
#pragma unroll
        for (int half = 0; half < 2; half++) {
            long row = bm + r0 + g4 + 8 * half;
            *(uint32_t*)(y2 + row * 64 + col) =
                packh2(fmaxf(acc[nt][2 * half], 0.f), fmaxf(acc[nt][2 * half + 1], 0.f));
        }
    }
}

// ---------------- maxpool 3x3 s2 p1 on NHWC (+ optional pos-emb add) ----------------
template <typename Ti, typename To>
__global__ void maxpool_k(const Ti* __restrict__ in, To* __restrict__ out,
                          int Bn, int IH, int IW, int C, int OH, int OW,
                          const float* __restrict__ pos) {
    long idx = (long)blockIdx.x * blockDim.x + threadIdx.x;
    long total = (long)Bn * OH * OW * C;
    if (idx >= total) return;
    int c = (int)(idx % C);
    long r = idx / C;
    int ow = (int)(r % OW); r /= OW;
    int oh = (int)(r % OH);
    int b  = (int)(r / OH);
    float m = -1e30f;
#pragma unroll
    for (int kh = 0; kh < 3; kh++) {
        int ih = oh * 2 - 1 + kh;
        if (ih < 0 || ih >= IH) continue;
#pragma unroll
        for (int kw = 0; kw < 3; kw++) {
            int iw = ow * 2 - 1 + kw;
            if (iw < 0 || iw >= IW) continue;
            m = fmaxf(m, (float)in[(((long)b * IH + ih) * IW + iw) * C + c]);
        }
    }
    if (pos) m += pos[(oh * OW + ow) * C + c];
    out[idx] = (To)m;
}

// ---------------- LN1 -> fp16, one warp per token ----------------
__global__ void ln1h_k(const float* __restrict__ x, const float* __restrict__ g,
                       const float* __restrict__ bta, __half* __restrict__ o, int ntok) {
    int warp = (blockIdx.x * blockDim.x + threadIdx.x) >> 5;
    int lane = threadIdx.x & 31;
    if (warp >= ntok) return;
    float v0 = x[(long)warp * 64 + lane];
    float v1 = x[(long)warp * 64 + 32 + lane];
    float s = v0 + v1;
#pragma unroll
    for (int off = 16; off; off >>= 1) s += __shfl_xor_sync(0xffffffffu, s, off);
    float mean = s * (1.f / 64.f);
    float d0 = v0 - mean, d1 = v1 - mean;
    float q = d0 * d0 + d1 * d1;
#pragma unroll
    for (int off = 16; off; off >>= 1) q += __shfl_xor_sync(0xffffffffu, q, off);
    float rstd = rsqrtf(q * (1.f / 64.f) + 1e-5f);
    o[(long)warp * 64 + lane]      = __float2half(d0 * rstd * g[lane] + bta[lane]);
    o[(long)warp * 64 + 32 + lane] = __float2half(d1 * rstd * g[lane + 32] + bta[lane + 32]);
}

// ---------------- fully-fused attention: scores in registers, fp16 out ----------------
#define ATTNH_SMEM ((3 * 192 * 72 + 3 * 64 * 72) * 2)

__global__ void __launch_bounds__(384, 1) attn_fused_k(const __half* __restrict__ h16g,
                                                       const __half* __restrict__ qh,
                                                       __half* __restrict__ out) {
    extern __shared__ __half smh[];
    __half* H16 = smh;
    __half* K16 = smh + 192 * 72;
    __half* V16 = smh + 2 * 192 * 72;
    __half* W16 = smh + 3 * 192 * 72;

    int b = blockIdx.x / 12, h = blockIdx.x % 12;
    int tid = threadIdx.x, lane = tid & 31, w = tid >> 5;
    int g4 = lane >> 2, c4 = lane & 3;
    int lmrow = lane & 15, lmk = (lane >> 4) * 8;
    int b2row = lane & 7, b2k = ((lane >> 3) & 1) * 8;
    const int r0 = w * 16;

    // ---- stage W16 (vector copies) ----
    {
        const __half* qsrc = qh + (long)h * 12288;
        for (int idx = tid; idx < 192 * 8; idx += 384) {
            int row = idx >> 3, q = idx & 7;
            *(uint4*)&W16[row * 72 + q * 8] = *(const uint4*)(qsrc + row * 64 + q * 8);
        }
    }
    // ---- stage H16 from precomputed LN (vector copies) ----
    {
        const __half* hb = h16g + (long)b * 180 * 64;
        for (int idx = tid; idx < 180 * 8; idx += 384) {
            int row = idx >> 3, q = idx & 7;
            *(uint4*)&H16[row * 72 + q * 8] = *(const uint4*)(hb + row * 64 + q * 8);
        }
        for (int i = tid; i < 12 * 72; i += 384) H16[180 * 72 + i] = __float2half(0.f);
    }
    __syncthreads();

    uint32_t afr[4][4];
#pragma unroll
    for (int ks = 0; ks < 4; ks++)
        ldsm_x4(afr[ks], smem_u32(&H16[(r0 + lmrow) * 72 + ks * 16 + lmk]));

#pragma unroll
    for (int mat = 0; mat < 2; mat++) {
        const __half* Wm = W16 + mat * 64 * 72;
        __half* dst = mat ? V16 : K16;
#pragma unroll
        for (int nt = 0; nt < 8; nt++) {
            float acc[4] = {0.f, 0.f, 0.f, 0.f};
#pragma unroll
            for (int ks = 0; ks < 4; ks++) {
                uint32_t bf[2];
                ldsm_x2(bf, smem_u32(&Wm[(nt * 8 + b2row) * 72 + ks * 16 + b2k]));
                mma_f16(acc, afr[ks], bf, acc);
            }
            int col = nt * 8 + 2 * c4;
            *(uint32_t*)&dst[(r0 + g4) * 72 + col]     = packh2(acc[0], acc[1]);
            *(uint32_t*)&dst[(r0 + g4 + 8) * 72 + col] = packh2(acc[2], acc[3]);
        }
    }

    uint32_t afq[4][4];
    {
        const __half* Wm = W16 + 2 * 64 * 72;
        float qacc[8][4];
#pragma unroll
        for (int nt = 0; nt < 8; nt++) {
#pragma unroll
            for (int i = 0; i < 4; i++) qacc[nt][i] = 0.f;
#pragma unroll
            for (int ks = 0; ks < 4; ks++) {
                uint32_t bf[2];
                ldsm_x2(bf, smem_u32(&Wm[(nt * 8 + b2row) * 72 + ks * 16 + b2k]));
                mma_f16(qacc[nt], afr[ks], bf, qacc[nt]);
            }
        }
#pragma unroll
        for (int kt = 0; kt < 4; kt++) {
            afq[kt][0] = packh2(qacc[2 * kt][0],     qacc[2 * kt][1]);
            afq[kt][1] = packh2(qacc[2 * kt][2],     qacc[2 * kt][3]);
            afq[kt][2] = packh2(qacc[2 * kt + 1][0], qacc[2 * kt + 1][1]);
            afq[kt][3] = packh2(qacc[2 * kt + 1][2], qacc[2 * kt + 1][3]);
        }
    }
    __syncthreads();

    float S[24][4];
#pragma unroll
    for (int nt = 0; nt < 24; nt++) {
        float acc[4] = {0.f, 0.f, 0.f, 0.f};
#pragma unroll
        for (int ks = 0; ks < 4; ks++) {
            uint32_t bf[2];
            ldsm_x2(bf, smem_u32(&K16[(nt * 8 + b2row) * 72 + ks * 16 + b2k]));
            mma_f16(acc, afq[ks], bf, acc);
        }
#pragma unroll
        for (int i = 0; i < 4; i++) S[nt][i] = acc[i] * 0.125f;
    }

    {
        float mx0 = -1e30f, mx1 = -1e30f;
#pragma unroll
        for (int nt = 0; nt < 24; nt++) {
#pragma unroll
            for (int j = 0; j < 2; j++) {
                int col = nt * 8 + 2 * c4 + j;
                if (col < 180) {
                    mx0 = fmaxf(mx0, S[nt][j]);
                    mx1 = fmaxf(mx1, S[nt][2 + j]);
                }
            }
        }
        mx0 = fmaxf(mx0, __shfl_xor_sync(0xffffffffu, mx0, 1));
        mx0 = fmaxf(mx0, __shfl_xor_sync(0xffffffffu, mx0, 2));
        mx1 = fmaxf(mx1, __shfl_xor_sync(0xffffffffu, mx1, 1));
        mx1 = fmaxf(mx1, __shfl_xor_sync(0xffffffffu, mx1, 2));
        float sum0 = 0.f, sum1 = 0.f;
#pragma unroll
        for (int nt = 0; nt < 24; nt++) {
#pragma unroll
            for (int j = 0; j < 2; j++) {
                int col = nt * 8 + 2 * c4 + j;
                float e0 = (col < 180) ? __expf(S[nt][j] - mx0) : 0.f;
                float e1 = (col < 180) ? __expf(S[nt][2 + j] - mx1) : 0.f;
                S[nt][j] = e0; S[nt][2 + j] = e1;
                sum0 += e0; sum1 += e1;
            }
        }
        sum0 += __shfl_xor_sync(0xffffffffu, sum0, 1);
        sum0 += __shfl_xor_sync(0xffffffffu, sum0, 2);
        sum1 += __shfl_xor_sync(0xffffffffu, sum1, 1);
        sum1 += __shfl_xor_sync(0xffffffffu, sum1, 2);
        float inv0 = 1.f / sum0, inv1 = 1.f / sum1;
#pragma unroll
        for (int nt = 0; nt < 24; nt++) {
            S[nt][0] *= inv0; S[nt][1] *= inv0;
            S[nt][2] *= inv1; S[nt][3] *= inv1;
        }
    }

    uint32_t P[12][4];
#pragma unroll
    for (int kt = 0; kt < 12; kt++) {
        P[kt][0] = packh2(S[2 * kt][0],     S[2 * kt][1]);
        P[kt][1] = packh2(S[2 * kt][2],     S[2 * kt][3]);
        P[kt][2] = packh2(S[2 * kt + 1][0], S[2 * kt + 1][1]);
        P[kt][3] = packh2(S[2 * kt + 1][2], S[2 * kt + 1][3]);
    }

    {
        __half* outb = out + (long)b * 180 * 768 + h * 64;
#pragma unroll
        for (int nt = 0; nt < 8; nt++) {
            float acc[4] = {0.f, 0.f, 0.f, 0.f};
#pragma unroll
            for (int kt = 0; kt < 12; kt++) {
                uint32_t bv[2];
                ldsm_x2_t(bv, smem_u32(&V16[(kt * 16 + lmrow) * 72 + nt * 8]));
                mma_f16(acc, P[kt], bv, acc);
            }
            int row = r0 + g4;
            long col = nt * 8 + 2 * c4;
            if (row < 180)
                *(uint32_t*)(outb + (long)row * 768 + col) = packh2(acc[0], acc[1]);
            if (row + 8 < 180)
                *(uint32_t*)(outb + (long)(row + 8) * 768 + col) = packh2(acc[2], acc[3]);
        }
    }
}

// ---------------- fused tail: outproj + LN2 + MLP, 3 chunks/block ----------------
#define T_WS   0
#define T_ASHS 49664
#define T_W1S  58880
#define T_W2S  77312
#define TAIL_SMEM 188416

__global__ void __launch_bounds__(256) tail_fused_k(const __half* __restrict__ ao,
                                                    const __half* __restrict__ owh,
                                                    const float* __restrict__ ob,
                                                    const float* __restrict__ x,
                                                    const __half* __restrict__ w1h,
                                                    const float* __restrict__ b1,
                                                    const __half* __restrict__ w2h,
                                                    const float* __restrict__ b2,
                                                    const float* __restrict__ lng,
                                                    const float* __restrict__ lnb,
                                                    float* __restrict__ outx) {
    extern __shared__ __half smt[];
    __half* Ws  = smt + T_WS;
    __half* As  = smt + T_ASHS;   // also Hs
    __half* W1s = smt + T_W1S;
    __half* W2s = smt + T_W2S;

    const int tid = threadIdx.x, lane = tid & 31, w = tid >> 5;
    const int g4 = lane >> 2, c4 = lane & 3;
    const int lmrow = lane & 15, lmk = (lane >> 4) * 8;
    const int b2row = lane & 7, b2k = ((lane >> 3) & 1) * 8;
    const int r0 = w * 16;

    for (int idx = tid; idx < 64 * 96; idx += 256) {
        int n = idx / 96, q = idx % 96;
        *(uint4*)&Ws[n * 776 + q * 8] = *(const uint4*)(owh + n * 768 + q * 8);
    }
    for (int idx = tid; idx < 256 * 8; idx += 256) {
        int n = idx >> 3, q = idx & 7;
        *(uint4*)&W1s[n * 72 + q * 8] = *(const uint4*)(w1h + n * 64 + q * 8);
    }
    for (int idx = tid; idx < 64 * 32; idx += 256) {
        int n = idx >> 5, q = idx & 31;
        *(uint4*)&W2s[n * 264 + q * 8] = *(const uint4*)(w2h + n * 256 + q * 8);
    }
    __syncthreads();

    const int ar = tid >> 1, apart = (tid & 1) * 32;

    for (int c = 0; c < 3; c++) {
        const long bm = ((long)blockIdx.x * 3 + c) * 128;

        float acc[8][4];
#pragma unroll
        for (int nt = 0; nt < 8; nt++)
#pragma unroll
            for (int i = 0; i < 4; i++) acc[nt][i] = 0.f;

        for (int kc = 0; kc < 12; kc++) {
            {
                const uint4* src = (const uint4*)(ao + (bm + ar) * 768 + kc * 64 + apart);
                uint4* dst = (uint4*)&As[ar * 72 + apart];
                dst[0] = src[0]; dst[1] = src[1]; dst[2] = src[2]; dst[3] = src[3];
            }
            __syncwarp();
            uint32_t afr[4][4];
#pragma unroll
            for (int ks = 0; ks < 4; ks++)
                ldsm_x4(afr[ks], smem_u32(&As[(r0 + lmrow) * 72 + ks * 16 + lmk]));
#pragma unroll
            for (int nt = 0; nt < 8; nt++) {
#pragma unroll
                for (int ks = 0; ks < 4; ks++) {
                    uint32_t bf[2];
                    ldsm_x2(bf, smem_u32(&Ws[(nt * 8 + b2row) * 776 + kc * 64 + ks * 16 + b2k]));
                    mma_f16(acc[nt], afr[ks], bf, acc[nt]);
                }
            }
            __syncwarp();
        }

        float xres[8][4];
#pragma unroll
        for (int nt = 0; nt < 8; nt++) {
            int col = nt * 8 + 2 * c4;
            float b0 = ob[col], b1v = ob[col + 1];
#pragma unroll
            for (int half = 0; half < 2; half++) {
                long row = bm + r0 + g4 + 8 * half;
                float2 r = *(const float2*)(x + row * 64 + col);
                xres[nt][2 * half]     = acc[nt][2 * half] + b0 + r.x;
                xres[nt][2 * half + 1] = acc[nt][2 * half + 1] + b1v + r.y;
            }
        }
        {
            float s0 = 0.f, s1 = 0.f;
#pragma unroll
            for (int nt = 0; nt < 8; nt++) {
                s0 += xres[nt][0] + xres[nt][1];
                s1 += xres[nt][2] + xres[nt][3];
            }
            s0 += __shfl_xor_sync(0xffffffffu, s0, 1);
            s0 += __shfl_xor_sync(0xffffffffu, s0, 2);
            s1 += __shfl_xor_sync(0xffffffffu, s1, 1);
            s1 += __shfl_xor_sync(0xffffffffu, s1, 2);
            float m0 = s0 * (1.f / 64.f), m1 = s1 * (1.f / 64.f);
            float q0 = 0.f, q1 = 0.f;
#pragma unroll
            for (int nt = 0; nt < 8; nt++) {
                float d0 = xres[nt][0] - m0, d1 = xres[nt][1] - m0;
                float d2 = xres[nt][2] - m1, d3 = xres[nt][3] - m1;
                q0 += d0 * d0 + d1 * d1;
                q1 += d2 * d2 + d3 * d3;
            }
            q0 += __shfl_xor_sync(0xffffffffu, q0, 1);
            q0 += __shfl_xor_sync(0xffffffffu, q0, 2);
            q1 += __shfl_xor_sync(0xffffffffu, q1, 1);
            q1 += __shfl_xor_sync(0xffffffffu, q1, 2);
            float rs0 = rsqrtf(q0 * (1.f / 64.f) + 1e-5f);
            float rs1 = rsqrtf(q1 * (1.f / 64.f) + 1e-5f);
#pragma unroll
            for (int nt = 0; nt < 8; nt++) {
                int col = nt * 8 + 2 * c4;
                float g0 = lng[col], g1 = lng[col + 1];
                float be0 = lnb[col], be1 = lnb[col + 1];
                float h0 = (xres[nt][0] - m0) * rs0 * g0 + be0;
                float h1 = (xres[nt][1] - m0) * rs0 * g1 + be1;
                float h2 = (xres[nt][2] - m1) * rs1 * g0 + be0;
                float h3 = (xres[nt][3] - m1) * rs1 * g1 + be1;
                *(uint32_t*)&As[(r0 + g4) * 72 + col]     = packh2(h0, h1);
                *(uint32_t*)&As[(r0 + g4 + 8) * 72 + col] = packh2(h2, h3);
            }
        }
        __syncwarp();

        uint32_t afg[16][4];
        {
            uint32_t afr[4][4];
#pragma unroll
            for (int ks = 0; ks < 4; ks++)
                ldsm_x4(afr[ks], smem_u32(&As[(r0 + lmrow) * 72 + ks * 16 + lmk]));
#pragma unroll
            for (int kt = 0; kt < 16; kt++) {
                float d0[4] = {0.f, 0.f, 0.f, 0.f}, d1[4] = {0.f, 0.f, 0.f, 0.f};
#pragma unroll
                for (int ks = 0; ks < 4; ks++) {
                    uint32_t bf[2];
                    ldsm_x2(bf, smem_u32(&W1s[((2 * kt) * 8 + b2row) * 72 + ks * 16 + b2k]));
                    mma_f16(d0, afr[ks], bf, d0);
                    ldsm_x2(bf, smem_u32(&W1s[((2 * kt + 1) * 8 + b2row) * 72 + ks * 16 + b2k]));
                    mma_f16(d1, afr[ks], bf, d1);
                }
                int col0 = (2 * kt) * 8 + 2 * c4, col1 = (2 * kt + 1) * 8 + 2 * c4;
                float a0 = d0[0] + b1[col0],     a1 = d0[1] + b1[col0 + 1];
                float a2 = d0[2] + b1[col0],     a3 = d0[3] + b1[col0 + 1];
                float a4 = d1[0] + b1[col1],     a5 = d1[1] + b1[col1 + 1];
                float a6 = d1[2] + b1[col1],     a7 = d1[3] + b1[col1 + 1];
                a0 = 0.5f * a0 * (1.f + erff(a0 * 0.70710678118654752f));
                a1 = 0.5f * a1 * (1.f + erff(a1 * 0.70710678118654752f));
                a2 = 0.5f * a2 * (1.f + erff(a2 * 0.70710678118654752f));
                a3 = 0.5f * a3 * (1.f + erff(a3 * 0.70710678118654752f));
                a4 = 0.5f * a4 * (1.f + erff(a4 * 0.70710678118654752f));
                a5 = 0.5f * a5 * (1.f + erff(a5 * 0.70710678118654752f));
                a6 = 0.5f * a6 * (1.f + erff(a6 * 0.70710678118654752f));
                a7 = 0.5f * a7 * (1.f + erff(a7 * 0.70710678118654752f));
                afg[kt][0] = packh2(a0, a1);
                afg[kt][1] = packh2(a2, a3);
                afg[kt][2] = packh2(a4, a5);
                afg[kt][3] = packh2(a6, a7);
            }
        }

#pragma unroll
        for (int nt = 0; nt < 8; nt++) {
            float a2c[4] = {0.f, 0.f, 0.f, 0.f};
#pragma unroll
            for (int kt = 0; kt < 16; kt++) {
                uint32_t bf[2];
                ldsm_x2(bf, smem_u32(&W2s[(nt * 8 + b2row) * 264 + kt * 16 + b2k]));
                mma_f16(a2c, afg[kt], bf, a2c);
            }
            int col = nt * 8 + 2 * c4;
            float bb0 = b2[col], bb1 = b2[col + 1];
#pragma unroll
            for (int half = 0; half < 2; half++) {
                long row = bm + r0 + g4 + 8 * half;
                float v0 = a2c[2 * half] + bb0 + xres[nt][2 * half];
                float v1 = a2c[2 * half + 1] + bb1 + xres[nt][2 * half + 1];
                *(float2*)(outx + row * 64 + col) = make_float2(v0, v1);
            }
        }
        __syncwarp();
    }
}

// ---------------- primary caps: gather + squash ----------------
__global__ void caps_squash_k(const float* __restrict__ pc, float* __restrict__ caps) {
    int idx = blockIdx.x * blockDim.x + threadIdx.x;
    if (idx >= 256 * 1024) return;
    int i = idx & 1023, b = idx >> 10;
    int i32 = i >> 5, y = (i >> 3) & 3, xq = i & 7;
    const float* src = pc + (((long)b * 4 + y) * 8 + xq) * 256 + i32 * 8;
    float t[8];
    float l2 = 0.f;
#pragma unroll
    for (int e = 0; e < 8; e++) { t[e] = src[e]; l2 += t[e] * t[e]; }
    float sc = sqrtf(l2) / (1.f + l2);
#pragma unroll
    for (int e = 0; e < 8; e++) caps[(long)idx * 8 + e] = t[e] * sc;
}

// ---------------- capsule predictions u[b,i,:] ----------------
__global__ void caps_u_k(const float* __restrict__ caps, const float* __restrict__ cw,
                         float* __restrict__ u) {
    __shared__ float w_s[8 * 48];
    int i = blockIdx.x;
    for (int t = threadIdx.x; t < 384; t += 256) w_s[t] = cw[(long)i * 384 + t];
    __syncthreads();
    int b = threadIdx.x;
    float ce[8];
    const float* cp = caps + ((long)b * 1024 + i) * 8;
#pragma unroll
    for (int e = 0; e < 8; e++) ce[e] = cp[e];
    float* up = u + ((long)b * 1024 + i) * 48;
#pragma unroll 4
    for (int o = 0; o < 48; o++) {
        float s = 0.f;
#pragma unroll
        for (int e = 0; e < 8; e++) s = fmaf(ce[e], w_s[e * 48 + o], s);
        up[o] = s;
    }
}

// ---------------- dynamic routing, u staged in smem ----------------
#define ROUT_SMEM ((49152 + 3072 + 96) * 4)
__global__ void __launch_bounds__(256) routing_k(const float* __restrict__ u,
                                                 const float* __restrict__ br,
                                                 float* __restrict__ out) {
    extern __shared__ float smr[];
    float* us = smr;
    float* bb = smr + 49152;
    float* S  = bb + 3072;
    float* v  = S + 48;
    int b = blockIdx.x, tid = threadIdx.x, lane = tid & 31;
    const float* ub = u + (long)b * 1024 * 48;
    for (int i = tid; i < 49152; i += 256) us[i] = ub[i];
    for (int i = tid; i < 3072; i += 256) bb[i] = br[i];
    __syncthreads();

    for (int it = 0; it < 4; it++) {
        if (tid < 48) S[tid] = 0.f;
        __syncthreads();
        float acc[48];
#pragma unroll
        for (int o = 0; o < 48; o++) acc[o] = 0.f;
        for (int i = tid; i < 1024; i += 256) {
            float b0 = bb[i * 3], b1 = bb[i * 3 + 1], b2 = bb[i * 3 + 2];
            float m = fmaxf(b0, fmaxf(b1, b2));
            float e0 = expf(b0 - m), e1 = expf(b1 - m), e2 = expf(b2 - m);
            float inv = 1.f / (e0 + e1 + e2);
            float c[3] = {e0 * inv, e1 * inv, e2 * inv};
            const float* up = &us[i * 48];
#pragma unroll
            for (int j = 0; j < 3; j++)
#pragma unroll
                for (int o = 0; o < 16; o++)
                    acc[j * 16 + o] = fmaf(c[j], up[j * 16 + o], acc[j * 16 + o]);
        }
#pragma unroll
        for (int o = 0; o < 48; o++) {
            float s = acc[o];
#pragma unroll
            for (int d = 16; d; d >>= 1) s += __shfl_xor_sync(0xffffffffu, s, d);
            if (lane == 0) atomicAdd(&S[o], s);
        }
        __syncthreads();
        if (tid < 3) {
            float l2 = 0.f;
            for (int o = 0; o < 16; o++) { float t = S[tid * 16 + o]; l2 += t * t; }
            float sc = sqrtf(l2) / (1.f + l2);
            for (int o = 0; o < 16; o++) v[tid * 16 + o] = S[tid * 16 + o] * sc;
            if (it == 3) out[b * 3 + tid] = l2 / (1.f + l2);
        }
        __syncthreads();
        if (it < 3) {
            for (int i = tid; i < 1024; i += 256) {
                const float* up = &us[i * 48];
#pragma unroll
                for (int j = 0; j < 3; j++) {
                    float s = 0.f;
#pragma unroll
                    for (int o = 0; o < 16; o++) s = fmaf(up[j * 16 + o], v[j * 16 + o], s);
                    bb[i * 3 + j] += s;
                }
            }
            __syncthreads();
        }
    }
}

// ---------------- host ----------------
extern "C" void kernel_launch(void* const* d_in, const int* in_sizes, int n_in,
                              void* d_out, int out_size) {
    const float* x_in    = (const float*)d_in[0];
    const float* conv1_w = (const float*)d_in[1];
    const float* conv2_w = (const float*)d_in[2];
    const float* pos_emb = (const float*)d_in[3];
    const float* ln1_g   = (const float*)d_in[4];
    const float* ln1_b   = (const float*)d_in[5];
    const float* qkv_w   = (const float*)d_in[6];
    const float* out_w   = (const float*)d_in[7];
    const float* out_b   = (const float*)d_in[8];
    const float* ln2_g   = (const float*)d_in[9];
    const float* ln2_b   = (const float*)d_in[10];
    const float* ff1_w   = (const float*)d_in[11];
    const float* ff1_b   = (const float*)d_in[12];
    const float* ff2_w   = (const float*)d_in[13];
    const float* ff2_b   = (const float*)d_in[14];
    const float* pcaps_w = (const float*)d_in[15];
    const float* pcaps_b = (const float*)d_in[16];
    const float* caps_w  = (const float*)d_in[17];
    const float* b_route = (const float*)d_in[18];
    float* out = (float*)d_out;

    float *xb, *col3, *wtp, *pc, *caps, *u;
    __half *col1h, *y1h, *p1h, *y2h, *h16g, *aoh, *qh, *owh, *w1h, *w2h, *cw1h, *cw2h;
    cudaGetSymbolAddress((void**)&col1h, g_col1h);
    cudaGetSymbolAddress((void**)&y1h,  g_y1h);
    cudaGetSymbolAddress((void**)&p1h,  g_p1h);
    cudaGetSymbolAddress((void**)&y2h,  g_y2h);
    cudaGetSymbolAddress((void**)&xb,   g_x);
    cudaGetSymbolAddress((void**)&h16g, g_h16);
    cudaGetSymbolAddress((void**)&aoh,  g_aoh);
    cudaGetSymbolAddress((void**)&col3, g_col3);
    cudaGetSymbolAddress((void**)&wtp,  g_wtp);
    cudaGetSymbolAddress((void**)&pc,   g_pc);
    cudaGetSymbolAddress((void**)&caps, g_caps);
    cudaGetSymbolAddress((void**)&u,    g_u);
    cudaGetSymbolAddress((void**)&qh,   g_qh);
    cudaGetSymbolAddress((void**)&owh,  g_owh);
    cudaGetSymbolAddress((void**)&w1h,  g_w1h);
    cudaGetSymbolAddress((void**)&w2h,  g_w2h);
    cudaGetSymbolAddress((void**)&cw1h, g_cw1h);
    cudaGetSymbolAddress((void**)&cw2h, g_cw2h);

    cudaFuncSetAttribute(attn_fused_k, cudaFuncAttributeMaxDynamicSharedMemorySize, ATTNH_SMEM);
    cudaFuncSetAttribute(tail_fused_k, cudaFuncAttributeMaxDynamicSharedMemorySize, TAIL_SMEM);
    cudaFuncSetAttribute(hconv1_k,     cudaFuncAttributeMaxDynamicSharedMemorySize, HC1_SMEM);
    cudaFuncSetAttribute(hconv2_k,     cudaFuncAttributeMaxDynamicSharedMemorySize, HC2_SMEM);
    cudaFuncSetAttribute(routing_k,    cudaFuncAttributeMaxDynamicSharedMemorySize, ROUT_SMEM);

    // ---- weight prep (fp16, pre-transposed) ----
    prep_qkv_k<<<CDIV(12 * 12 * 3 * 4096, 256), 256>>>(qkv_w, qh);
    prep_ow_k <<<CDIV(12 * 64 * 768, 256), 256>>>(out_w, owh);
    prep_w1_k <<<CDIV(12 * 256 * 64, 256), 256>>>(ff1_w, w1h);
    prep_w2_k <<<CDIV(12 * 64 * 256, 256), 256>>>(ff2_w, w2h);
    prep_cw1_k<<<CDIV(64 * 32, 256), 256>>>(conv1_w, cw1h);
    prep_cw2_k<<<CDIV(64 * 576, 256), 256>>>(conv2_w, cw2h);

    // ---- ConvEmbed (all fp16 MMA) ----
    im2col1h_k<<<(int)CDIV((long)737280 * 32, 256), 256>>>(x_in, col1h);
    hconv1_k<<<737280 / 128, 256, HC1_SMEM>>>(col1h, cw1h, y1h);
    maxpool_k<__half, __half><<<(int)CDIV((long)256 * 20 * 36 * 64, 256), 256>>>(
        y1h, p1h, 256, 40, 72, 64, 20, 36, nullptr);
    hconv2_k<<<184320 / 128, 256, HC2_SMEM>>>(p1h, cw2h, y2h);
    maxpool_k<__half, float><<<(int)CDIV((long)256 * 10 * 18 * 64, 256), 256>>>(
        y2h, xb, 256, 20, 36, 64, 10, 18, pos_emb);

    // ---- Transformer: 12 shared layers applied twice ----
    const int M = 46080;
    for (int pass = 0; pass < 2; pass++) {
        for (int l = 0; l < 12; l++) {
            ln1h_k<<<M / 8, 256>>>(xb, ln1_g + l * 64, ln1_b + l * 64, h16g, M);
            attn_fused_k<<<256 * 12, 384, ATTNH_SMEM>>>(h16g, qh + (long)l * 147456, aoh);
            tail_fused_k<<<120, 256, TAIL_SMEM>>>(aoh, owh + (long)l * 49152, out_b + l * 64,
                                                  xb, w1h + (long)l * 16384, ff1_b + l * 256,
                                                  w2h + (long)l * 16384, ff2_b + l * 64,
                                                  ln2_g + l * 64, ln2_b + l * 64, xb);
        }
    }

    // ---- PrimaryCaps + routing ----
    im2col3_k<<<(int)CDIV((long)8192 * 576, 256), 256>>>(xb, col3);
    wtrans_hwc<<<CDIV(256 * 576, 256), 256>>>(pcaps_w, wtp, 256, 64);
    tgemm_k<2><<<dim3(256 / 64, 8192 / 128), 256>>>(col3, wtp, pcaps_b, pc, 8192, 256, 576);
    caps_squash_k<<<CDIV(256 * 1024, 256), 256>>>(pc, caps);
    caps_u_k<<<1024, 256>>>(caps, caps_w, u);
    routing_k<<<256, 256, ROUT_SMEM>>>(u, b_route, out);
}